// round 2
// baseline (speedup 1.0000x reference)
#include <cuda_runtime.h>
#include <cstdint>

#define BB 2
#define SS 2048
#define EE 768
#define HH 12
#define DD 64
#define FFF 3072
#define MM (BB*SS)          // 4096 rows
#define BH (BB*HH)          // 24
#define NROWS (BH*SS)       // 49152 attention rows
#define KTILES (SS/128)     // 16

// ---------------- scratch (device globals; no allocation) ----------------
__device__ float g_q  [MM*EE];
__device__ float g_k  [MM*EE];
__device__ float g_v  [MM*EE];
__device__ float g_ctx[MM*EE];
__device__ float g_h  [MM*EE];
__device__ float g_ff1[(size_t)MM*FFF];
__device__ float g_part[(size_t)NROWS*KTILES];
__device__ float g_inv [NROWS];

// ---------------- helpers -------------------------------------------------
__device__ __forceinline__ uint32_t f32_to_tf32(float x) {
    uint32_t r;
    asm("cvt.rna.tf32.f32 %0, %1;" : "=r"(r) : "f"(x));
    return r;
}

__device__ __forceinline__ void mma_tf32(float* d, const uint32_t* a, const uint32_t* b) {
    asm volatile(
        "mma.sync.aligned.m16n8k8.row.col.f32.tf32.tf32.f32 "
        "{%0,%1,%2,%3}, {%4,%5,%6,%7}, {%8,%9}, {%0,%1,%2,%3};\n"
        : "+f"(d[0]), "+f"(d[1]), "+f"(d[2]), "+f"(d[3])
        : "r"(a[0]), "r"(a[1]), "r"(a[2]), "r"(a[3]), "r"(b[0]), "r"(b[1]));
}

// ---------------- tf32 3-split GEMM: C = A[MxK] @ B[KxN] + bias ----------
// 128x128 block tile, BK=16, 256 threads (8 warps, 2x4), warp tile 64x32.
template<bool RELU>
__global__ __launch_bounds__(256) void sgemm_tf32_kernel(
    const float* __restrict__ A, const float* __restrict__ B,
    const float* __restrict__ bias, float* __restrict__ C,
    int M, int N, int K)
{
    __shared__ float Ahi[16][136];   // [k][m]
    __shared__ float Alo[16][136];
    __shared__ float Bhi[16][136];   // [k][n]
    __shared__ float Blo[16][136];

    const int t = threadIdx.x;
    const int m0 = blockIdx.y * 128;
    const int n0 = blockIdx.x * 128;
    const int warp = t >> 5;
    const int lane = t & 31;
    const int wm = warp >> 2;        // 0..1
    const int wn = warp & 3;         // 0..3
    const int g = lane >> 2;         // 0..7
    const int qd = lane & 3;         // 0..3

    float acc[4][4][4];
#pragma unroll
    for (int i = 0; i < 4; i++)
#pragma unroll
        for (int j = 0; j < 4; j++)
#pragma unroll
            for (int u = 0; u < 4; u++) acc[i][j][u] = 0.f;

    for (int kt = 0; kt < K; kt += 16) {
        // load + convert to tf32 hi/lo
#pragma unroll
        for (int i = 0; i < 2; i++) {
            int idx = t + i * 256;                 // 512 float4s each matrix
            int row = idx >> 2, c4 = idx & 3;      // A: 128 rows x 4 float4
            float4 av = *(const float4*)&A[(size_t)(m0 + row) * K + kt + c4 * 4];
            float avs[4] = {av.x, av.y, av.z, av.w};
#pragma unroll
            for (int u = 0; u < 4; u++) {
                float hif = __uint_as_float(f32_to_tf32(avs[u]));
                float lof = __uint_as_float(f32_to_tf32(avs[u] - hif));
                Ahi[c4 * 4 + u][row] = hif;
                Alo[c4 * 4 + u][row] = lof;
            }
            int kr = idx >> 5, n4 = idx & 31;      // B: 16 rows x 32 float4
            float4 bv = *(const float4*)&B[(size_t)(kt + kr) * N + n0 + n4 * 4];
            float bvs[4] = {bv.x, bv.y, bv.z, bv.w};
#pragma unroll
            for (int u = 0; u < 4; u++) {
                float hif = __uint_as_float(f32_to_tf32(bvs[u]));
                float lof = __uint_as_float(f32_to_tf32(bvs[u] - hif));
                Bhi[kr][n4 * 4 + u] = hif;
                Blo[kr][n4 * 4 + u] = lof;
            }
        }
        __syncthreads();

#pragma unroll
        for (int s = 0; s < 2; s++) {
            const int kc = s * 8;
            uint32_t afh[4][4], afl[4][4], bfh[4][2], bfl[4][2];
#pragma unroll
            for (int i = 0; i < 4; i++) {
                int mr = wm * 64 + i * 16 + g;
                afh[i][0] = __float_as_uint(Ahi[kc + qd    ][mr    ]);
                afh[i][1] = __float_as_uint(Ahi[kc + qd    ][mr + 8]);
                afh[i][2] = __float_as_uint(Ahi[kc + qd + 4][mr    ]);
                afh[i][3] = __float_as_uint(Ahi[kc + qd + 4][mr + 8]);
                afl[i][0] = __float_as_uint(Alo[kc + qd    ][mr    ]);
                afl[i][1] = __float_as_uint(Alo[kc + qd    ][mr + 8]);
                afl[i][2] = __float_as_uint(Alo[kc + qd + 4][mr    ]);
                afl[i][3] = __float_as_uint(Alo[kc + qd + 4][mr + 8]);
            }
#pragma unroll
            for (int j = 0; j < 4; j++) {
                int nc = wn * 32 + j * 8 + g;
                bfh[j][0] = __float_as_uint(Bhi[kc + qd    ][nc]);
                bfh[j][1] = __float_as_uint(Bhi[kc + qd + 4][nc]);
                bfl[j][0] = __float_as_uint(Blo[kc + qd    ][nc]);
                bfl[j][1] = __float_as_uint(Blo[kc + qd + 4][nc]);
            }
#pragma unroll
            for (int i = 0; i < 4; i++)
#pragma unroll
                for (int j = 0; j < 4; j++) {
                    mma_tf32(acc[i][j], afh[i], bfh[j]);
                    mma_tf32(acc[i][j], afh[i], bfl[j]);
                    mma_tf32(acc[i][j], afl[i], bfh[j]);
                }
        }
        __syncthreads();
    }

    // epilogue
#pragma unroll
    for (int i = 0; i < 4; i++) {
        int r0 = m0 + wm * 64 + i * 16 + g;
#pragma unroll
        for (int j = 0; j < 4; j++) {
            int c0 = n0 + wn * 32 + j * 8 + qd * 2;
            float bx = __ldg(&bias[c0]);
            float by = __ldg(&bias[c0 + 1]);
            float v0 = acc[i][j][0] + bx, v1 = acc[i][j][1] + by;
            float v2 = acc[i][j][2] + bx, v3 = acc[i][j][3] + by;
            if (RELU) {
                v0 = fmaxf(v0, 0.f); v1 = fmaxf(v1, 0.f);
                v2 = fmaxf(v2, 0.f); v3 = fmaxf(v3, 0.f);
            }
            float2 o01 = {v0, v1};
            float2 o23 = {v2, v3};
            *(float2*)&C[(size_t)r0 * N + c0]       = o01;
            *(float2*)&C[(size_t)(r0 + 8) * N + c0] = o23;
        }
    }
}

// ---------------- scores+exp: P = exp(QK^T/8 - |i-j|), partial row sums ---
// grid (S/128 ktiles, S/128 qtiles, B*H), 256 threads, 128x128 tile,
// D=64 chunked by 32, 8x8 per-thread microtile.
__global__ __launch_bounds__(256) void scores_kernel(
    const float* __restrict__ q, const float* __restrict__ k,
    float* __restrict__ P, float* __restrict__ partials)
{
    __shared__ float Qs[32][136];   // [d][qrow]
    __shared__ float Ks[32][136];   // [d][krow]
    __shared__ float red[128][17];

    const int bh = blockIdx.z;
    const int b  = bh / HH, h = bh % HH;
    const int q0 = blockIdx.y * 128, k0 = blockIdx.x * 128;
    const int t  = threadIdx.x;
    const int tx = t & 15, ty = t >> 4;

    float acc[8][8];
#pragma unroll
    for (int i = 0; i < 8; i++)
#pragma unroll
        for (int j = 0; j < 8; j++) acc[i][j] = 0.f;

#pragma unroll
    for (int kd = 0; kd < 64; kd += 32) {
#pragma unroll
        for (int i = 0; i < 4; i++) {
            int idx = t + i * 256;             // 1024 float4s: 128 rows x 8 c4
            int row = idx >> 3, c4 = idx & 7;
            size_t qo = ((size_t)(b * SS + q0 + row) * HH + h) * DD + kd + c4 * 4;
            float4 qv = *(const float4*)&q[qo];
            Qs[c4 * 4 + 0][row] = qv.x; Qs[c4 * 4 + 1][row] = qv.y;
            Qs[c4 * 4 + 2][row] = qv.z; Qs[c4 * 4 + 3][row] = qv.w;
            size_t ko = ((size_t)(b * SS + k0 + row) * HH + h) * DD + kd + c4 * 4;
            float4 kv = *(const float4*)&k[ko];
            Ks[c4 * 4 + 0][row] = kv.x; Ks[c4 * 4 + 1][row] = kv.y;
            Ks[c4 * 4 + 2][row] = kv.z; Ks[c4 * 4 + 3][row] = kv.w;
        }
        __syncthreads();

#pragma unroll
        for (int kk = 0; kk < 32; kk++) {
            float4 a0 = *(float4*)&Qs[kk][ty * 8];
            float4 a1 = *(float4*)&Qs[kk][ty * 8 + 4];
            float4 b0 = *(float4*)&Ks[kk][tx * 8];
            float4 b1 = *(float4*)&Ks[kk][tx * 8 + 4];
            float a[8] = {a0.x, a0.y, a0.z, a0.w, a1.x, a1.y, a1.z, a1.w};
            float c[8] = {b0.x, b0.y, b0.z, b0.w, b1.x, b1.y, b1.z, b1.w};
#pragma unroll
            for (int i = 0; i < 8; i++)
#pragma unroll
                for (int j = 0; j < 8; j++)
                    acc[i][j] = fmaf(a[i], c[j], acc[i][j]);
        }
        __syncthreads();
    }

    // exp (no max-sub: scores bounded ~|3|; softmax shift-invariant) + sums
#pragma unroll
    for (int i = 0; i < 8; i++) {
        int qi = q0 + ty * 8 + i;
        float rowsum = 0.f;
#pragma unroll
        for (int j4 = 0; j4 < 2; j4++) {
            int kj = k0 + tx * 8 + j4 * 4;
            float4 o;
            o.x = __expf(acc[i][j4 * 4 + 0] * 0.125f - fabsf((float)(qi - (kj + 0))));
            o.y = __expf(acc[i][j4 * 4 + 1] * 0.125f - fabsf((float)(qi - (kj + 1))));
            o.z = __expf(acc[i][j4 * 4 + 2] * 0.125f - fabsf((float)(qi - (kj + 2))));
            o.w = __expf(acc[i][j4 * 4 + 3] * 0.125f - fabsf((float)(qi - (kj + 3))));
            rowsum += (o.x + o.y) + (o.z + o.w);
            *(float4*)&P[((size_t)bh * SS + qi) * SS + kj] = o;
        }
        red[ty * 8 + i][tx] = rowsum;
    }
    __syncthreads();
    if (t < 128) {
        float s = 0.f;
#pragma unroll
        for (int x = 0; x < 16; x++) s += red[t][x];
        partials[((size_t)bh * SS + q0 + t) * KTILES + blockIdx.x] = s;
    }
}

// ---------------- reduce partial row sums -> 1/sum -------------------------
__global__ __launch_bounds__(256) void rowsum_kernel(
    const float* __restrict__ partials, float* __restrict__ inv)
{
    int r = blockIdx.x * 256 + threadIdx.x;
    float s = 0.f;
#pragma unroll
    for (int i = 0; i < KTILES; i++) s += partials[(size_t)r * KTILES + i];
    inv[r] = 1.0f / s;
}

// ---------------- ctx = Pn @ V ; also write normalized P back in place ----
__global__ __launch_bounds__(256) void ctx_kernel(
    float* __restrict__ P, const float* __restrict__ v,
    const float* __restrict__ inv, float* __restrict__ ctx)
{
    __shared__ float Ps[128][33];
    __shared__ float Vs[32][64];
    __shared__ float invs[128];

    const int bh = blockIdx.y;
    const int b  = bh / HH, h = bh % HH;
    const int q0 = blockIdx.x * 128;
    const int t  = threadIdx.x;
    const int tx = t & 15, ty = t >> 4;
    float* Pb = P + (size_t)bh * SS * SS;

    if (t < 128) invs[t] = inv[(size_t)bh * SS + q0 + t];
    __syncthreads();

    float acc[8][4];
#pragma unroll
    for (int i = 0; i < 8; i++)
#pragma unroll
        for (int j = 0; j < 4; j++) acc[i][j] = 0.f;

    for (int kt = 0; kt < SS; kt += 32) {
#pragma unroll
        for (int i = 0; i < 4; i++) {
            int idx = t + i * 256;               // 1024 float4s = 128x32
            int row = idx >> 3, c4 = idx & 7;
            size_t off = (size_t)(q0 + row) * SS + kt + c4 * 4;
            float4 pv = *(const float4*)&Pb[off];
            float iv = invs[row];
            pv.x *= iv; pv.y *= iv; pv.z *= iv; pv.w *= iv;
            *(float4*)&Pb[off] = pv;             // normalized attn_map out
            Ps[row][c4 * 4 + 0] = pv.x; Ps[row][c4 * 4 + 1] = pv.y;
            Ps[row][c4 * 4 + 2] = pv.z; Ps[row][c4 * 4 + 3] = pv.w;
        }
#pragma unroll
        for (int i = 0; i < 2; i++) {
            int idx = t + i * 256;               // 512 float4s = 32x64
            int kr = idx >> 4, c4 = idx & 15;
            *(float4*)&Vs[kr][c4 * 4] =
                *(const float4*)&v[((size_t)(b * SS + kt + kr) * HH + h) * DD + c4 * 4];
        }
        __syncthreads();

#pragma unroll
        for (int kk = 0; kk < 32; kk++) {
            float4 bv = *(float4*)&Vs[kk][tx * 4];
#pragma unroll
            for (int i = 0; i < 8; i++) {
                float a = Ps[ty * 8 + i][kk];
                acc[i][0] = fmaf(a, bv.x, acc[i][0]);
                acc[i][1] = fmaf(a, bv.y, acc[i][1]);
                acc[i][2] = fmaf(a, bv.z, acc[i][2]);
                acc[i][3] = fmaf(a, bv.w, acc[i][3]);
            }
        }
        __syncthreads();
    }

#pragma unroll
    for (int i = 0; i < 8; i++) {
        float4 o = {acc[i][0], acc[i][1], acc[i][2], acc[i][3]};
        *(float4*)&ctx[((size_t)(b * SS + q0 + ty * 8 + i) * HH + h) * DD + tx * 4] = o;
    }
}

// ---------------- out = LayerNorm(A + B) * g + be --------------------------
__global__ __launch_bounds__(256) void add_ln_kernel(
    const float* __restrict__ A, const float* __restrict__ Bi,
    const float* __restrict__ g, const float* __restrict__ be,
    float* __restrict__ out)
{
    __shared__ float rs[256];
    __shared__ float rs2[256];
    const size_t off = (size_t)blockIdx.x * EE;
    const int t = threadIdx.x;

    float x[3];
    float s = 0.f, s2 = 0.f;
#pragma unroll
    for (int i = 0; i < 3; i++) {
        int c = t + i * 256;
        x[i] = A[off + c] + Bi[off + c];
        s += x[i]; s2 += x[i] * x[i];
    }
    rs[t] = s; rs2[t] = s2; __syncthreads();
    for (int st = 128; st > 0; st >>= 1) {
        if (t < st) { rs[t] += rs[t + st]; rs2[t] += rs2[t + st]; }
        __syncthreads();
    }
    const float mu  = rs[0] * (1.0f / EE);
    const float var = rs2[0] * (1.0f / EE) - mu * mu;
    const float r   = rsqrtf(var + 1e-5f);
#pragma unroll
    for (int i = 0; i < 3; i++) {
        int c = t + i * 256;
        out[off + c] = (x[i] - mu) * r * g[c] + be[c];
    }
}

// ---------------- launch --------------------------------------------------
extern "C" void kernel_launch(void* const* d_in, const int* in_sizes, int n_in,
                              void* d_out, int out_size)
{
    const float* x  = (const float*)d_in[0];
    const float* Wq = (const float*)d_in[1];
    const float* bq = (const float*)d_in[2];
    const float* Wk = (const float*)d_in[3];
    const float* bk = (const float*)d_in[4];
    const float* Wv = (const float*)d_in[5];
    const float* bv = (const float*)d_in[6];
    const float* Wo = (const float*)d_in[7];
    const float* bo = (const float*)d_in[8];
    const float* W1 = (const float*)d_in[9];
    const float* b1 = (const float*)d_in[10];
    const float* W2 = (const float*)d_in[11];
    const float* b2 = (const float*)d_in[12];
    const float* g1 = (const float*)d_in[13];
    const float* be1= (const float*)d_in[14];
    const float* g2 = (const float*)d_in[15];
    const float* be2= (const float*)d_in[16];

    float* out  = (float*)d_out;
    float* attn = out + (size_t)BB * SS * EE;   // [B,H,S,S] region of d_out

    float *q, *k, *v, *ctxp, *h, *ff1, *part, *inv;
    cudaGetSymbolAddress((void**)&q,    g_q);
    cudaGetSymbolAddress((void**)&k,    g_k);
    cudaGetSymbolAddress((void**)&v,    g_v);
    cudaGetSymbolAddress((void**)&ctxp, g_ctx);
    cudaGetSymbolAddress((void**)&h,    g_h);
    cudaGetSymbolAddress((void**)&ff1,  g_ff1);
    cudaGetSymbolAddress((void**)&part, g_part);
    cudaGetSymbolAddress((void**)&inv,  g_inv);

    dim3 gE (EE  / 128, MM / 128);   // (6, 32)
    dim3 gFF(FFF / 128, MM / 128);   // (24, 32)

    // QKV projections (tf32 3-split tensor GEMM)
    sgemm_tf32_kernel<false><<<gE, 256>>>(x, Wq, bq, q, MM, EE, EE);
    sgemm_tf32_kernel<false><<<gE, 256>>>(x, Wk, bk, k, MM, EE, EE);
    sgemm_tf32_kernel<false><<<gE, 256>>>(x, Wv, bv, v, MM, EE, EE);

    // attention: scores+exp -> rowsum -> ctx (normalizes + writes attn_map)
    scores_kernel<<<dim3(SS / 128, SS / 128, BH), 256>>>(q, k, attn, part);
    rowsum_kernel<<<NROWS / 256, 256>>>(part, inv);
    ctx_kernel   <<<dim3(SS / 128, BH), 256>>>(attn, v, inv, ctxp);

    // output projection (reuse q as attn_out) + residual LN
    sgemm_tf32_kernel<false><<<gE, 256>>>(ctxp, Wo, bo, q, MM, EE, EE);
    add_ln_kernel<<<MM, 256>>>(x, q, g1, be1, h);

    // FFN (reuse k as ff2) + residual LN -> final out
    sgemm_tf32_kernel<true ><<<gFF, 256>>>(h, W1, b1, ff1, MM, FFF, EE);
    sgemm_tf32_kernel<false><<<gE, 256>>>(ff1, W2, b2, k, MM, EE, FFF);
    add_ln_kernel<<<MM, 256>>>(h, k, g2, be2, out);
}

// round 4
// speedup vs baseline: 1.5710x; 1.5710x over previous
#include <cuda_runtime.h>
#include <cuda_bf16.h>
#include <cstdint>

#define BB 2
#define SS 2048
#define EE 768
#define HH 12
#define DD 64
#define FFF 3072
#define MM (BB*SS)          // 4096
#define BH (BB*HH)          // 24
#define NROWS (BH*SS)       // 49152
#define KTILES (SS/128)     // 16

// ---------------- scratch (device globals; no allocation) ----------------
__device__ float g_q  [MM*EE];
__device__ float g_k  [MM*EE];
__device__ float g_v  [MM*EE];
__device__ float g_ctx[MM*EE];
__device__ float g_h  [MM*EE];
__device__ float g_ff1[(size_t)MM*FFF];
__device__ float g_part[(size_t)NROWS*KTILES];
__device__ float g_inv [NROWS];
__device__ __nv_bfloat16 g_wqt_h[EE*EE],  g_wqt_l[EE*EE];
__device__ __nv_bfloat16 g_wkt_h[EE*EE],  g_wkt_l[EE*EE];
__device__ __nv_bfloat16 g_wvt_h[EE*EE],  g_wvt_l[EE*EE];
__device__ __nv_bfloat16 g_wot_h[EE*EE],  g_wot_l[EE*EE];
__device__ __nv_bfloat16 g_w1t_h[EE*FFF], g_w1t_l[EE*FFF];
__device__ __nv_bfloat16 g_w2t_h[EE*FFF], g_w2t_l[EE*FFF];

// ---------------- helpers ---------------------------------------------------
__device__ __forceinline__ uint32_t smem_u32(const void* p) {
    uint32_t a;
    asm("{ .reg .u64 t; cvta.to.shared.u64 t, %1; cvt.u32.u64 %0, t; }"
        : "=r"(a) : "l"(p));
    return a;
}
__device__ __forceinline__ void ldmx4(uint32_t* r, uint32_t addr) {
    asm volatile("ldmatrix.sync.aligned.m8n8.x4.shared.b16 {%0,%1,%2,%3}, [%4];"
        : "=r"(r[0]), "=r"(r[1]), "=r"(r[2]), "=r"(r[3]) : "r"(addr));
}
__device__ __forceinline__ void ldmx2(uint32_t* r, uint32_t addr) {
    asm volatile("ldmatrix.sync.aligned.m8n8.x2.shared.b16 {%0,%1}, [%2];"
        : "=r"(r[0]), "=r"(r[1]) : "r"(addr));
}
__device__ __forceinline__ void mma_bf16(float* d, const uint32_t* a, const uint32_t* b) {
    asm volatile("mma.sync.aligned.m16n8k16.row.col.f32.bf16.bf16.f32 "
        "{%0,%1,%2,%3}, {%4,%5,%6,%7}, {%8,%9}, {%0,%1,%2,%3};"
        : "+f"(d[0]), "+f"(d[1]), "+f"(d[2]), "+f"(d[3])
        : "r"(a[0]), "r"(a[1]), "r"(a[2]), "r"(a[3]), "r"(b[0]), "r"(b[1]));
}
__device__ __forceinline__ void split2(float x, float y, uint32_t& hi, uint32_t& lo) {
    __nv_bfloat16 hx = __float2bfloat16_rn(x);
    __nv_bfloat16 hy = __float2bfloat16_rn(y);
    __nv_bfloat16 lx = __float2bfloat16_rn(x - __bfloat162float(hx));
    __nv_bfloat16 ly = __float2bfloat16_rn(y - __bfloat162float(hy));
    hi = ((uint32_t)__bfloat16_as_ushort(hy) << 16) | __bfloat16_as_ushort(hx);
    lo = ((uint32_t)__bfloat16_as_ushort(ly) << 16) | __bfloat16_as_ushort(lx);
}

// ---------------- weight transpose+split: W[K][N] -> Th/Tl[N][K] ----------
__global__ __launch_bounds__(256) void wtrans_kernel(
    const float* __restrict__ W, __nv_bfloat16* __restrict__ Th,
    __nv_bfloat16* __restrict__ Tl, int K, int N)
{
    __shared__ float tile[32][33];
    const int n0 = blockIdx.x * 32, k0 = blockIdx.y * 32;
    const int tx = threadIdx.x & 31, ty = threadIdx.x >> 5;   // 32 x 8
#pragma unroll
    for (int i = 0; i < 32; i += 8)
        tile[ty + i][tx] = W[(size_t)(k0 + ty + i) * N + n0 + tx];
    __syncthreads();
#pragma unroll
    for (int i = 0; i < 32; i += 8) {
        float x = tile[tx][ty + i];
        __nv_bfloat16 h = __float2bfloat16_rn(x);
        __nv_bfloat16 l = __float2bfloat16_rn(x - __bfloat162float(h));
        size_t o = (size_t)(n0 + ty + i) * K + k0 + tx;
        Th[o] = h; Tl[o] = l;
    }
}

// ---------------- bf16 3-split tensor GEMM: C = A @ Wt^T + bias -----------
// A fp32 [M][K] row-major; Wt hi/lo bf16 [N][K]. Tile 128x128, BK=32,
// 256 threads = 8 warps (2m x 4n), warp tile 64x32.
// smem (bytes): Ah[128][40]b16 @0, Al @10240, Bh @20480, Bl @30720 = 40960.
// 80B row stride => all ldmatrix 8-row phases hit distinct 16B banks.
template<bool RELU>
__global__ __launch_bounds__(256) void gemm_mma_kernel(
    const float* __restrict__ A,
    const __nv_bfloat16* __restrict__ Bth, const __nv_bfloat16* __restrict__ Btl,
    const float* __restrict__ bias, float* __restrict__ C, int N, int K)
{
    extern __shared__ char sm[];
    const int t = threadIdx.x, lane = t & 31, warp = t >> 5;
    const int wm = warp >> 2, wn = warp & 3;
    const int m0 = blockIdx.y * 128, n0 = blockIdx.x * 128;
    const uint32_t sb = smem_u32(sm);

    float acc[4][4][4];
#pragma unroll
    for (int i = 0; i < 4; i++)
#pragma unroll
        for (int j = 0; j < 4; j++)
#pragma unroll
            for (int u = 0; u < 4; u++) acc[i][j][u] = 0.f;

    // register staging for global->smem
    float4 areg[4];
    uint4  bh_reg[2], bl_reg[2];
    const int ar = t >> 3, ac4 = t & 7;    // A rows ar, ar+32, ar+64, ar+96
    const int br = t >> 2, bc8 = t & 3;    // B rows br, br+64

    const int nch = K / 32;

    // prologue loads (chunk 0)
#pragma unroll
    for (int i = 0; i < 4; i++)
        areg[i] = *(const float4*)&A[(size_t)(m0 + ar + i * 32) * K + ac4 * 4];
#pragma unroll
    for (int i = 0; i < 2; i++) {
        size_t o = (size_t)(n0 + br + i * 64) * K + bc8 * 8;
        bh_reg[i] = *(const uint4*)&Bth[o];
        bl_reg[i] = *(const uint4*)&Btl[o];
    }

    // ldmatrix base addresses
    const uint32_t aAddr = sb + (uint32_t)(wm * 64 + (lane & 15)) * 80
                              + (uint32_t)(lane >> 4) * 16;
    const uint32_t bAddr = sb + 20480
                              + (uint32_t)(wn * 32 + (lane & 7)) * 80
                              + (uint32_t)((lane >> 3) & 1) * 16;

    for (int ch = 0; ch < nch; ch++) {
        // store staged regs -> smem (convert A to bf16 hi/lo)
#pragma unroll
        for (int i = 0; i < 4; i++) {
            uint32_t h0, l0, h1, l1;
            split2(areg[i].x, areg[i].y, h0, l0);
            split2(areg[i].z, areg[i].w, h1, l1);
            uint32_t off = (uint32_t)(ar + i * 32) * 80 + (uint32_t)ac4 * 8;
            *(uint2*)(sm + off)         = make_uint2(h0, h1);
            *(uint2*)(sm + 10240 + off) = make_uint2(l0, l1);
        }
#pragma unroll
        for (int i = 0; i < 2; i++) {
            uint32_t off = (uint32_t)(br + i * 64) * 80 + (uint32_t)bc8 * 16;
            *(uint4*)(sm + 20480 + off) = bh_reg[i];
            *(uint4*)(sm + 30720 + off) = bl_reg[i];
        }
        __syncthreads();

        // issue next chunk's global loads (overlap with MMAs below)
        if (ch + 1 < nch) {
            const int kof = (ch + 1) * 32;
#pragma unroll
            for (int i = 0; i < 4; i++)
                areg[i] = *(const float4*)&A[(size_t)(m0 + ar + i * 32) * K + kof + ac4 * 4];
#pragma unroll
            for (int i = 0; i < 2; i++) {
                size_t o = (size_t)(n0 + br + i * 64) * K + kof + bc8 * 8;
                bh_reg[i] = *(const uint4*)&Bth[o];
                bl_reg[i] = *(const uint4*)&Btl[o];
            }
        }

        // compute: 2 k-steps of k16
#pragma unroll
        for (int kk = 0; kk < 2; kk++) {
            uint32_t ah[4][4], al[4][4], bh[4][2], bl[4][2];
#pragma unroll
            for (int i = 0; i < 4; i++) {
                ldmx4(ah[i], aAddr + (uint32_t)i * 1280 + (uint32_t)kk * 32);
                ldmx4(al[i], aAddr + 10240 + (uint32_t)i * 1280 + (uint32_t)kk * 32);
            }
#pragma unroll
            for (int j = 0; j < 4; j++) {
                ldmx2(bh[j], bAddr + (uint32_t)j * 640 + (uint32_t)kk * 32);
                ldmx2(bl[j], bAddr + 10240 + (uint32_t)j * 640 + (uint32_t)kk * 32);
            }
#pragma unroll
            for (int i = 0; i < 4; i++)
#pragma unroll
                for (int j = 0; j < 4; j++) {
                    mma_bf16(acc[i][j], ah[i], bh[j]);
                    mma_bf16(acc[i][j], ah[i], bl[j]);
                    mma_bf16(acc[i][j], al[i], bh[j]);
                }
        }
        __syncthreads();
    }

    // epilogue: direct global stores
    const int g = lane >> 2, qd = lane & 3;
#pragma unroll
    for (int i = 0; i < 4; i++) {
        int r0 = m0 + wm * 64 + i * 16 + g;
#pragma unroll
        for (int j = 0; j < 4; j++) {
            int c = n0 + wn * 32 + j * 8 + qd * 2;
            float bx = __ldg(&bias[c]), by = __ldg(&bias[c + 1]);
            float v0 = acc[i][j][0] + bx, v1 = acc[i][j][1] + by;
            float v2 = acc[i][j][2] + bx, v3 = acc[i][j][3] + by;
            if (RELU) {
                v0 = fmaxf(v0, 0.f); v1 = fmaxf(v1, 0.f);
                v2 = fmaxf(v2, 0.f); v3 = fmaxf(v3, 0.f);
            }
            float2 o01 = {v0, v1};
            float2 o23 = {v2, v3};
            *(float2*)&C[(size_t)r0 * N + c]       = o01;
            *(float2*)&C[(size_t)(r0 + 8) * N + c] = o23;
        }
    }
}

// ---------------- scores+exp: P = exp(QK^T/8 - |i-j|), partial row sums ---
__global__ __launch_bounds__(256) void scores_kernel(
    const float* __restrict__ q, const float* __restrict__ k,
    float* __restrict__ P, float* __restrict__ partials)
{
    __shared__ float Qs[32][136];
    __shared__ float Ks[32][136];
    __shared__ float red[128][17];

    const int bh = blockIdx.z;
    const int b  = bh / HH, h = bh % HH;
    const int q0 = blockIdx.y * 128, k0 = blockIdx.x * 128;
    const int t  = threadIdx.x;
    const int tx = t & 15, ty = t >> 4;

    float acc[8][8];
#pragma unroll
    for (int i = 0; i < 8; i++)
#pragma unroll
        for (int j = 0; j < 8; j++) acc[i][j] = 0.f;

#pragma unroll
    for (int kd = 0; kd < 64; kd += 32) {
#pragma unroll
        for (int i = 0; i < 4; i++) {
            int idx = t + i * 256;
            int row = idx >> 3, c4 = idx & 7;
            size_t qo = ((size_t)(b * SS + q0 + row) * HH + h) * DD + kd + c4 * 4;
            float4 qv = *(const float4*)&q[qo];
            Qs[c4 * 4 + 0][row] = qv.x; Qs[c4 * 4 + 1][row] = qv.y;
            Qs[c4 * 4 + 2][row] = qv.z; Qs[c4 * 4 + 3][row] = qv.w;
            size_t ko = ((size_t)(b * SS + k0 + row) * HH + h) * DD + kd + c4 * 4;
            float4 kv = *(const float4*)&k[ko];
            Ks[c4 * 4 + 0][row] = kv.x; Ks[c4 * 4 + 1][row] = kv.y;
            Ks[c4 * 4 + 2][row] = kv.z; Ks[c4 * 4 + 3][row] = kv.w;
        }
        __syncthreads();

#pragma unroll
        for (int kk = 0; kk < 32; kk++) {
            float4 a0 = *(float4*)&Qs[kk][ty * 8];
            float4 a1 = *(float4*)&Qs[kk][ty * 8 + 4];
            float4 b0 = *(float4*)&Ks[kk][tx * 8];
            float4 b1 = *(float4*)&Ks[kk][tx * 8 + 4];
            float a[8] = {a0.x, a0.y, a0.z, a0.w, a1.x, a1.y, a1.z, a1.w};
            float c[8] = {b0.x, b0.y, b0.z, b0.w, b1.x, b1.y, b1.z, b1.w};
#pragma unroll
            for (int i = 0; i < 8; i++)
#pragma unroll
                for (int j = 0; j < 8; j++)
                    acc[i][j] = fmaf(a[i], c[j], acc[i][j]);
        }
        __syncthreads();
    }

#pragma unroll
    for (int i = 0; i < 8; i++) {
        int qi = q0 + ty * 8 + i;
        float rowsum = 0.f;
#pragma unroll
        for (int j4 = 0; j4 < 2; j4++) {
            int kj = k0 + tx * 8 + j4 * 4;
            float4 o;
            o.x = __expf(acc[i][j4 * 4 + 0] * 0.125f - fabsf((float)(qi - (kj + 0))));
            o.y = __expf(acc[i][j4 * 4 + 1] * 0.125f - fabsf((float)(qi - (kj + 1))));
            o.z = __expf(acc[i][j4 * 4 + 2] * 0.125f - fabsf((float)(qi - (kj + 2))));
            o.w = __expf(acc[i][j4 * 4 + 3] * 0.125f - fabsf((float)(qi - (kj + 3))));
            rowsum += (o.x + o.y) + (o.z + o.w);
            *(float4*)&P[((size_t)bh * SS + qi) * SS + kj] = o;
        }
        red[ty * 8 + i][tx] = rowsum;
    }
    __syncthreads();
    if (t < 128) {
        float s = 0.f;
#pragma unroll
        for (int x = 0; x < 16; x++) s += red[t][x];
        partials[((size_t)bh * SS + q0 + t) * KTILES + blockIdx.x] = s;
    }
}

// ---------------- reduce partial row sums -> 1/sum -------------------------
__global__ __launch_bounds__(256) void rowsum_kernel(
    const float* __restrict__ partials, float* __restrict__ inv)
{
    int r = blockIdx.x * 256 + threadIdx.x;
    float s = 0.f;
#pragma unroll
    for (int i = 0; i < KTILES; i++) s += partials[(size_t)r * KTILES + i];
    inv[r] = 1.0f / s;
}

// ---------------- ctx = Pn @ V ; normalized P written back -----------------
__global__ __launch_bounds__(256) void ctx_kernel(
    float* __restrict__ P, const float* __restrict__ v,
    const float* __restrict__ inv, float* __restrict__ ctx)
{
    __shared__ float Ps[128][33];
    __shared__ float Vs[32][64];
    __shared__ float invs[128];

    const int bh = blockIdx.y;
    const int b  = bh / HH, h = bh % HH;
    const int q0 = blockIdx.x * 128;
    const int t  = threadIdx.x;
    const int tx = t & 15, ty = t >> 4;
    float* Pb = P + (size_t)bh * SS * SS;

    if (t < 128) invs[t] = inv[(size_t)bh * SS + q0 + t];
    __syncthreads();

    float acc[8][4];
#pragma unroll
    for (int i = 0; i < 8; i++)
#pragma unroll
        for (int j = 0; j < 4; j++) acc[i][j] = 0.f;

    for (int kt = 0; kt < SS; kt += 32) {
#pragma unroll
        for (int i = 0; i < 4; i++) {
            int idx = t + i * 256;
            int row = idx >> 3, c4 = idx & 7;
            size_t off = (size_t)(q0 + row) * SS + kt + c4 * 4;
            float4 pv = *(const float4*)&Pb[off];
            float iv = invs[row];
            pv.x *= iv; pv.y *= iv; pv.z *= iv; pv.w *= iv;
            *(float4*)&Pb[off] = pv;
            Ps[row][c4 * 4 + 0] = pv.x; Ps[row][c4 * 4 + 1] = pv.y;
            Ps[row][c4 * 4 + 2] = pv.z; Ps[row][c4 * 4 + 3] = pv.w;
        }
#pragma unroll
        for (int i = 0; i < 2; i++) {
            int idx = t + i * 256;
            int kr = idx >> 4, c4 = idx & 15;
            *(float4*)&Vs[kr][c4 * 4] =
                *(const float4*)&v[((size_t)(b * SS + kt + kr) * HH + h) * DD + c4 * 4];
        }
        __syncthreads();

#pragma unroll
        for (int kk = 0; kk < 32; kk++) {
            float4 bv = *(float4*)&Vs[kk][tx * 4];
#pragma unroll
            for (int i = 0; i < 8; i++) {
                float a = Ps[ty * 8 + i][kk];
                acc[i][0] = fmaf(a, bv.x, acc[i][0]);
                acc[i][1] = fmaf(a, bv.y, acc[i][1]);
                acc[i][2] = fmaf(a, bv.z, acc[i][2]);
                acc[i][3] = fmaf(a, bv.w, acc[i][3]);
            }
        }
        __syncthreads();
    }

#pragma unroll
    for (int i = 0; i < 8; i++) {
        float4 o = {acc[i][0], acc[i][1], acc[i][2], acc[i][3]};
        *(float4*)&ctx[((size_t)(b * SS + q0 + ty * 8 + i) * HH + h) * DD + tx * 4] = o;
    }
}

// ---------------- out = LayerNorm(A + B) * g + be --------------------------
__global__ __launch_bounds__(256) void add_ln_kernel(
    const float* __restrict__ A, const float* __restrict__ Bi,
    const float* __restrict__ g, const float* __restrict__ be,
    float* __restrict__ out)
{
    __shared__ float rs[256];
    __shared__ float rs2[256];
    const size_t off = (size_t)blockIdx.x * EE;
    const int t = threadIdx.x;
    float x[3];
    float s = 0.f, s2 = 0.f;
#pragma unroll
    for (int i = 0; i < 3; i++) {
        int c = t + i * 256;
        x[i] = A[off + c] + Bi[off + c];
        s += x[i]; s2 += x[i] * x[i];
    }
    rs[t] = s; rs2[t] = s2; __syncthreads();
    for (int st = 128; st > 0; st >>= 1) {
        if (t < st) { rs[t] += rs[t + st]; rs2[t] += rs2[t + st]; }
        __syncthreads();
    }
    const float mu  = rs[0] * (1.0f / EE);
    const float var = rs2[0] * (1.0f / EE) - mu * mu;
    const float r   = rsqrtf(var + 1e-5f);
#pragma unroll
    for (int i = 0; i < 3; i++) {
        int c = t + i * 256;
        out[off + c] = (x[i] - mu) * r * g[c] + be[c];
    }
}

// ---------------- launch --------------------------------------------------
extern "C" void kernel_launch(void* const* d_in, const int* in_sizes, int n_in,
                              void* d_out, int out_size)
{
    const float* x  = (const float*)d_in[0];
    const float* Wq = (const float*)d_in[1];
    const float* bq = (const float*)d_in[2];
    const float* Wk = (const float*)d_in[3];
    const float* bk = (const float*)d_in[4];
    const float* Wv = (const float*)d_in[5];
    const float* bv = (const float*)d_in[6];
    const float* Wo = (const float*)d_in[7];
    const float* bo = (const float*)d_in[8];
    const float* W1 = (const float*)d_in[9];
    const float* b1 = (const float*)d_in[10];
    const float* W2 = (const float*)d_in[11];
    const float* b2 = (const float*)d_in[12];
    const float* g1 = (const float*)d_in[13];
    const float* be1= (const float*)d_in[14];
    const float* g2 = (const float*)d_in[15];
    const float* be2= (const float*)d_in[16];

    float* out  = (float*)d_out;
    float* attn = out + (size_t)BB * SS * EE;

    float *q, *k, *v, *ctxp, *h, *ff1, *part, *inv;
    cudaGetSymbolAddress((void**)&q,    g_q);
    cudaGetSymbolAddress((void**)&k,    g_k);
    cudaGetSymbolAddress((void**)&v,    g_v);
    cudaGetSymbolAddress((void**)&ctxp, g_ctx);
    cudaGetSymbolAddress((void**)&h,    g_h);
    cudaGetSymbolAddress((void**)&ff1,  g_ff1);
    cudaGetSymbolAddress((void**)&part, g_part);
    cudaGetSymbolAddress((void**)&inv,  g_inv);
    __nv_bfloat16 *wqh,*wql,*wkh,*wkl,*wvh,*wvl,*woh,*wol,*w1h,*w1l,*w2h,*w2l;
    cudaGetSymbolAddress((void**)&wqh, g_wqt_h); cudaGetSymbolAddress((void**)&wql, g_wqt_l);
    cudaGetSymbolAddress((void**)&wkh, g_wkt_h); cudaGetSymbolAddress((void**)&wkl, g_wkt_l);
    cudaGetSymbolAddress((void**)&wvh, g_wvt_h); cudaGetSymbolAddress((void**)&wvl, g_wvt_l);
    cudaGetSymbolAddress((void**)&woh, g_wot_h); cudaGetSymbolAddress((void**)&wol, g_wot_l);
    cudaGetSymbolAddress((void**)&w1h, g_w1t_h); cudaGetSymbolAddress((void**)&w1l, g_w1t_l);
    cudaGetSymbolAddress((void**)&w2h, g_w2t_h); cudaGetSymbolAddress((void**)&w2l, g_w2t_l);

    // weight transposes + bf16 split
    wtrans_kernel<<<dim3(EE/32,  EE/32),  256>>>(Wq, wqh, wql, EE, EE);
    wtrans_kernel<<<dim3(EE/32,  EE/32),  256>>>(Wk, wkh, wkl, EE, EE);
    wtrans_kernel<<<dim3(EE/32,  EE/32),  256>>>(Wv, wvh, wvl, EE, EE);
    wtrans_kernel<<<dim3(EE/32,  EE/32),  256>>>(Wo, woh, wol, EE, EE);
    wtrans_kernel<<<dim3(FFF/32, EE/32),  256>>>(W1, w1h, w1l, EE, FFF);
    wtrans_kernel<<<dim3(EE/32,  FFF/32), 256>>>(W2, w2h, w2l, FFF, EE);

    dim3 gE (EE / 128,  MM / 128);
    dim3 gFF(FFF / 128, MM / 128);
    const int GSM = 40960;

    gemm_mma_kernel<false><<<gE, 256, GSM>>>(x, wqh, wql, bq, q, EE, EE);
    gemm_mma_kernel<false><<<gE, 256, GSM>>>(x, wkh, wkl, bk, k, EE, EE);
    gemm_mma_kernel<false><<<gE, 256, GSM>>>(x, wvh, wvl, bv, v, EE, EE);

    scores_kernel<<<dim3(SS/128, SS/128, BH), 256>>>(q, k, attn, part);
    rowsum_kernel<<<NROWS / 256, 256>>>(part, inv);
    ctx_kernel   <<<dim3(SS/128, BH), 256>>>(attn, v, inv, ctxp);

    gemm_mma_kernel<false><<<gE, 256, GSM>>>(ctxp, woh, wol, bo, q, EE, EE);
    add_ln_kernel<<<MM, 256>>>(x, q, g1, be1, h);

    gemm_mma_kernel<true ><<<gFF, 256, GSM>>>(h, w1h, w1l, b1, ff1, FFF, EE);
    gemm_mma_kernel<false><<<gE, 256, GSM>>>(ff1, w2h, w2l, b2, k, EE, FFF);
    add_ln_kernel<<<MM, 256>>>(h, k, g2, be2, out);
}

// round 6
// speedup vs baseline: 2.0547x; 1.3079x over previous
#include <cuda_runtime.h>
#include <cuda_bf16.h>
#include <cstdint>

#define BB 2
#define SS 2048
#define EE 768
#define HH 12
#define DD 64
#define FFF 3072
#define MM (BB*SS)          // 4096
#define BH (BB*HH)          // 24
#define NROWS (BH*SS)       // 49152
#define KTILES (SS/128)     // 16

// ---------------- scratch (device globals; no allocation) ----------------
__device__ float g_q  [MM*EE];
__device__ float g_k  [MM*EE];
__device__ float g_v  [MM*EE];
__device__ float g_ctx[MM*EE];
__device__ float g_h  [MM*EE];
__device__ float g_ff1[(size_t)MM*FFF];
__device__ float g_part[(size_t)NROWS*KTILES];
__device__ float g_inv [NROWS];
__device__ __nv_bfloat16 g_wqt_h[EE*EE],  g_wqt_l[EE*EE];
__device__ __nv_bfloat16 g_wkt_h[EE*EE],  g_wkt_l[EE*EE];
__device__ __nv_bfloat16 g_wvt_h[EE*EE],  g_wvt_l[EE*EE];
__device__ __nv_bfloat16 g_wot_h[EE*EE],  g_wot_l[EE*EE];
__device__ __nv_bfloat16 g_w1t_h[EE*FFF], g_w1t_l[EE*FFF];
__device__ __nv_bfloat16 g_w2t_h[EE*FFF], g_w2t_l[EE*FFF];
__device__ __nv_bfloat16 g_qh[MM*EE], g_ql[MM*EE];
__device__ __nv_bfloat16 g_kh[MM*EE], g_kl[MM*EE];
__device__ __nv_bfloat16 g_vth[(size_t)BH*DD*SS], g_vtl[(size_t)BH*DD*SS];
__device__ __nv_bfloat16 g_ph[(size_t)BH*SS*SS], g_pl[(size_t)BH*SS*SS];

// ---------------- helpers ---------------------------------------------------
__device__ __forceinline__ uint32_t smem_u32(const void* p) {
    uint32_t a;
    asm("{ .reg .u64 t; cvta.to.shared.u64 t, %1; cvt.u32.u64 %0, t; }"
        : "=r"(a) : "l"(p));
    return a;
}
__device__ __forceinline__ void ldmx4(uint32_t* r, uint32_t addr) {
    asm volatile("ldmatrix.sync.aligned.m8n8.x4.shared.b16 {%0,%1,%2,%3}, [%4];"
        : "=r"(r[0]), "=r"(r[1]), "=r"(r[2]), "=r"(r[3]) : "r"(addr));
}
__device__ __forceinline__ void ldmx2(uint32_t* r, uint32_t addr) {
    asm volatile("ldmatrix.sync.aligned.m8n8.x2.shared.b16 {%0,%1}, [%2];"
        : "=r"(r[0]), "=r"(r[1]) : "r"(addr));
}
__device__ __forceinline__ void mma_bf16(float* d, const uint32_t* a, const uint32_t* b) {
    asm volatile("mma.sync.aligned.m16n8k16.row.col.f32.bf16.bf16.f32 "
        "{%0,%1,%2,%3}, {%4,%5,%6,%7}, {%8,%9}, {%0,%1,%2,%3};"
        : "+f"(d[0]), "+f"(d[1]), "+f"(d[2]), "+f"(d[3])
        : "r"(a[0]), "r"(a[1]), "r"(a[2]), "r"(a[3]), "r"(b[0]), "r"(b[1]));
}
__device__ __forceinline__ void split2(float x, float y, uint32_t& hi, uint32_t& lo) {
    __nv_bfloat16 hx = __float2bfloat16_rn(x);
    __nv_bfloat16 hy = __float2bfloat16_rn(y);
    __nv_bfloat16 lx = __float2bfloat16_rn(x - __bfloat162float(hx));
    __nv_bfloat16 ly = __float2bfloat16_rn(y - __bfloat162float(hy));
    hi = ((uint32_t)__bfloat16_as_ushort(hy) << 16) | __bfloat16_as_ushort(hx);
    lo = ((uint32_t)__bfloat16_as_ushort(ly) << 16) | __bfloat16_as_ushort(lx);
}

// ---------------- weight transpose+split: W[K][N] -> Th/Tl[N][K] ----------
__global__ __launch_bounds__(256) void wtrans_kernel(
    const float* __restrict__ W, __nv_bfloat16* __restrict__ Th,
    __nv_bfloat16* __restrict__ Tl, int K, int N)
{
    __shared__ float tile[32][33];
    const int n0 = blockIdx.x * 32, k0 = blockIdx.y * 32;
    const int tx = threadIdx.x & 31, ty = threadIdx.x >> 5;
#pragma unroll
    for (int i = 0; i < 32; i += 8)
        tile[ty + i][tx] = W[(size_t)(k0 + ty + i) * N + n0 + tx];
    __syncthreads();
#pragma unroll
    for (int i = 0; i < 32; i += 8) {
        float x = tile[tx][ty + i];
        __nv_bfloat16 h = __float2bfloat16_rn(x);
        __nv_bfloat16 l = __float2bfloat16_rn(x - __bfloat162float(h));
        size_t o = (size_t)(n0 + ty + i) * K + k0 + tx;
        Th[o] = h; Tl[o] = l;
    }
}

// ---------------- elementwise fp32 -> bf16 hi/lo split ---------------------
__global__ __launch_bounds__(256) void split_kernel(
    const float* __restrict__ A, __nv_bfloat16* __restrict__ Ah,
    __nv_bfloat16* __restrict__ Al)
{
    size_t idx = ((size_t)blockIdx.x * 256 + threadIdx.x) * 4;
    float4 v = *(const float4*)&A[idx];
    uint32_t h0, l0, h1, l1;
    split2(v.x, v.y, h0, l0);
    split2(v.z, v.w, h1, l1);
    *(uint2*)&Ah[idx] = make_uint2(h0, h1);
    *(uint2*)&Al[idx] = make_uint2(l0, l1);
}

// ---------------- v transpose+split: v[b,s,h,d] -> vt[bh][d][s] ------------
__global__ __launch_bounds__(256) void vtrans_kernel(
    const float* __restrict__ v, __nv_bfloat16* __restrict__ Th,
    __nv_bfloat16* __restrict__ Tl)
{
    __shared__ float tile[32][33];
    const int s0 = blockIdx.x * 32, d0 = blockIdx.y * 32, bh = blockIdx.z;
    const int b = bh / HH, h = bh % HH;
    const int tx = threadIdx.x & 31, ty = threadIdx.x >> 5;
#pragma unroll
    for (int i = 0; i < 32; i += 8)
        tile[ty + i][tx] = v[(size_t)(b * SS + s0 + ty + i) * EE + h * DD + d0 + tx];
    __syncthreads();
#pragma unroll
    for (int i = 0; i < 32; i += 8) {
        float x = tile[tx][ty + i];
        __nv_bfloat16 hh = __float2bfloat16_rn(x);
        __nv_bfloat16 ll = __float2bfloat16_rn(x - __bfloat162float(hh));
        size_t o = ((size_t)bh * DD + d0 + ty + i) * SS + s0 + tx;
        Th[o] = hh; Tl[o] = ll;
    }
}

// ---------------- bf16 3-split tensor GEMM: C = A @ Wt^T + bias -----------
template<bool RELU>
__global__ __launch_bounds__(256) void gemm_mma_kernel(
    const float* __restrict__ A,
    const __nv_bfloat16* __restrict__ Bth, const __nv_bfloat16* __restrict__ Btl,
    const float* __restrict__ bias, float* __restrict__ C, int N, int K)
{
    extern __shared__ char sm[];
    const int t = threadIdx.x, lane = t & 31, warp = t >> 5;
    const int wm = warp >> 2, wn = warp & 3;
    const int m0 = blockIdx.y * 128, n0 = blockIdx.x * 128;
    const uint32_t sb = smem_u32(sm);

    float acc[4][4][4];
#pragma unroll
    for (int i = 0; i < 4; i++)
#pragma unroll
        for (int j = 0; j < 4; j++)
#pragma unroll
            for (int u = 0; u < 4; u++) acc[i][j][u] = 0.f;

    float4 areg[4];
    uint4  bh_reg[2], bl_reg[2];
    const int ar = t >> 3, ac4 = t & 7;
    const int br = t >> 2, bc8 = t & 3;
    const int nch = K / 32;

#pragma unroll
    for (int i = 0; i < 4; i++)
        areg[i] = *(const float4*)&A[(size_t)(m0 + ar + i * 32) * K + ac4 * 4];
#pragma unroll
    for (int i = 0; i < 2; i++) {
        size_t o = (size_t)(n0 + br + i * 64) * K + bc8 * 8;
        bh_reg[i] = *(const uint4*)&Bth[o];
        bl_reg[i] = *(const uint4*)&Btl[o];
    }

    const uint32_t aAddr = sb + (uint32_t)(wm * 64 + (lane & 15)) * 80
                              + (uint32_t)(lane >> 4) * 16;
    const uint32_t bAddr = sb + 20480
                              + (uint32_t)(wn * 32 + (lane & 7)) * 80
                              + (uint32_t)((lane >> 3) & 1) * 16;

    for (int ch = 0; ch < nch; ch++) {
#pragma unroll
        for (int i = 0; i < 4; i++) {
            uint32_t h0, l0, h1, l1;
            split2(areg[i].x, areg[i].y, h0, l0);
            split2(areg[i].z, areg[i].w, h1, l1);
            uint32_t off = (uint32_t)(ar + i * 32) * 80 + (uint32_t)ac4 * 8;
            *(uint2*)(sm + off)         = make_uint2(h0, h1);
            *(uint2*)(sm + 10240 + off) = make_uint2(l0, l1);
        }
#pragma unroll
        for (int i = 0; i < 2; i++) {
            uint32_t off = (uint32_t)(br + i * 64) * 80 + (uint32_t)bc8 * 16;
            *(uint4*)(sm + 20480 + off) = bh_reg[i];
            *(uint4*)(sm + 30720 + off) = bl_reg[i];
        }
        __syncthreads();

        if (ch + 1 < nch) {
            const int kof = (ch + 1) * 32;
#pragma unroll
            for (int i = 0; i < 4; i++)
                areg[i] = *(const float4*)&A[(size_t)(m0 + ar + i * 32) * K + kof + ac4 * 4];
#pragma unroll
            for (int i = 0; i < 2; i++) {
                size_t o = (size_t)(n0 + br + i * 64) * K + kof + bc8 * 8;
                bh_reg[i] = *(const uint4*)&Bth[o];
                bl_reg[i] = *(const uint4*)&Btl[o];
            }
        }

#pragma unroll
        for (int kk = 0; kk < 2; kk++) {
            uint32_t ah[4][4], al[4][4], bh[4][2], bl[4][2];
#pragma unroll
            for (int i = 0; i < 4; i++) {
                ldmx4(ah[i], aAddr + (uint32_t)i * 1280 + (uint32_t)kk * 32);
                ldmx4(al[i], aAddr + 10240 + (uint32_t)i * 1280 + (uint32_t)kk * 32);
            }
#pragma unroll
            for (int j = 0; j < 4; j++) {
                ldmx2(bh[j], bAddr + (uint32_t)j * 640 + (uint32_t)kk * 32);
                ldmx2(bl[j], bAddr + 10240 + (uint32_t)j * 640 + (uint32_t)kk * 32);
            }
#pragma unroll
            for (int i = 0; i < 4; i++)
#pragma unroll
                for (int j = 0; j < 4; j++) {
                    mma_bf16(acc[i][j], ah[i], bh[j]);
                    mma_bf16(acc[i][j], ah[i], bl[j]);
                    mma_bf16(acc[i][j], al[i], bh[j]);
                }
        }
        __syncthreads();
    }

    const int g = lane >> 2, qd = lane & 3;
#pragma unroll
    for (int i = 0; i < 4; i++) {
        int r0 = m0 + wm * 64 + i * 16 + g;
#pragma unroll
        for (int j = 0; j < 4; j++) {
            int c = n0 + wn * 32 + j * 8 + qd * 2;
            float bx = __ldg(&bias[c]), by = __ldg(&bias[c + 1]);
            float v0 = acc[i][j][0] + bx, v1 = acc[i][j][1] + by;
            float v2 = acc[i][j][2] + bx, v3 = acc[i][j][3] + by;
            if (RELU) {
                v0 = fmaxf(v0, 0.f); v1 = fmaxf(v1, 0.f);
                v2 = fmaxf(v2, 0.f); v3 = fmaxf(v3, 0.f);
            }
            float2 o01 = {v0, v1};
            float2 o23 = {v2, v3};
            *(float2*)&C[(size_t)r0 * N + c]       = o01;
            *(float2*)&C[(size_t)(r0 + 8) * N + c] = o23;
        }
    }
}

// ---------------- scores via MMA: Ph/Pl = exp(QK^T/8-|i-j|) bf16 ----------
// smem: QH@0 QL@18432 KH@36864 KL@55296 (128 rows x 144B), RED@73728 -> 75776
__global__ __launch_bounds__(256) void scores_mma_kernel(
    const __nv_bfloat16* __restrict__ qh, const __nv_bfloat16* __restrict__ ql,
    const __nv_bfloat16* __restrict__ kh, const __nv_bfloat16* __restrict__ kl,
    __nv_bfloat16* __restrict__ Ph, __nv_bfloat16* __restrict__ Pl,
    float* __restrict__ partials)
{
    extern __shared__ char sm[];
    const uint32_t sb = smem_u32(sm);
    const int t = threadIdx.x, lane = t & 31, warp = t >> 5;
    const int wm = warp >> 2, wn = warp & 3;
    const int bh = blockIdx.z, b = bh / HH, h = bh % HH;
    const int q0 = blockIdx.y * 128, k0 = blockIdx.x * 128;
    float* red = (float*)(sm + 73728);   // [128][4]

#pragma unroll
    for (int i = 0; i < 4; i++) {
        int idx = t + i * 256;
        int row = idx >> 3, c = idx & 7;
        uint32_t off = (uint32_t)row * 144 + (uint32_t)c * 16;
        size_t qg = (size_t)(b * SS + q0 + row) * EE + h * DD + c * 8;
        size_t kg = (size_t)(b * SS + k0 + row) * EE + h * DD + c * 8;
        *(uint4*)(sm + off)         = *(const uint4*)&qh[qg];
        *(uint4*)(sm + 18432 + off) = *(const uint4*)&ql[qg];
        *(uint4*)(sm + 36864 + off) = *(const uint4*)&kh[kg];
        *(uint4*)(sm + 55296 + off) = *(const uint4*)&kl[kg];
    }
    __syncthreads();

    float acc[4][4][4];
#pragma unroll
    for (int i = 0; i < 4; i++)
#pragma unroll
        for (int j = 0; j < 4; j++)
#pragma unroll
            for (int u = 0; u < 4; u++) acc[i][j][u] = 0.f;

    const uint32_t aAddr = sb + (uint32_t)(wm * 64 + (lane & 15)) * 144
                              + (uint32_t)(lane >> 4) * 16;
    const uint32_t bAddr = sb + 36864
                              + (uint32_t)(wn * 32 + (lane & 7)) * 144
                              + (uint32_t)((lane >> 3) & 1) * 16;
#pragma unroll
    for (int kk = 0; kk < 4; kk++) {
        uint32_t ah[4][4], al[4][4], bhf[4][2], blf[4][2];
#pragma unroll
        for (int i = 0; i < 4; i++) {
            ldmx4(ah[i], aAddr + (uint32_t)i * 2304 + (uint32_t)kk * 32);
            ldmx4(al[i], aAddr + 18432 + (uint32_t)i * 2304 + (uint32_t)kk * 32);
        }
#pragma unroll
        for (int j = 0; j < 4; j++) {
            ldmx2(bhf[j], bAddr + (uint32_t)j * 1152 + (uint32_t)kk * 32);
            ldmx2(blf[j], bAddr + 18432 + (uint32_t)j * 1152 + (uint32_t)kk * 32);
        }
#pragma unroll
        for (int i = 0; i < 4; i++)
#pragma unroll
            for (int j = 0; j < 4; j++) {
                mma_bf16(acc[i][j], ah[i], bhf[j]);
                mma_bf16(acc[i][j], ah[i], blf[j]);
                mma_bf16(acc[i][j], al[i], bhf[j]);
            }
    }

    const int g = lane >> 2, qd = lane & 3;
#pragma unroll
    for (int i = 0; i < 4; i++) {
        int rloc = wm * 64 + i * 16 + g;
        int qi = q0 + rloc;
        float s0 = 0.f, s1 = 0.f;
#pragma unroll
        for (int j = 0; j < 4; j++) {
            int kj = k0 + wn * 32 + j * 8 + qd * 2;
            float e0 = __expf(acc[i][j][0] * 0.125f - fabsf((float)(qi - kj)));
            float e1 = __expf(acc[i][j][1] * 0.125f - fabsf((float)(qi - kj - 1)));
            float e2 = __expf(acc[i][j][2] * 0.125f - fabsf((float)(qi + 8 - kj)));
            float e3 = __expf(acc[i][j][3] * 0.125f - fabsf((float)(qi + 8 - kj - 1)));
            s0 += e0 + e1; s1 += e2 + e3;
            uint32_t h0, l0, h1, l1;
            split2(e0, e1, h0, l0);
            split2(e2, e3, h1, l1);
            size_t o0 = ((size_t)bh * SS + qi) * SS + kj;
            size_t o1 = ((size_t)bh * SS + qi + 8) * SS + kj;
            *(uint32_t*)(Ph + o0) = h0; *(uint32_t*)(Pl + o0) = l0;
            *(uint32_t*)(Ph + o1) = h1; *(uint32_t*)(Pl + o1) = l1;
        }
        s0 += __shfl_xor_sync(0xFFFFFFFF, s0, 1);
        s0 += __shfl_xor_sync(0xFFFFFFFF, s0, 2);
        s1 += __shfl_xor_sync(0xFFFFFFFF, s1, 1);
        s1 += __shfl_xor_sync(0xFFFFFFFF, s1, 2);
        if (qd == 0) {
            red[rloc * 4 + wn]       = s0;
            red[(rloc + 8) * 4 + wn] = s1;
        }
    }
    __syncthreads();
    if (t < 128) {
        float s = red[t * 4] + red[t * 4 + 1] + red[t * 4 + 2] + red[t * 4 + 3];
        partials[((size_t)bh * SS + q0 + t) * KTILES + blockIdx.x] = s;
    }
}

// ---------------- reduce partial row sums -> 1/sum -------------------------
__global__ __launch_bounds__(256) void rowsum_kernel(
    const float* __restrict__ partials, float* __restrict__ inv)
{
    int r = blockIdx.x * 256 + threadIdx.x;
    float s = 0.f;
#pragma unroll
    for (int i = 0; i < KTILES; i++) s += partials[(size_t)r * KTILES + i];
    inv[r] = 1.0f / s;
}

// ---------------- ctx via MMA; writes normalized fp32 attn_map -------------
// smem: PH@0 (10240) PL@10240 VH@20480 (5120) VL@25600, INV@30720 -> 31232
__global__ __launch_bounds__(256) void ctx_mma_kernel(
    const __nv_bfloat16* __restrict__ Ph, const __nv_bfloat16* __restrict__ Pl,
    const __nv_bfloat16* __restrict__ Vth, const __nv_bfloat16* __restrict__ Vtl,
    const float* __restrict__ inv, float* __restrict__ attn,
    float* __restrict__ ctx)
{
    extern __shared__ char sm[];
    const uint32_t sb = smem_u32(sm);
    const int t = threadIdx.x, lane = t & 31, warp = t >> 5;
    const int wm = warp >> 1, wn = warp & 1;
    const int bh = blockIdx.y, b = bh / HH, h = bh % HH;
    const int q0 = blockIdx.x * 128;
    float* invs = (float*)(sm + 30720);

    if (t < 128) invs[t] = inv[(size_t)bh * SS + q0 + t];
    __syncthreads();

    const __nv_bfloat16* Phb = Ph + (size_t)bh * SS * SS;
    const __nv_bfloat16* Plb = Pl + (size_t)bh * SS * SS;
    float* attnb = attn + (size_t)bh * SS * SS;

    float acc[2][4][4];
#pragma unroll
    for (int i = 0; i < 2; i++)
#pragma unroll
        for (int j = 0; j < 4; j++)
#pragma unroll
            for (int u = 0; u < 4; u++) acc[i][j][u] = 0.f;

    uint4 ph_r[2], pl_r[2], vh_r, vl_r;
    const int vr = t >> 2, vc = t & 3;

    // prologue: load chunk 0 + write its normalized attn
    {
        const int kt = 0;
#pragma unroll
        for (int i = 0; i < 2; i++) {
            int idx = t + i * 256;
            int row = idx >> 2, c = idx & 3;
            size_t go = (size_t)(q0 + row) * SS + kt + c * 8;
            ph_r[i] = *(const uint4*)(Phb + go);
            pl_r[i] = *(const uint4*)(Plb + go);
        }
        vh_r = *(const uint4*)(Vth + ((size_t)bh * DD + vr) * SS + kt + vc * 8);
        vl_r = *(const uint4*)(Vtl + ((size_t)bh * DD + vr) * SS + kt + vc * 8);
#pragma unroll
        for (int i = 0; i < 2; i++) {
            int idx = t + i * 256;
            int row = idx >> 2, c = idx & 3;
            float iv = invs[row];
            const __nv_bfloat162* hp = (const __nv_bfloat162*)&ph_r[i];
            const __nv_bfloat162* lp = (const __nv_bfloat162*)&pl_r[i];
            float out8[8];
#pragma unroll
            for (int u = 0; u < 4; u++) {
                float2 fh = __bfloat1622float2(hp[u]);
                float2 fl = __bfloat1622float2(lp[u]);
                out8[u * 2]     = (fh.x + fl.x) * iv;
                out8[u * 2 + 1] = (fh.y + fl.y) * iv;
            }
            size_t ao = (size_t)(q0 + row) * SS + kt + c * 8;
            *(float4*)(attnb + ao)     = *(float4*)&out8[0];
            *(float4*)(attnb + ao + 4) = *(float4*)&out8[4];
        }
    }

    const uint32_t aAddr = sb + (uint32_t)(wm * 32 + (lane & 15)) * 80
                              + (uint32_t)(lane >> 4) * 16;
    const uint32_t bAddr = sb + 20480
                              + (uint32_t)(wn * 32 + (lane & 7)) * 80
                              + (uint32_t)((lane >> 3) & 1) * 16;

    for (int ch = 0; ch < SS / 32; ch++) {
#pragma unroll
        for (int i = 0; i < 2; i++) {
            int idx = t + i * 256;
            int row = idx >> 2, c = idx & 3;
            uint32_t off = (uint32_t)row * 80 + (uint32_t)c * 16;
            *(uint4*)(sm + off)         = ph_r[i];
            *(uint4*)(sm + 10240 + off) = pl_r[i];
        }
        {
            uint32_t off = (uint32_t)vr * 80 + (uint32_t)vc * 16;
            *(uint4*)(sm + 20480 + off) = vh_r;
            *(uint4*)(sm + 25600 + off) = vl_r;
        }
        __syncthreads();

        if (ch + 1 < SS / 32) {
            const int kt = (ch + 1) * 32;
#pragma unroll
            for (int i = 0; i < 2; i++) {
                int idx = t + i * 256;
                int row = idx >> 2, c = idx & 3;
                size_t go = (size_t)(q0 + row) * SS + kt + c * 8;
                ph_r[i] = *(const uint4*)(Phb + go);
                pl_r[i] = *(const uint4*)(Plb + go);
            }
            vh_r = *(const uint4*)(Vth + ((size_t)bh * DD + vr) * SS + kt + vc * 8);
            vl_r = *(const uint4*)(Vtl + ((size_t)bh * DD + vr) * SS + kt + vc * 8);
#pragma unroll
            for (int i = 0; i < 2; i++) {
                int idx = t + i * 256;
                int row = idx >> 2, c = idx & 3;
                float iv = invs[row];
                const __nv_bfloat162* hp = (const __nv_bfloat162*)&ph_r[i];
                const __nv_bfloat162* lp = (const __nv_bfloat162*)&pl_r[i];
                float out8[8];
#pragma unroll
                for (int u = 0; u < 4; u++) {
                    float2 fh = __bfloat1622float2(hp[u]);
                    float2 fl = __bfloat1622float2(lp[u]);
                    out8[u * 2]     = (fh.x + fl.x) * iv;
                    out8[u * 2 + 1] = (fh.y + fl.y) * iv;
                }
                size_t ao = (size_t)(q0 + row) * SS + kt + c * 8;
                *(float4*)(attnb + ao)     = *(float4*)&out8[0];
                *(float4*)(attnb + ao + 4) = *(float4*)&out8[4];
            }
        }

#pragma unroll
        for (int kk = 0; kk < 2; kk++) {
            uint32_t ah[2][4], al[2][4], bhf[4][2], blf[4][2];
#pragma unroll
            for (int i = 0; i < 2; i++) {
                ldmx4(ah[i], aAddr + (uint32_t)i * 1280 + (uint32_t)kk * 32);
                ldmx4(al[i], aAddr + 10240 + (uint32_t)i * 1280 + (uint32_t)kk * 32);
            }
#pragma unroll
            for (int j = 0; j < 4; j++) {
                ldmx2(bhf[j], bAddr + (uint32_t)j * 640 + (uint32_t)kk * 32);
                ldmx2(blf[j], bAddr + 5120 + (uint32_t)j * 640 + (uint32_t)kk * 32);  // FIX: VL is 5120B past VH
            }
#pragma unroll
            for (int i = 0; i < 2; i++)
#pragma unroll
                for (int j = 0; j < 4; j++) {
                    mma_bf16(acc[i][j], ah[i], bhf[j]);
                    mma_bf16(acc[i][j], ah[i], blf[j]);
                    mma_bf16(acc[i][j], al[i], bhf[j]);
                }
        }
        __syncthreads();
    }

    const int g = lane >> 2, qd = lane & 3;
#pragma unroll
    for (int i = 0; i < 2; i++) {
        int rloc = wm * 32 + i * 16 + g;
        float iv0 = invs[rloc], iv1 = invs[rloc + 8];
#pragma unroll
        for (int j = 0; j < 4; j++) {
            int c = wn * 32 + j * 8 + qd * 2;
            float2 o01 = {acc[i][j][0] * iv0, acc[i][j][1] * iv0};
            float2 o23 = {acc[i][j][2] * iv1, acc[i][j][3] * iv1};
            *(float2*)&ctx[((size_t)(b * SS + q0 + rloc) * HH + h) * DD + c]     = o01;
            *(float2*)&ctx[((size_t)(b * SS + q0 + rloc + 8) * HH + h) * DD + c] = o23;
        }
    }
}

// ---------------- out = LayerNorm(A + B) * g + be --------------------------
__global__ __launch_bounds__(256) void add_ln_kernel(
    const float* __restrict__ A, const float* __restrict__ Bi,
    const float* __restrict__ g, const float* __restrict__ be,
    float* __restrict__ out)
{
    __shared__ float rs[256];
    __shared__ float rs2[256];
    const size_t off = (size_t)blockIdx.x * EE;
    const int t = threadIdx.x;
    float x[3];
    float s = 0.f, s2 = 0.f;
#pragma unroll
    for (int i = 0; i < 3; i++) {
        int c = t + i * 256;
        x[i] = A[off + c] + Bi[off + c];
        s += x[i]; s2 += x[i] * x[i];
    }
    rs[t] = s; rs2[t] = s2; __syncthreads();
    for (int st = 128; st > 0; st >>= 1) {
        if (t < st) { rs[t] += rs[t + st]; rs2[t] += rs2[t + st]; }
        __syncthreads();
    }
    const float mu  = rs[0] * (1.0f / EE);
    const float var = rs2[0] * (1.0f / EE) - mu * mu;
    const float r   = rsqrtf(var + 1e-5f);
#pragma unroll
    for (int i = 0; i < 3; i++) {
        int c = t + i * 256;
        out[off + c] = (x[i] - mu) * r * g[c] + be[c];
    }
}

// ---------------- launch --------------------------------------------------
extern "C" void kernel_launch(void* const* d_in, const int* in_sizes, int n_in,
                              void* d_out, int out_size)
{
    const float* x  = (const float*)d_in[0];
    const float* Wq = (const float*)d_in[1];
    const float* bq = (const float*)d_in[2];
    const float* Wk = (const float*)d_in[3];
    const float* bk = (const float*)d_in[4];
    const float* Wv = (const float*)d_in[5];
    const float* bv = (const float*)d_in[6];
    const float* Wo = (const float*)d_in[7];
    const float* bo = (const float*)d_in[8];
    const float* W1 = (const float*)d_in[9];
    const float* b1 = (const float*)d_in[10];
    const float* W2 = (const float*)d_in[11];
    const float* b2 = (const float*)d_in[12];
    const float* g1 = (const float*)d_in[13];
    const float* be1= (const float*)d_in[14];
    const float* g2 = (const float*)d_in[15];
    const float* be2= (const float*)d_in[16];

    float* out  = (float*)d_out;
    float* attn = out + (size_t)BB * SS * EE;

    float *q, *k, *v, *ctxp, *h, *ff1, *part, *inv;
    cudaGetSymbolAddress((void**)&q,    g_q);
    cudaGetSymbolAddress((void**)&k,    g_k);
    cudaGetSymbolAddress((void**)&v,    g_v);
    cudaGetSymbolAddress((void**)&ctxp, g_ctx);
    cudaGetSymbolAddress((void**)&h,    g_h);
    cudaGetSymbolAddress((void**)&ff1,  g_ff1);
    cudaGetSymbolAddress((void**)&part, g_part);
    cudaGetSymbolAddress((void**)&inv,  g_inv);
    __nv_bfloat16 *wqh,*wql,*wkh,*wkl,*wvh,*wvl,*woh,*wol,*w1h,*w1l,*w2h,*w2l;
    __nv_bfloat16 *qh,*ql,*kh,*kl,*vth,*vtl,*ph,*pl;
    cudaGetSymbolAddress((void**)&wqh, g_wqt_h); cudaGetSymbolAddress((void**)&wql, g_wqt_l);
    cudaGetSymbolAddress((void**)&wkh, g_wkt_h); cudaGetSymbolAddress((void**)&wkl, g_wkt_l);
    cudaGetSymbolAddress((void**)&wvh, g_wvt_h); cudaGetSymbolAddress((void**)&wvl, g_wvt_l);
    cudaGetSymbolAddress((void**)&woh, g_wot_h); cudaGetSymbolAddress((void**)&wol, g_wot_l);
    cudaGetSymbolAddress((void**)&w1h, g_w1t_h); cudaGetSymbolAddress((void**)&w1l, g_w1t_l);
    cudaGetSymbolAddress((void**)&w2h, g_w2t_h); cudaGetSymbolAddress((void**)&w2l, g_w2t_l);
    cudaGetSymbolAddress((void**)&qh, g_qh); cudaGetSymbolAddress((void**)&ql, g_ql);
    cudaGetSymbolAddress((void**)&kh, g_kh); cudaGetSymbolAddress((void**)&kl, g_kl);
    cudaGetSymbolAddress((void**)&vth, g_vth); cudaGetSymbolAddress((void**)&vtl, g_vtl);
    cudaGetSymbolAddress((void**)&ph, g_ph); cudaGetSymbolAddress((void**)&pl, g_pl);

    cudaFuncSetAttribute(scores_mma_kernel, cudaFuncAttributeMaxDynamicSharedMemorySize, 75776);
    cudaFuncSetAttribute(ctx_mma_kernel,    cudaFuncAttributeMaxDynamicSharedMemorySize, 31232);

    // weight transposes + bf16 split
    wtrans_kernel<<<dim3(EE/32,  EE/32),  256>>>(Wq, wqh, wql, EE, EE);
    wtrans_kernel<<<dim3(EE/32,  EE/32),  256>>>(Wk, wkh, wkl, EE, EE);
    wtrans_kernel<<<dim3(EE/32,  EE/32),  256>>>(Wv, wvh, wvl, EE, EE);
    wtrans_kernel<<<dim3(EE/32,  EE/32),  256>>>(Wo, woh, wol, EE, EE);
    wtrans_kernel<<<dim3(FFF/32, EE/32),  256>>>(W1, w1h, w1l, EE, FFF);
    wtrans_kernel<<<dim3(EE/32,  FFF/32), 256>>>(W2, w2h, w2l, FFF, EE);

    dim3 gE (EE / 128,  MM / 128);
    dim3 gFF(FFF / 128, MM / 128);
    const int GSM = 40960;

    gemm_mma_kernel<false><<<gE, 256, GSM>>>(x, wqh, wql, bq, q, EE, EE);
    gemm_mma_kernel<false><<<gE, 256, GSM>>>(x, wkh, wkl, bk, k, EE, EE);
    gemm_mma_kernel<false><<<gE, 256, GSM>>>(x, wvh, wvl, bv, v, EE, EE);

    split_kernel<<<MM*EE/1024, 256>>>(q, qh, ql);
    split_kernel<<<MM*EE/1024, 256>>>(k, kh, kl);
    vtrans_kernel<<<dim3(SS/32, DD/32, BH), 256>>>(v, vth, vtl);

    scores_mma_kernel<<<dim3(SS/128, SS/128, BH), 256, 75776>>>(qh, ql, kh, kl, ph, pl, part);
    rowsum_kernel<<<NROWS / 256, 256>>>(part, inv);
    ctx_mma_kernel<<<dim3(SS/128, BH), 256, 31232>>>(ph, pl, vth, vtl, inv, attn, ctxp);

    gemm_mma_kernel<false><<<gE, 256, GSM>>>(ctxp, woh, wol, bo, q, EE, EE);
    add_ln_kernel<<<MM, 256>>>(x, q, g1, be1, h);

    gemm_mma_kernel<true ><<<gFF, 256, GSM>>>(h, w1h, w1l, b1, ff1, FFF, EE);
    gemm_mma_kernel<false><<<gE, 256, GSM>>>(ff1, w2h, w2l, b2, k, EE, FFF);
    add_ln_kernel<<<MM, 256>>>(h, k, g2, be2, out);
}

// round 7
// speedup vs baseline: 2.6805x; 1.3046x over previous
#include <cuda_runtime.h>
#include <cuda_bf16.h>
#include <cstdint>

#define BB 2
#define SS 2048
#define EE 768
#define HH 12
#define DD 64
#define FFF 3072
#define MM (BB*SS)          // 4096
#define BH (BB*HH)          // 24
#define NROWS (BH*SS)       // 49152
#define NQT (SS/128)        // 16 q-tiles
#define BANDW 3             // ktile in {qt-1, qt, qt+1}

// ---------------- scratch (device globals; no allocation) ----------------
__device__ float g_q  [MM*EE];
__device__ float g_k  [MM*EE];
__device__ float g_v  [MM*EE];
__device__ float g_ctx[MM*EE];
__device__ float g_h  [MM*EE];
__device__ float g_ff1[(size_t)MM*FFF];
__device__ float g_part[(size_t)NROWS*BANDW];
__device__ float g_inv [NROWS];
__device__ __nv_bfloat16 g_wqt_h[EE*EE],  g_wqt_l[EE*EE];
__device__ __nv_bfloat16 g_wkt_h[EE*EE],  g_wkt_l[EE*EE];
__device__ __nv_bfloat16 g_wvt_h[EE*EE],  g_wvt_l[EE*EE];
__device__ __nv_bfloat16 g_wot_h[EE*EE],  g_wot_l[EE*EE];
__device__ __nv_bfloat16 g_w1t_h[EE*FFF], g_w1t_l[EE*FFF];
__device__ __nv_bfloat16 g_w2t_h[EE*FFF], g_w2t_l[EE*FFF];
__device__ __nv_bfloat16 g_qh[MM*EE], g_ql[MM*EE];
__device__ __nv_bfloat16 g_kh[MM*EE], g_kl[MM*EE];
__device__ __nv_bfloat16 g_vth[(size_t)BH*DD*SS], g_vtl[(size_t)BH*DD*SS];
__device__ __nv_bfloat16 g_ph[(size_t)BH*SS*SS], g_pl[(size_t)BH*SS*SS];

// ---------------- helpers ---------------------------------------------------
__device__ __forceinline__ uint32_t smem_u32(const void* p) {
    uint32_t a;
    asm("{ .reg .u64 t; cvta.to.shared.u64 t, %1; cvt.u32.u64 %0, t; }"
        : "=r"(a) : "l"(p));
    return a;
}
__device__ __forceinline__ void ldmx4(uint32_t* r, uint32_t addr) {
    asm volatile("ldmatrix.sync.aligned.m8n8.x4.shared.b16 {%0,%1,%2,%3}, [%4];"
        : "=r"(r[0]), "=r"(r[1]), "=r"(r[2]), "=r"(r[3]) : "r"(addr));
}
__device__ __forceinline__ void ldmx2(uint32_t* r, uint32_t addr) {
    asm volatile("ldmatrix.sync.aligned.m8n8.x2.shared.b16 {%0,%1}, [%2];"
        : "=r"(r[0]), "=r"(r[1]) : "r"(addr));
}
__device__ __forceinline__ void mma_bf16(float* d, const uint32_t* a, const uint32_t* b) {
    asm volatile("mma.sync.aligned.m16n8k16.row.col.f32.bf16.bf16.f32 "
        "{%0,%1,%2,%3}, {%4,%5,%6,%7}, {%8,%9}, {%0,%1,%2,%3};"
        : "+f"(d[0]), "+f"(d[1]), "+f"(d[2]), "+f"(d[3])
        : "r"(a[0]), "r"(a[1]), "r"(a[2]), "r"(a[3]), "r"(b[0]), "r"(b[1]));
}
__device__ __forceinline__ void split2(float x, float y, uint32_t& hi, uint32_t& lo) {
    __nv_bfloat16 hx = __float2bfloat16_rn(x);
    __nv_bfloat16 hy = __float2bfloat16_rn(y);
    __nv_bfloat16 lx = __float2bfloat16_rn(x - __bfloat162float(hx));
    __nv_bfloat16 ly = __float2bfloat16_rn(y - __bfloat162float(hy));
    hi = ((uint32_t)__bfloat16_as_ushort(hy) << 16) | __bfloat16_as_ushort(hx);
    lo = ((uint32_t)__bfloat16_as_ushort(ly) << 16) | __bfloat16_as_ushort(lx);
}

// ---------------- weight transpose+split: W[K][N] -> Th/Tl[N][K] ----------
__global__ __launch_bounds__(256) void wtrans_kernel(
    const float* __restrict__ W, __nv_bfloat16* __restrict__ Th,
    __nv_bfloat16* __restrict__ Tl, int K, int N)
{
    __shared__ float tile[32][33];
    const int n0 = blockIdx.x * 32, k0 = blockIdx.y * 32;
    const int tx = threadIdx.x & 31, ty = threadIdx.x >> 5;
#pragma unroll
    for (int i = 0; i < 32; i += 8)
        tile[ty + i][tx] = W[(size_t)(k0 + ty + i) * N + n0 + tx];
    __syncthreads();
#pragma unroll
    for (int i = 0; i < 32; i += 8) {
        float x = tile[tx][ty + i];
        __nv_bfloat16 h = __float2bfloat16_rn(x);
        __nv_bfloat16 l = __float2bfloat16_rn(x - __bfloat162float(h));
        size_t o = (size_t)(n0 + ty + i) * K + k0 + tx;
        Th[o] = h; Tl[o] = l;
    }
}

// ---------------- elementwise fp32 -> bf16 hi/lo split ---------------------
__global__ __launch_bounds__(256) void split_kernel(
    const float* __restrict__ A, __nv_bfloat16* __restrict__ Ah,
    __nv_bfloat16* __restrict__ Al)
{
    size_t idx = ((size_t)blockIdx.x * 256 + threadIdx.x) * 4;
    float4 v = *(const float4*)&A[idx];
    uint32_t h0, l0, h1, l1;
    split2(v.x, v.y, h0, l0);
    split2(v.z, v.w, h1, l1);
    *(uint2*)&Ah[idx] = make_uint2(h0, h1);
    *(uint2*)&Al[idx] = make_uint2(l0, l1);
}

// ---------------- v transpose+split: v[b,s,h,d] -> vt[bh][d][s] ------------
__global__ __launch_bounds__(256) void vtrans_kernel(
    const float* __restrict__ v, __nv_bfloat16* __restrict__ Th,
    __nv_bfloat16* __restrict__ Tl)
{
    __shared__ float tile[32][33];
    const int s0 = blockIdx.x * 32, d0 = blockIdx.y * 32, bh = blockIdx.z;
    const int b = bh / HH, h = bh % HH;
    const int tx = threadIdx.x & 31, ty = threadIdx.x >> 5;
#pragma unroll
    for (int i = 0; i < 32; i += 8)
        tile[ty + i][tx] = v[(size_t)(b * SS + s0 + ty + i) * EE + h * DD + d0 + tx];
    __syncthreads();
#pragma unroll
    for (int i = 0; i < 32; i += 8) {
        float x = tile[tx][ty + i];
        __nv_bfloat16 hh = __float2bfloat16_rn(x);
        __nv_bfloat16 ll = __float2bfloat16_rn(x - __bfloat162float(hh));
        size_t o = ((size_t)bh * DD + d0 + ty + i) * SS + s0 + tx;
        Th[o] = hh; Tl[o] = ll;
    }
}

// ---------------- bf16 3-split tensor GEMM: C = A @ Wt^T + bias -----------
template<bool RELU>
__global__ __launch_bounds__(256) void gemm_mma_kernel(
    const float* __restrict__ A,
    const __nv_bfloat16* __restrict__ Bth, const __nv_bfloat16* __restrict__ Btl,
    const float* __restrict__ bias, float* __restrict__ C, int N, int K)
{
    extern __shared__ char sm[];
    const int t = threadIdx.x, lane = t & 31, warp = t >> 5;
    const int wm = warp >> 2, wn = warp & 3;
    const int m0 = blockIdx.y * 128, n0 = blockIdx.x * 128;
    const uint32_t sb = smem_u32(sm);

    float acc[4][4][4];
#pragma unroll
    for (int i = 0; i < 4; i++)
#pragma unroll
        for (int j = 0; j < 4; j++)
#pragma unroll
            for (int u = 0; u < 4; u++) acc[i][j][u] = 0.f;

    float4 areg[4];
    uint4  bh_reg[2], bl_reg[2];
    const int ar = t >> 3, ac4 = t & 7;
    const int br = t >> 2, bc8 = t & 3;
    const int nch = K / 32;

#pragma unroll
    for (int i = 0; i < 4; i++)
        areg[i] = *(const float4*)&A[(size_t)(m0 + ar + i * 32) * K + ac4 * 4];
#pragma unroll
    for (int i = 0; i < 2; i++) {
        size_t o = (size_t)(n0 + br + i * 64) * K + bc8 * 8;
        bh_reg[i] = *(const uint4*)&Bth[o];
        bl_reg[i] = *(const uint4*)&Btl[o];
    }

    const uint32_t aAddr = sb + (uint32_t)(wm * 64 + (lane & 15)) * 80
                              + (uint32_t)(lane >> 4) * 16;
    const uint32_t bAddr = sb + 20480
                              + (uint32_t)(wn * 32 + (lane & 7)) * 80
                              + (uint32_t)((lane >> 3) & 1) * 16;

    for (int ch = 0; ch < nch; ch++) {
#pragma unroll
        for (int i = 0; i < 4; i++) {
            uint32_t h0, l0, h1, l1;
            split2(areg[i].x, areg[i].y, h0, l0);
            split2(areg[i].z, areg[i].w, h1, l1);
            uint32_t off = (uint32_t)(ar + i * 32) * 80 + (uint32_t)ac4 * 8;
            *(uint2*)(sm + off)         = make_uint2(h0, h1);
            *(uint2*)(sm + 10240 + off) = make_uint2(l0, l1);
        }
#pragma unroll
        for (int i = 0; i < 2; i++) {
            uint32_t off = (uint32_t)(br + i * 64) * 80 + (uint32_t)bc8 * 16;
            *(uint4*)(sm + 20480 + off) = bh_reg[i];
            *(uint4*)(sm + 30720 + off) = bl_reg[i];
        }
        __syncthreads();

        if (ch + 1 < nch) {
            const int kof = (ch + 1) * 32;
#pragma unroll
            for (int i = 0; i < 4; i++)
                areg[i] = *(const float4*)&A[(size_t)(m0 + ar + i * 32) * K + kof + ac4 * 4];
#pragma unroll
            for (int i = 0; i < 2; i++) {
                size_t o = (size_t)(n0 + br + i * 64) * K + kof + bc8 * 8;
                bh_reg[i] = *(const uint4*)&Bth[o];
                bl_reg[i] = *(const uint4*)&Btl[o];
            }
        }

#pragma unroll
        for (int kk = 0; kk < 2; kk++) {
            uint32_t ah[4][4], al[4][4], bh[4][2], bl[4][2];
#pragma unroll
            for (int i = 0; i < 4; i++) {
                ldmx4(ah[i], aAddr + (uint32_t)i * 1280 + (uint32_t)kk * 32);
                ldmx4(al[i], aAddr + 10240 + (uint32_t)i * 1280 + (uint32_t)kk * 32);
            }
#pragma unroll
            for (int j = 0; j < 4; j++) {
                ldmx2(bh[j], bAddr + (uint32_t)j * 640 + (uint32_t)kk * 32);
                ldmx2(bl[j], bAddr + 10240 + (uint32_t)j * 640 + (uint32_t)kk * 32);
            }
#pragma unroll
            for (int i = 0; i < 4; i++)
#pragma unroll
                for (int j = 0; j < 4; j++) {
                    mma_bf16(acc[i][j], ah[i], bh[j]);
                    mma_bf16(acc[i][j], ah[i], bl[j]);
                    mma_bf16(acc[i][j], al[i], bh[j]);
                }
        }
        __syncthreads();
    }

    const int g = lane >> 2, qd = lane & 3;
#pragma unroll
    for (int i = 0; i < 4; i++) {
        int r0 = m0 + wm * 64 + i * 16 + g;
#pragma unroll
        for (int j = 0; j < 4; j++) {
            int c = n0 + wn * 32 + j * 8 + qd * 2;
            float bx = __ldg(&bias[c]), by = __ldg(&bias[c + 1]);
            float v0 = acc[i][j][0] + bx, v1 = acc[i][j][1] + by;
            float v2 = acc[i][j][2] + bx, v3 = acc[i][j][3] + by;
            if (RELU) {
                v0 = fmaxf(v0, 0.f); v1 = fmaxf(v1, 0.f);
                v2 = fmaxf(v2, 0.f); v3 = fmaxf(v3, 0.f);
            }
            float2 o01 = {v0, v1};
            float2 o23 = {v2, v3};
            *(float2*)&C[(size_t)r0 * N + c]       = o01;
            *(float2*)&C[(size_t)(r0 + 8) * N + c] = o23;
        }
    }
}

// ---------------- scores via MMA (band tiles only) -------------------------
// grid (BANDW, NQT, BH); ktile = qtile + bx - 1. Off-range: zero partials.
// smem: QH@0 QL@18432 KH@36864 KL@55296 (128 rows x 144B), RED@73728 -> 75776
__global__ __launch_bounds__(256) void scores_mma_kernel(
    const __nv_bfloat16* __restrict__ qh, const __nv_bfloat16* __restrict__ ql,
    const __nv_bfloat16* __restrict__ kh, const __nv_bfloat16* __restrict__ kl,
    __nv_bfloat16* __restrict__ Ph, __nv_bfloat16* __restrict__ Pl,
    float* __restrict__ partials)
{
    extern __shared__ char sm[];
    const uint32_t sb = smem_u32(sm);
    const int t = threadIdx.x, lane = t & 31, warp = t >> 5;
    const int wm = warp >> 2, wn = warp & 3;
    const int bh = blockIdx.z, b = bh / HH, h = bh % HH;
    const int qt = blockIdx.y;
    const int kt = qt + (int)blockIdx.x - 1;
    const int q0 = qt * 128;

    if (kt < 0 || kt >= NQT) {
        if (t < 128)
            partials[((size_t)bh * SS + q0 + t) * BANDW + blockIdx.x] = 0.f;
        return;
    }
    const int k0 = kt * 128;
    float* red = (float*)(sm + 73728);   // [128][4]

#pragma unroll
    for (int i = 0; i < 4; i++) {
        int idx = t + i * 256;
        int row = idx >> 3, c = idx & 7;
        uint32_t off = (uint32_t)row * 144 + (uint32_t)c * 16;
        size_t qg = (size_t)(b * SS + q0 + row) * EE + h * DD + c * 8;
        size_t kg = (size_t)(b * SS + k0 + row) * EE + h * DD + c * 8;
        *(uint4*)(sm + off)         = *(const uint4*)&qh[qg];
        *(uint4*)(sm + 18432 + off) = *(const uint4*)&ql[qg];
        *(uint4*)(sm + 36864 + off) = *(const uint4*)&kh[kg];
        *(uint4*)(sm + 55296 + off) = *(const uint4*)&kl[kg];
    }
    __syncthreads();

    float acc[4][4][4];
#pragma unroll
    for (int i = 0; i < 4; i++)
#pragma unroll
        for (int j = 0; j < 4; j++)
#pragma unroll
            for (int u = 0; u < 4; u++) acc[i][j][u] = 0.f;

    const uint32_t aAddr = sb + (uint32_t)(wm * 64 + (lane & 15)) * 144
                              + (uint32_t)(lane >> 4) * 16;
    const uint32_t bAddr = sb + 36864
                              + (uint32_t)(wn * 32 + (lane & 7)) * 144
                              + (uint32_t)((lane >> 3) & 1) * 16;
#pragma unroll
    for (int kk = 0; kk < 4; kk++) {
        uint32_t ah[4][4], al[4][4], bhf[4][2], blf[4][2];
#pragma unroll
        for (int i = 0; i < 4; i++) {
            ldmx4(ah[i], aAddr + (uint32_t)i * 2304 + (uint32_t)kk * 32);
            ldmx4(al[i], aAddr + 18432 + (uint32_t)i * 2304 + (uint32_t)kk * 32);
        }
#pragma unroll
        for (int j = 0; j < 4; j++) {
            ldmx2(bhf[j], bAddr + (uint32_t)j * 1152 + (uint32_t)kk * 32);
            ldmx2(blf[j], bAddr + 18432 + (uint32_t)j * 1152 + (uint32_t)kk * 32);
        }
#pragma unroll
        for (int i = 0; i < 4; i++)
#pragma unroll
            for (int j = 0; j < 4; j++) {
                mma_bf16(acc[i][j], ah[i], bhf[j]);
                mma_bf16(acc[i][j], ah[i], blf[j]);
                mma_bf16(acc[i][j], al[i], bhf[j]);
            }
    }

    const int g = lane >> 2, qd = lane & 3;
#pragma unroll
    for (int i = 0; i < 4; i++) {
        int rloc = wm * 64 + i * 16 + g;
        int qi = q0 + rloc;
        float s0 = 0.f, s1 = 0.f;
#pragma unroll
        for (int j = 0; j < 4; j++) {
            int kj = k0 + wn * 32 + j * 8 + qd * 2;
            float e0 = __expf(acc[i][j][0] * 0.125f - fabsf((float)(qi - kj)));
            float e1 = __expf(acc[i][j][1] * 0.125f - fabsf((float)(qi - kj - 1)));
            float e2 = __expf(acc[i][j][2] * 0.125f - fabsf((float)(qi + 8 - kj)));
            float e3 = __expf(acc[i][j][3] * 0.125f - fabsf((float)(qi + 8 - kj - 1)));
            s0 += e0 + e1; s1 += e2 + e3;
            uint32_t h0, l0, h1, l1;
            split2(e0, e1, h0, l0);
            split2(e2, e3, h1, l1);
            size_t o0 = ((size_t)bh * SS + qi) * SS + kj;
            size_t o1 = ((size_t)bh * SS + qi + 8) * SS + kj;
            *(uint32_t*)(Ph + o0) = h0; *(uint32_t*)(Pl + o0) = l0;
            *(uint32_t*)(Ph + o1) = h1; *(uint32_t*)(Pl + o1) = l1;
        }
        s0 += __shfl_xor_sync(0xFFFFFFFF, s0, 1);
        s0 += __shfl_xor_sync(0xFFFFFFFF, s0, 2);
        s1 += __shfl_xor_sync(0xFFFFFFFF, s1, 1);
        s1 += __shfl_xor_sync(0xFFFFFFFF, s1, 2);
        if (qd == 0) {
            red[rloc * 4 + wn]       = s0;
            red[(rloc + 8) * 4 + wn] = s1;
        }
    }
    __syncthreads();
    if (t < 128) {
        float s = red[t * 4] + red[t * 4 + 1] + red[t * 4 + 2] + red[t * 4 + 3];
        partials[((size_t)bh * SS + q0 + t) * BANDW + blockIdx.x] = s;
    }
}

// ---------------- reduce partial row sums -> 1/sum -------------------------
__global__ __launch_bounds__(256) void rowsum_kernel(
    const float* __restrict__ partials, float* __restrict__ inv)
{
    int r = blockIdx.x * 256 + threadIdx.x;
    float s = 0.f;
#pragma unroll
    for (int i = 0; i < BANDW; i++) s += partials[(size_t)r * BANDW + i];
    inv[r] = 1.0f / s;
}

// ---------------- ctx via MMA (band only); zero-fills off-band attn --------
// smem: PH@0 (10240) PL@10240 VH@20480 (5120) VL@25600, INV@30720 -> 31232
__global__ __launch_bounds__(256) void ctx_mma_kernel(
    const __nv_bfloat16* __restrict__ Ph, const __nv_bfloat16* __restrict__ Pl,
    const __nv_bfloat16* __restrict__ Vth, const __nv_bfloat16* __restrict__ Vtl,
    const float* __restrict__ inv, float* __restrict__ attn,
    float* __restrict__ ctx)
{
    extern __shared__ char sm[];
    const uint32_t sb = smem_u32(sm);
    const int t = threadIdx.x, lane = t & 31, warp = t >> 5;
    const int wm = warp >> 1, wn = warp & 1;
    const int bh = blockIdx.y, b = bh / HH, h = bh % HH;
    const int qt = blockIdx.x;
    const int q0 = qt * 128;
    float* invs = (float*)(sm + 30720);

    if (t < 128) invs[t] = inv[(size_t)bh * SS + q0 + t];
    __syncthreads();

    const __nv_bfloat16* Phb = Ph + (size_t)bh * SS * SS;
    const __nv_bfloat16* Plb = Pl + (size_t)bh * SS * SS;
    float* attnb = attn + (size_t)bh * SS * SS;

    // band tile range and chunk range (chunks of 32)
    const int tlo = (qt > 0) ? qt - 1 : 0;
    const int thi = (qt + 2 < NQT) ? qt + 2 : NQT;
    const int c_lo = tlo * 4, c_hi = thi * 4;

    // zero-fill off-band attn columns (exactly 0 in ref too — fp32 underflow)
    {
        const float4 fz = {0.f, 0.f, 0.f, 0.f};
#pragma unroll
        for (int seg = 0; seg < 2; seg++) {
            const int cbeg = seg ? thi * 128 : 0;
            const int cend = seg ? SS : tlo * 128;
            const int w4 = (cend - cbeg) >> 2;
            if (w4 <= 0) continue;
            const int n4 = 128 * w4;
            for (int i = t; i < n4; i += 256) {
                int row = i / w4, cc = i % w4;
                *(float4*)&attnb[(size_t)(q0 + row) * SS + cbeg + cc * 4] = fz;
            }
        }
    }

    float acc[2][4][4];
#pragma unroll
    for (int i = 0; i < 2; i++)
#pragma unroll
        for (int j = 0; j < 4; j++)
#pragma unroll
            for (int u = 0; u < 4; u++) acc[i][j][u] = 0.f;

    uint4 ph_r[2], pl_r[2], vh_r, vl_r;
    const int vr = t >> 2, vc = t & 3;

    // prologue: load chunk c_lo + write its normalized attn
    {
        const int kt = c_lo * 32;
#pragma unroll
        for (int i = 0; i < 2; i++) {
            int idx = t + i * 256;
            int row = idx >> 2, c = idx & 3;
            size_t go = (size_t)(q0 + row) * SS + kt + c * 8;
            ph_r[i] = *(const uint4*)(Phb + go);
            pl_r[i] = *(const uint4*)(Plb + go);
        }
        vh_r = *(const uint4*)(Vth + ((size_t)bh * DD + vr) * SS + kt + vc * 8);
        vl_r = *(const uint4*)(Vtl + ((size_t)bh * DD + vr) * SS + kt + vc * 8);
#pragma unroll
        for (int i = 0; i < 2; i++) {
            int idx = t + i * 256;
            int row = idx >> 2, c = idx & 3;
            float iv = invs[row];
            const __nv_bfloat162* hp = (const __nv_bfloat162*)&ph_r[i];
            const __nv_bfloat162* lp = (const __nv_bfloat162*)&pl_r[i];
            float out8[8];
#pragma unroll
            for (int u = 0; u < 4; u++) {
                float2 fh = __bfloat1622float2(hp[u]);
                float2 fl = __bfloat1622float2(lp[u]);
                out8[u * 2]     = (fh.x + fl.x) * iv;
                out8[u * 2 + 1] = (fh.y + fl.y) * iv;
            }
            size_t ao = (size_t)(q0 + row) * SS + kt + c * 8;
            *(float4*)(attnb + ao)     = *(float4*)&out8[0];
            *(float4*)(attnb + ao + 4) = *(float4*)&out8[4];
        }
    }

    const uint32_t aAddr = sb + (uint32_t)(wm * 32 + (lane & 15)) * 80
                              + (uint32_t)(lane >> 4) * 16;
    const uint32_t bAddr = sb + 20480
                              + (uint32_t)(wn * 32 + (lane & 7)) * 80
                              + (uint32_t)((lane >> 3) & 1) * 16;

    for (int ch = c_lo; ch < c_hi; ch++) {
#pragma unroll
        for (int i = 0; i < 2; i++) {
            int idx = t + i * 256;
            int row = idx >> 2, c = idx & 3;
            uint32_t off = (uint32_t)row * 80 + (uint32_t)c * 16;
            *(uint4*)(sm + off)         = ph_r[i];
            *(uint4*)(sm + 10240 + off) = pl_r[i];
        }
        {
            uint32_t off = (uint32_t)vr * 80 + (uint32_t)vc * 16;
            *(uint4*)(sm + 20480 + off) = vh_r;
            *(uint4*)(sm + 25600 + off) = vl_r;
        }
        __syncthreads();

        if (ch + 1 < c_hi) {
            const int kt = (ch + 1) * 32;
#pragma unroll
            for (int i = 0; i < 2; i++) {
                int idx = t + i * 256;
                int row = idx >> 2, c = idx & 3;
                size_t go = (size_t)(q0 + row) * SS + kt + c * 8;
                ph_r[i] = *(const uint4*)(Phb + go);
                pl_r[i] = *(const uint4*)(Plb + go);
            }
            vh_r = *(const uint4*)(Vth + ((size_t)bh * DD + vr) * SS + kt + vc * 8);
            vl_r = *(const uint4*)(Vtl + ((size_t)bh * DD + vr) * SS + kt + vc * 8);
#pragma unroll
            for (int i = 0; i < 2; i++) {
                int idx = t + i * 256;
                int row = idx >> 2, c = idx & 3;
                float iv = invs[row];
                const __nv_bfloat162* hp = (const __nv_bfloat162*)&ph_r[i];
                const __nv_bfloat162* lp = (const __nv_bfloat162*)&pl_r[i];
                float out8[8];
#pragma unroll
                for (int u = 0; u < 4; u++) {
                    float2 fh = __bfloat1622float2(hp[u]);
                    float2 fl = __bfloat1622float2(lp[u]);
                    out8[u * 2]     = (fh.x + fl.x) * iv;
                    out8[u * 2 + 1] = (fh.y + fl.y) * iv;
                }
                size_t ao = (size_t)(q0 + row) * SS + kt + c * 8;
                *(float4*)(attnb + ao)     = *(float4*)&out8[0];
                *(float4*)(attnb + ao + 4) = *(float4*)&out8[4];
            }
        }

#pragma unroll
        for (int kk = 0; kk < 2; kk++) {
            uint32_t ah[2][4], al[2][4], bhf[4][2], blf[4][2];
#pragma unroll
            for (int i = 0; i < 2; i++) {
                ldmx4(ah[i], aAddr + (uint32_t)i * 1280 + (uint32_t)kk * 32);
                ldmx4(al[i], aAddr + 10240 + (uint32_t)i * 1280 + (uint32_t)kk * 32);
            }
#pragma unroll
            for (int j = 0; j < 4; j++) {
                ldmx2(bhf[j], bAddr + (uint32_t)j * 640 + (uint32_t)kk * 32);
                ldmx2(blf[j], bAddr + 5120 + (uint32_t)j * 640 + (uint32_t)kk * 32);
            }
#pragma unroll
            for (int i = 0; i < 2; i++)
#pragma unroll
                for (int j = 0; j < 4; j++) {
                    mma_bf16(acc[i][j], ah[i], bhf[j]);
                    mma_bf16(acc[i][j], ah[i], blf[j]);
                    mma_bf16(acc[i][j], al[i], bhf[j]);
                }
        }
        __syncthreads();
    }

    const int g = lane >> 2, qd = lane & 3;
#pragma unroll
    for (int i = 0; i < 2; i++) {
        int rloc = wm * 32 + i * 16 + g;
        float iv0 = invs[rloc], iv1 = invs[rloc + 8];
#pragma unroll
        for (int j = 0; j < 4; j++) {
            int c = wn * 32 + j * 8 + qd * 2;
            float2 o01 = {acc[i][j][0] * iv0, acc[i][j][1] * iv0};
            float2 o23 = {acc[i][j][2] * iv1, acc[i][j][3] * iv1};
            *(float2*)&ctx[((size_t)(b * SS + q0 + rloc) * HH + h) * DD + c]     = o01;
            *(float2*)&ctx[((size_t)(b * SS + q0 + rloc + 8) * HH + h) * DD + c] = o23;
        }
    }
}

// ---------------- out = LayerNorm(A + B) * g + be --------------------------
__global__ __launch_bounds__(256) void add_ln_kernel(
    const float* __restrict__ A, const float* __restrict__ Bi,
    const float* __restrict__ g, const float* __restrict__ be,
    float* __restrict__ out)
{
    __shared__ float rs[256];
    __shared__ float rs2[256];
    const size_t off = (size_t)blockIdx.x * EE;
    const int t = threadIdx.x;
    float x[3];
    float s = 0.f, s2 = 0.f;
#pragma unroll
    for (int i = 0; i < 3; i++) {
        int c = t + i * 256;
        x[i] = A[off + c] + Bi[off + c];
        s += x[i]; s2 += x[i] * x[i];
    }
    rs[t] = s; rs2[t] = s2; __syncthreads();
    for (int st = 128; st > 0; st >>= 1) {
        if (t < st) { rs[t] += rs[t + st]; rs2[t] += rs2[t + st]; }
        __syncthreads();
    }
    const float mu  = rs[0] * (1.0f / EE);
    const float var = rs2[0] * (1.0f / EE) - mu * mu;
    const float r   = rsqrtf(var + 1e-5f);
#pragma unroll
    for (int i = 0; i < 3; i++) {
        int c = t + i * 256;
        out[off + c] = (x[i] - mu) * r * g[c] + be[c];
    }
}

// ---------------- launch --------------------------------------------------
extern "C" void kernel_launch(void* const* d_in, const int* in_sizes, int n_in,
                              void* d_out, int out_size)
{
    const float* x  = (const float*)d_in[0];
    const float* Wq = (const float*)d_in[1];
    const float* bq = (const float*)d_in[2];
    const float* Wk = (const float*)d_in[3];
    const float* bk = (const float*)d_in[4];
    const float* Wv = (const float*)d_in[5];
    const float* bv = (const float*)d_in[6];
    const float* Wo = (const float*)d_in[7];
    const float* bo = (const float*)d_in[8];
    const float* W1 = (const float*)d_in[9];
    const float* b1 = (const float*)d_in[10];
    const float* W2 = (const float*)d_in[11];
    const float* b2 = (const float*)d_in[12];
    const float* g1 = (const float*)d_in[13];
    const float* be1= (const float*)d_in[14];
    const float* g2 = (const float*)d_in[15];
    const float* be2= (const float*)d_in[16];

    float* out  = (float*)d_out;
    float* attn = out + (size_t)BB * SS * EE;

    float *q, *k, *v, *ctxp, *h, *ff1, *part, *inv;
    cudaGetSymbolAddress((void**)&q,    g_q);
    cudaGetSymbolAddress((void**)&k,    g_k);
    cudaGetSymbolAddress((void**)&v,    g_v);
    cudaGetSymbolAddress((void**)&ctxp, g_ctx);
    cudaGetSymbolAddress((void**)&h,    g_h);
    cudaGetSymbolAddress((void**)&ff1,  g_ff1);
    cudaGetSymbolAddress((void**)&part, g_part);
    cudaGetSymbolAddress((void**)&inv,  g_inv);
    __nv_bfloat16 *wqh,*wql,*wkh,*wkl,*wvh,*wvl,*woh,*wol,*w1h,*w1l,*w2h,*w2l;
    __nv_bfloat16 *qh,*ql,*kh,*kl,*vth,*vtl,*ph,*pl;
    cudaGetSymbolAddress((void**)&wqh, g_wqt_h); cudaGetSymbolAddress((void**)&wql, g_wqt_l);
    cudaGetSymbolAddress((void**)&wkh, g_wkt_h); cudaGetSymbolAddress((void**)&wkl, g_wkt_l);
    cudaGetSymbolAddress((void**)&wvh, g_wvt_h); cudaGetSymbolAddress((void**)&wvl, g_wvt_l);
    cudaGetSymbolAddress((void**)&woh, g_wot_h); cudaGetSymbolAddress((void**)&wol, g_wot_l);
    cudaGetSymbolAddress((void**)&w1h, g_w1t_h); cudaGetSymbolAddress((void**)&w1l, g_w1t_l);
    cudaGetSymbolAddress((void**)&w2h, g_w2t_h); cudaGetSymbolAddress((void**)&w2l, g_w2t_l);
    cudaGetSymbolAddress((void**)&qh, g_qh); cudaGetSymbolAddress((void**)&ql, g_ql);
    cudaGetSymbolAddress((void**)&kh, g_kh); cudaGetSymbolAddress((void**)&kl, g_kl);
    cudaGetSymbolAddress((void**)&vth, g_vth); cudaGetSymbolAddress((void**)&vtl, g_vtl);
    cudaGetSymbolAddress((void**)&ph, g_ph); cudaGetSymbolAddress((void**)&pl, g_pl);

    cudaFuncSetAttribute(scores_mma_kernel, cudaFuncAttributeMaxDynamicSharedMemorySize, 75776);
    cudaFuncSetAttribute(ctx_mma_kernel,    cudaFuncAttributeMaxDynamicSharedMemorySize, 31232);

    // weight transposes + bf16 split
    wtrans_kernel<<<dim3(EE/32,  EE/32),  256>>>(Wq, wqh, wql, EE, EE);
    wtrans_kernel<<<dim3(EE/32,  EE/32),  256>>>(Wk, wkh, wkl, EE, EE);
    wtrans_kernel<<<dim3(EE/32,  EE/32),  256>>>(Wv, wvh, wvl, EE, EE);
    wtrans_kernel<<<dim3(EE/32,  EE/32),  256>>>(Wo, woh, wol, EE, EE);
    wtrans_kernel<<<dim3(FFF/32, EE/32),  256>>>(W1, w1h, w1l, EE, FFF);
    wtrans_kernel<<<dim3(EE/32,  FFF/32), 256>>>(W2, w2h, w2l, FFF, EE);

    dim3 gE (EE / 128,  MM / 128);
    dim3 gFF(FFF / 128, MM / 128);
    const int GSM = 40960;

    gemm_mma_kernel<false><<<gE, 256, GSM>>>(x, wqh, wql, bq, q, EE, EE);
    gemm_mma_kernel<false><<<gE, 256, GSM>>>(x, wkh, wkl, bk, k, EE, EE);
    gemm_mma_kernel<false><<<gE, 256, GSM>>>(x, wvh, wvl, bv, v, EE, EE);

    split_kernel<<<MM*EE/1024, 256>>>(q, qh, ql);
    split_kernel<<<MM*EE/1024, 256>>>(k, kh, kl);
    vtrans_kernel<<<dim3(SS/32, DD/32, BH), 256>>>(v, vth, vtl);

    scores_mma_kernel<<<dim3(BANDW, NQT, BH), 256, 75776>>>(qh, ql, kh, kl, ph, pl, part);
    rowsum_kernel<<<NROWS / 256, 256>>>(part, inv);
    ctx_mma_kernel<<<dim3(NQT, BH), 256, 31232>>>(ph, pl, vth, vtl, inv, attn, ctxp);

    gemm_mma_kernel<false><<<gE, 256, GSM>>>(ctxp, woh, wol, bo, q, EE, EE);
    add_ln_kernel<<<MM, 256>>>(x, q, g1, be1, h);

    gemm_mma_kernel<true ><<<gFF, 256, GSM>>>(h, w1h, w1l, b1, ff1, FFF, EE);
    gemm_mma_kernel<false><<<gE, 256, GSM>>>(ff1, w2h, w2l, b2, k, EE, FFF);
    add_ln_kernel<<<MM, 256>>>(h, k, g2, be2, out);
}

// round 8
// speedup vs baseline: 3.1002x; 1.1566x over previous
#include <cuda_runtime.h>
#include <cuda_bf16.h>
#include <cstdint>

#define BB 2
#define SS 2048
#define EE 768
#define HH 12
#define DD 64
#define FFF 3072
#define MM (BB*SS)          // 4096
#define BH (BB*HH)          // 24
#define NROWS (BH*SS)       // 49152
#define NQT (SS/128)        // 16 q-tiles
#define BANDW 3             // ktile in {qt-1, qt, qt+1}

// ---------------- scratch (device globals; no allocation) ----------------
__device__ float g_attnout[MM*EE];
__device__ float g_h  [MM*EE];
__device__ float g_ff2[MM*EE];
__device__ float g_part[(size_t)NROWS*BANDW];
__device__ float g_inv [NROWS];
__device__ __nv_bfloat16 g_wqt_h[EE*EE],  g_wqt_l[EE*EE];
__device__ __nv_bfloat16 g_wkt_h[EE*EE],  g_wkt_l[EE*EE];
__device__ __nv_bfloat16 g_wvt_h[EE*EE],  g_wvt_l[EE*EE];
__device__ __nv_bfloat16 g_wot_h[EE*EE],  g_wot_l[EE*EE];
__device__ __nv_bfloat16 g_w1t_h[EE*FFF], g_w1t_l[EE*FFF];
__device__ __nv_bfloat16 g_w2t_h[EE*FFF], g_w2t_l[EE*FFF];
__device__ __nv_bfloat16 g_xh[MM*EE],  g_xl[MM*EE];
__device__ __nv_bfloat16 g_qh[MM*EE],  g_ql[MM*EE];
__device__ __nv_bfloat16 g_kh[MM*EE],  g_kl[MM*EE];
__device__ __nv_bfloat16 g_vh[MM*EE],  g_vl[MM*EE];
__device__ __nv_bfloat16 g_hh[MM*EE],  g_hl[MM*EE];
__device__ __nv_bfloat16 g_ctxh[MM*EE], g_ctxl[MM*EE];
__device__ __nv_bfloat16 g_f1h[(size_t)MM*FFF], g_f1l[(size_t)MM*FFF];
__device__ __nv_bfloat16 g_vth[(size_t)BH*DD*SS], g_vtl[(size_t)BH*DD*SS];
__device__ __nv_bfloat16 g_ph[(size_t)BH*SS*SS], g_pl[(size_t)BH*SS*SS];

// ---------------- helpers ---------------------------------------------------
__device__ __forceinline__ uint32_t smem_u32(const void* p) {
    uint32_t a;
    asm("{ .reg .u64 t; cvta.to.shared.u64 t, %1; cvt.u32.u64 %0, t; }"
        : "=r"(a) : "l"(p));
    return a;
}
__device__ __forceinline__ void ldmx4(uint32_t* r, uint32_t addr) {
    asm volatile("ldmatrix.sync.aligned.m8n8.x4.shared.b16 {%0,%1,%2,%3}, [%4];"
        : "=r"(r[0]), "=r"(r[1]), "=r"(r[2]), "=r"(r[3]) : "r"(addr));
}
__device__ __forceinline__ void ldmx2(uint32_t* r, uint32_t addr) {
    asm volatile("ldmatrix.sync.aligned.m8n8.x2.shared.b16 {%0,%1}, [%2];"
        : "=r"(r[0]), "=r"(r[1]) : "r"(addr));
}
__device__ __forceinline__ void mma_bf16(float* d, const uint32_t* a, const uint32_t* b) {
    asm volatile("mma.sync.aligned.m16n8k16.row.col.f32.bf16.bf16.f32 "
        "{%0,%1,%2,%3}, {%4,%5,%6,%7}, {%8,%9}, {%0,%1,%2,%3};"
        : "+f"(d[0]), "+f"(d[1]), "+f"(d[2]), "+f"(d[3])
        : "r"(a[0]), "r"(a[1]), "r"(a[2]), "r"(a[3]), "r"(b[0]), "r"(b[1]));
}
__device__ __forceinline__ void split2(float x, float y, uint32_t& hi, uint32_t& lo) {
    __nv_bfloat16 hx = __float2bfloat16_rn(x);
    __nv_bfloat16 hy = __float2bfloat16_rn(y);
    __nv_bfloat16 lx = __float2bfloat16_rn(x - __bfloat162float(hx));
    __nv_bfloat16 ly = __float2bfloat16_rn(y - __bfloat162float(hy));
    hi = ((uint32_t)__bfloat16_as_ushort(hy) << 16) | __bfloat16_as_ushort(hx);
    lo = ((uint32_t)__bfloat16_as_ushort(ly) << 16) | __bfloat16_as_ushort(lx);
}
__device__ __forceinline__ void cp16(uint32_t s, const void* g) {
    asm volatile("cp.async.cg.shared.global [%0], [%1], 16;" :: "r"(s), "l"(g));
}
__device__ __forceinline__ void cpcommit() {
    asm volatile("cp.async.commit_group;" ::: "memory");
}
__device__ __forceinline__ void cpwait1() {
    asm volatile("cp.async.wait_group 1;" ::: "memory");
}
__device__ __forceinline__ void cpwait0() {
    asm volatile("cp.async.wait_group 0;" ::: "memory");
}

// ---------------- weight transpose+split: W[K][N] -> Th/Tl[N][K] ----------
__global__ __launch_bounds__(256) void wtrans_kernel(
    const float* __restrict__ W, __nv_bfloat16* __restrict__ Th,
    __nv_bfloat16* __restrict__ Tl, int K, int N)
{
    __shared__ float tile[32][33];
    const int n0 = blockIdx.x * 32, k0 = blockIdx.y * 32;
    const int tx = threadIdx.x & 31, ty = threadIdx.x >> 5;
#pragma unroll
    for (int i = 0; i < 32; i += 8)
        tile[ty + i][tx] = W[(size_t)(k0 + ty + i) * N + n0 + tx];
    __syncthreads();
#pragma unroll
    for (int i = 0; i < 32; i += 8) {
        float x = tile[tx][ty + i];
        __nv_bfloat16 h = __float2bfloat16_rn(x);
        __nv_bfloat16 l = __float2bfloat16_rn(x - __bfloat162float(h));
        size_t o = (size_t)(n0 + ty + i) * K + k0 + tx;
        Th[o] = h; Tl[o] = l;
    }
}

// ---------------- elementwise fp32 -> bf16 hi/lo split ---------------------
__global__ __launch_bounds__(256) void split_kernel(
    const float* __restrict__ A, __nv_bfloat16* __restrict__ Ah,
    __nv_bfloat16* __restrict__ Al)
{
    size_t idx = ((size_t)blockIdx.x * 256 + threadIdx.x) * 4;
    float4 v = *(const float4*)&A[idx];
    uint32_t h0, l0, h1, l1;
    split2(v.x, v.y, h0, l0);
    split2(v.z, v.w, h1, l1);
    *(uint2*)&Ah[idx] = make_uint2(h0, h1);
    *(uint2*)&Al[idx] = make_uint2(l0, l1);
}

// ---------------- v transpose (from pairs): -> vt[bh][d][s] pairs ----------
__global__ __launch_bounds__(256) void vtrans_kernel(
    const __nv_bfloat16* __restrict__ vh, const __nv_bfloat16* __restrict__ vl,
    __nv_bfloat16* __restrict__ Th, __nv_bfloat16* __restrict__ Tl)
{
    __shared__ float tile[32][33];
    const int s0 = blockIdx.x * 32, d0 = blockIdx.y * 32, bh = blockIdx.z;
    const int b = bh / HH, h = bh % HH;
    const int tx = threadIdx.x & 31, ty = threadIdx.x >> 5;
#pragma unroll
    for (int i = 0; i < 32; i += 8) {
        size_t o = (size_t)(b * SS + s0 + ty + i) * EE + h * DD + d0 + tx;
        tile[ty + i][tx] = __bfloat162float(vh[o]) + __bfloat162float(vl[o]);
    }
    __syncthreads();
#pragma unroll
    for (int i = 0; i < 32; i += 8) {
        float x = tile[tx][ty + i];
        __nv_bfloat16 hh = __float2bfloat16_rn(x);
        __nv_bfloat16 ll = __float2bfloat16_rn(x - __bfloat162float(hh));
        size_t o = ((size_t)bh * DD + d0 + ty + i) * SS + s0 + tx;
        Th[o] = hh; Tl[o] = ll;
    }
}

// ---------------- bf16 3-split GEMM (pre-split A, cp.async pipeline) -------
// A pairs [M][K], B pairs [N][K]. Tile 128x128, BK=32, 256 threads.
// smem: double buffer, each 40960: Ah@0 Al@10240 Bh@20480 Bl@30720; total 81920.
// EMIT: 0 = fp32 C, 1 = bf16 hi/lo pair C.
template<int EMIT, bool RELU>
__global__ __launch_bounds__(256) void gemm_mma_kernel(
    const __nv_bfloat16* __restrict__ Ath, const __nv_bfloat16* __restrict__ Atl,
    const __nv_bfloat16* __restrict__ Bth, const __nv_bfloat16* __restrict__ Btl,
    const float* __restrict__ bias, float* __restrict__ Cf,
    __nv_bfloat16* __restrict__ Ch, __nv_bfloat16* __restrict__ Cl,
    int N, int K)
{
    extern __shared__ char sm[];
    const int t = threadIdx.x, lane = t & 31, warp = t >> 5;
    const int wm = warp >> 2, wn = warp & 3;
    const int m0 = blockIdx.y * 128, n0 = blockIdx.x * 128;
    const uint32_t sb = smem_u32(sm);
    const int nch = K / 32;

    float acc[4][4][4];
#pragma unroll
    for (int i = 0; i < 4; i++)
#pragma unroll
        for (int j = 0; j < 4; j++)
#pragma unroll
            for (int u = 0; u < 4; u++) acc[i][j][u] = 0.f;

    // cp.async mapping: 512 x 16B per matrix per chunk; row = idx>>2, c16 = idx&3
    const int r0i = t >> 2, c16 = t & 3;

    // prologue: chunk 0 -> buffer 0
    {
        const int koff = 0;
#pragma unroll
        for (int i = 0; i < 2; i++) {
            int row = r0i + i * 64;
            uint32_t so = (uint32_t)row * 80 + (uint32_t)c16 * 16;
            cp16(sb + so,         Ath + (size_t)(m0 + row) * K + koff + c16 * 8);
            cp16(sb + 10240 + so, Atl + (size_t)(m0 + row) * K + koff + c16 * 8);
            cp16(sb + 20480 + so, Bth + (size_t)(n0 + row) * K + koff + c16 * 8);
            cp16(sb + 30720 + so, Btl + (size_t)(n0 + row) * K + koff + c16 * 8);
        }
        cpcommit();
    }

    const uint32_t aBase = sb + (uint32_t)(wm * 64 + (lane & 15)) * 80
                              + (uint32_t)(lane >> 4) * 16;
    const uint32_t bBase = sb + 20480
                              + (uint32_t)(wn * 32 + (lane & 7)) * 80
                              + (uint32_t)((lane >> 3) & 1) * 16;

    for (int ch = 0; ch < nch; ch++) {
        if (ch + 1 < nch) {
            const int koff = (ch + 1) * 32;
            const uint32_t bp = (uint32_t)((ch + 1) & 1) * 40960;
#pragma unroll
            for (int i = 0; i < 2; i++) {
                int row = r0i + i * 64;
                uint32_t so = bp + (uint32_t)row * 80 + (uint32_t)c16 * 16;
                cp16(sb + so,         Ath + (size_t)(m0 + row) * K + koff + c16 * 8);
                cp16(sb + 10240 + so, Atl + (size_t)(m0 + row) * K + koff + c16 * 8);
                cp16(sb + 20480 + so, Bth + (size_t)(n0 + row) * K + koff + c16 * 8);
                cp16(sb + 30720 + so, Btl + (size_t)(n0 + row) * K + koff + c16 * 8);
            }
            cpcommit();
            cpwait1();
        } else {
            cpwait0();
        }
        __syncthreads();

        const uint32_t bp = (uint32_t)(ch & 1) * 40960;
#pragma unroll
        for (int kk = 0; kk < 2; kk++) {
            uint32_t ah[4][4], al[4][4], bh[4][2], bl[4][2];
#pragma unroll
            for (int i = 0; i < 4; i++) {
                ldmx4(ah[i], aBase + bp + (uint32_t)i * 1280 + (uint32_t)kk * 32);
                ldmx4(al[i], aBase + bp + 10240 + (uint32_t)i * 1280 + (uint32_t)kk * 32);
            }
#pragma unroll
            for (int j = 0; j < 4; j++) {
                ldmx2(bh[j], bBase + bp + (uint32_t)j * 640 + (uint32_t)kk * 32);
                ldmx2(bl[j], bBase + bp + 10240 + (uint32_t)j * 640 + (uint32_t)kk * 32);
            }
#pragma unroll
            for (int i = 0; i < 4; i++)
#pragma unroll
                for (int j = 0; j < 4; j++) {
                    mma_bf16(acc[i][j], ah[i], bh[j]);
                    mma_bf16(acc[i][j], ah[i], bl[j]);
                    mma_bf16(acc[i][j], al[i], bh[j]);
                }
        }
        __syncthreads();
    }

    const int g = lane >> 2, qd = lane & 3;
#pragma unroll
    for (int i = 0; i < 4; i++) {
        int r0 = m0 + wm * 64 + i * 16 + g;
#pragma unroll
        for (int j = 0; j < 4; j++) {
            int c = n0 + wn * 32 + j * 8 + qd * 2;
            float bx = __ldg(&bias[c]), by = __ldg(&bias[c + 1]);
            float v0 = acc[i][j][0] + bx, v1 = acc[i][j][1] + by;
            float v2 = acc[i][j][2] + bx, v3 = acc[i][j][3] + by;
            if (RELU) {
                v0 = fmaxf(v0, 0.f); v1 = fmaxf(v1, 0.f);
                v2 = fmaxf(v2, 0.f); v3 = fmaxf(v3, 0.f);
            }
            if (EMIT == 0) {
                float2 o01 = {v0, v1};
                float2 o23 = {v2, v3};
                *(float2*)&Cf[(size_t)r0 * N + c]       = o01;
                *(float2*)&Cf[(size_t)(r0 + 8) * N + c] = o23;
            } else {
                uint32_t h01, l01, h23, l23;
                split2(v0, v1, h01, l01);
                split2(v2, v3, h23, l23);
                *(uint32_t*)&Ch[(size_t)r0 * N + c]       = h01;
                *(uint32_t*)&Cl[(size_t)r0 * N + c]       = l01;
                *(uint32_t*)&Ch[(size_t)(r0 + 8) * N + c] = h23;
                *(uint32_t*)&Cl[(size_t)(r0 + 8) * N + c] = l23;
            }
        }
    }
}

// ---------------- scores via MMA (band tiles only) -------------------------
// smem: QH@0 QL@18432 KH@36864 KL@55296 (128 rows x 144B), RED@73728 -> 75776
__global__ __launch_bounds__(256) void scores_mma_kernel(
    const __nv_bfloat16* __restrict__ qh, const __nv_bfloat16* __restrict__ ql,
    const __nv_bfloat16* __restrict__ kh, const __nv_bfloat16* __restrict__ kl,
    __nv_bfloat16* __restrict__ Ph, __nv_bfloat16* __restrict__ Pl,
    float* __restrict__ partials)
{
    extern __shared__ char sm[];
    const uint32_t sb = smem_u32(sm);
    const int t = threadIdx.x, lane = t & 31, warp = t >> 5;
    const int wm = warp >> 2, wn = warp & 3;
    const int bh = blockIdx.z, b = bh / HH, h = bh % HH;
    const int qt = blockIdx.y;
    const int kt = qt + (int)blockIdx.x - 1;
    const int q0 = qt * 128;

    if (kt < 0 || kt >= NQT) {
        if (t < 128)
            partials[((size_t)bh * SS + q0 + t) * BANDW + blockIdx.x] = 0.f;
        return;
    }
    const int k0 = kt * 128;
    float* red = (float*)(sm + 73728);   // [128][4]

#pragma unroll
    for (int i = 0; i < 4; i++) {
        int idx = t + i * 256;
        int row = idx >> 3, c = idx & 7;
        uint32_t off = (uint32_t)row * 144 + (uint32_t)c * 16;
        size_t qg = (size_t)(b * SS + q0 + row) * EE + h * DD + c * 8;
        size_t kg = (size_t)(b * SS + k0 + row) * EE + h * DD + c * 8;
        *(uint4*)(sm + off)         = *(const uint4*)&qh[qg];
        *(uint4*)(sm + 18432 + off) = *(const uint4*)&ql[qg];
        *(uint4*)(sm + 36864 + off) = *(const uint4*)&kh[kg];
        *(uint4*)(sm + 55296 + off) = *(const uint4*)&kl[kg];
    }
    __syncthreads();

    float acc[4][4][4];
#pragma unroll
    for (int i = 0; i < 4; i++)
#pragma unroll
        for (int j = 0; j < 4; j++)
#pragma unroll
            for (int u = 0; u < 4; u++) acc[i][j][u] = 0.f;

    const uint32_t aAddr = sb + (uint32_t)(wm * 64 + (lane & 15)) * 144
                              + (uint32_t)(lane >> 4) * 16;
    const uint32_t bAddr = sb + 36864
                              + (uint32_t)(wn * 32 + (lane & 7)) * 144
                              + (uint32_t)((lane >> 3) & 1) * 16;
#pragma unroll
    for (int kk = 0; kk < 4; kk++) {
        uint32_t ah[4][4], al[4][4], bhf[4][2], blf[4][2];
#pragma unroll
        for (int i = 0; i < 4; i++) {
            ldmx4(ah[i], aAddr + (uint32_t)i * 2304 + (uint32_t)kk * 32);
            ldmx4(al[i], aAddr + 18432 + (uint32_t)i * 2304 + (uint32_t)kk * 32);
        }
#pragma unroll
        for (int j = 0; j < 4; j++) {
            ldmx2(bhf[j], bAddr + (uint32_t)j * 1152 + (uint32_t)kk * 32);
            ldmx2(blf[j], bAddr + 18432 + (uint32_t)j * 1152 + (uint32_t)kk * 32);
        }
#pragma unroll
        for (int i = 0; i < 4; i++)
#pragma unroll
            for (int j = 0; j < 4; j++) {
                mma_bf16(acc[i][j], ah[i], bhf[j]);
                mma_bf16(acc[i][j], ah[i], blf[j]);
                mma_bf16(acc[i][j], al[i], bhf[j]);
            }
    }

    const int g = lane >> 2, qd = lane & 3;
#pragma unroll
    for (int i = 0; i < 4; i++) {
        int rloc = wm * 64 + i * 16 + g;
        int qi = q0 + rloc;
        float s0 = 0.f, s1 = 0.f;
#pragma unroll
        for (int j = 0; j < 4; j++) {
            int kj = k0 + wn * 32 + j * 8 + qd * 2;
            float e0 = __expf(acc[i][j][0] * 0.125f - fabsf((float)(qi - kj)));
            float e1 = __expf(acc[i][j][1] * 0.125f - fabsf((float)(qi - kj - 1)));
            float e2 = __expf(acc[i][j][2] * 0.125f - fabsf((float)(qi + 8 - kj)));
            float e3 = __expf(acc[i][j][3] * 0.125f - fabsf((float)(qi + 8 - kj - 1)));
            s0 += e0 + e1; s1 += e2 + e3;
            uint32_t h0, l0, h1, l1;
            split2(e0, e1, h0, l0);
            split2(e2, e3, h1, l1);
            size_t o0 = ((size_t)bh * SS + qi) * SS + kj;
            size_t o1 = ((size_t)bh * SS + qi + 8) * SS + kj;
            *(uint32_t*)(Ph + o0) = h0; *(uint32_t*)(Pl + o0) = l0;
            *(uint32_t*)(Ph + o1) = h1; *(uint32_t*)(Pl + o1) = l1;
        }
        s0 += __shfl_xor_sync(0xFFFFFFFF, s0, 1);
        s0 += __shfl_xor_sync(0xFFFFFFFF, s0, 2);
        s1 += __shfl_xor_sync(0xFFFFFFFF, s1, 1);
        s1 += __shfl_xor_sync(0xFFFFFFFF, s1, 2);
        if (qd == 0) {
            red[rloc * 4 + wn]       = s0;
            red[(rloc + 8) * 4 + wn] = s1;
        }
    }
    __syncthreads();
    if (t < 128) {
        float s = red[t * 4] + red[t * 4 + 1] + red[t * 4 + 2] + red[t * 4 + 3];
        partials[((size_t)bh * SS + q0 + t) * BANDW + blockIdx.x] = s;
    }
}

// ---------------- reduce partial row sums -> 1/sum -------------------------
__global__ __launch_bounds__(256) void rowsum_kernel(
    const float* __restrict__ partials, float* __restrict__ inv)
{
    int r = blockIdx.x * 256 + threadIdx.x;
    float s = 0.f;
#pragma unroll
    for (int i = 0; i < BANDW; i++) s += partials[(size_t)r * BANDW + i];
    inv[r] = 1.0f / s;
}

// ---------------- ctx via MMA (band only); emits ctx bf16 pairs ------------
// smem: PH@0 (10240) PL@10240 VH@20480 (5120) VL@25600, INV@30720 -> 31232
__global__ __launch_bounds__(256) void ctx_mma_kernel(
    const __nv_bfloat16* __restrict__ Ph, const __nv_bfloat16* __restrict__ Pl,
    const __nv_bfloat16* __restrict__ Vth, const __nv_bfloat16* __restrict__ Vtl,
    const float* __restrict__ inv, float* __restrict__ attn,
    __nv_bfloat16* __restrict__ ctxh, __nv_bfloat16* __restrict__ ctxl)
{
    extern __shared__ char sm[];
    const uint32_t sb = smem_u32(sm);
    const int t = threadIdx.x, lane = t & 31, warp = t >> 5;
    const int wm = warp >> 1, wn = warp & 1;
    const int bh = blockIdx.y, b = bh / HH, h = bh % HH;
    const int qt = blockIdx.x;
    const int q0 = qt * 128;
    float* invs = (float*)(sm + 30720);

    if (t < 128) invs[t] = inv[(size_t)bh * SS + q0 + t];
    __syncthreads();

    const __nv_bfloat16* Phb = Ph + (size_t)bh * SS * SS;
    const __nv_bfloat16* Plb = Pl + (size_t)bh * SS * SS;
    float* attnb = attn + (size_t)bh * SS * SS;

    const int tlo = (qt > 0) ? qt - 1 : 0;
    const int thi = (qt + 2 < NQT) ? qt + 2 : NQT;
    const int c_lo = tlo * 4, c_hi = thi * 4;

    // zero-fill off-band attn columns (exactly 0 in ref too — fp32 underflow)
    {
        const float4 fz = {0.f, 0.f, 0.f, 0.f};
#pragma unroll
        for (int seg = 0; seg < 2; seg++) {
            const int cbeg = seg ? thi * 128 : 0;
            const int cend = seg ? SS : tlo * 128;
            const int w4 = (cend - cbeg) >> 2;
            if (w4 <= 0) continue;
            const int n4 = 128 * w4;
            for (int i = t; i < n4; i += 256) {
                int row = i / w4, cc = i % w4;
                *(float4*)&attnb[(size_t)(q0 + row) * SS + cbeg + cc * 4] = fz;
            }
        }
    }

    float acc[2][4][4];
#pragma unroll
    for (int i = 0; i < 2; i++)
#pragma unroll
        for (int j = 0; j < 4; j++)
#pragma unroll
            for (int u = 0; u < 4; u++) acc[i][j][u] = 0.f;

    uint4 ph_r[2], pl_r[2], vh_r, vl_r;
    const int vr = t >> 2, vc = t & 3;

    // prologue: load chunk c_lo + write its normalized attn
    {
        const int kt = c_lo * 32;
#pragma unroll
        for (int i = 0; i < 2; i++) {
            int idx = t + i * 256;
            int row = idx >> 2, c = idx & 3;
            size_t go = (size_t)(q0 + row) * SS + kt + c * 8;
            ph_r[i] = *(const uint4*)(Phb + go);
            pl_r[i] = *(const uint4*)(Plb + go);
        }
        vh_r = *(const uint4*)(Vth + ((size_t)bh * DD + vr) * SS + kt + vc * 8);
        vl_r = *(const uint4*)(Vtl + ((size_t)bh * DD + vr) * SS + kt + vc * 8);
#pragma unroll
        for (int i = 0; i < 2; i++) {
            int idx = t + i * 256;
            int row = idx >> 2, c = idx & 3;
            float iv = invs[row];
            const __nv_bfloat162* hp = (const __nv_bfloat162*)&ph_r[i];
            const __nv_bfloat162* lp = (const __nv_bfloat162*)&pl_r[i];
            float out8[8];
#pragma unroll
            for (int u = 0; u < 4; u++) {
                float2 fh = __bfloat1622float2(hp[u]);
                float2 fl = __bfloat1622float2(lp[u]);
                out8[u * 2]     = (fh.x + fl.x) * iv;
                out8[u * 2 + 1] = (fh.y + fl.y) * iv;
            }
            size_t ao = (size_t)(q0 + row) * SS + kt + c * 8;
            *(float4*)(attnb + ao)     = *(float4*)&out8[0];
            *(float4*)(attnb + ao + 4) = *(float4*)&out8[4];
        }
    }

    const uint32_t aAddr = sb + (uint32_t)(wm * 32 + (lane & 15)) * 80
                              + (uint32_t)(lane >> 4) * 16;
    const uint32_t bAddr = sb + 20480
                              + (uint32_t)(wn * 32 + (lane & 7)) * 80
                              + (uint32_t)((lane >> 3) & 1) * 16;

    for (int ch = c_lo; ch < c_hi; ch++) {
#pragma unroll
        for (int i = 0; i < 2; i++) {
            int idx = t + i * 256;
            int row = idx >> 2, c = idx & 3;
            uint32_t off = (uint32_t)row * 80 + (uint32_t)c * 16;
            *(uint4*)(sm + off)         = ph_r[i];
            *(uint4*)(sm + 10240 + off) = pl_r[i];
        }
        {
            uint32_t off = (uint32_t)vr * 80 + (uint32_t)vc * 16;
            *(uint4*)(sm + 20480 + off) = vh_r;
            *(uint4*)(sm + 25600 + off) = vl_r;
        }
        __syncthreads();

        if (ch + 1 < c_hi) {
            const int kt = (ch + 1) * 32;
#pragma unroll
            for (int i = 0; i < 2; i++) {
                int idx = t + i * 256;
                int row = idx >> 2, c = idx & 3;
                size_t go = (size_t)(q0 + row) * SS + kt + c * 8;
                ph_r[i] = *(const uint4*)(Phb + go);
                pl_r[i] = *(const uint4*)(Plb + go);
            }
            vh_r = *(const uint4*)(Vth + ((size_t)bh * DD + vr) * SS + kt + vc * 8);
            vl_r = *(const uint4*)(Vtl + ((size_t)bh * DD + vr) * SS + kt + vc * 8);
#pragma unroll
            for (int i = 0; i < 2; i++) {
                int idx = t + i * 256;
                int row = idx >> 2, c = idx & 3;
                float iv = invs[row];
                const __nv_bfloat162* hp = (const __nv_bfloat162*)&ph_r[i];
                const __nv_bfloat162* lp = (const __nv_bfloat162*)&pl_r[i];
                float out8[8];
#pragma unroll
                for (int u = 0; u < 4; u++) {
                    float2 fh = __bfloat1622float2(hp[u]);
                    float2 fl = __bfloat1622float2(lp[u]);
                    out8[u * 2]     = (fh.x + fl.x) * iv;
                    out8[u * 2 + 1] = (fh.y + fl.y) * iv;
                }
                size_t ao = (size_t)(q0 + row) * SS + kt + c * 8;
                *(float4*)(attnb + ao)     = *(float4*)&out8[0];
                *(float4*)(attnb + ao + 4) = *(float4*)&out8[4];
            }
        }

#pragma unroll
        for (int kk = 0; kk < 2; kk++) {
            uint32_t ah[2][4], al[2][4], bhf[4][2], blf[4][2];
#pragma unroll
            for (int i = 0; i < 2; i++) {
                ldmx4(ah[i], aAddr + (uint32_t)i * 1280 + (uint32_t)kk * 32);
                ldmx4(al[i], aAddr + 10240 + (uint32_t)i * 1280 + (uint32_t)kk * 32);
            }
#pragma unroll
            for (int j = 0; j < 4; j++) {
                ldmx2(bhf[j], bAddr + (uint32_t)j * 640 + (uint32_t)kk * 32);
                ldmx2(blf[j], bAddr + 5120 + (uint32_t)j * 640 + (uint32_t)kk * 32);
            }
#pragma unroll
            for (int i = 0; i < 2; i++)
#pragma unroll
                for (int j = 0; j < 4; j++) {
                    mma_bf16(acc[i][j], ah[i], bhf[j]);
                    mma_bf16(acc[i][j], ah[i], blf[j]);
                    mma_bf16(acc[i][j], al[i], bhf[j]);
                }
        }
        __syncthreads();
    }

    const int g = lane >> 2, qd = lane & 3;
#pragma unroll
    for (int i = 0; i < 2; i++) {
        int rloc = wm * 32 + i * 16 + g;
        float iv0 = invs[rloc], iv1 = invs[rloc + 8];
#pragma unroll
        for (int j = 0; j < 4; j++) {
            int c = wn * 32 + j * 8 + qd * 2;
            float v0 = acc[i][j][0] * iv0, v1 = acc[i][j][1] * iv0;
            float v2 = acc[i][j][2] * iv1, v3 = acc[i][j][3] * iv1;
            uint32_t h01, l01, h23, l23;
            split2(v0, v1, h01, l01);
            split2(v2, v3, h23, l23);
            size_t o0 = ((size_t)(b * SS + q0 + rloc) * HH + h) * DD + c;
            size_t o1 = ((size_t)(b * SS + q0 + rloc + 8) * HH + h) * DD + c;
            *(uint32_t*)&ctxh[o0] = h01; *(uint32_t*)&ctxl[o0] = l01;
            *(uint32_t*)&ctxh[o1] = h23; *(uint32_t*)&ctxl[o1] = l23;
        }
    }
}

// ---------------- out = LayerNorm(A + B) * g + be (opt bf16 pair emit) -----
template<bool PAIR>
__global__ __launch_bounds__(256) void add_ln_kernel(
    const float* __restrict__ A, const float* __restrict__ Bi,
    const float* __restrict__ g, const float* __restrict__ be,
    float* __restrict__ out, __nv_bfloat16* __restrict__ Oh,
    __nv_bfloat16* __restrict__ Ol)
{
    __shared__ float rs[256];
    __shared__ float rs2[256];
    const size_t off = (size_t)blockIdx.x * EE;
    const int t = threadIdx.x;
    float x[3];
    float s = 0.f, s2 = 0.f;
#pragma unroll
    for (int i = 0; i < 3; i++) {
        int c = t + i * 256;
        x[i] = A[off + c] + Bi[off + c];
        s += x[i]; s2 += x[i] * x[i];
    }
    rs[t] = s; rs2[t] = s2; __syncthreads();
    for (int st = 128; st > 0; st >>= 1) {
        if (t < st) { rs[t] += rs[t + st]; rs2[t] += rs2[t + st]; }
        __syncthreads();
    }
    const float mu  = rs[0] * (1.0f / EE);
    const float var = rs2[0] * (1.0f / EE) - mu * mu;
    const float r   = rsqrtf(var + 1e-5f);
#pragma unroll
    for (int i = 0; i < 3; i++) {
        int c = t + i * 256;
        float y = (x[i] - mu) * r * g[c] + be[c];
        out[off + c] = y;
        if (PAIR) {
            __nv_bfloat16 hh = __float2bfloat16_rn(y);
            Oh[off + c] = hh;
            Ol[off + c] = __float2bfloat16_rn(y - __bfloat162float(hh));
        }
    }
}

// ---------------- launch --------------------------------------------------
extern "C" void kernel_launch(void* const* d_in, const int* in_sizes, int n_in,
                              void* d_out, int out_size)
{
    const float* x  = (const float*)d_in[0];
    const float* Wq = (const float*)d_in[1];
    const float* bq = (const float*)d_in[2];
    const float* Wk = (const float*)d_in[3];
    const float* bk = (const float*)d_in[4];
    const float* Wv = (const float*)d_in[5];
    const float* bv = (const float*)d_in[6];
    const float* Wo = (const float*)d_in[7];
    const float* bo = (const float*)d_in[8];
    const float* W1 = (const float*)d_in[9];
    const float* b1 = (const float*)d_in[10];
    const float* W2 = (const float*)d_in[11];
    const float* b2 = (const float*)d_in[12];
    const float* g1 = (const float*)d_in[13];
    const float* be1= (const float*)d_in[14];
    const float* g2 = (const float*)d_in[15];
    const float* be2= (const float*)d_in[16];

    float* out  = (float*)d_out;
    float* attn = out + (size_t)BB * SS * EE;

    float *attnout, *h, *ff2, *part, *inv;
    cudaGetSymbolAddress((void**)&attnout, g_attnout);
    cudaGetSymbolAddress((void**)&h,    g_h);
    cudaGetSymbolAddress((void**)&ff2,  g_ff2);
    cudaGetSymbolAddress((void**)&part, g_part);
    cudaGetSymbolAddress((void**)&inv,  g_inv);
    __nv_bfloat16 *wqh,*wql,*wkh,*wkl,*wvh,*wvl,*woh,*wol,*w1h,*w1l,*w2h,*w2l;
    __nv_bfloat16 *xh,*xl,*qh,*ql,*kh,*kl,*vh,*vl,*hh,*hl,*ctxh,*ctxl,*f1h,*f1l;
    __nv_bfloat16 *vth,*vtl,*ph,*pl;
    cudaGetSymbolAddress((void**)&wqh, g_wqt_h); cudaGetSymbolAddress((void**)&wql, g_wqt_l);
    cudaGetSymbolAddress((void**)&wkh, g_wkt_h); cudaGetSymbolAddress((void**)&wkl, g_wkt_l);
    cudaGetSymbolAddress((void**)&wvh, g_wvt_h); cudaGetSymbolAddress((void**)&wvl, g_wvt_l);
    cudaGetSymbolAddress((void**)&woh, g_wot_h); cudaGetSymbolAddress((void**)&wol, g_wot_l);
    cudaGetSymbolAddress((void**)&w1h, g_w1t_h); cudaGetSymbolAddress((void**)&w1l, g_w1t_l);
    cudaGetSymbolAddress((void**)&w2h, g_w2t_h); cudaGetSymbolAddress((void**)&w2l, g_w2t_l);
    cudaGetSymbolAddress((void**)&xh, g_xh); cudaGetSymbolAddress((void**)&xl, g_xl);
    cudaGetSymbolAddress((void**)&qh, g_qh); cudaGetSymbolAddress((void**)&ql, g_ql);
    cudaGetSymbolAddress((void**)&kh, g_kh); cudaGetSymbolAddress((void**)&kl, g_kl);
    cudaGetSymbolAddress((void**)&vh, g_vh); cudaGetSymbolAddress((void**)&vl, g_vl);
    cudaGetSymbolAddress((void**)&hh, g_hh); cudaGetSymbolAddress((void**)&hl, g_hl);
    cudaGetSymbolAddress((void**)&ctxh, g_ctxh); cudaGetSymbolAddress((void**)&ctxl, g_ctxl);
    cudaGetSymbolAddress((void**)&f1h, g_f1h); cudaGetSymbolAddress((void**)&f1l, g_f1l);
    cudaGetSymbolAddress((void**)&vth, g_vth); cudaGetSymbolAddress((void**)&vtl, g_vtl);
    cudaGetSymbolAddress((void**)&ph, g_ph); cudaGetSymbolAddress((void**)&pl, g_pl);

    const int GSM = 81920;
    cudaFuncSetAttribute(gemm_mma_kernel<0,false>, cudaFuncAttributeMaxDynamicSharedMemorySize, GSM);
    cudaFuncSetAttribute(gemm_mma_kernel<1,false>, cudaFuncAttributeMaxDynamicSharedMemorySize, GSM);
    cudaFuncSetAttribute(gemm_mma_kernel<1,true>,  cudaFuncAttributeMaxDynamicSharedMemorySize, GSM);
    cudaFuncSetAttribute(scores_mma_kernel, cudaFuncAttributeMaxDynamicSharedMemorySize, 75776);
    cudaFuncSetAttribute(ctx_mma_kernel,    cudaFuncAttributeMaxDynamicSharedMemorySize, 31232);

    // prep: split x; transpose+split weights
    split_kernel<<<MM*EE/1024, 256>>>(x, xh, xl);
    wtrans_kernel<<<dim3(EE/32,  EE/32),  256>>>(Wq, wqh, wql, EE, EE);
    wtrans_kernel<<<dim3(EE/32,  EE/32),  256>>>(Wk, wkh, wkl, EE, EE);
    wtrans_kernel<<<dim3(EE/32,  EE/32),  256>>>(Wv, wvh, wvl, EE, EE);
    wtrans_kernel<<<dim3(EE/32,  EE/32),  256>>>(Wo, woh, wol, EE, EE);
    wtrans_kernel<<<dim3(FFF/32, EE/32),  256>>>(W1, w1h, w1l, EE, FFF);
    wtrans_kernel<<<dim3(EE/32,  FFF/32), 256>>>(W2, w2h, w2l, FFF, EE);

    dim3 gE (EE / 128,  MM / 128);
    dim3 gFF(FFF / 128, MM / 128);

    // QKV projections — emit bf16 pairs directly
    gemm_mma_kernel<1,false><<<gE, 256, GSM>>>(xh, xl, wqh, wql, bq, nullptr, qh, ql, EE, EE);
    gemm_mma_kernel<1,false><<<gE, 256, GSM>>>(xh, xl, wkh, wkl, bk, nullptr, kh, kl, EE, EE);
    gemm_mma_kernel<1,false><<<gE, 256, GSM>>>(xh, xl, wvh, wvl, bv, nullptr, vh, vl, EE, EE);
    vtrans_kernel<<<dim3(SS/32, DD/32, BH), 256>>>(vh, vl, vth, vtl);

    // attention (banded)
    scores_mma_kernel<<<dim3(BANDW, NQT, BH), 256, 75776>>>(qh, ql, kh, kl, ph, pl, part);
    rowsum_kernel<<<NROWS / 256, 256>>>(part, inv);
    ctx_mma_kernel<<<dim3(NQT, BH), 256, 31232>>>(ph, pl, vth, vtl, inv, attn, ctxh, ctxl);

    // output projection + residual LN (emit h pairs for FFN1)
    gemm_mma_kernel<0,false><<<gE, 256, GSM>>>(ctxh, ctxl, woh, wol, bo, attnout, nullptr, nullptr, EE, EE);
    add_ln_kernel<true><<<MM, 256>>>(x, attnout, g1, be1, h, hh, hl);

    // FFN
    gemm_mma_kernel<1,true ><<<gFF, 256, GSM>>>(hh, hl, w1h, w1l, b1, nullptr, f1h, f1l, FFF, EE);
    gemm_mma_kernel<0,false><<<gE, 256, GSM>>>(f1h, f1l, w2h, w2l, b2, ff2, nullptr, nullptr, EE, FFF);
    add_ln_kernel<false><<<MM, 256>>>(h, ff2, g2, be2, out, nullptr, nullptr);
}

// round 9
// speedup vs baseline: 3.5141x; 1.1335x over previous
#include <cuda_runtime.h>
#include <cuda_bf16.h>
#include <cstdint>

#define BB 2
#define SS 2048
#define EE 768
#define HH 12
#define DD 64
#define FFF 3072
#define MM (BB*SS)          // 4096
#define BH (BB*HH)          // 24
#define NROWS (BH*SS)       // 49152
#define NQT (SS/128)        // 16 q-tiles
#define BANDW 3             // ktile in {qt-1, qt, qt+1}

// ---------------- scratch (device globals; no allocation) ----------------
__device__ float g_p0 [MM*EE];
__device__ float g_p1 [MM*EE];
__device__ float g_h  [MM*EE];
__device__ float g_part[(size_t)NROWS*BANDW];
__device__ float g_inv [NROWS];
__device__ __nv_bfloat16 g_wqt_h[EE*EE],  g_wqt_l[EE*EE];
__device__ __nv_bfloat16 g_wkt_h[EE*EE],  g_wkt_l[EE*EE];
__device__ __nv_bfloat16 g_wvt_h[EE*EE],  g_wvt_l[EE*EE];
__device__ __nv_bfloat16 g_wot_h[EE*EE],  g_wot_l[EE*EE];
__device__ __nv_bfloat16 g_w1t_h[EE*FFF], g_w1t_l[EE*FFF];
__device__ __nv_bfloat16 g_w2t_h[EE*FFF], g_w2t_l[EE*FFF];
__device__ __nv_bfloat16 g_xh[MM*EE],  g_xl[MM*EE];
__device__ __nv_bfloat16 g_qh[MM*EE],  g_ql[MM*EE];
__device__ __nv_bfloat16 g_kh[MM*EE],  g_kl[MM*EE];
__device__ __nv_bfloat16 g_vh[MM*EE],  g_vl[MM*EE];
__device__ __nv_bfloat16 g_hh[MM*EE],  g_hl[MM*EE];
__device__ __nv_bfloat16 g_ctxh[MM*EE], g_ctxl[MM*EE];
__device__ __nv_bfloat16 g_f1h[(size_t)MM*FFF], g_f1l[(size_t)MM*FFF];
__device__ __nv_bfloat16 g_vth[(size_t)BH*DD*SS], g_vtl[(size_t)BH*DD*SS];
__device__ __nv_bfloat16 g_ph[(size_t)BH*SS*SS], g_pl[(size_t)BH*SS*SS];

// ---------------- helpers ---------------------------------------------------
__device__ __forceinline__ uint32_t smem_u32(const void* p) {
    uint32_t a;
    asm("{ .reg .u64 t; cvta.to.shared.u64 t, %1; cvt.u32.u64 %0, t; }"
        : "=r"(a) : "l"(p));
    return a;
}
__device__ __forceinline__ void ldmx4(uint32_t* r, uint32_t addr) {
    asm volatile("ldmatrix.sync.aligned.m8n8.x4.shared.b16 {%0,%1,%2,%3}, [%4];"
        : "=r"(r[0]), "=r"(r[1]), "=r"(r[2]), "=r"(r[3]) : "r"(addr));
}
__device__ __forceinline__ void ldmx2(uint32_t* r, uint32_t addr) {
    asm volatile("ldmatrix.sync.aligned.m8n8.x2.shared.b16 {%0,%1}, [%2];"
        : "=r"(r[0]), "=r"(r[1]) : "r"(addr));
}
__device__ __forceinline__ void mma_bf16(float* d, const uint32_t* a, const uint32_t* b) {
    asm volatile("mma.sync.aligned.m16n8k16.row.col.f32.bf16.bf16.f32 "
        "{%0,%1,%2,%3}, {%4,%5,%6,%7}, {%8,%9}, {%0,%1,%2,%3};"
        : "+f"(d[0]), "+f"(d[1]), "+f"(d[2]), "+f"(d[3])
        : "r"(a[0]), "r"(a[1]), "r"(a[2]), "r"(a[3]), "r"(b[0]), "r"(b[1]));
}
__device__ __forceinline__ void split2(float x, float y, uint32_t& hi, uint32_t& lo) {
    __nv_bfloat16 hx = __float2bfloat16_rn(x);
    __nv_bfloat16 hy = __float2bfloat16_rn(y);
    __nv_bfloat16 lx = __float2bfloat16_rn(x - __bfloat162float(hx));
    __nv_bfloat16 ly = __float2bfloat16_rn(y - __bfloat162float(hy));
    hi = ((uint32_t)__bfloat16_as_ushort(hy) << 16) | __bfloat16_as_ushort(hx);
    lo = ((uint32_t)__bfloat16_as_ushort(ly) << 16) | __bfloat16_as_ushort(lx);
}
__device__ __forceinline__ void cp16(uint32_t s, const void* g) {
    asm volatile("cp.async.cg.shared.global [%0], [%1], 16;" :: "r"(s), "l"(g));
}
__device__ __forceinline__ void cpcommit() {
    asm volatile("cp.async.commit_group;" ::: "memory");
}
__device__ __forceinline__ void cpwait1() {
    asm volatile("cp.async.wait_group 1;" ::: "memory");
}
__device__ __forceinline__ void cpwait0() {
    asm volatile("cp.async.wait_group 0;" ::: "memory");
}

// ---------------- weight transpose+split: W[K][N] -> Th/Tl[N][K] ----------
__global__ __launch_bounds__(256) void wtrans_kernel(
    const float* __restrict__ W, __nv_bfloat16* __restrict__ Th,
    __nv_bfloat16* __restrict__ Tl, int K, int N)
{
    __shared__ float tile[32][33];
    const int n0 = blockIdx.x * 32, k0 = blockIdx.y * 32;
    const int tx = threadIdx.x & 31, ty = threadIdx.x >> 5;
#pragma unroll
    for (int i = 0; i < 32; i += 8)
        tile[ty + i][tx] = W[(size_t)(k0 + ty + i) * N + n0 + tx];
    __syncthreads();
#pragma unroll
    for (int i = 0; i < 32; i += 8) {
        float x = tile[tx][ty + i];
        __nv_bfloat16 h = __float2bfloat16_rn(x);
        __nv_bfloat16 l = __float2bfloat16_rn(x - __bfloat162float(h));
        size_t o = (size_t)(n0 + ty + i) * K + k0 + tx;
        Th[o] = h; Tl[o] = l;
    }
}

// ---------------- elementwise fp32 -> bf16 hi/lo split ---------------------
__global__ __launch_bounds__(256) void split_kernel(
    const float* __restrict__ A, __nv_bfloat16* __restrict__ Ah,
    __nv_bfloat16* __restrict__ Al)
{
    size_t idx = ((size_t)blockIdx.x * 256 + threadIdx.x) * 4;
    float4 v = *(const float4*)&A[idx];
    uint32_t h0, l0, h1, l1;
    split2(v.x, v.y, h0, l0);
    split2(v.z, v.w, h1, l1);
    *(uint2*)&Ah[idx] = make_uint2(h0, h1);
    *(uint2*)&Al[idx] = make_uint2(l0, l1);
}

// ---------------- v transpose (from pairs): -> vt[bh][d][s] pairs ----------
__global__ __launch_bounds__(256) void vtrans_kernel(
    const __nv_bfloat16* __restrict__ vh, const __nv_bfloat16* __restrict__ vl,
    __nv_bfloat16* __restrict__ Th, __nv_bfloat16* __restrict__ Tl)
{
    __shared__ float tile[32][33];
    const int s0 = blockIdx.x * 32, d0 = blockIdx.y * 32, bh = blockIdx.z;
    const int b = bh / HH, h = bh % HH;
    const int tx = threadIdx.x & 31, ty = threadIdx.x >> 5;
#pragma unroll
    for (int i = 0; i < 32; i += 8) {
        size_t o = (size_t)(b * SS + s0 + ty + i) * EE + h * DD + d0 + tx;
        tile[ty + i][tx] = __bfloat162float(vh[o]) + __bfloat162float(vl[o]);
    }
    __syncthreads();
#pragma unroll
    for (int i = 0; i < 32; i += 8) {
        float x = tile[tx][ty + i];
        __nv_bfloat16 hh = __float2bfloat16_rn(x);
        __nv_bfloat16 ll = __float2bfloat16_rn(x - __bfloat162float(hh));
        size_t o = ((size_t)bh * DD + d0 + ty + i) * SS + s0 + tx;
        Th[o] = hh; Tl[o] = ll;
    }
}

// ============ shared GEMM mainloop macro pieces (tile 128x128, BK=32) ======
// smem: double buffer, each 40960: Ah@0 Al@10240 Bh@20480 Bl@30720.

// ---------------- generic GEMM with optional K-split ----------------------
// grid.z selects K-half (kbase = z*ksize); Cf = z ? Cf1 : Cf0 (EMIT==0).
// bias==nullptr -> no bias add.
template<int EMIT, bool RELU>
__global__ __launch_bounds__(256) void gemm_mma_kernel(
    const __nv_bfloat16* __restrict__ Ath, const __nv_bfloat16* __restrict__ Atl,
    const __nv_bfloat16* __restrict__ Bth, const __nv_bfloat16* __restrict__ Btl,
    const float* __restrict__ bias, float* __restrict__ Cf0, float* __restrict__ Cf1,
    __nv_bfloat16* __restrict__ Ch, __nv_bfloat16* __restrict__ Cl,
    int N, int K, int ksize)
{
    extern __shared__ char sm[];
    const int t = threadIdx.x, lane = t & 31, warp = t >> 5;
    const int wm = warp >> 2, wn = warp & 3;
    const int m0 = blockIdx.y * 128, n0 = blockIdx.x * 128;
    const int kbase = blockIdx.z * ksize;
    float* Cf = blockIdx.z ? Cf1 : Cf0;
    const uint32_t sb = smem_u32(sm);
    const int nch = ksize / 32;

    float acc[4][4][4];
#pragma unroll
    for (int i = 0; i < 4; i++)
#pragma unroll
        for (int j = 0; j < 4; j++)
#pragma unroll
            for (int u = 0; u < 4; u++) acc[i][j][u] = 0.f;

    const int r0i = t >> 2, c16 = t & 3;

    {
        const int koff = kbase;
#pragma unroll
        for (int i = 0; i < 2; i++) {
            int row = r0i + i * 64;
            uint32_t so = (uint32_t)row * 80 + (uint32_t)c16 * 16;
            cp16(sb + so,         Ath + (size_t)(m0 + row) * K + koff + c16 * 8);
            cp16(sb + 10240 + so, Atl + (size_t)(m0 + row) * K + koff + c16 * 8);
            cp16(sb + 20480 + so, Bth + (size_t)(n0 + row) * K + koff + c16 * 8);
            cp16(sb + 30720 + so, Btl + (size_t)(n0 + row) * K + koff + c16 * 8);
        }
        cpcommit();
    }

    const uint32_t aBase = sb + (uint32_t)(wm * 64 + (lane & 15)) * 80
                              + (uint32_t)(lane >> 4) * 16;
    const uint32_t bBase = sb + 20480
                              + (uint32_t)(wn * 32 + (lane & 7)) * 80
                              + (uint32_t)((lane >> 3) & 1) * 16;

    for (int ch = 0; ch < nch; ch++) {
        if (ch + 1 < nch) {
            const int koff = kbase + (ch + 1) * 32;
            const uint32_t bp = (uint32_t)((ch + 1) & 1) * 40960;
#pragma unroll
            for (int i = 0; i < 2; i++) {
                int row = r0i + i * 64;
                uint32_t so = bp + (uint32_t)row * 80 + (uint32_t)c16 * 16;
                cp16(sb + so,         Ath + (size_t)(m0 + row) * K + koff + c16 * 8);
                cp16(sb + 10240 + so, Atl + (size_t)(m0 + row) * K + koff + c16 * 8);
                cp16(sb + 20480 + so, Bth + (size_t)(n0 + row) * K + koff + c16 * 8);
                cp16(sb + 30720 + so, Btl + (size_t)(n0 + row) * K + koff + c16 * 8);
            }
            cpcommit();
            cpwait1();
        } else {
            cpwait0();
        }
        __syncthreads();

        const uint32_t bp = (uint32_t)(ch & 1) * 40960;
#pragma unroll
        for (int kk = 0; kk < 2; kk++) {
            uint32_t ah[4][4], al[4][4], bh[4][2], bl[4][2];
#pragma unroll
            for (int i = 0; i < 4; i++) {
                ldmx4(ah[i], aBase + bp + (uint32_t)i * 1280 + (uint32_t)kk * 32);
                ldmx4(al[i], aBase + bp + 10240 + (uint32_t)i * 1280 + (uint32_t)kk * 32);
            }
#pragma unroll
            for (int j = 0; j < 4; j++) {
                ldmx2(bh[j], bBase + bp + (uint32_t)j * 640 + (uint32_t)kk * 32);
                ldmx2(bl[j], bBase + bp + 10240 + (uint32_t)j * 640 + (uint32_t)kk * 32);
            }
#pragma unroll
            for (int i = 0; i < 4; i++)
#pragma unroll
                for (int j = 0; j < 4; j++) {
                    mma_bf16(acc[i][j], ah[i], bh[j]);
                    mma_bf16(acc[i][j], ah[i], bl[j]);
                    mma_bf16(acc[i][j], al[i], bh[j]);
                }
        }
        __syncthreads();
    }

    const int g = lane >> 2, qd = lane & 3;
#pragma unroll
    for (int i = 0; i < 4; i++) {
        int r0 = m0 + wm * 64 + i * 16 + g;
#pragma unroll
        for (int j = 0; j < 4; j++) {
            int c = n0 + wn * 32 + j * 8 + qd * 2;
            float bx = bias ? __ldg(&bias[c]) : 0.f;
            float by = bias ? __ldg(&bias[c + 1]) : 0.f;
            float v0 = acc[i][j][0] + bx, v1 = acc[i][j][1] + by;
            float v2 = acc[i][j][2] + bx, v3 = acc[i][j][3] + by;
            if (RELU) {
                v0 = fmaxf(v0, 0.f); v1 = fmaxf(v1, 0.f);
                v2 = fmaxf(v2, 0.f); v3 = fmaxf(v3, 0.f);
            }
            if (EMIT == 0) {
                float2 o01 = {v0, v1};
                float2 o23 = {v2, v3};
                *(float2*)&Cf[(size_t)r0 * N + c]       = o01;
                *(float2*)&Cf[(size_t)(r0 + 8) * N + c] = o23;
            } else {
                uint32_t h01, l01, h23, l23;
                split2(v0, v1, h01, l01);
                split2(v2, v3, h23, l23);
                *(uint32_t*)&Ch[(size_t)r0 * N + c]       = h01;
                *(uint32_t*)&Cl[(size_t)r0 * N + c]       = l01;
                *(uint32_t*)&Ch[(size_t)(r0 + 8) * N + c] = h23;
                *(uint32_t*)&Cl[(size_t)(r0 + 8) * N + c] = l23;
            }
        }
    }
}

// ---------------- fused QKV GEMM: one launch, per-block W/out select -------
struct QKVParams {
    const __nv_bfloat16* bh[3];
    const __nv_bfloat16* bl[3];
    const float* bias[3];
    __nv_bfloat16* ch[3];
    __nv_bfloat16* cl[3];
};
__global__ __launch_bounds__(256) void qkv_gemm_kernel(
    const __nv_bfloat16* __restrict__ Ath, const __nv_bfloat16* __restrict__ Atl,
    QKVParams P)
{
    extern __shared__ char sm[];
    const int t = threadIdx.x, lane = t & 31, warp = t >> 5;
    const int wm = warp >> 2, wn = warp & 3;
    const int m0 = blockIdx.y * 128;
    const int sel = blockIdx.x / 6;
    const int n0  = (blockIdx.x % 6) * 128;
    const __nv_bfloat16* Bth = P.bh[sel];
    const __nv_bfloat16* Btl = P.bl[sel];
    const float* bias = P.bias[sel];
    __nv_bfloat16* Ch = P.ch[sel];
    __nv_bfloat16* Cl = P.cl[sel];
    const uint32_t sb = smem_u32(sm);
    const int K = EE, N = EE;
    const int nch = K / 32;

    float acc[4][4][4];
#pragma unroll
    for (int i = 0; i < 4; i++)
#pragma unroll
        for (int j = 0; j < 4; j++)
#pragma unroll
            for (int u = 0; u < 4; u++) acc[i][j][u] = 0.f;

    const int r0i = t >> 2, c16 = t & 3;
    {
#pragma unroll
        for (int i = 0; i < 2; i++) {
            int row = r0i + i * 64;
            uint32_t so = (uint32_t)row * 80 + (uint32_t)c16 * 16;
            cp16(sb + so,         Ath + (size_t)(m0 + row) * K + c16 * 8);
            cp16(sb + 10240 + so, Atl + (size_t)(m0 + row) * K + c16 * 8);
            cp16(sb + 20480 + so, Bth + (size_t)(n0 + row) * K + c16 * 8);
            cp16(sb + 30720 + so, Btl + (size_t)(n0 + row) * K + c16 * 8);
        }
        cpcommit();
    }

    const uint32_t aBase = sb + (uint32_t)(wm * 64 + (lane & 15)) * 80
                              + (uint32_t)(lane >> 4) * 16;
    const uint32_t bBase = sb + 20480
                              + (uint32_t)(wn * 32 + (lane & 7)) * 80
                              + (uint32_t)((lane >> 3) & 1) * 16;

    for (int ch = 0; ch < nch; ch++) {
        if (ch + 1 < nch) {
            const int koff = (ch + 1) * 32;
            const uint32_t bp = (uint32_t)((ch + 1) & 1) * 40960;
#pragma unroll
            for (int i = 0; i < 2; i++) {
                int row = r0i + i * 64;
                uint32_t so = bp + (uint32_t)row * 80 + (uint32_t)c16 * 16;
                cp16(sb + so,         Ath + (size_t)(m0 + row) * K + koff + c16 * 8);
                cp16(sb + 10240 + so, Atl + (size_t)(m0 + row) * K + koff + c16 * 8);
                cp16(sb + 20480 + so, Bth + (size_t)(n0 + row) * K + koff + c16 * 8);
                cp16(sb + 30720 + so, Btl + (size_t)(n0 + row) * K + koff + c16 * 8);
            }
            cpcommit();
            cpwait1();
        } else {
            cpwait0();
        }
        __syncthreads();

        const uint32_t bp = (uint32_t)(ch & 1) * 40960;
#pragma unroll
        for (int kk = 0; kk < 2; kk++) {
            uint32_t ah[4][4], al[4][4], bh[4][2], bl[4][2];
#pragma unroll
            for (int i = 0; i < 4; i++) {
                ldmx4(ah[i], aBase + bp + (uint32_t)i * 1280 + (uint32_t)kk * 32);
                ldmx4(al[i], aBase + bp + 10240 + (uint32_t)i * 1280 + (uint32_t)kk * 32);
            }
#pragma unroll
            for (int j = 0; j < 4; j++) {
                ldmx2(bh[j], bBase + bp + (uint32_t)j * 640 + (uint32_t)kk * 32);
                ldmx2(bl[j], bBase + bp + 10240 + (uint32_t)j * 640 + (uint32_t)kk * 32);
            }
#pragma unroll
            for (int i = 0; i < 4; i++)
#pragma unroll
                for (int j = 0; j < 4; j++) {
                    mma_bf16(acc[i][j], ah[i], bh[j]);
                    mma_bf16(acc[i][j], ah[i], bl[j]);
                    mma_bf16(acc[i][j], al[i], bh[j]);
                }
        }
        __syncthreads();
    }

    const int g = lane >> 2, qd = lane & 3;
#pragma unroll
    for (int i = 0; i < 4; i++) {
        int r0 = m0 + wm * 64 + i * 16 + g;
#pragma unroll
        for (int j = 0; j < 4; j++) {
            int c = n0 + wn * 32 + j * 8 + qd * 2;
            float bx = __ldg(&bias[c]), by = __ldg(&bias[c + 1]);
            float v0 = acc[i][j][0] + bx, v1 = acc[i][j][1] + by;
            float v2 = acc[i][j][2] + bx, v3 = acc[i][j][3] + by;
            uint32_t h01, l01, h23, l23;
            split2(v0, v1, h01, l01);
            split2(v2, v3, h23, l23);
            *(uint32_t*)&Ch[(size_t)r0 * N + c]       = h01;
            *(uint32_t*)&Cl[(size_t)r0 * N + c]       = l01;
            *(uint32_t*)&Ch[(size_t)(r0 + 8) * N + c] = h23;
            *(uint32_t*)&Cl[(size_t)(r0 + 8) * N + c] = l23;
        }
    }
}

// ---------------- scores via MMA (band tiles only) -------------------------
__global__ __launch_bounds__(256) void scores_mma_kernel(
    const __nv_bfloat16* __restrict__ qh, const __nv_bfloat16* __restrict__ ql,
    const __nv_bfloat16* __restrict__ kh, const __nv_bfloat16* __restrict__ kl,
    __nv_bfloat16* __restrict__ Ph, __nv_bfloat16* __restrict__ Pl,
    float* __restrict__ partials)
{
    extern __shared__ char sm[];
    const uint32_t sb = smem_u32(sm);
    const int t = threadIdx.x, lane = t & 31, warp = t >> 5;
    const int wm = warp >> 2, wn = warp & 3;
    const int bh = blockIdx.z, b = bh / HH, h = bh % HH;
    const int qt = blockIdx.y;
    const int kt = qt + (int)blockIdx.x - 1;
    const int q0 = qt * 128;

    if (kt < 0 || kt >= NQT) {
        if (t < 128)
            partials[((size_t)bh * SS + q0 + t) * BANDW + blockIdx.x] = 0.f;
        return;
    }
    const int k0 = kt * 128;
    float* red = (float*)(sm + 73728);

#pragma unroll
    for (int i = 0; i < 4; i++) {
        int idx = t + i * 256;
        int row = idx >> 3, c = idx & 7;
        uint32_t off = (uint32_t)row * 144 + (uint32_t)c * 16;
        size_t qg = (size_t)(b * SS + q0 + row) * EE + h * DD + c * 8;
        size_t kg = (size_t)(b * SS + k0 + row) * EE + h * DD + c * 8;
        *(uint4*)(sm + off)         = *(const uint4*)&qh[qg];
        *(uint4*)(sm + 18432 + off) = *(const uint4*)&ql[qg];
        *(uint4*)(sm + 36864 + off) = *(const uint4*)&kh[kg];
        *(uint4*)(sm + 55296 + off) = *(const uint4*)&kl[kg];
    }
    __syncthreads();

    float acc[4][4][4];
#pragma unroll
    for (int i = 0; i < 4; i++)
#pragma unroll
        for (int j = 0; j < 4; j++)
#pragma unroll
            for (int u = 0; u < 4; u++) acc[i][j][u] = 0.f;

    const uint32_t aAddr = sb + (uint32_t)(wm * 64 + (lane & 15)) * 144
                              + (uint32_t)(lane >> 4) * 16;
    const uint32_t bAddr = sb + 36864
                              + (uint32_t)(wn * 32 + (lane & 7)) * 144
                              + (uint32_t)((lane >> 3) & 1) * 16;
#pragma unroll
    for (int kk = 0; kk < 4; kk++) {
        uint32_t ah[4][4], al[4][4], bhf[4][2], blf[4][2];
#pragma unroll
        for (int i = 0; i < 4; i++) {
            ldmx4(ah[i], aAddr + (uint32_t)i * 2304 + (uint32_t)kk * 32);
            ldmx4(al[i], aAddr + 18432 + (uint32_t)i * 2304 + (uint32_t)kk * 32);
        }
#pragma unroll
        for (int j = 0; j < 4; j++) {
            ldmx2(bhf[j], bAddr + (uint32_t)j * 1152 + (uint32_t)kk * 32);
            ldmx2(blf[j], bAddr + 18432 + (uint32_t)j * 1152 + (uint32_t)kk * 32);
        }
#pragma unroll
        for (int i = 0; i < 4; i++)
#pragma unroll
            for (int j = 0; j < 4; j++) {
                mma_bf16(acc[i][j], ah[i], bhf[j]);
                mma_bf16(acc[i][j], ah[i], blf[j]);
                mma_bf16(acc[i][j], al[i], bhf[j]);
            }
    }

    const int g = lane >> 2, qd = lane & 3;
#pragma unroll
    for (int i = 0; i < 4; i++) {
        int rloc = wm * 64 + i * 16 + g;
        int qi = q0 + rloc;
        float s0 = 0.f, s1 = 0.f;
#pragma unroll
        for (int j = 0; j < 4; j++) {
            int kj = k0 + wn * 32 + j * 8 + qd * 2;
            float e0 = __expf(acc[i][j][0] * 0.125f - fabsf((float)(qi - kj)));
            float e1 = __expf(acc[i][j][1] * 0.125f - fabsf((float)(qi - kj - 1)));
            float e2 = __expf(acc[i][j][2] * 0.125f - fabsf((float)(qi + 8 - kj)));
            float e3 = __expf(acc[i][j][3] * 0.125f - fabsf((float)(qi + 8 - kj - 1)));
            s0 += e0 + e1; s1 += e2 + e3;
            uint32_t h0, l0, h1, l1;
            split2(e0, e1, h0, l0);
            split2(e2, e3, h1, l1);
            size_t o0 = ((size_t)bh * SS + qi) * SS + kj;
            size_t o1 = ((size_t)bh * SS + qi + 8) * SS + kj;
            *(uint32_t*)(Ph + o0) = h0; *(uint32_t*)(Pl + o0) = l0;
            *(uint32_t*)(Ph + o1) = h1; *(uint32_t*)(Pl + o1) = l1;
        }
        s0 += __shfl_xor_sync(0xFFFFFFFF, s0, 1);
        s0 += __shfl_xor_sync(0xFFFFFFFF, s0, 2);
        s1 += __shfl_xor_sync(0xFFFFFFFF, s1, 1);
        s1 += __shfl_xor_sync(0xFFFFFFFF, s1, 2);
        if (qd == 0) {
            red[rloc * 4 + wn]       = s0;
            red[(rloc + 8) * 4 + wn] = s1;
        }
    }
    __syncthreads();
    if (t < 128) {
        float s = red[t * 4] + red[t * 4 + 1] + red[t * 4 + 2] + red[t * 4 + 3];
        partials[((size_t)bh * SS + q0 + t) * BANDW + blockIdx.x] = s;
    }
}

// ---------------- reduce partial row sums -> 1/sum -------------------------
__global__ __launch_bounds__(256) void rowsum_kernel(
    const float* __restrict__ partials, float* __restrict__ inv)
{
    int r = blockIdx.x * 256 + threadIdx.x;
    float s = 0.f;
#pragma unroll
    for (int i = 0; i < BANDW; i++) s += partials[(size_t)r * BANDW + i];
    inv[r] = 1.0f / s;
}

// ---------------- ctx via MMA (band only); emits ctx bf16 pairs ------------
__global__ __launch_bounds__(256) void ctx_mma_kernel(
    const __nv_bfloat16* __restrict__ Ph, const __nv_bfloat16* __restrict__ Pl,
    const __nv_bfloat16* __restrict__ Vth, const __nv_bfloat16* __restrict__ Vtl,
    const float* __restrict__ inv, float* __restrict__ attn,
    __nv_bfloat16* __restrict__ ctxh, __nv_bfloat16* __restrict__ ctxl)
{
    extern __shared__ char sm[];
    const uint32_t sb = smem_u32(sm);
    const int t = threadIdx.x, lane = t & 31, warp = t >> 5;
    const int wm = warp >> 1, wn = warp & 1;
    const int bh = blockIdx.y, b = bh / HH, h = bh % HH;
    const int qt = blockIdx.x;
    const int q0 = qt * 128;
    float* invs = (float*)(sm + 30720);

    if (t < 128) invs[t] = inv[(size_t)bh * SS + q0 + t];
    __syncthreads();

    const __nv_bfloat16* Phb = Ph + (size_t)bh * SS * SS;
    const __nv_bfloat16* Plb = Pl + (size_t)bh * SS * SS;
    float* attnb = attn + (size_t)bh * SS * SS;

    const int tlo = (qt > 0) ? qt - 1 : 0;
    const int thi = (qt + 2 < NQT) ? qt + 2 : NQT;
    const int c_lo = tlo * 4, c_hi = thi * 4;

    {
        const float4 fz = {0.f, 0.f, 0.f, 0.f};
#pragma unroll
        for (int seg = 0; seg < 2; seg++) {
            const int cbeg = seg ? thi * 128 : 0;
            const int cend = seg ? SS : tlo * 128;
            const int w4 = (cend - cbeg) >> 2;
            if (w4 <= 0) continue;
            const int n4 = 128 * w4;
            for (int i = t; i < n4; i += 256) {
                int row = i / w4, cc = i % w4;
                *(float4*)&attnb[(size_t)(q0 + row) * SS + cbeg + cc * 4] = fz;
            }
        }
    }

    float acc[2][4][4];
#pragma unroll
    for (int i = 0; i < 2; i++)
#pragma unroll
        for (int j = 0; j < 4; j++)
#pragma unroll
            for (int u = 0; u < 4; u++) acc[i][j][u] = 0.f;

    uint4 ph_r[2], pl_r[2], vh_r, vl_r;
    const int vr = t >> 2, vc = t & 3;

    {
        const int kt = c_lo * 32;
#pragma unroll
        for (int i = 0; i < 2; i++) {
            int idx = t + i * 256;
            int row = idx >> 2, c = idx & 3;
            size_t go = (size_t)(q0 + row) * SS + kt + c * 8;
            ph_r[i] = *(const uint4*)(Phb + go);
            pl_r[i] = *(const uint4*)(Plb + go);
        }
        vh_r = *(const uint4*)(Vth + ((size_t)bh * DD + vr) * SS + kt + vc * 8);
        vl_r = *(const uint4*)(Vtl + ((size_t)bh * DD + vr) * SS + kt + vc * 8);
#pragma unroll
        for (int i = 0; i < 2; i++) {
            int idx = t + i * 256;
            int row = idx >> 2, c = idx & 3;
            float iv = invs[row];
            const __nv_bfloat162* hp = (const __nv_bfloat162*)&ph_r[i];
            const __nv_bfloat162* lp = (const __nv_bfloat162*)&pl_r[i];
            float out8[8];
#pragma unroll
            for (int u = 0; u < 4; u++) {
                float2 fh = __bfloat1622float2(hp[u]);
                float2 fl = __bfloat1622float2(lp[u]);
                out8[u * 2]     = (fh.x + fl.x) * iv;
                out8[u * 2 + 1] = (fh.y + fl.y) * iv;
            }
            size_t ao = (size_t)(q0 + row) * SS + kt + c * 8;
            *(float4*)(attnb + ao)     = *(float4*)&out8[0];
            *(float4*)(attnb + ao + 4) = *(float4*)&out8[4];
        }
    }

    const uint32_t aAddr = sb + (uint32_t)(wm * 32 + (lane & 15)) * 80
                              + (uint32_t)(lane >> 4) * 16;
    const uint32_t bAddr = sb + 20480
                              + (uint32_t)(wn * 32 + (lane & 7)) * 80
                              + (uint32_t)((lane >> 3) & 1) * 16;

    for (int ch = c_lo; ch < c_hi; ch++) {
#pragma unroll
        for (int i = 0; i < 2; i++) {
            int idx = t + i * 256;
            int row = idx >> 2, c = idx & 3;
            uint32_t off = (uint32_t)row * 80 + (uint32_t)c * 16;
            *(uint4*)(sm + off)         = ph_r[i];
            *(uint4*)(sm + 10240 + off) = pl_r[i];
        }
        {
            uint32_t off = (uint32_t)vr * 80 + (uint32_t)vc * 16;
            *(uint4*)(sm + 20480 + off) = vh_r;
            *(uint4*)(sm + 25600 + off) = vl_r;
        }
        __syncthreads();

        if (ch + 1 < c_hi) {
            const int kt = (ch + 1) * 32;
#pragma unroll
            for (int i = 0; i < 2; i++) {
                int idx = t + i * 256;
                int row = idx >> 2, c = idx & 3;
                size_t go = (size_t)(q0 + row) * SS + kt + c * 8;
                ph_r[i] = *(const uint4*)(Phb + go);
                pl_r[i] = *(const uint4*)(Plb + go);
            }
            vh_r = *(const uint4*)(Vth + ((size_t)bh * DD + vr) * SS + kt + vc * 8);
            vl_r = *(const uint4*)(Vtl + ((size_t)bh * DD + vr) * SS + kt + vc * 8);
#pragma unroll
            for (int i = 0; i < 2; i++) {
                int idx = t + i * 256;
                int row = idx >> 2, c = idx & 3;
                float iv = invs[row];
                const __nv_bfloat162* hp = (const __nv_bfloat162*)&ph_r[i];
                const __nv_bfloat162* lp = (const __nv_bfloat162*)&pl_r[i];
                float out8[8];
#pragma unroll
                for (int u = 0; u < 4; u++) {
                    float2 fh = __bfloat1622float2(hp[u]);
                    float2 fl = __bfloat1622float2(lp[u]);
                    out8[u * 2]     = (fh.x + fl.x) * iv;
                    out8[u * 2 + 1] = (fh.y + fl.y) * iv;
                }
                size_t ao = (size_t)(q0 + row) * SS + kt + c * 8;
                *(float4*)(attnb + ao)     = *(float4*)&out8[0];
                *(float4*)(attnb + ao + 4) = *(float4*)&out8[4];
            }
        }

#pragma unroll
        for (int kk = 0; kk < 2; kk++) {
            uint32_t ah[2][4], al[2][4], bhf[4][2], blf[4][2];
#pragma unroll
            for (int i = 0; i < 2; i++) {
                ldmx4(ah[i], aAddr + (uint32_t)i * 1280 + (uint32_t)kk * 32);
                ldmx4(al[i], aAddr + 10240 + (uint32_t)i * 1280 + (uint32_t)kk * 32);
            }
#pragma unroll
            for (int j = 0; j < 4; j++) {
                ldmx2(bhf[j], bAddr + (uint32_t)j * 640 + (uint32_t)kk * 32);
                ldmx2(blf[j], bAddr + 5120 + (uint32_t)j * 640 + (uint32_t)kk * 32);
            }
#pragma unroll
            for (int i = 0; i < 2; i++)
#pragma unroll
                for (int j = 0; j < 4; j++) {
                    mma_bf16(acc[i][j], ah[i], bhf[j]);
                    mma_bf16(acc[i][j], ah[i], blf[j]);
                    mma_bf16(acc[i][j], al[i], bhf[j]);
                }
        }
        __syncthreads();
    }

    const int g = lane >> 2, qd = lane & 3;
#pragma unroll
    for (int i = 0; i < 2; i++) {
        int rloc = wm * 32 + i * 16 + g;
        float iv0 = invs[rloc], iv1 = invs[rloc + 8];
#pragma unroll
        for (int j = 0; j < 4; j++) {
            int c = wn * 32 + j * 8 + qd * 2;
            float v0 = acc[i][j][0] * iv0, v1 = acc[i][j][1] * iv0;
            float v2 = acc[i][j][2] * iv1, v3 = acc[i][j][3] * iv1;
            uint32_t h01, l01, h23, l23;
            split2(v0, v1, h01, l01);
            split2(v2, v3, h23, l23);
            size_t o0 = ((size_t)(b * SS + q0 + rloc) * HH + h) * DD + c;
            size_t o1 = ((size_t)(b * SS + q0 + rloc + 8) * HH + h) * DD + c;
            *(uint32_t*)&ctxh[o0] = h01; *(uint32_t*)&ctxl[o0] = l01;
            *(uint32_t*)&ctxh[o1] = h23; *(uint32_t*)&ctxl[o1] = l23;
        }
    }
}

// ------ out = LayerNorm(A + P0 + P1 + bias) * g + be (opt bf16 pairs) -----
template<bool PAIR>
__global__ __launch_bounds__(256) void add_ln_kernel(
    const float* __restrict__ A, const float* __restrict__ P0,
    const float* __restrict__ P1, const float* __restrict__ bias,
    const float* __restrict__ g, const float* __restrict__ be,
    float* __restrict__ out, __nv_bfloat16* __restrict__ Oh,
    __nv_bfloat16* __restrict__ Ol)
{
    __shared__ float rs[256];
    __shared__ float rs2[256];
    const size_t off = (size_t)blockIdx.x * EE;
    const int t = threadIdx.x;
    float x[3];
    float s = 0.f, s2 = 0.f;
#pragma unroll
    for (int i = 0; i < 3; i++) {
        int c = t + i * 256;
        x[i] = A[off + c] + (P0[off + c] + P1[off + c] + bias[c]);
        s += x[i]; s2 += x[i] * x[i];
    }
    rs[t] = s; rs2[t] = s2; __syncthreads();
    for (int st = 128; st > 0; st >>= 1) {
        if (t < st) { rs[t] += rs[t + st]; rs2[t] += rs2[t + st]; }
        __syncthreads();
    }
    const float mu  = rs[0] * (1.0f / EE);
    const float var = rs2[0] * (1.0f / EE) - mu * mu;
    const float r   = rsqrtf(var + 1e-5f);
#pragma unroll
    for (int i = 0; i < 3; i++) {
        int c = t + i * 256;
        float y = (x[i] - mu) * r * g[c] + be[c];
        out[off + c] = y;
        if (PAIR) {
            __nv_bfloat16 hh = __float2bfloat16_rn(y);
            Oh[off + c] = hh;
            Ol[off + c] = __float2bfloat16_rn(y - __bfloat162float(hh));
        }
    }
}

// ---------------- launch --------------------------------------------------
extern "C" void kernel_launch(void* const* d_in, const int* in_sizes, int n_in,
                              void* d_out, int out_size)
{
    const float* x  = (const float*)d_in[0];
    const float* Wq = (const float*)d_in[1];
    const float* bq = (const float*)d_in[2];
    const float* Wk = (const float*)d_in[3];
    const float* bk = (const float*)d_in[4];
    const float* Wv = (const float*)d_in[5];
    const float* bv = (const float*)d_in[6];
    const float* Wo = (const float*)d_in[7];
    const float* bo = (const float*)d_in[8];
    const float* W1 = (const float*)d_in[9];
    const float* b1 = (const float*)d_in[10];
    const float* W2 = (const float*)d_in[11];
    const float* b2 = (const float*)d_in[12];
    const float* g1 = (const float*)d_in[13];
    const float* be1= (const float*)d_in[14];
    const float* g2 = (const float*)d_in[15];
    const float* be2= (const float*)d_in[16];

    float* out  = (float*)d_out;
    float* attn = out + (size_t)BB * SS * EE;

    float *p0, *p1, *h, *part, *inv;
    cudaGetSymbolAddress((void**)&p0,   g_p0);
    cudaGetSymbolAddress((void**)&p1,   g_p1);
    cudaGetSymbolAddress((void**)&h,    g_h);
    cudaGetSymbolAddress((void**)&part, g_part);
    cudaGetSymbolAddress((void**)&inv,  g_inv);
    __nv_bfloat16 *wqh,*wql,*wkh,*wkl,*wvh,*wvl,*woh,*wol,*w1h,*w1l,*w2h,*w2l;
    __nv_bfloat16 *xh,*xl,*qh,*ql,*kh,*kl,*vh,*vl,*hh,*hl,*ctxh,*ctxl,*f1h,*f1l;
    __nv_bfloat16 *vth,*vtl,*ph,*pl;
    cudaGetSymbolAddress((void**)&wqh, g_wqt_h); cudaGetSymbolAddress((void**)&wql, g_wqt_l);
    cudaGetSymbolAddress((void**)&wkh, g_wkt_h); cudaGetSymbolAddress((void**)&wkl, g_wkt_l);
    cudaGetSymbolAddress((void**)&wvh, g_wvt_h); cudaGetSymbolAddress((void**)&wvl, g_wvt_l);
    cudaGetSymbolAddress((void**)&woh, g_wot_h); cudaGetSymbolAddress((void**)&wol, g_wot_l);
    cudaGetSymbolAddress((void**)&w1h, g_w1t_h); cudaGetSymbolAddress((void**)&w1l, g_w1t_l);
    cudaGetSymbolAddress((void**)&w2h, g_w2t_h); cudaGetSymbolAddress((void**)&w2l, g_w2t_l);
    cudaGetSymbolAddress((void**)&xh, g_xh); cudaGetSymbolAddress((void**)&xl, g_xl);
    cudaGetSymbolAddress((void**)&qh, g_qh); cudaGetSymbolAddress((void**)&ql, g_ql);
    cudaGetSymbolAddress((void**)&kh, g_kh); cudaGetSymbolAddress((void**)&kl, g_kl);
    cudaGetSymbolAddress((void**)&vh, g_vh); cudaGetSymbolAddress((void**)&vl, g_vl);
    cudaGetSymbolAddress((void**)&hh, g_hh); cudaGetSymbolAddress((void**)&hl, g_hl);
    cudaGetSymbolAddress((void**)&ctxh, g_ctxh); cudaGetSymbolAddress((void**)&ctxl, g_ctxl);
    cudaGetSymbolAddress((void**)&f1h, g_f1h); cudaGetSymbolAddress((void**)&f1l, g_f1l);
    cudaGetSymbolAddress((void**)&vth, g_vth); cudaGetSymbolAddress((void**)&vtl, g_vtl);
    cudaGetSymbolAddress((void**)&ph, g_ph); cudaGetSymbolAddress((void**)&pl, g_pl);

    const int GSM = 81920;
    cudaFuncSetAttribute(gemm_mma_kernel<0,false>, cudaFuncAttributeMaxDynamicSharedMemorySize, GSM);
    cudaFuncSetAttribute(gemm_mma_kernel<1,true>,  cudaFuncAttributeMaxDynamicSharedMemorySize, GSM);
    cudaFuncSetAttribute(qkv_gemm_kernel,          cudaFuncAttributeMaxDynamicSharedMemorySize, GSM);
    cudaFuncSetAttribute(scores_mma_kernel, cudaFuncAttributeMaxDynamicSharedMemorySize, 75776);
    cudaFuncSetAttribute(ctx_mma_kernel,    cudaFuncAttributeMaxDynamicSharedMemorySize, 31232);

    // prep: split x; transpose+split weights
    split_kernel<<<MM*EE/1024, 256>>>(x, xh, xl);
    wtrans_kernel<<<dim3(EE/32,  EE/32),  256>>>(Wq, wqh, wql, EE, EE);
    wtrans_kernel<<<dim3(EE/32,  EE/32),  256>>>(Wk, wkh, wkl, EE, EE);
    wtrans_kernel<<<dim3(EE/32,  EE/32),  256>>>(Wv, wvh, wvl, EE, EE);
    wtrans_kernel<<<dim3(EE/32,  EE/32),  256>>>(Wo, woh, wol, EE, EE);
    wtrans_kernel<<<dim3(FFF/32, EE/32),  256>>>(W1, w1h, w1l, EE, FFF);
    wtrans_kernel<<<dim3(EE/32,  FFF/32), 256>>>(W2, w2h, w2l, FFF, EE);

    // fused QKV projection (one launch, 576 CTAs)
    QKVParams qp;
    qp.bh[0] = wqh; qp.bh[1] = wkh; qp.bh[2] = wvh;
    qp.bl[0] = wql; qp.bl[1] = wkl; qp.bl[2] = wvl;
    qp.bias[0] = bq; qp.bias[1] = bk; qp.bias[2] = bv;
    qp.ch[0] = qh; qp.ch[1] = kh; qp.ch[2] = vh;
    qp.cl[0] = ql; qp.cl[1] = kl; qp.cl[2] = vl;
    qkv_gemm_kernel<<<dim3(18, MM/128), 256, GSM>>>(xh, xl, qp);
    vtrans_kernel<<<dim3(SS/32, DD/32, BH), 256>>>(vh, vl, vth, vtl);

    // attention (banded)
    scores_mma_kernel<<<dim3(BANDW, NQT, BH), 256, 75776>>>(qh, ql, kh, kl, ph, pl, part);
    rowsum_kernel<<<NROWS / 256, 256>>>(part, inv);
    ctx_mma_kernel<<<dim3(NQT, BH), 256, 31232>>>(ph, pl, vth, vtl, inv, attn, ctxh, ctxl);

    // output projection: K-split x2 into p0/p1; merge+bias in add_ln
    gemm_mma_kernel<0,false><<<dim3(EE/128, MM/128, 2), 256, GSM>>>(
        ctxh, ctxl, woh, wol, nullptr, p0, p1, nullptr, nullptr, EE, EE, EE/2);
    add_ln_kernel<true><<<MM, 256>>>(x, p0, p1, bo, g1, be1, h, hh, hl);

    // FFN1 (full K) then FFN2 K-split x2; merge+bias in final add_ln
    gemm_mma_kernel<1,true><<<dim3(FFF/128, MM/128, 1), 256, GSM>>>(
        hh, hl, w1h, w1l, b1, nullptr, nullptr, f1h, f1l, FFF, EE, EE);
    gemm_mma_kernel<0,false><<<dim3(EE/128, MM/128, 2), 256, GSM>>>(
        f1h, f1l, w2h, w2l, nullptr, p0, p1, nullptr, nullptr, EE, FFF, FFF/2);
    add_ln_kernel<false><<<MM, 256>>>(h, p0, p1, b2, g2, be2, out, nullptr, nullptr);
}

// round 10
// speedup vs baseline: 3.6524x; 1.0394x over previous
#include <cuda_runtime.h>
#include <cuda_bf16.h>
#include <cstdint>

#define BB 2
#define SS 2048
#define EE 768
#define HH 12
#define DD 64
#define FFF 3072
#define MM (BB*SS)          // 4096
#define BH (BB*HH)          // 24
#define NROWS (BH*SS)       // 49152
#define NQT (SS/128)        // 16 q-tiles
#define BANDW 3             // ktile in {qt-1, qt, qt+1}

// ---------------- scratch (device globals; no allocation) ----------------
__device__ float g_p0 [MM*EE];
__device__ float g_p1 [MM*EE];
__device__ float g_h  [MM*EE];
__device__ float g_part[(size_t)NROWS*BANDW];
__device__ float g_inv [NROWS];
__device__ __nv_bfloat16 g_wqt_h[EE*EE],  g_wqt_l[EE*EE];
__device__ __nv_bfloat16 g_wkt_h[EE*EE],  g_wkt_l[EE*EE];
__device__ __nv_bfloat16 g_wvt_h[EE*EE],  g_wvt_l[EE*EE];
__device__ __nv_bfloat16 g_wot_h[EE*EE],  g_wot_l[EE*EE];
__device__ __nv_bfloat16 g_w1t_h[EE*FFF], g_w1t_l[EE*FFF];
__device__ __nv_bfloat16 g_w2t_h[EE*FFF], g_w2t_l[EE*FFF];
__device__ __nv_bfloat16 g_xh[MM*EE],  g_xl[MM*EE];
__device__ __nv_bfloat16 g_qh[MM*EE],  g_ql[MM*EE];
__device__ __nv_bfloat16 g_kh[MM*EE],  g_kl[MM*EE];
__device__ __nv_bfloat16 g_vh[MM*EE],  g_vl[MM*EE];
__device__ __nv_bfloat16 g_hh[MM*EE],  g_hl[MM*EE];
__device__ __nv_bfloat16 g_ctxh[MM*EE], g_ctxl[MM*EE];
__device__ __nv_bfloat16 g_f1h[(size_t)MM*FFF], g_f1l[(size_t)MM*FFF];
__device__ __nv_bfloat16 g_vth[(size_t)BH*DD*SS], g_vtl[(size_t)BH*DD*SS];
__device__ __nv_bfloat16 g_ph[(size_t)BH*SS*SS], g_pl[(size_t)BH*SS*SS];

// ---------------- helpers ---------------------------------------------------
__device__ __forceinline__ uint32_t smem_u32(const void* p) {
    uint32_t a;
    asm("{ .reg .u64 t; cvta.to.shared.u64 t, %1; cvt.u32.u64 %0, t; }"
        : "=r"(a) : "l"(p));
    return a;
}
__device__ __forceinline__ void ldmx4(uint32_t* r, uint32_t addr) {
    asm volatile("ldmatrix.sync.aligned.m8n8.x4.shared.b16 {%0,%1,%2,%3}, [%4];"
        : "=r"(r[0]), "=r"(r[1]), "=r"(r[2]), "=r"(r[3]) : "r"(addr));
}
__device__ __forceinline__ void ldmx2(uint32_t* r, uint32_t addr) {
    asm volatile("ldmatrix.sync.aligned.m8n8.x2.shared.b16 {%0,%1}, [%2];"
        : "=r"(r[0]), "=r"(r[1]) : "r"(addr));
}
__device__ __forceinline__ void mma_bf16(float* d, const uint32_t* a, const uint32_t* b) {
    asm volatile("mma.sync.aligned.m16n8k16.row.col.f32.bf16.bf16.f32 "
        "{%0,%1,%2,%3}, {%4,%5,%6,%7}, {%8,%9}, {%0,%1,%2,%3};"
        : "+f"(d[0]), "+f"(d[1]), "+f"(d[2]), "+f"(d[3])
        : "r"(a[0]), "r"(a[1]), "r"(a[2]), "r"(a[3]), "r"(b[0]), "r"(b[1]));
}
__device__ __forceinline__ void split2(float x, float y, uint32_t& hi, uint32_t& lo) {
    __nv_bfloat16 hx = __float2bfloat16_rn(x);
    __nv_bfloat16 hy = __float2bfloat16_rn(y);
    __nv_bfloat16 lx = __float2bfloat16_rn(x - __bfloat162float(hx));
    __nv_bfloat16 ly = __float2bfloat16_rn(y - __bfloat162float(hy));
    hi = ((uint32_t)__bfloat16_as_ushort(hy) << 16) | __bfloat16_as_ushort(hx);
    lo = ((uint32_t)__bfloat16_as_ushort(ly) << 16) | __bfloat16_as_ushort(lx);
}
__device__ __forceinline__ void cp16(uint32_t s, const void* g) {
    asm volatile("cp.async.cg.shared.global [%0], [%1], 16;" :: "r"(s), "l"(g));
}
__device__ __forceinline__ void cpcommit() {
    asm volatile("cp.async.commit_group;" ::: "memory");
}
__device__ __forceinline__ void cpwait0() {
    asm volatile("cp.async.wait_group 0;" ::: "memory");
}

// ---------------- weight transpose+split: W[K][N] -> Th/Tl[N][K] ----------
__global__ __launch_bounds__(256) void wtrans_kernel(
    const float* __restrict__ W, __nv_bfloat16* __restrict__ Th,
    __nv_bfloat16* __restrict__ Tl, int K, int N)
{
    __shared__ float tile[32][33];
    const int n0 = blockIdx.x * 32, k0 = blockIdx.y * 32;
    const int tx = threadIdx.x & 31, ty = threadIdx.x >> 5;
#pragma unroll
    for (int i = 0; i < 32; i += 8)
        tile[ty + i][tx] = W[(size_t)(k0 + ty + i) * N + n0 + tx];
    __syncthreads();
#pragma unroll
    for (int i = 0; i < 32; i += 8) {
        float x = tile[tx][ty + i];
        __nv_bfloat16 h = __float2bfloat16_rn(x);
        __nv_bfloat16 l = __float2bfloat16_rn(x - __bfloat162float(h));
        size_t o = (size_t)(n0 + ty + i) * K + k0 + tx;
        Th[o] = h; Tl[o] = l;
    }
}

// ---------------- elementwise fp32 -> bf16 hi/lo split ---------------------
__global__ __launch_bounds__(256) void split_kernel(
    const float* __restrict__ A, __nv_bfloat16* __restrict__ Ah,
    __nv_bfloat16* __restrict__ Al)
{
    size_t idx = ((size_t)blockIdx.x * 256 + threadIdx.x) * 4;
    float4 v = *(const float4*)&A[idx];
    uint32_t h0, l0, h1, l1;
    split2(v.x, v.y, h0, l0);
    split2(v.z, v.w, h1, l1);
    *(uint2*)&Ah[idx] = make_uint2(h0, h1);
    *(uint2*)&Al[idx] = make_uint2(l0, l1);
}

// ---------------- v transpose (from pairs): -> vt[bh][d][s] pairs ----------
__global__ __launch_bounds__(256) void vtrans_kernel(
    const __nv_bfloat16* __restrict__ vh, const __nv_bfloat16* __restrict__ vl,
    __nv_bfloat16* __restrict__ Th, __nv_bfloat16* __restrict__ Tl)
{
    __shared__ float tile[32][33];
    const int s0 = blockIdx.x * 32, d0 = blockIdx.y * 32, bh = blockIdx.z;
    const int b = bh / HH, h = bh % HH;
    const int tx = threadIdx.x & 31, ty = threadIdx.x >> 5;
#pragma unroll
    for (int i = 0; i < 32; i += 8) {
        size_t o = (size_t)(b * SS + s0 + ty + i) * EE + h * DD + d0 + tx;
        tile[ty + i][tx] = __bfloat162float(vh[o]) + __bfloat162float(vl[o]);
    }
    __syncthreads();
#pragma unroll
    for (int i = 0; i < 32; i += 8) {
        float x = tile[tx][ty + i];
        __nv_bfloat16 hh = __float2bfloat16_rn(x);
        __nv_bfloat16 ll = __float2bfloat16_rn(x - __bfloat162float(hh));
        size_t o = ((size_t)bh * DD + d0 + ty + i) * SS + s0 + tx;
        Th[o] = hh; Tl[o] = ll;
    }
}

// ============ GEMM mainloop (tile 128x128, BK=32, single-sync pipeline) ====
// smem: double buffer, each 40960: Ah@0 Al@10240 Bh@20480 Bl@30720.

// ---------------- generic GEMM with optional K-split ----------------------
template<int EMIT, bool RELU>
__global__ __launch_bounds__(256) void gemm_mma_kernel(
    const __nv_bfloat16* __restrict__ Ath, const __nv_bfloat16* __restrict__ Atl,
    const __nv_bfloat16* __restrict__ Bth, const __nv_bfloat16* __restrict__ Btl,
    const float* __restrict__ bias, float* __restrict__ Cf0, float* __restrict__ Cf1,
    __nv_bfloat16* __restrict__ Ch, __nv_bfloat16* __restrict__ Cl,
    int N, int K, int ksize)
{
    extern __shared__ char sm[];
    const int t = threadIdx.x, lane = t & 31, warp = t >> 5;
    const int wm = warp >> 2, wn = warp & 3;
    const int m0 = blockIdx.y * 128, n0 = blockIdx.x * 128;
    const int kbase = blockIdx.z * ksize;
    float* Cf = blockIdx.z ? Cf1 : Cf0;
    const uint32_t sb = smem_u32(sm);
    const int nch = ksize / 32;

    float acc[4][4][4];
#pragma unroll
    for (int i = 0; i < 4; i++)
#pragma unroll
        for (int j = 0; j < 4; j++)
#pragma unroll
            for (int u = 0; u < 4; u++) acc[i][j][u] = 0.f;

    const int r0i = t >> 2, c16 = t & 3;

    // prologue: chunk 0 -> buffer 0
    {
        const int koff = kbase;
#pragma unroll
        for (int i = 0; i < 2; i++) {
            int row = r0i + i * 64;
            uint32_t so = (uint32_t)row * 80 + (uint32_t)c16 * 16;
            cp16(sb + so,         Ath + (size_t)(m0 + row) * K + koff + c16 * 8);
            cp16(sb + 10240 + so, Atl + (size_t)(m0 + row) * K + koff + c16 * 8);
            cp16(sb + 20480 + so, Bth + (size_t)(n0 + row) * K + koff + c16 * 8);
            cp16(sb + 30720 + so, Btl + (size_t)(n0 + row) * K + koff + c16 * 8);
        }
        cpcommit();
    }

    const uint32_t aBase = sb + (uint32_t)(wm * 64 + (lane & 15)) * 80
                              + (uint32_t)(lane >> 4) * 16;
    // paired-B ldmx4 base: row = wn*32 + (lane>>4)*8 + (lane&7); khalf = (lane>>3)&1
    const uint32_t bBase = sb + 20480
                              + (uint32_t)(wn * 32 + (lane >> 4) * 8 + (lane & 7)) * 80
                              + (uint32_t)((lane >> 3) & 1) * 16;

    for (int ch = 0; ch < nch; ch++) {
        cpwait0();
        __syncthreads();
        if (ch + 1 < nch) {
            const int koff = kbase + (ch + 1) * 32;
            const uint32_t bp = (uint32_t)((ch + 1) & 1) * 40960;
#pragma unroll
            for (int i = 0; i < 2; i++) {
                int row = r0i + i * 64;
                uint32_t so = bp + (uint32_t)row * 80 + (uint32_t)c16 * 16;
                cp16(sb + so,         Ath + (size_t)(m0 + row) * K + koff + c16 * 8);
                cp16(sb + 10240 + so, Atl + (size_t)(m0 + row) * K + koff + c16 * 8);
                cp16(sb + 20480 + so, Bth + (size_t)(n0 + row) * K + koff + c16 * 8);
                cp16(sb + 30720 + so, Btl + (size_t)(n0 + row) * K + koff + c16 * 8);
            }
            cpcommit();
        }

        const uint32_t bp = (uint32_t)(ch & 1) * 40960;
#pragma unroll
        for (int kk = 0; kk < 2; kk++) {
            uint32_t ah[4][4], al[4][4], bh[2][4], bl[2][4];
#pragma unroll
            for (int i = 0; i < 4; i++) {
                ldmx4(ah[i], aBase + bp + (uint32_t)i * 1280 + (uint32_t)kk * 32);
                ldmx4(al[i], aBase + bp + 10240 + (uint32_t)i * 1280 + (uint32_t)kk * 32);
            }
#pragma unroll
            for (int p = 0; p < 2; p++) {
                ldmx4(bh[p], bBase + bp + (uint32_t)p * 1280 + (uint32_t)kk * 32);
                ldmx4(bl[p], bBase + bp + 10240 + (uint32_t)p * 1280 + (uint32_t)kk * 32);
            }
#pragma unroll
            for (int i = 0; i < 4; i++)
#pragma unroll
                for (int j = 0; j < 4; j++) {
                    const uint32_t* bhj = &bh[j >> 1][(j & 1) * 2];
                    const uint32_t* blj = &bl[j >> 1][(j & 1) * 2];
                    mma_bf16(acc[i][j], ah[i], bhj);
                    mma_bf16(acc[i][j], ah[i], blj);
                    mma_bf16(acc[i][j], al[i], bhj);
                }
        }
    }

    const int g = lane >> 2, qd = lane & 3;
#pragma unroll
    for (int i = 0; i < 4; i++) {
        int r0 = m0 + wm * 64 + i * 16 + g;
#pragma unroll
        for (int j = 0; j < 4; j++) {
            int c = n0 + wn * 32 + j * 8 + qd * 2;
            float bx = bias ? __ldg(&bias[c]) : 0.f;
            float by = bias ? __ldg(&bias[c + 1]) : 0.f;
            float v0 = acc[i][j][0] + bx, v1 = acc[i][j][1] + by;
            float v2 = acc[i][j][2] + bx, v3 = acc[i][j][3] + by;
            if (RELU) {
                v0 = fmaxf(v0, 0.f); v1 = fmaxf(v1, 0.f);
                v2 = fmaxf(v2, 0.f); v3 = fmaxf(v3, 0.f);
            }
            if (EMIT == 0) {
                float2 o01 = {v0, v1};
                float2 o23 = {v2, v3};
                *(float2*)&Cf[(size_t)r0 * N + c]       = o01;
                *(float2*)&Cf[(size_t)(r0 + 8) * N + c] = o23;
            } else {
                uint32_t h01, l01, h23, l23;
                split2(v0, v1, h01, l01);
                split2(v2, v3, h23, l23);
                *(uint32_t*)&Ch[(size_t)r0 * N + c]       = h01;
                *(uint32_t*)&Cl[(size_t)r0 * N + c]       = l01;
                *(uint32_t*)&Ch[(size_t)(r0 + 8) * N + c] = h23;
                *(uint32_t*)&Cl[(size_t)(r0 + 8) * N + c] = l23;
            }
        }
    }
}

// ---------------- fused QKV GEMM: one launch, per-block W/out select -------
struct QKVParams {
    const __nv_bfloat16* bh[3];
    const __nv_bfloat16* bl[3];
    const float* bias[3];
    __nv_bfloat16* ch[3];
    __nv_bfloat16* cl[3];
};
__global__ __launch_bounds__(256) void qkv_gemm_kernel(
    const __nv_bfloat16* __restrict__ Ath, const __nv_bfloat16* __restrict__ Atl,
    QKVParams P)
{
    extern __shared__ char sm[];
    const int t = threadIdx.x, lane = t & 31, warp = t >> 5;
    const int wm = warp >> 2, wn = warp & 3;
    const int m0 = blockIdx.y * 128;
    const int sel = blockIdx.x / 6;
    const int n0  = (blockIdx.x % 6) * 128;
    const __nv_bfloat16* Bth = P.bh[sel];
    const __nv_bfloat16* Btl = P.bl[sel];
    const float* bias = P.bias[sel];
    __nv_bfloat16* Ch = P.ch[sel];
    __nv_bfloat16* Cl = P.cl[sel];
    const uint32_t sb = smem_u32(sm);
    const int K = EE, N = EE;
    const int nch = K / 32;

    float acc[4][4][4];
#pragma unroll
    for (int i = 0; i < 4; i++)
#pragma unroll
        for (int j = 0; j < 4; j++)
#pragma unroll
            for (int u = 0; u < 4; u++) acc[i][j][u] = 0.f;

    const int r0i = t >> 2, c16 = t & 3;
    {
#pragma unroll
        for (int i = 0; i < 2; i++) {
            int row = r0i + i * 64;
            uint32_t so = (uint32_t)row * 80 + (uint32_t)c16 * 16;
            cp16(sb + so,         Ath + (size_t)(m0 + row) * K + c16 * 8);
            cp16(sb + 10240 + so, Atl + (size_t)(m0 + row) * K + c16 * 8);
            cp16(sb + 20480 + so, Bth + (size_t)(n0 + row) * K + c16 * 8);
            cp16(sb + 30720 + so, Btl + (size_t)(n0 + row) * K + c16 * 8);
        }
        cpcommit();
    }

    const uint32_t aBase = sb + (uint32_t)(wm * 64 + (lane & 15)) * 80
                              + (uint32_t)(lane >> 4) * 16;
    const uint32_t bBase = sb + 20480
                              + (uint32_t)(wn * 32 + (lane >> 4) * 8 + (lane & 7)) * 80
                              + (uint32_t)((lane >> 3) & 1) * 16;

    for (int ch = 0; ch < nch; ch++) {
        cpwait0();
        __syncthreads();
        if (ch + 1 < nch) {
            const int koff = (ch + 1) * 32;
            const uint32_t bp = (uint32_t)((ch + 1) & 1) * 40960;
#pragma unroll
            for (int i = 0; i < 2; i++) {
                int row = r0i + i * 64;
                uint32_t so = bp + (uint32_t)row * 80 + (uint32_t)c16 * 16;
                cp16(sb + so,         Ath + (size_t)(m0 + row) * K + koff + c16 * 8);
                cp16(sb + 10240 + so, Atl + (size_t)(m0 + row) * K + koff + c16 * 8);
                cp16(sb + 20480 + so, Bth + (size_t)(n0 + row) * K + koff + c16 * 8);
                cp16(sb + 30720 + so, Btl + (size_t)(n0 + row) * K + koff + c16 * 8);
            }
            cpcommit();
        }

        const uint32_t bp = (uint32_t)(ch & 1) * 40960;
#pragma unroll
        for (int kk = 0; kk < 2; kk++) {
            uint32_t ah[4][4], al[4][4], bh[2][4], bl[2][4];
#pragma unroll
            for (int i = 0; i < 4; i++) {
                ldmx4(ah[i], aBase + bp + (uint32_t)i * 1280 + (uint32_t)kk * 32);
                ldmx4(al[i], aBase + bp + 10240 + (uint32_t)i * 1280 + (uint32_t)kk * 32);
            }
#pragma unroll
            for (int p = 0; p < 2; p++) {
                ldmx4(bh[p], bBase + bp + (uint32_t)p * 1280 + (uint32_t)kk * 32);
                ldmx4(bl[p], bBase + bp + 10240 + (uint32_t)p * 1280 + (uint32_t)kk * 32);
            }
#pragma unroll
            for (int i = 0; i < 4; i++)
#pragma unroll
                for (int j = 0; j < 4; j++) {
                    const uint32_t* bhj = &bh[j >> 1][(j & 1) * 2];
                    const uint32_t* blj = &bl[j >> 1][(j & 1) * 2];
                    mma_bf16(acc[i][j], ah[i], bhj);
                    mma_bf16(acc[i][j], ah[i], blj);
                    mma_bf16(acc[i][j], al[i], bhj);
                }
        }
    }

    const int g = lane >> 2, qd = lane & 3;
#pragma unroll
    for (int i = 0; i < 4; i++) {
        int r0 = m0 + wm * 64 + i * 16 + g;
#pragma unroll
        for (int j = 0; j < 4; j++) {
            int c = n0 + wn * 32 + j * 8 + qd * 2;
            float bx = __ldg(&bias[c]), by = __ldg(&bias[c + 1]);
            float v0 = acc[i][j][0] + bx, v1 = acc[i][j][1] + by;
            float v2 = acc[i][j][2] + bx, v3 = acc[i][j][3] + by;
            uint32_t h01, l01, h23, l23;
            split2(v0, v1, h01, l01);
            split2(v2, v3, h23, l23);
            *(uint32_t*)&Ch[(size_t)r0 * N + c]       = h01;
            *(uint32_t*)&Cl[(size_t)r0 * N + c]       = l01;
            *(uint32_t*)&Ch[(size_t)(r0 + 8) * N + c] = h23;
            *(uint32_t*)&Cl[(size_t)(r0 + 8) * N + c] = l23;
        }
    }
}

// ---------------- scores via MMA (band tiles only) -------------------------
__global__ __launch_bounds__(256) void scores_mma_kernel(
    const __nv_bfloat16* __restrict__ qh, const __nv_bfloat16* __restrict__ ql,
    const __nv_bfloat16* __restrict__ kh, const __nv_bfloat16* __restrict__ kl,
    __nv_bfloat16* __restrict__ Ph, __nv_bfloat16* __restrict__ Pl,
    float* __restrict__ partials)
{
    extern __shared__ char sm[];
    const uint32_t sb = smem_u32(sm);
    const int t = threadIdx.x, lane = t & 31, warp = t >> 5;
    const int wm = warp >> 2, wn = warp & 3;
    const int bh = blockIdx.z, b = bh / HH, h = bh % HH;
    const int qt = blockIdx.y;
    const int kt = qt + (int)blockIdx.x - 1;
    const int q0 = qt * 128;

    if (kt < 0 || kt >= NQT) {
        if (t < 128)
            partials[((size_t)bh * SS + q0 + t) * BANDW + blockIdx.x] = 0.f;
        return;
    }
    const int k0 = kt * 128;
    float* red = (float*)(sm + 73728);

#pragma unroll
    for (int i = 0; i < 4; i++) {
        int idx = t + i * 256;
        int row = idx >> 3, c = idx & 7;
        uint32_t off = (uint32_t)row * 144 + (uint32_t)c * 16;
        size_t qg = (size_t)(b * SS + q0 + row) * EE + h * DD + c * 8;
        size_t kg = (size_t)(b * SS + k0 + row) * EE + h * DD + c * 8;
        *(uint4*)(sm + off)         = *(const uint4*)&qh[qg];
        *(uint4*)(sm + 18432 + off) = *(const uint4*)&ql[qg];
        *(uint4*)(sm + 36864 + off) = *(const uint4*)&kh[kg];
        *(uint4*)(sm + 55296 + off) = *(const uint4*)&kl[kg];
    }
    __syncthreads();

    float acc[4][4][4];
#pragma unroll
    for (int i = 0; i < 4; i++)
#pragma unroll
        for (int j = 0; j < 4; j++)
#pragma unroll
            for (int u = 0; u < 4; u++) acc[i][j][u] = 0.f;

    const uint32_t aAddr = sb + (uint32_t)(wm * 64 + (lane & 15)) * 144
                              + (uint32_t)(lane >> 4) * 16;
    const uint32_t bAddr = sb + 36864
                              + (uint32_t)(wn * 32 + (lane & 7)) * 144
                              + (uint32_t)((lane >> 3) & 1) * 16;
#pragma unroll
    for (int kk = 0; kk < 4; kk++) {
        uint32_t ah[4][4], al[4][4], bhf[4][2], blf[4][2];
#pragma unroll
        for (int i = 0; i < 4; i++) {
            ldmx4(ah[i], aAddr + (uint32_t)i * 2304 + (uint32_t)kk * 32);
            ldmx4(al[i], aAddr + 18432 + (uint32_t)i * 2304 + (uint32_t)kk * 32);
        }
#pragma unroll
        for (int j = 0; j < 4; j++) {
            ldmx2(bhf[j], bAddr + (uint32_t)j * 1152 + (uint32_t)kk * 32);
            ldmx2(blf[j], bAddr + 18432 + (uint32_t)j * 1152 + (uint32_t)kk * 32);
        }
#pragma unroll
        for (int i = 0; i < 4; i++)
#pragma unroll
            for (int j = 0; j < 4; j++) {
                mma_bf16(acc[i][j], ah[i], bhf[j]);
                mma_bf16(acc[i][j], ah[i], blf[j]);
                mma_bf16(acc[i][j], al[i], bhf[j]);
            }
    }

    const int g = lane >> 2, qd = lane & 3;
#pragma unroll
    for (int i = 0; i < 4; i++) {
        int rloc = wm * 64 + i * 16 + g;
        int qi = q0 + rloc;
        float s0 = 0.f, s1 = 0.f;
#pragma unroll
        for (int j = 0; j < 4; j++) {
            int kj = k0 + wn * 32 + j * 8 + qd * 2;
            float e0 = __expf(acc[i][j][0] * 0.125f - fabsf((float)(qi - kj)));
            float e1 = __expf(acc[i][j][1] * 0.125f - fabsf((float)(qi - kj - 1)));
            float e2 = __expf(acc[i][j][2] * 0.125f - fabsf((float)(qi + 8 - kj)));
            float e3 = __expf(acc[i][j][3] * 0.125f - fabsf((float)(qi + 8 - kj - 1)));
            s0 += e0 + e1; s1 += e2 + e3;
            uint32_t h0, l0, h1, l1;
            split2(e0, e1, h0, l0);
            split2(e2, e3, h1, l1);
            size_t o0 = ((size_t)bh * SS + qi) * SS + kj;
            size_t o1 = ((size_t)bh * SS + qi + 8) * SS + kj;
            *(uint32_t*)(Ph + o0) = h0; *(uint32_t*)(Pl + o0) = l0;
            *(uint32_t*)(Ph + o1) = h1; *(uint32_t*)(Pl + o1) = l1;
        }
        s0 += __shfl_xor_sync(0xFFFFFFFF, s0, 1);
        s0 += __shfl_xor_sync(0xFFFFFFFF, s0, 2);
        s1 += __shfl_xor_sync(0xFFFFFFFF, s1, 1);
        s1 += __shfl_xor_sync(0xFFFFFFFF, s1, 2);
        if (qd == 0) {
            red[rloc * 4 + wn]       = s0;
            red[(rloc + 8) * 4 + wn] = s1;
        }
    }
    __syncthreads();
    if (t < 128) {
        float s = red[t * 4] + red[t * 4 + 1] + red[t * 4 + 2] + red[t * 4 + 3];
        partials[((size_t)bh * SS + q0 + t) * BANDW + blockIdx.x] = s;
    }
}

// ---------------- reduce partial row sums -> 1/sum -------------------------
__global__ __launch_bounds__(256) void rowsum_kernel(
    const float* __restrict__ partials, float* __restrict__ inv)
{
    int r = blockIdx.x * 256 + threadIdx.x;
    float s = 0.f;
#pragma unroll
    for (int i = 0; i < BANDW; i++) s += partials[(size_t)r * BANDW + i];
    inv[r] = 1.0f / s;
}

// ---------------- ctx via MMA (band only); emits ctx bf16 pairs ------------
__global__ __launch_bounds__(256) void ctx_mma_kernel(
    const __nv_bfloat16* __restrict__ Ph, const __nv_bfloat16* __restrict__ Pl,
    const __nv_bfloat16* __restrict__ Vth, const __nv_bfloat16* __restrict__ Vtl,
    const float* __restrict__ inv, float* __restrict__ attn,
    __nv_bfloat16* __restrict__ ctxh, __nv_bfloat16* __restrict__ ctxl)
{
    extern __shared__ char sm[];
    const uint32_t sb = smem_u32(sm);
    const int t = threadIdx.x, lane = t & 31, warp = t >> 5;
    const int wm = warp >> 1, wn = warp & 1;
    const int bh = blockIdx.y, b = bh / HH, h = bh % HH;
    const int qt = blockIdx.x;
    const int q0 = qt * 128;
    float* invs = (float*)(sm + 30720);

    if (t < 128) invs[t] = inv[(size_t)bh * SS + q0 + t];
    __syncthreads();

    const __nv_bfloat16* Phb = Ph + (size_t)bh * SS * SS;
    const __nv_bfloat16* Plb = Pl + (size_t)bh * SS * SS;
    float* attnb = attn + (size_t)bh * SS * SS;

    const int tlo = (qt > 0) ? qt - 1 : 0;
    const int thi = (qt + 2 < NQT) ? qt + 2 : NQT;
    const int c_lo = tlo * 4, c_hi = thi * 4;

    {
        const float4 fz = {0.f, 0.f, 0.f, 0.f};
#pragma unroll
        for (int seg = 0; seg < 2; seg++) {
            const int cbeg = seg ? thi * 128 : 0;
            const int cend = seg ? SS : tlo * 128;
            const int w4 = (cend - cbeg) >> 2;
            if (w4 <= 0) continue;
            const int n4 = 128 * w4;
            for (int i = t; i < n4; i += 256) {
                int row = i / w4, cc = i % w4;
                *(float4*)&attnb[(size_t)(q0 + row) * SS + cbeg + cc * 4] = fz;
            }
        }
    }

    float acc[2][4][4];
#pragma unroll
    for (int i = 0; i < 2; i++)
#pragma unroll
        for (int j = 0; j < 4; j++)
#pragma unroll
            for (int u = 0; u < 4; u++) acc[i][j][u] = 0.f;

    uint4 ph_r[2], pl_r[2], vh_r, vl_r;
    const int vr = t >> 2, vc = t & 3;

    {
        const int kt = c_lo * 32;
#pragma unroll
        for (int i = 0; i < 2; i++) {
            int idx = t + i * 256;
            int row = idx >> 2, c = idx & 3;
            size_t go = (size_t)(q0 + row) * SS + kt + c * 8;
            ph_r[i] = *(const uint4*)(Phb + go);
            pl_r[i] = *(const uint4*)(Plb + go);
        }
        vh_r = *(const uint4*)(Vth + ((size_t)bh * DD + vr) * SS + kt + vc * 8);
        vl_r = *(const uint4*)(Vtl + ((size_t)bh * DD + vr) * SS + kt + vc * 8);
#pragma unroll
        for (int i = 0; i < 2; i++) {
            int idx = t + i * 256;
            int row = idx >> 2, c = idx & 3;
            float iv = invs[row];
            const __nv_bfloat162* hp = (const __nv_bfloat162*)&ph_r[i];
            const __nv_bfloat162* lp = (const __nv_bfloat162*)&pl_r[i];
            float out8[8];
#pragma unroll
            for (int u = 0; u < 4; u++) {
                float2 fh = __bfloat1622float2(hp[u]);
                float2 fl = __bfloat1622float2(lp[u]);
                out8[u * 2]     = (fh.x + fl.x) * iv;
                out8[u * 2 + 1] = (fh.y + fl.y) * iv;
            }
            size_t ao = (size_t)(q0 + row) * SS + kt + c * 8;
            *(float4*)(attnb + ao)     = *(float4*)&out8[0];
            *(float4*)(attnb + ao + 4) = *(float4*)&out8[4];
        }
    }

    const uint32_t aAddr = sb + (uint32_t)(wm * 32 + (lane & 15)) * 80
                              + (uint32_t)(lane >> 4) * 16;
    const uint32_t bAddr = sb + 20480
                              + (uint32_t)(wn * 32 + (lane & 7)) * 80
                              + (uint32_t)((lane >> 3) & 1) * 16;

    for (int ch = c_lo; ch < c_hi; ch++) {
#pragma unroll
        for (int i = 0; i < 2; i++) {
            int idx = t + i * 256;
            int row = idx >> 2, c = idx & 3;
            uint32_t off = (uint32_t)row * 80 + (uint32_t)c * 16;
            *(uint4*)(sm + off)         = ph_r[i];
            *(uint4*)(sm + 10240 + off) = pl_r[i];
        }
        {
            uint32_t off = (uint32_t)vr * 80 + (uint32_t)vc * 16;
            *(uint4*)(sm + 20480 + off) = vh_r;
            *(uint4*)(sm + 25600 + off) = vl_r;
        }
        __syncthreads();

        if (ch + 1 < c_hi) {
            const int kt = (ch + 1) * 32;
#pragma unroll
            for (int i = 0; i < 2; i++) {
                int idx = t + i * 256;
                int row = idx >> 2, c = idx & 3;
                size_t go = (size_t)(q0 + row) * SS + kt + c * 8;
                ph_r[i] = *(const uint4*)(Phb + go);
                pl_r[i] = *(const uint4*)(Plb + go);
            }
            vh_r = *(const uint4*)(Vth + ((size_t)bh * DD + vr) * SS + kt + vc * 8);
            vl_r = *(const uint4*)(Vtl + ((size_t)bh * DD + vr) * SS + kt + vc * 8);
#pragma unroll
            for (int i = 0; i < 2; i++) {
                int idx = t + i * 256;
                int row = idx >> 2, c = idx & 3;
                float iv = invs[row];
                const __nv_bfloat162* hp = (const __nv_bfloat162*)&ph_r[i];
                const __nv_bfloat162* lp = (const __nv_bfloat162*)&pl_r[i];
                float out8[8];
#pragma unroll
                for (int u = 0; u < 4; u++) {
                    float2 fh = __bfloat1622float2(hp[u]);
                    float2 fl = __bfloat1622float2(lp[u]);
                    out8[u * 2]     = (fh.x + fl.x) * iv;
                    out8[u * 2 + 1] = (fh.y + fl.y) * iv;
                }
                size_t ao = (size_t)(q0 + row) * SS + kt + c * 8;
                *(float4*)(attnb + ao)     = *(float4*)&out8[0];
                *(float4*)(attnb + ao + 4) = *(float4*)&out8[4];
            }
        }

#pragma unroll
        for (int kk = 0; kk < 2; kk++) {
            uint32_t ah[2][4], al[2][4], bhf[4][2], blf[4][2];
#pragma unroll
            for (int i = 0; i < 2; i++) {
                ldmx4(ah[i], aAddr + (uint32_t)i * 1280 + (uint32_t)kk * 32);
                ldmx4(al[i], aAddr + 10240 + (uint32_t)i * 1280 + (uint32_t)kk * 32);
            }
#pragma unroll
            for (int j = 0; j < 4; j++) {
                ldmx2(bhf[j], bAddr + (uint32_t)j * 640 + (uint32_t)kk * 32);
                ldmx2(blf[j], bAddr + 5120 + (uint32_t)j * 640 + (uint32_t)kk * 32);
            }
#pragma unroll
            for (int i = 0; i < 2; i++)
#pragma unroll
                for (int j = 0; j < 4; j++) {
                    mma_bf16(acc[i][j], ah[i], bhf[j]);
                    mma_bf16(acc[i][j], ah[i], blf[j]);
                    mma_bf16(acc[i][j], al[i], bhf[j]);
                }
        }
        __syncthreads();
    }

    const int g = lane >> 2, qd = lane & 3;
#pragma unroll
    for (int i = 0; i < 2; i++) {
        int rloc = wm * 32 + i * 16 + g;
        float iv0 = invs[rloc], iv1 = invs[rloc + 8];
#pragma unroll
        for (int j = 0; j < 4; j++) {
            int c = wn * 32 + j * 8 + qd * 2;
            float v0 = acc[i][j][0] * iv0, v1 = acc[i][j][1] * iv0;
            float v2 = acc[i][j][2] * iv1, v3 = acc[i][j][3] * iv1;
            uint32_t h01, l01, h23, l23;
            split2(v0, v1, h01, l01);
            split2(v2, v3, h23, l23);
            size_t o0 = ((size_t)(b * SS + q0 + rloc) * HH + h) * DD + c;
            size_t o1 = ((size_t)(b * SS + q0 + rloc + 8) * HH + h) * DD + c;
            *(uint32_t*)&ctxh[o0] = h01; *(uint32_t*)&ctxl[o0] = l01;
            *(uint32_t*)&ctxh[o1] = h23; *(uint32_t*)&ctxl[o1] = l23;
        }
    }
}

// ------ out = LayerNorm(A + P0 + P1 + bias) * g + be (opt bf16 pairs) -----
template<bool PAIR>
__global__ __launch_bounds__(256) void add_ln_kernel(
    const float* __restrict__ A, const float* __restrict__ P0,
    const float* __restrict__ P1, const float* __restrict__ bias,
    const float* __restrict__ g, const float* __restrict__ be,
    float* __restrict__ out, __nv_bfloat16* __restrict__ Oh,
    __nv_bfloat16* __restrict__ Ol)
{
    __shared__ float rs[256];
    __shared__ float rs2[256];
    const size_t off = (size_t)blockIdx.x * EE;
    const int t = threadIdx.x;
    float x[3];
    float s = 0.f, s2 = 0.f;
#pragma unroll
    for (int i = 0; i < 3; i++) {
        int c = t + i * 256;
        x[i] = A[off + c] + (P0[off + c] + P1[off + c] + bias[c]);
        s += x[i]; s2 += x[i] * x[i];
    }
    rs[t] = s; rs2[t] = s2; __syncthreads();
    for (int st = 128; st > 0; st >>= 1) {
        if (t < st) { rs[t] += rs[t + st]; rs2[t] += rs2[t + st]; }
        __syncthreads();
    }
    const float mu  = rs[0] * (1.0f / EE);
    const float var = rs2[0] * (1.0f / EE) - mu * mu;
    const float r   = rsqrtf(var + 1e-5f);
#pragma unroll
    for (int i = 0; i < 3; i++) {
        int c = t + i * 256;
        float y = (x[i] - mu) * r * g[c] + be[c];
        out[off + c] = y;
        if (PAIR) {
            __nv_bfloat16 hh = __float2bfloat16_rn(y);
            Oh[off + c] = hh;
            Ol[off + c] = __float2bfloat16_rn(y - __bfloat162float(hh));
        }
    }
}

// ---------------- launch --------------------------------------------------
extern "C" void kernel_launch(void* const* d_in, const int* in_sizes, int n_in,
                              void* d_out, int out_size)
{
    const float* x  = (const float*)d_in[0];
    const float* Wq = (const float*)d_in[1];
    const float* bq = (const float*)d_in[2];
    const float* Wk = (const float*)d_in[3];
    const float* bk = (const float*)d_in[4];
    const float* Wv = (const float*)d_in[5];
    const float* bv = (const float*)d_in[6];
    const float* Wo = (const float*)d_in[7];
    const float* bo = (const float*)d_in[8];
    const float* W1 = (const float*)d_in[9];
    const float* b1 = (const float*)d_in[10];
    const float* W2 = (const float*)d_in[11];
    const float* b2 = (const float*)d_in[12];
    const float* g1 = (const float*)d_in[13];
    const float* be1= (const float*)d_in[14];
    const float* g2 = (const float*)d_in[15];
    const float* be2= (const float*)d_in[16];

    float* out  = (float*)d_out;
    float* attn = out + (size_t)BB * SS * EE;

    float *p0, *p1, *h, *part, *inv;
    cudaGetSymbolAddress((void**)&p0,   g_p0);
    cudaGetSymbolAddress((void**)&p1,   g_p1);
    cudaGetSymbolAddress((void**)&h,    g_h);
    cudaGetSymbolAddress((void**)&part, g_part);
    cudaGetSymbolAddress((void**)&inv,  g_inv);
    __nv_bfloat16 *wqh,*wql,*wkh,*wkl,*wvh,*wvl,*woh,*wol,*w1h,*w1l,*w2h,*w2l;
    __nv_bfloat16 *xh,*xl,*qh,*ql,*kh,*kl,*vh,*vl,*hh,*hl,*ctxh,*ctxl,*f1h,*f1l;
    __nv_bfloat16 *vth,*vtl,*ph,*pl;
    cudaGetSymbolAddress((void**)&wqh, g_wqt_h); cudaGetSymbolAddress((void**)&wql, g_wqt_l);
    cudaGetSymbolAddress((void**)&wkh, g_wkt_h); cudaGetSymbolAddress((void**)&wkl, g_wkt_l);
    cudaGetSymbolAddress((void**)&wvh, g_wvt_h); cudaGetSymbolAddress((void**)&wvl, g_wvt_l);
    cudaGetSymbolAddress((void**)&woh, g_wot_h); cudaGetSymbolAddress((void**)&wol, g_wot_l);
    cudaGetSymbolAddress((void**)&w1h, g_w1t_h); cudaGetSymbolAddress((void**)&w1l, g_w1t_l);
    cudaGetSymbolAddress((void**)&w2h, g_w2t_h); cudaGetSymbolAddress((void**)&w2l, g_w2t_l);
    cudaGetSymbolAddress((void**)&xh, g_xh); cudaGetSymbolAddress((void**)&xl, g_xl);
    cudaGetSymbolAddress((void**)&qh, g_qh); cudaGetSymbolAddress((void**)&ql, g_ql);
    cudaGetSymbolAddress((void**)&kh, g_kh); cudaGetSymbolAddress((void**)&kl, g_kl);
    cudaGetSymbolAddress((void**)&vh, g_vh); cudaGetSymbolAddress((void**)&vl, g_vl);
    cudaGetSymbolAddress((void**)&hh, g_hh); cudaGetSymbolAddress((void**)&hl, g_hl);
    cudaGetSymbolAddress((void**)&ctxh, g_ctxh); cudaGetSymbolAddress((void**)&ctxl, g_ctxl);
    cudaGetSymbolAddress((void**)&f1h, g_f1h); cudaGetSymbolAddress((void**)&f1l, g_f1l);
    cudaGetSymbolAddress((void**)&vth, g_vth); cudaGetSymbolAddress((void**)&vtl, g_vtl);
    cudaGetSymbolAddress((void**)&ph, g_ph); cudaGetSymbolAddress((void**)&pl, g_pl);

    const int GSM = 81920;
    cudaFuncSetAttribute(gemm_mma_kernel<0,false>, cudaFuncAttributeMaxDynamicSharedMemorySize, GSM);
    cudaFuncSetAttribute(gemm_mma_kernel<1,true>,  cudaFuncAttributeMaxDynamicSharedMemorySize, GSM);
    cudaFuncSetAttribute(qkv_gemm_kernel,          cudaFuncAttributeMaxDynamicSharedMemorySize, GSM);
    cudaFuncSetAttribute(scores_mma_kernel, cudaFuncAttributeMaxDynamicSharedMemorySize, 75776);
    cudaFuncSetAttribute(ctx_mma_kernel,    cudaFuncAttributeMaxDynamicSharedMemorySize, 31232);

    // prep: split x; transpose+split weights
    split_kernel<<<MM*EE/1024, 256>>>(x, xh, xl);
    wtrans_kernel<<<dim3(EE/32,  EE/32),  256>>>(Wq, wqh, wql, EE, EE);
    wtrans_kernel<<<dim3(EE/32,  EE/32),  256>>>(Wk, wkh, wkl, EE, EE);
    wtrans_kernel<<<dim3(EE/32,  EE/32),  256>>>(Wv, wvh, wvl, EE, EE);
    wtrans_kernel<<<dim3(EE/32,  EE/32),  256>>>(Wo, woh, wol, EE, EE);
    wtrans_kernel<<<dim3(FFF/32, EE/32),  256>>>(W1, w1h, w1l, EE, FFF);
    wtrans_kernel<<<dim3(EE/32,  FFF/32), 256>>>(W2, w2h, w2l, FFF, EE);

    // fused QKV projection (one launch, 576 CTAs)
    QKVParams qp;
    qp.bh[0] = wqh; qp.bh[1] = wkh; qp.bh[2] = wvh;
    qp.bl[0] = wql; qp.bl[1] = wkl; qp.bl[2] = wvl;
    qp.bias[0] = bq; qp.bias[1] = bk; qp.bias[2] = bv;
    qp.ch[0] = qh; qp.ch[1] = kh; qp.ch[2] = vh;
    qp.cl[0] = ql; qp.cl[1] = kl; qp.cl[2] = vl;
    qkv_gemm_kernel<<<dim3(18, MM/128), 256, GSM>>>(xh, xl, qp);
    vtrans_kernel<<<dim3(SS/32, DD/32, BH), 256>>>(vh, vl, vth, vtl);

    // attention (banded)
    scores_mma_kernel<<<dim3(BANDW, NQT, BH), 256, 75776>>>(qh, ql, kh, kl, ph, pl, part);
    rowsum_kernel<<<NROWS / 256, 256>>>(part, inv);
    ctx_mma_kernel<<<dim3(NQT, BH), 256, 31232>>>(ph, pl, vth, vtl, inv, attn, ctxh, ctxl);

    // output projection: K-split x2 into p0/p1; merge+bias in add_ln
    gemm_mma_kernel<0,false><<<dim3(EE/128, MM/128, 2), 256, GSM>>>(
        ctxh, ctxl, woh, wol, nullptr, p0, p1, nullptr, nullptr, EE, EE, EE/2);
    add_ln_kernel<true><<<MM, 256>>>(x, p0, p1, bo, g1, be1, h, hh, hl);

    // FFN1 (full K) then FFN2 K-split x2; merge+bias in final add_ln
    gemm_mma_kernel<1,true><<<dim3(FFF/128, MM/128, 1), 256, GSM>>>(
        hh, hl, w1h, w1l, b1, nullptr, nullptr, f1h, f1l, FFF, EE, EE);
    gemm_mma_kernel<0,false><<<dim3(EE/128, MM/128, 2), 256, GSM>>>(
        f1h, f1l, w2h, w2l, nullptr, p0, p1, nullptr, nullptr, EE, FFF, FFF/2);
    add_ln_kernel<false><<<MM, 256>>>(h, p0, p1, b2, g2, be2, out, nullptr, nullptr);
}

// round 11
// speedup vs baseline: 4.4734x; 1.2248x over previous
#include <cuda_runtime.h>
#include <cuda_bf16.h>
#include <cuda_fp16.h>
#include <cstdint>

#define BB 2
#define SS 2048
#define EE 768
#define HH 12
#define DD 64
#define FFF 3072
#define MM (BB*SS)          // 4096
#define BH (BB*HH)          // 24
#define NROWS (BH*SS)       // 49152
#define NQT (SS/128)        // 16 q-tiles
#define BANDW 3             // ktile in {qt-1, qt, qt+1}

// ---------------- scratch (device globals; no allocation) ----------------
__device__ float g_p0 [MM*EE];
__device__ float g_p1 [MM*EE];
__device__ float g_h  [MM*EE];
__device__ float g_part[(size_t)NROWS*BANDW];
__device__ float g_inv [NROWS];
__device__ __nv_bfloat16 g_wqt_h[EE*EE],  g_wqt_l[EE*EE];
__device__ __nv_bfloat16 g_wkt_h[EE*EE],  g_wkt_l[EE*EE];
__device__ __nv_bfloat16 g_wvt_h[EE*EE],  g_wvt_l[EE*EE];
__device__ __half g_wot16_h[EE*EE],  g_wot16_l[EE*EE];
__device__ __half g_w1t16_h[EE*FFF], g_w1t16_l[EE*FFF];
__device__ __half g_w2t16_h[EE*FFF], g_w2t16_l[EE*FFF];
__device__ __nv_bfloat16 g_xh[MM*EE],  g_xl[MM*EE];
__device__ __nv_bfloat16 g_qh[MM*EE],  g_ql[MM*EE];
__device__ __nv_bfloat16 g_kh[MM*EE],  g_kl[MM*EE];
__device__ __nv_bfloat16 g_vh[MM*EE],  g_vl[MM*EE];
__device__ __half g_hf16 [MM*EE];
__device__ __half g_ctx16[MM*EE];
__device__ __half g_f116 [(size_t)MM*FFF];
__device__ __nv_bfloat16 g_vth[(size_t)BH*DD*SS], g_vtl[(size_t)BH*DD*SS];
__device__ __nv_bfloat16 g_ph[(size_t)BH*SS*SS], g_pl[(size_t)BH*SS*SS];

// ---------------- helpers ---------------------------------------------------
__device__ __forceinline__ uint32_t smem_u32(const void* p) {
    uint32_t a;
    asm("{ .reg .u64 t; cvta.to.shared.u64 t, %1; cvt.u32.u64 %0, t; }"
        : "=r"(a) : "l"(p));
    return a;
}
__device__ __forceinline__ void ldmx4(uint32_t* r, uint32_t addr) {
    asm volatile("ldmatrix.sync.aligned.m8n8.x4.shared.b16 {%0,%1,%2,%3}, [%4];"
        : "=r"(r[0]), "=r"(r[1]), "=r"(r[2]), "=r"(r[3]) : "r"(addr));
}
__device__ __forceinline__ void ldmx2(uint32_t* r, uint32_t addr) {
    asm volatile("ldmatrix.sync.aligned.m8n8.x2.shared.b16 {%0,%1}, [%2];"
        : "=r"(r[0]), "=r"(r[1]) : "r"(addr));
}
__device__ __forceinline__ void mma_bf16(float* d, const uint32_t* a, const uint32_t* b) {
    asm volatile("mma.sync.aligned.m16n8k16.row.col.f32.bf16.bf16.f32 "
        "{%0,%1,%2,%3}, {%4,%5,%6,%7}, {%8,%9}, {%0,%1,%2,%3};"
        : "+f"(d[0]), "+f"(d[1]), "+f"(d[2]), "+f"(d[3])
        : "r"(a[0]), "r"(a[1]), "r"(a[2]), "r"(a[3]), "r"(b[0]), "r"(b[1]));
}
__device__ __forceinline__ void mma_fp16(float* d, const uint32_t* a, const uint32_t* b) {
    asm volatile("mma.sync.aligned.m16n8k16.row.col.f32.f16.f16.f32 "
        "{%0,%1,%2,%3}, {%4,%5,%6,%7}, {%8,%9}, {%0,%1,%2,%3};"
        : "+f"(d[0]), "+f"(d[1]), "+f"(d[2]), "+f"(d[3])
        : "r"(a[0]), "r"(a[1]), "r"(a[2]), "r"(a[3]), "r"(b[0]), "r"(b[1]));
}
__device__ __forceinline__ void split2(float x, float y, uint32_t& hi, uint32_t& lo) {
    __nv_bfloat16 hx = __float2bfloat16_rn(x);
    __nv_bfloat16 hy = __float2bfloat16_rn(y);
    __nv_bfloat16 lx = __float2bfloat16_rn(x - __bfloat162float(hx));
    __nv_bfloat16 ly = __float2bfloat16_rn(y - __bfloat162float(hy));
    hi = ((uint32_t)__bfloat16_as_ushort(hy) << 16) | __bfloat16_as_ushort(hx);
    lo = ((uint32_t)__bfloat16_as_ushort(ly) << 16) | __bfloat16_as_ushort(lx);
}
__device__ __forceinline__ uint32_t pack_h2(float a, float b) {
    __half2 h = __floats2half2_rn(a, b);
    return *(uint32_t*)&h;
}
__device__ __forceinline__ void cp16(uint32_t s, const void* g) {
    asm volatile("cp.async.cg.shared.global [%0], [%1], 16;" :: "r"(s), "l"(g));
}
__device__ __forceinline__ void cpcommit() {
    asm volatile("cp.async.commit_group;" ::: "memory");
}
__device__ __forceinline__ void cpwait0() {
    asm volatile("cp.async.wait_group 0;" ::: "memory");
}

// ---------------- weight transpose+split (bf16 pairs) ----------------------
__global__ __launch_bounds__(256) void wtrans_kernel(
    const float* __restrict__ W, __nv_bfloat16* __restrict__ Th,
    __nv_bfloat16* __restrict__ Tl, int K, int N)
{
    __shared__ float tile[32][33];
    const int n0 = blockIdx.x * 32, k0 = blockIdx.y * 32;
    const int tx = threadIdx.x & 31, ty = threadIdx.x >> 5;
#pragma unroll
    for (int i = 0; i < 32; i += 8)
        tile[ty + i][tx] = W[(size_t)(k0 + ty + i) * N + n0 + tx];
    __syncthreads();
#pragma unroll
    for (int i = 0; i < 32; i += 8) {
        float x = tile[tx][ty + i];
        __nv_bfloat16 h = __float2bfloat16_rn(x);
        __nv_bfloat16 l = __float2bfloat16_rn(x - __bfloat162float(h));
        size_t o = (size_t)(n0 + ty + i) * K + k0 + tx;
        Th[o] = h; Tl[o] = l;
    }
}

// ---------------- weight transpose+split (fp16 pairs) ----------------------
__global__ __launch_bounds__(256) void wtrans16_kernel(
    const float* __restrict__ W, __half* __restrict__ Th,
    __half* __restrict__ Tl, int K, int N)
{
    __shared__ float tile[32][33];
    const int n0 = blockIdx.x * 32, k0 = blockIdx.y * 32;
    const int tx = threadIdx.x & 31, ty = threadIdx.x >> 5;
#pragma unroll
    for (int i = 0; i < 32; i += 8)
        tile[ty + i][tx] = W[(size_t)(k0 + ty + i) * N + n0 + tx];
    __syncthreads();
#pragma unroll
    for (int i = 0; i < 32; i += 8) {
        float x = tile[tx][ty + i];
        __half h = __float2half_rn(x);
        __half l = __float2half_rn(x - __half2float(h));
        size_t o = (size_t)(n0 + ty + i) * K + k0 + tx;
        Th[o] = h; Tl[o] = l;
    }
}

// ---------------- elementwise fp32 -> bf16 hi/lo split ---------------------
__global__ __launch_bounds__(256) void split_kernel(
    const float* __restrict__ A, __nv_bfloat16* __restrict__ Ah,
    __nv_bfloat16* __restrict__ Al)
{
    size_t idx = ((size_t)blockIdx.x * 256 + threadIdx.x) * 4;
    float4 v = *(const float4*)&A[idx];
    uint32_t h0, l0, h1, l1;
    split2(v.x, v.y, h0, l0);
    split2(v.z, v.w, h1, l1);
    *(uint2*)&Ah[idx] = make_uint2(h0, h1);
    *(uint2*)&Al[idx] = make_uint2(l0, l1);
}

// ---------------- v transpose (from pairs): -> vt[bh][d][s] pairs ----------
__global__ __launch_bounds__(256) void vtrans_kernel(
    const __nv_bfloat16* __restrict__ vh, const __nv_bfloat16* __restrict__ vl,
    __nv_bfloat16* __restrict__ Th, __nv_bfloat16* __restrict__ Tl)
{
    __shared__ float tile[32][33];
    const int s0 = blockIdx.x * 32, d0 = blockIdx.y * 32, bh = blockIdx.z;
    const int b = bh / HH, h = bh % HH;
    const int tx = threadIdx.x & 31, ty = threadIdx.x >> 5;
#pragma unroll
    for (int i = 0; i < 32; i += 8) {
        size_t o = (size_t)(b * SS + s0 + ty + i) * EE + h * DD + d0 + tx;
        tile[ty + i][tx] = __bfloat162float(vh[o]) + __bfloat162float(vl[o]);
    }
    __syncthreads();
#pragma unroll
    for (int i = 0; i < 32; i += 8) {
        float x = tile[tx][ty + i];
        __nv_bfloat16 hh = __float2bfloat16_rn(x);
        __nv_bfloat16 ll = __float2bfloat16_rn(x - __bfloat162float(hh));
        size_t o = ((size_t)bh * DD + d0 + ty + i) * SS + s0 + tx;
        Th[o] = hh; Tl[o] = ll;
    }
}

// ============ fp16 2-term GEMM (A single fp16, B fp16 hi/lo) ===============
// Tile 128x128, BK=32; smem per buffer 30720: A@0 Bh@10240 Bl@20480; x2=61440.
// EMIT 0: fp32 Cf (K-split via blockIdx.z). EMIT 1: fp16 single out.
template<int EMIT, bool RELU>
__global__ __launch_bounds__(256) void gemm_fp16_kernel(
    const __half* __restrict__ Ah_, const __half* __restrict__ Bth,
    const __half* __restrict__ Btl, const float* __restrict__ bias,
    float* __restrict__ Cf0, float* __restrict__ Cf1, __half* __restrict__ Ch,
    int N, int K, int ksize)
{
    extern __shared__ char sm[];
    const int t = threadIdx.x, lane = t & 31, warp = t >> 5;
    const int wm = warp >> 2, wn = warp & 3;
    const int m0 = blockIdx.y * 128, n0 = blockIdx.x * 128;
    const int kbase = blockIdx.z * ksize;
    float* Cf = blockIdx.z ? Cf1 : Cf0;
    const uint32_t sb = smem_u32(sm);
    const int nch = ksize / 32;

    float acc[4][4][4];
#pragma unroll
    for (int i = 0; i < 4; i++)
#pragma unroll
        for (int j = 0; j < 4; j++)
#pragma unroll
            for (int u = 0; u < 4; u++) acc[i][j][u] = 0.f;

    const int r0i = t >> 2, c16 = t & 3;

    // prologue: chunk 0 -> buffer 0
    {
        const int koff = kbase;
#pragma unroll
        for (int i = 0; i < 2; i++) {
            int row = r0i + i * 64;
            uint32_t so = (uint32_t)row * 80 + (uint32_t)c16 * 16;
            cp16(sb + so,         Ah_ + (size_t)(m0 + row) * K + koff + c16 * 8);
            cp16(sb + 10240 + so, Bth + (size_t)(n0 + row) * K + koff + c16 * 8);
            cp16(sb + 20480 + so, Btl + (size_t)(n0 + row) * K + koff + c16 * 8);
        }
        cpcommit();
    }

    const uint32_t aBase = sb + (uint32_t)(wm * 64 + (lane & 15)) * 80
                              + (uint32_t)(lane >> 4) * 16;
    const uint32_t bBase = sb + 10240
                              + (uint32_t)(wn * 32 + (lane >> 4) * 8 + (lane & 7)) * 80
                              + (uint32_t)((lane >> 3) & 1) * 16;

    for (int ch = 0; ch < nch; ch++) {
        cpwait0();
        __syncthreads();
        if (ch + 1 < nch) {
            const int koff = kbase + (ch + 1) * 32;
            const uint32_t bp = (uint32_t)((ch + 1) & 1) * 30720;
#pragma unroll
            for (int i = 0; i < 2; i++) {
                int row = r0i + i * 64;
                uint32_t so = bp + (uint32_t)row * 80 + (uint32_t)c16 * 16;
                cp16(sb + so,         Ah_ + (size_t)(m0 + row) * K + koff + c16 * 8);
                cp16(sb + 10240 + so, Bth + (size_t)(n0 + row) * K + koff + c16 * 8);
                cp16(sb + 20480 + so, Btl + (size_t)(n0 + row) * K + koff + c16 * 8);
            }
            cpcommit();
        }

        const uint32_t bp = (uint32_t)(ch & 1) * 30720;
#pragma unroll
        for (int kk = 0; kk < 2; kk++) {
            uint32_t ah[4][4], bh[2][4], bl[2][4];
#pragma unroll
            for (int i = 0; i < 4; i++)
                ldmx4(ah[i], aBase + bp + (uint32_t)i * 1280 + (uint32_t)kk * 32);
#pragma unroll
            for (int p = 0; p < 2; p++) {
                ldmx4(bh[p], bBase + bp + (uint32_t)p * 1280 + (uint32_t)kk * 32);
                ldmx4(bl[p], bBase + bp + 10240 + (uint32_t)p * 1280 + (uint32_t)kk * 32);
            }
#pragma unroll
            for (int i = 0; i < 4; i++)
#pragma unroll
                for (int j = 0; j < 4; j++) {
                    const uint32_t* bhj = &bh[j >> 1][(j & 1) * 2];
                    const uint32_t* blj = &bl[j >> 1][(j & 1) * 2];
                    mma_fp16(acc[i][j], ah[i], bhj);
                    mma_fp16(acc[i][j], ah[i], blj);
                }
        }
    }

    const int g = lane >> 2, qd = lane & 3;
#pragma unroll
    for (int i = 0; i < 4; i++) {
        int r0 = m0 + wm * 64 + i * 16 + g;
#pragma unroll
        for (int j = 0; j < 4; j++) {
            int c = n0 + wn * 32 + j * 8 + qd * 2;
            float bx = bias ? __ldg(&bias[c]) : 0.f;
            float by = bias ? __ldg(&bias[c + 1]) : 0.f;
            float v0 = acc[i][j][0] + bx, v1 = acc[i][j][1] + by;
            float v2 = acc[i][j][2] + bx, v3 = acc[i][j][3] + by;
            if (RELU) {
                v0 = fmaxf(v0, 0.f); v1 = fmaxf(v1, 0.f);
                v2 = fmaxf(v2, 0.f); v3 = fmaxf(v3, 0.f);
            }
            if (EMIT == 0) {
                float2 o01 = {v0, v1};
                float2 o23 = {v2, v3};
                *(float2*)&Cf[(size_t)r0 * N + c]       = o01;
                *(float2*)&Cf[(size_t)(r0 + 8) * N + c] = o23;
            } else {
                *(uint32_t*)&Ch[(size_t)r0 * N + c]       = pack_h2(v0, v1);
                *(uint32_t*)&Ch[(size_t)(r0 + 8) * N + c] = pack_h2(v2, v3);
            }
        }
    }
}

// ---------------- fused QKV GEMM (bf16 3-term; unchanged math) --------------
struct QKVParams {
    const __nv_bfloat16* bh[3];
    const __nv_bfloat16* bl[3];
    const float* bias[3];
    __nv_bfloat16* ch[3];
    __nv_bfloat16* cl[3];
};
__global__ __launch_bounds__(256) void qkv_gemm_kernel(
    const __nv_bfloat16* __restrict__ Ath, const __nv_bfloat16* __restrict__ Atl,
    QKVParams P)
{
    extern __shared__ char sm[];
    const int t = threadIdx.x, lane = t & 31, warp = t >> 5;
    const int wm = warp >> 2, wn = warp & 3;
    const int m0 = blockIdx.y * 128;
    const int sel = blockIdx.x / 6;
    const int n0  = (blockIdx.x % 6) * 128;
    const __nv_bfloat16* Bth = P.bh[sel];
    const __nv_bfloat16* Btl = P.bl[sel];
    const float* bias = P.bias[sel];
    __nv_bfloat16* Ch = P.ch[sel];
    __nv_bfloat16* Cl = P.cl[sel];
    const uint32_t sb = smem_u32(sm);
    const int K = EE, N = EE;
    const int nch = K / 32;

    float acc[4][4][4];
#pragma unroll
    for (int i = 0; i < 4; i++)
#pragma unroll
        for (int j = 0; j < 4; j++)
#pragma unroll
            for (int u = 0; u < 4; u++) acc[i][j][u] = 0.f;

    const int r0i = t >> 2, c16 = t & 3;
    {
#pragma unroll
        for (int i = 0; i < 2; i++) {
            int row = r0i + i * 64;
            uint32_t so = (uint32_t)row * 80 + (uint32_t)c16 * 16;
            cp16(sb + so,         Ath + (size_t)(m0 + row) * K + c16 * 8);
            cp16(sb + 10240 + so, Atl + (size_t)(m0 + row) * K + c16 * 8);
            cp16(sb + 20480 + so, Bth + (size_t)(n0 + row) * K + c16 * 8);
            cp16(sb + 30720 + so, Btl + (size_t)(n0 + row) * K + c16 * 8);
        }
        cpcommit();
    }

    const uint32_t aBase = sb + (uint32_t)(wm * 64 + (lane & 15)) * 80
                              + (uint32_t)(lane >> 4) * 16;
    const uint32_t bBase = sb + 20480
                              + (uint32_t)(wn * 32 + (lane >> 4) * 8 + (lane & 7)) * 80
                              + (uint32_t)((lane >> 3) & 1) * 16;

    for (int ch = 0; ch < nch; ch++) {
        cpwait0();
        __syncthreads();
        if (ch + 1 < nch) {
            const int koff = (ch + 1) * 32;
            const uint32_t bp = (uint32_t)((ch + 1) & 1) * 40960;
#pragma unroll
            for (int i = 0; i < 2; i++) {
                int row = r0i + i * 64;
                uint32_t so = bp + (uint32_t)row * 80 + (uint32_t)c16 * 16;
                cp16(sb + so,         Ath + (size_t)(m0 + row) * K + koff + c16 * 8);
                cp16(sb + 10240 + so, Atl + (size_t)(m0 + row) * K + koff + c16 * 8);
                cp16(sb + 20480 + so, Bth + (size_t)(n0 + row) * K + koff + c16 * 8);
                cp16(sb + 30720 + so, Btl + (size_t)(n0 + row) * K + koff + c16 * 8);
            }
            cpcommit();
        }

        const uint32_t bp = (uint32_t)(ch & 1) * 40960;
#pragma unroll
        for (int kk = 0; kk < 2; kk++) {
            uint32_t ah[4][4], al[4][4], bh[2][4], bl[2][4];
#pragma unroll
            for (int i = 0; i < 4; i++) {
                ldmx4(ah[i], aBase + bp + (uint32_t)i * 1280 + (uint32_t)kk * 32);
                ldmx4(al[i], aBase + bp + 10240 + (uint32_t)i * 1280 + (uint32_t)kk * 32);
            }
#pragma unroll
            for (int p = 0; p < 2; p++) {
                ldmx4(bh[p], bBase + bp + (uint32_t)p * 1280 + (uint32_t)kk * 32);
                ldmx4(bl[p], bBase + bp + 10240 + (uint32_t)p * 1280 + (uint32_t)kk * 32);
            }
#pragma unroll
            for (int i = 0; i < 4; i++)
#pragma unroll
                for (int j = 0; j < 4; j++) {
                    const uint32_t* bhj = &bh[j >> 1][(j & 1) * 2];
                    const uint32_t* blj = &bl[j >> 1][(j & 1) * 2];
                    mma_bf16(acc[i][j], ah[i], bhj);
                    mma_bf16(acc[i][j], ah[i], blj);
                    mma_bf16(acc[i][j], al[i], bhj);
                }
        }
    }

    const int g = lane >> 2, qd = lane & 3;
#pragma unroll
    for (int i = 0; i < 4; i++) {
        int r0 = m0 + wm * 64 + i * 16 + g;
#pragma unroll
        for (int j = 0; j < 4; j++) {
            int c = n0 + wn * 32 + j * 8 + qd * 2;
            float bx = __ldg(&bias[c]), by = __ldg(&bias[c + 1]);
            float v0 = acc[i][j][0] + bx, v1 = acc[i][j][1] + by;
            float v2 = acc[i][j][2] + bx, v3 = acc[i][j][3] + by;
            uint32_t h01, l01, h23, l23;
            split2(v0, v1, h01, l01);
            split2(v2, v3, h23, l23);
            *(uint32_t*)&Ch[(size_t)r0 * N + c]       = h01;
            *(uint32_t*)&Cl[(size_t)r0 * N + c]       = l01;
            *(uint32_t*)&Ch[(size_t)(r0 + 8) * N + c] = h23;
            *(uint32_t*)&Cl[(size_t)(r0 + 8) * N + c] = l23;
        }
    }
}

// ---------------- scores via MMA (band tiles only) -------------------------
__global__ __launch_bounds__(256) void scores_mma_kernel(
    const __nv_bfloat16* __restrict__ qh, const __nv_bfloat16* __restrict__ ql,
    const __nv_bfloat16* __restrict__ kh, const __nv_bfloat16* __restrict__ kl,
    __nv_bfloat16* __restrict__ Ph, __nv_bfloat16* __restrict__ Pl,
    float* __restrict__ partials)
{
    extern __shared__ char sm[];
    const uint32_t sb = smem_u32(sm);
    const int t = threadIdx.x, lane = t & 31, warp = t >> 5;
    const int wm = warp >> 2, wn = warp & 3;
    const int bh = blockIdx.z, b = bh / HH, h = bh % HH;
    const int qt = blockIdx.y;
    const int kt = qt + (int)blockIdx.x - 1;
    const int q0 = qt * 128;

    if (kt < 0 || kt >= NQT) {
        if (t < 128)
            partials[((size_t)bh * SS + q0 + t) * BANDW + blockIdx.x] = 0.f;
        return;
    }
    const int k0 = kt * 128;
    float* red = (float*)(sm + 73728);

#pragma unroll
    for (int i = 0; i < 4; i++) {
        int idx = t + i * 256;
        int row = idx >> 3, c = idx & 7;
        uint32_t off = (uint32_t)row * 144 + (uint32_t)c * 16;
        size_t qg = (size_t)(b * SS + q0 + row) * EE + h * DD + c * 8;
        size_t kg = (size_t)(b * SS + k0 + row) * EE + h * DD + c * 8;
        *(uint4*)(sm + off)         = *(const uint4*)&qh[qg];
        *(uint4*)(sm + 18432 + off) = *(const uint4*)&ql[qg];
        *(uint4*)(sm + 36864 + off) = *(const uint4*)&kh[kg];
        *(uint4*)(sm + 55296 + off) = *(const uint4*)&kl[kg];
    }
    __syncthreads();

    float acc[4][4][4];
#pragma unroll
    for (int i = 0; i < 4; i++)
#pragma unroll
        for (int j = 0; j < 4; j++)
#pragma unroll
            for (int u = 0; u < 4; u++) acc[i][j][u] = 0.f;

    const uint32_t aAddr = sb + (uint32_t)(wm * 64 + (lane & 15)) * 144
                              + (uint32_t)(lane >> 4) * 16;
    const uint32_t bAddr = sb + 36864
                              + (uint32_t)(wn * 32 + (lane & 7)) * 144
                              + (uint32_t)((lane >> 3) & 1) * 16;
#pragma unroll
    for (int kk = 0; kk < 4; kk++) {
        uint32_t ah[4][4], al[4][4], bhf[4][2], blf[4][2];
#pragma unroll
        for (int i = 0; i < 4; i++) {
            ldmx4(ah[i], aAddr + (uint32_t)i * 2304 + (uint32_t)kk * 32);
            ldmx4(al[i], aAddr + 18432 + (uint32_t)i * 2304 + (uint32_t)kk * 32);
        }
#pragma unroll
        for (int j = 0; j < 4; j++) {
            ldmx2(bhf[j], bAddr + (uint32_t)j * 1152 + (uint32_t)kk * 32);
            ldmx2(blf[j], bAddr + 18432 + (uint32_t)j * 1152 + (uint32_t)kk * 32);
        }
#pragma unroll
        for (int i = 0; i < 4; i++)
#pragma unroll
            for (int j = 0; j < 4; j++) {
                mma_bf16(acc[i][j], ah[i], bhf[j]);
                mma_bf16(acc[i][j], ah[i], blf[j]);
                mma_bf16(acc[i][j], al[i], bhf[j]);
            }
    }

    const int g = lane >> 2, qd = lane & 3;
#pragma unroll
    for (int i = 0; i < 4; i++) {
        int rloc = wm * 64 + i * 16 + g;
        int qi = q0 + rloc;
        float s0 = 0.f, s1 = 0.f;
#pragma unroll
        for (int j = 0; j < 4; j++) {
            int kj = k0 + wn * 32 + j * 8 + qd * 2;
            float e0 = __expf(acc[i][j][0] * 0.125f - fabsf((float)(qi - kj)));
            float e1 = __expf(acc[i][j][1] * 0.125f - fabsf((float)(qi - kj - 1)));
            float e2 = __expf(acc[i][j][2] * 0.125f - fabsf((float)(qi + 8 - kj)));
            float e3 = __expf(acc[i][j][3] * 0.125f - fabsf((float)(qi + 8 - kj - 1)));
            s0 += e0 + e1; s1 += e2 + e3;
            uint32_t h0, l0, h1, l1;
            split2(e0, e1, h0, l0);
            split2(e2, e3, h1, l1);
            size_t o0 = ((size_t)bh * SS + qi) * SS + kj;
            size_t o1 = ((size_t)bh * SS + qi + 8) * SS + kj;
            *(uint32_t*)(Ph + o0) = h0; *(uint32_t*)(Pl + o0) = l0;
            *(uint32_t*)(Ph + o1) = h1; *(uint32_t*)(Pl + o1) = l1;
        }
        s0 += __shfl_xor_sync(0xFFFFFFFF, s0, 1);
        s0 += __shfl_xor_sync(0xFFFFFFFF, s0, 2);
        s1 += __shfl_xor_sync(0xFFFFFFFF, s1, 1);
        s1 += __shfl_xor_sync(0xFFFFFFFF, s1, 2);
        if (qd == 0) {
            red[rloc * 4 + wn]       = s0;
            red[(rloc + 8) * 4 + wn] = s1;
        }
    }
    __syncthreads();
    if (t < 128) {
        float s = red[t * 4] + red[t * 4 + 1] + red[t * 4 + 2] + red[t * 4 + 3];
        partials[((size_t)bh * SS + q0 + t) * BANDW + blockIdx.x] = s;
    }
}

// ---------------- reduce partial row sums -> 1/sum -------------------------
__global__ __launch_bounds__(256) void rowsum_kernel(
    const float* __restrict__ partials, float* __restrict__ inv)
{
    int r = blockIdx.x * 256 + threadIdx.x;
    float s = 0.f;
#pragma unroll
    for (int i = 0; i < BANDW; i++) s += partials[(size_t)r * BANDW + i];
    inv[r] = 1.0f / s;
}

// ---------------- ctx via MMA (band only); emits ctx fp16 single -----------
__global__ __launch_bounds__(256) void ctx_mma_kernel(
    const __nv_bfloat16* __restrict__ Ph, const __nv_bfloat16* __restrict__ Pl,
    const __nv_bfloat16* __restrict__ Vth, const __nv_bfloat16* __restrict__ Vtl,
    const float* __restrict__ inv, float* __restrict__ attn,
    __half* __restrict__ ctx16)
{
    extern __shared__ char sm[];
    const uint32_t sb = smem_u32(sm);
    const int t = threadIdx.x, lane = t & 31, warp = t >> 5;
    const int wm = warp >> 1, wn = warp & 1;
    const int bh = blockIdx.y, b = bh / HH, h = bh % HH;
    const int qt = blockIdx.x;
    const int q0 = qt * 128;
    float* invs = (float*)(sm + 30720);

    if (t < 128) invs[t] = inv[(size_t)bh * SS + q0 + t];
    __syncthreads();

    const __nv_bfloat16* Phb = Ph + (size_t)bh * SS * SS;
    const __nv_bfloat16* Plb = Pl + (size_t)bh * SS * SS;
    float* attnb = attn + (size_t)bh * SS * SS;

    const int tlo = (qt > 0) ? qt - 1 : 0;
    const int thi = (qt + 2 < NQT) ? qt + 2 : NQT;
    const int c_lo = tlo * 4, c_hi = thi * 4;

    {
        const float4 fz = {0.f, 0.f, 0.f, 0.f};
#pragma unroll
        for (int seg = 0; seg < 2; seg++) {
            const int cbeg = seg ? thi * 128 : 0;
            const int cend = seg ? SS : tlo * 128;
            const int w4 = (cend - cbeg) >> 2;
            if (w4 <= 0) continue;
            const int n4 = 128 * w4;
            for (int i = t; i < n4; i += 256) {
                int row = i / w4, cc = i % w4;
                *(float4*)&attnb[(size_t)(q0 + row) * SS + cbeg + cc * 4] = fz;
            }
        }
    }

    float acc[2][4][4];
#pragma unroll
    for (int i = 0; i < 2; i++)
#pragma unroll
        for (int j = 0; j < 4; j++)
#pragma unroll
            for (int u = 0; u < 4; u++) acc[i][j][u] = 0.f;

    uint4 ph_r[2], pl_r[2], vh_r, vl_r;
    const int vr = t >> 2, vc = t & 3;

    {
        const int kt = c_lo * 32;
#pragma unroll
        for (int i = 0; i < 2; i++) {
            int idx = t + i * 256;
            int row = idx >> 2, c = idx & 3;
            size_t go = (size_t)(q0 + row) * SS + kt + c * 8;
            ph_r[i] = *(const uint4*)(Phb + go);
            pl_r[i] = *(const uint4*)(Plb + go);
        }
        vh_r = *(const uint4*)(Vth + ((size_t)bh * DD + vr) * SS + kt + vc * 8);
        vl_r = *(const uint4*)(Vtl + ((size_t)bh * DD + vr) * SS + kt + vc * 8);
#pragma unroll
        for (int i = 0; i < 2; i++) {
            int idx = t + i * 256;
            int row = idx >> 2, c = idx & 3;
            float iv = invs[row];
            const __nv_bfloat162* hp = (const __nv_bfloat162*)&ph_r[i];
            const __nv_bfloat162* lp = (const __nv_bfloat162*)&pl_r[i];
            float out8[8];
#pragma unroll
            for (int u = 0; u < 4; u++) {
                float2 fh = __bfloat1622float2(hp[u]);
                float2 fl = __bfloat1622float2(lp[u]);
                out8[u * 2]     = (fh.x + fl.x) * iv;
                out8[u * 2 + 1] = (fh.y + fl.y) * iv;
            }
            size_t ao = (size_t)(q0 + row) * SS + kt + c * 8;
            *(float4*)(attnb + ao)     = *(float4*)&out8[0];
            *(float4*)(attnb + ao + 4) = *(float4*)&out8[4];
        }
    }

    const uint32_t aAddr = sb + (uint32_t)(wm * 32 + (lane & 15)) * 80
                              + (uint32_t)(lane >> 4) * 16;
    const uint32_t bAddr = sb + 20480
                              + (uint32_t)(wn * 32 + (lane & 7)) * 80
                              + (uint32_t)((lane >> 3) & 1) * 16;

    for (int ch = c_lo; ch < c_hi; ch++) {
#pragma unroll
        for (int i = 0; i < 2; i++) {
            int idx = t + i * 256;
            int row = idx >> 2, c = idx & 3;
            uint32_t off = (uint32_t)row * 80 + (uint32_t)c * 16;
            *(uint4*)(sm + off)         = ph_r[i];
            *(uint4*)(sm + 10240 + off) = pl_r[i];
        }
        {
            uint32_t off = (uint32_t)vr * 80 + (uint32_t)vc * 16;
            *(uint4*)(sm + 20480 + off) = vh_r;
            *(uint4*)(sm + 25600 + off) = vl_r;
        }
        __syncthreads();

        if (ch + 1 < c_hi) {
            const int kt = (ch + 1) * 32;
#pragma unroll
            for (int i = 0; i < 2; i++) {
                int idx = t + i * 256;
                int row = idx >> 2, c = idx & 3;
                size_t go = (size_t)(q0 + row) * SS + kt + c * 8;
                ph_r[i] = *(const uint4*)(Phb + go);
                pl_r[i] = *(const uint4*)(Plb + go);
            }
            vh_r = *(const uint4*)(Vth + ((size_t)bh * DD + vr) * SS + kt + vc * 8);
            vl_r = *(const uint4*)(Vtl + ((size_t)bh * DD + vr) * SS + kt + vc * 8);
#pragma unroll
            for (int i = 0; i < 2; i++) {
                int idx = t + i * 256;
                int row = idx >> 2, c = idx & 3;
                float iv = invs[row];
                const __nv_bfloat162* hp = (const __nv_bfloat162*)&ph_r[i];
                const __nv_bfloat162* lp = (const __nv_bfloat162*)&pl_r[i];
                float out8[8];
#pragma unroll
                for (int u = 0; u < 4; u++) {
                    float2 fh = __bfloat1622float2(hp[u]);
                    float2 fl = __bfloat1622float2(lp[u]);
                    out8[u * 2]     = (fh.x + fl.x) * iv;
                    out8[u * 2 + 1] = (fh.y + fl.y) * iv;
                }
                size_t ao = (size_t)(q0 + row) * SS + kt + c * 8;
                *(float4*)(attnb + ao)     = *(float4*)&out8[0];
                *(float4*)(attnb + ao + 4) = *(float4*)&out8[4];
            }
        }

#pragma unroll
        for (int kk = 0; kk < 2; kk++) {
            uint32_t ah[2][4], al[2][4], bhf[4][2], blf[4][2];
#pragma unroll
            for (int i = 0; i < 2; i++) {
                ldmx4(ah[i], aAddr + (uint32_t)i * 1280 + (uint32_t)kk * 32);
                ldmx4(al[i], aAddr + 10240 + (uint32_t)i * 1280 + (uint32_t)kk * 32);
            }
#pragma unroll
            for (int j = 0; j < 4; j++) {
                ldmx2(bhf[j], bAddr + (uint32_t)j * 640 + (uint32_t)kk * 32);
                ldmx2(blf[j], bAddr + 5120 + (uint32_t)j * 640 + (uint32_t)kk * 32);
            }
#pragma unroll
            for (int i = 0; i < 2; i++)
#pragma unroll
                for (int j = 0; j < 4; j++) {
                    mma_bf16(acc[i][j], ah[i], bhf[j]);
                    mma_bf16(acc[i][j], ah[i], blf[j]);
                    mma_bf16(acc[i][j], al[i], bhf[j]);
                }
        }
        __syncthreads();
    }

    const int g = lane >> 2, qd = lane & 3;
#pragma unroll
    for (int i = 0; i < 2; i++) {
        int rloc = wm * 32 + i * 16 + g;
        float iv0 = invs[rloc], iv1 = invs[rloc + 8];
#pragma unroll
        for (int j = 0; j < 4; j++) {
            int c = wn * 32 + j * 8 + qd * 2;
            float v0 = acc[i][j][0] * iv0, v1 = acc[i][j][1] * iv0;
            float v2 = acc[i][j][2] * iv1, v3 = acc[i][j][3] * iv1;
            size_t o0 = ((size_t)(b * SS + q0 + rloc) * HH + h) * DD + c;
            size_t o1 = ((size_t)(b * SS + q0 + rloc + 8) * HH + h) * DD + c;
            *(uint32_t*)&ctx16[o0] = pack_h2(v0, v1);
            *(uint32_t*)&ctx16[o1] = pack_h2(v2, v3);
        }
    }
}

// ------ out = LayerNorm(A + P0 + P1 + bias) * g + be (opt fp16 emit) -------
template<bool EMIT16>
__global__ __launch_bounds__(256) void add_ln_kernel(
    const float* __restrict__ A, const float* __restrict__ P0,
    const float* __restrict__ P1, const float* __restrict__ bias,
    const float* __restrict__ g, const float* __restrict__ be,
    float* __restrict__ out, __half* __restrict__ O16)
{
    __shared__ float rs[256];
    __shared__ float rs2[256];
    const size_t off = (size_t)blockIdx.x * EE;
    const int t = threadIdx.x;
    float x[3];
    float s = 0.f, s2 = 0.f;
#pragma unroll
    for (int i = 0; i < 3; i++) {
        int c = t + i * 256;
        x[i] = A[off + c] + (P0[off + c] + P1[off + c] + bias[c]);
        s += x[i]; s2 += x[i] * x[i];
    }
    rs[t] = s; rs2[t] = s2; __syncthreads();
    for (int st = 128; st > 0; st >>= 1) {
        if (t < st) { rs[t] += rs[t + st]; rs2[t] += rs2[t + st]; }
        __syncthreads();
    }
    const float mu  = rs[0] * (1.0f / EE);
    const float var = rs2[0] * (1.0f / EE) - mu * mu;
    const float r   = rsqrtf(var + 1e-5f);
#pragma unroll
    for (int i = 0; i < 3; i++) {
        int c = t + i * 256;
        float y = (x[i] - mu) * r * g[c] + be[c];
        out[off + c] = y;
        if (EMIT16) O16[off + c] = __float2half_rn(y);
    }
}

// ---------------- launch --------------------------------------------------
extern "C" void kernel_launch(void* const* d_in, const int* in_sizes, int n_in,
                              void* d_out, int out_size)
{
    const float* x  = (const float*)d_in[0];
    const float* Wq = (const float*)d_in[1];
    const float* bq = (const float*)d_in[2];
    const float* Wk = (const float*)d_in[3];
    const float* bk = (const float*)d_in[4];
    const float* Wv = (const float*)d_in[5];
    const float* bv = (const float*)d_in[6];
    const float* Wo = (const float*)d_in[7];
    const float* bo = (const float*)d_in[8];
    const float* W1 = (const float*)d_in[9];
    const float* b1 = (const float*)d_in[10];
    const float* W2 = (const float*)d_in[11];
    const float* b2 = (const float*)d_in[12];
    const float* g1 = (const float*)d_in[13];
    const float* be1= (const float*)d_in[14];
    const float* g2 = (const float*)d_in[15];
    const float* be2= (const float*)d_in[16];

    float* out  = (float*)d_out;
    float* attn = out + (size_t)BB * SS * EE;

    float *p0, *p1, *h, *part, *inv;
    cudaGetSymbolAddress((void**)&p0,   g_p0);
    cudaGetSymbolAddress((void**)&p1,   g_p1);
    cudaGetSymbolAddress((void**)&h,    g_h);
    cudaGetSymbolAddress((void**)&part, g_part);
    cudaGetSymbolAddress((void**)&inv,  g_inv);
    __nv_bfloat16 *wqh,*wql,*wkh,*wkl,*wvh,*wvl;
    __nv_bfloat16 *xh,*xl,*qh,*ql,*kh,*kl,*vh,*vl,*vth,*vtl,*ph,*pl;
    __half *woh16,*wol16,*w1h16,*w1l16,*w2h16,*w2l16,*hf16,*ctx16,*f116;
    cudaGetSymbolAddress((void**)&wqh, g_wqt_h); cudaGetSymbolAddress((void**)&wql, g_wqt_l);
    cudaGetSymbolAddress((void**)&wkh, g_wkt_h); cudaGetSymbolAddress((void**)&wkl, g_wkt_l);
    cudaGetSymbolAddress((void**)&wvh, g_wvt_h); cudaGetSymbolAddress((void**)&wvl, g_wvt_l);
    cudaGetSymbolAddress((void**)&woh16, g_wot16_h); cudaGetSymbolAddress((void**)&wol16, g_wot16_l);
    cudaGetSymbolAddress((void**)&w1h16, g_w1t16_h); cudaGetSymbolAddress((void**)&w1l16, g_w1t16_l);
    cudaGetSymbolAddress((void**)&w2h16, g_w2t16_h); cudaGetSymbolAddress((void**)&w2l16, g_w2t16_l);
    cudaGetSymbolAddress((void**)&xh, g_xh); cudaGetSymbolAddress((void**)&xl, g_xl);
    cudaGetSymbolAddress((void**)&qh, g_qh); cudaGetSymbolAddress((void**)&ql, g_ql);
    cudaGetSymbolAddress((void**)&kh, g_kh); cudaGetSymbolAddress((void**)&kl, g_kl);
    cudaGetSymbolAddress((void**)&vh, g_vh); cudaGetSymbolAddress((void**)&vl, g_vl);
    cudaGetSymbolAddress((void**)&hf16, g_hf16);
    cudaGetSymbolAddress((void**)&ctx16, g_ctx16);
    cudaGetSymbolAddress((void**)&f116, g_f116);
    cudaGetSymbolAddress((void**)&vth, g_vth); cudaGetSymbolAddress((void**)&vtl, g_vtl);
    cudaGetSymbolAddress((void**)&ph, g_ph); cudaGetSymbolAddress((void**)&pl, g_pl);

    const int GSM_BF = 81920;    // bf16 qkv kernel
    const int GSM_H  = 61440;    // fp16 2-term gemm
    cudaFuncSetAttribute(gemm_fp16_kernel<0,false>, cudaFuncAttributeMaxDynamicSharedMemorySize, GSM_H);
    cudaFuncSetAttribute(gemm_fp16_kernel<1,true>,  cudaFuncAttributeMaxDynamicSharedMemorySize, GSM_H);
    cudaFuncSetAttribute(qkv_gemm_kernel,           cudaFuncAttributeMaxDynamicSharedMemorySize, GSM_BF);
    cudaFuncSetAttribute(scores_mma_kernel, cudaFuncAttributeMaxDynamicSharedMemorySize, 75776);
    cudaFuncSetAttribute(ctx_mma_kernel,    cudaFuncAttributeMaxDynamicSharedMemorySize, 31232);

    // prep: split x (bf16 pairs); weight transposes
    split_kernel<<<MM*EE/1024, 256>>>(x, xh, xl);
    wtrans_kernel  <<<dim3(EE/32,  EE/32),  256>>>(Wq, wqh, wql, EE, EE);
    wtrans_kernel  <<<dim3(EE/32,  EE/32),  256>>>(Wk, wkh, wkl, EE, EE);
    wtrans_kernel  <<<dim3(EE/32,  EE/32),  256>>>(Wv, wvh, wvl, EE, EE);
    wtrans16_kernel<<<dim3(EE/32,  EE/32),  256>>>(Wo, woh16, wol16, EE, EE);
    wtrans16_kernel<<<dim3(FFF/32, EE/32),  256>>>(W1, w1h16, w1l16, EE, FFF);
    wtrans16_kernel<<<dim3(EE/32,  FFF/32), 256>>>(W2, w2h16, w2l16, FFF, EE);

    // fused QKV projection (bf16 3-term, one launch)
    QKVParams qp;
    qp.bh[0] = wqh; qp.bh[1] = wkh; qp.bh[2] = wvh;
    qp.bl[0] = wql; qp.bl[1] = wkl; qp.bl[2] = wvl;
    qp.bias[0] = bq; qp.bias[1] = bk; qp.bias[2] = bv;
    qp.ch[0] = qh; qp.ch[1] = kh; qp.ch[2] = vh;
    qp.cl[0] = ql; qp.cl[1] = kl; qp.cl[2] = vl;
    qkv_gemm_kernel<<<dim3(18, MM/128), 256, GSM_BF>>>(xh, xl, qp);
    vtrans_kernel<<<dim3(SS/32, DD/32, BH), 256>>>(vh, vl, vth, vtl);

    // attention (banded, bf16 3-term)
    scores_mma_kernel<<<dim3(BANDW, NQT, BH), 256, 75776>>>(qh, ql, kh, kl, ph, pl, part);
    rowsum_kernel<<<NROWS / 256, 256>>>(part, inv);
    ctx_mma_kernel<<<dim3(NQT, BH), 256, 31232>>>(ph, pl, vth, vtl, inv, attn, ctx16);

    // output projection (fp16 2-term): K-split x2; merge+bias in add_ln
    gemm_fp16_kernel<0,false><<<dim3(EE/128, MM/128, 2), 256, GSM_H>>>(
        ctx16, woh16, wol16, nullptr, p0, p1, nullptr, EE, EE, EE/2);
    add_ln_kernel<true><<<MM, 256>>>(x, p0, p1, bo, g1, be1, h, hf16);

    // FFN (fp16 2-term): FFN1 full K + ReLU -> f1 fp16; FFN2 K-split x2
    gemm_fp16_kernel<1,true><<<dim3(FFF/128, MM/128, 1), 256, GSM_H>>>(
        hf16, w1h16, w1l16, b1, nullptr, nullptr, f116, FFF, EE, EE);
    gemm_fp16_kernel<0,false><<<dim3(EE/128, MM/128, 2), 256, GSM_H>>>(
        f116, w2h16, w2l16, nullptr, p0, p1, nullptr, EE, FFF, FFF/2);
    add_ln_kernel<false><<<MM, 256>>>(h, p0, p1, b2, g2, be2, out, nullptr);
}

// round 12
// speedup vs baseline: 5.1992x; 1.1622x over previous
#include <cuda_runtime.h>
#include <cuda_bf16.h>
#include <cuda_fp16.h>
#include <cstdint>

#define BB 2
#define SS 2048
#define EE 768
#define HH 12
#define DD 64
#define FFF 3072
#define MM (BB*SS)          // 4096
#define BH (BB*HH)          // 24
#define NROWS (BH*SS)       // 49152
#define NQT (SS/128)        // 16
#define BANDW 3

// ---------------- scratch (device globals; no allocation) ----------------
__device__ float g_p0 [MM*EE];
__device__ float g_p1 [MM*EE];
__device__ float g_h  [MM*EE];
__device__ float g_part[(size_t)NROWS*BANDW];
__device__ float g_inv [NROWS];
__device__ __half g_wqt16_h[EE*EE],  g_wqt16_l[EE*EE];
__device__ __half g_wkt16_h[EE*EE],  g_wkt16_l[EE*EE];
__device__ __half g_wvt16_h[EE*EE],  g_wvt16_l[EE*EE];
__device__ __half g_wot16_h[EE*EE],  g_wot16_l[EE*EE];
__device__ __half g_w1t16_h[EE*FFF], g_w1t16_l[EE*FFF];
__device__ __half g_w2t16_h[EE*FFF], g_w2t16_l[EE*FFF];
__device__ __half g_x16[MM*EE];
__device__ __half g_q16[MM*EE];
__device__ __half g_kh16[MM*EE], g_kl16[MM*EE];
__device__ __half g_vh16[MM*EE], g_vl16[MM*EE];
__device__ __half g_hf16 [MM*EE];
__device__ __half g_ctx16[MM*EE];
__device__ __half g_f116 [(size_t)MM*FFF];
__device__ __half g_vth16[(size_t)BH*DD*SS], g_vtl16[(size_t)BH*DD*SS];
__device__ __half g_p16[(size_t)BH*SS*SS];

// ---------------- helpers ---------------------------------------------------
__device__ __forceinline__ uint32_t smem_u32(const void* p) {
    uint32_t a;
    asm("{ .reg .u64 t; cvta.to.shared.u64 t, %1; cvt.u32.u64 %0, t; }"
        : "=r"(a) : "l"(p));
    return a;
}
__device__ __forceinline__ void ldmx4(uint32_t* r, uint32_t addr) {
    asm volatile("ldmatrix.sync.aligned.m8n8.x4.shared.b16 {%0,%1,%2,%3}, [%4];"
        : "=r"(r[0]), "=r"(r[1]), "=r"(r[2]), "=r"(r[3]) : "r"(addr));
}
__device__ __forceinline__ void mma_fp16(float* d, const uint32_t* a, const uint32_t* b) {
    asm volatile("mma.sync.aligned.m16n8k16.row.col.f32.f16.f16.f32 "
        "{%0,%1,%2,%3}, {%4,%5,%6,%7}, {%8,%9}, {%0,%1,%2,%3};"
        : "+f"(d[0]), "+f"(d[1]), "+f"(d[2]), "+f"(d[3])
        : "r"(a[0]), "r"(a[1]), "r"(a[2]), "r"(a[3]), "r"(b[0]), "r"(b[1]));
}
__device__ __forceinline__ uint32_t pack_h2(float a, float b) {
    __half2 h = __floats2half2_rn(a, b);
    return *(uint32_t*)&h;
}
__device__ __forceinline__ void split16(float x, float y, uint32_t& hi, uint32_t& lo) {
    __half hx = __float2half_rn(x);
    __half hy = __float2half_rn(y);
    __half lx = __float2half_rn(x - __half2float(hx));
    __half ly = __float2half_rn(y - __half2float(hy));
    hi = ((uint32_t)__half_as_ushort(hy) << 16) | __half_as_ushort(hx);
    lo = ((uint32_t)__half_as_ushort(ly) << 16) | __half_as_ushort(lx);
}
__device__ __forceinline__ void cp16(uint32_t s, const void* g) {
    asm volatile("cp.async.cg.shared.global [%0], [%1], 16;" :: "r"(s), "l"(g));
}
__device__ __forceinline__ void cpcommit() {
    asm volatile("cp.async.commit_group;" ::: "memory");
}
__device__ __forceinline__ void cpwait0() {
    asm volatile("cp.async.wait_group 0;" ::: "memory");
}

// ---------------- weight transpose+split (fp16 pairs) ----------------------
__global__ __launch_bounds__(256) void wtrans16_kernel(
    const float* __restrict__ W, __half* __restrict__ Th,
    __half* __restrict__ Tl, int K, int N)
{
    __shared__ float tile[32][33];
    const int n0 = blockIdx.x * 32, k0 = blockIdx.y * 32;
    const int tx = threadIdx.x & 31, ty = threadIdx.x >> 5;
#pragma unroll
    for (int i = 0; i < 32; i += 8)
        tile[ty + i][tx] = W[(size_t)(k0 + ty + i) * N + n0 + tx];
    __syncthreads();
#pragma unroll
    for (int i = 0; i < 32; i += 8) {
        float x = tile[tx][ty + i];
        __half h = __float2half_rn(x);
        __half l = __float2half_rn(x - __half2float(h));
        size_t o = (size_t)(n0 + ty + i) * K + k0 + tx;
        Th[o] = h; Tl[o] = l;
    }
}

// ---------------- elementwise fp32 -> fp16 single --------------------------
__global__ __launch_bounds__(256) void tohalf_kernel(
    const float* __restrict__ A, __half* __restrict__ O)
{
    size_t idx = ((size_t)blockIdx.x * 256 + threadIdx.x) * 4;
    float4 v = *(const float4*)&A[idx];
    *(uint2*)&O[idx] = make_uint2(pack_h2(v.x, v.y), pack_h2(v.z, v.w));
}

// ---------------- v transpose (from fp16 pairs): -> vt[bh][d][s] pairs -----
__global__ __launch_bounds__(256) void vtrans16_kernel(
    const __half* __restrict__ vh, const __half* __restrict__ vl,
    __half* __restrict__ Th, __half* __restrict__ Tl)
{
    __shared__ float tile[32][33];
    const int s0 = blockIdx.x * 32, d0 = blockIdx.y * 32, bh = blockIdx.z;
    const int b = bh / HH, h = bh % HH;
    const int tx = threadIdx.x & 31, ty = threadIdx.x >> 5;
#pragma unroll
    for (int i = 0; i < 32; i += 8) {
        size_t o = (size_t)(b * SS + s0 + ty + i) * EE + h * DD + d0 + tx;
        tile[ty + i][tx] = __half2float(vh[o]) + __half2float(vl[o]);
    }
    __syncthreads();
#pragma unroll
    for (int i = 0; i < 32; i += 8) {
        float x = tile[tx][ty + i];
        __half hh = __float2half_rn(x);
        __half ll = __float2half_rn(x - __half2float(hh));
        size_t o = ((size_t)bh * DD + d0 + ty + i) * SS + s0 + tx;
        Th[o] = hh; Tl[o] = ll;
    }
}

// ============ fp16 2-term GEMM (A single fp16, B fp16 hi/lo) ===============
// Tile 128x128, BK=32; smem per buffer 30720: A@0 Bh@10240 Bl@20480; x2=61440.
template<int EMIT, bool RELU>   // EMIT 0: fp32 (K-split); 1: fp16 single
__global__ __launch_bounds__(256) void gemm_fp16_kernel(
    const __half* __restrict__ Ah_, const __half* __restrict__ Bth,
    const __half* __restrict__ Btl, const float* __restrict__ bias,
    float* __restrict__ Cf0, float* __restrict__ Cf1, __half* __restrict__ Ch,
    int N, int K, int ksize)
{
    extern __shared__ char sm[];
    const int t = threadIdx.x, lane = t & 31, warp = t >> 5;
    const int wm = warp >> 2, wn = warp & 3;
    const int m0 = blockIdx.y * 128, n0 = blockIdx.x * 128;
    const int kbase = blockIdx.z * ksize;
    float* Cf = blockIdx.z ? Cf1 : Cf0;
    const uint32_t sb = smem_u32(sm);
    const int nch = ksize / 32;

    float acc[4][4][4];
#pragma unroll
    for (int i = 0; i < 4; i++)
#pragma unroll
        for (int j = 0; j < 4; j++)
#pragma unroll
            for (int u = 0; u < 4; u++) acc[i][j][u] = 0.f;

    const int r0i = t >> 2, c16 = t & 3;
    {
#pragma unroll
        for (int i = 0; i < 2; i++) {
            int row = r0i + i * 64;
            uint32_t so = (uint32_t)row * 80 + (uint32_t)c16 * 16;
            cp16(sb + so,         Ah_ + (size_t)(m0 + row) * K + kbase + c16 * 8);
            cp16(sb + 10240 + so, Bth + (size_t)(n0 + row) * K + kbase + c16 * 8);
            cp16(sb + 20480 + so, Btl + (size_t)(n0 + row) * K + kbase + c16 * 8);
        }
        cpcommit();
    }

    const uint32_t aBase = sb + (uint32_t)(wm * 64 + (lane & 15)) * 80
                              + (uint32_t)(lane >> 4) * 16;
    const uint32_t bBase = sb + 10240
                              + (uint32_t)(wn * 32 + (lane >> 4) * 8 + (lane & 7)) * 80
                              + (uint32_t)((lane >> 3) & 1) * 16;

    for (int ch = 0; ch < nch; ch++) {
        cpwait0();
        __syncthreads();
        if (ch + 1 < nch) {
            const int koff = kbase + (ch + 1) * 32;
            const uint32_t bp = (uint32_t)((ch + 1) & 1) * 30720;
#pragma unroll
            for (int i = 0; i < 2; i++) {
                int row = r0i + i * 64;
                uint32_t so = bp + (uint32_t)row * 80 + (uint32_t)c16 * 16;
                cp16(sb + so,         Ah_ + (size_t)(m0 + row) * K + koff + c16 * 8);
                cp16(sb + 10240 + so, Bth + (size_t)(n0 + row) * K + koff + c16 * 8);
                cp16(sb + 20480 + so, Btl + (size_t)(n0 + row) * K + koff + c16 * 8);
            }
            cpcommit();
        }

        const uint32_t bp = (uint32_t)(ch & 1) * 30720;
#pragma unroll
        for (int kk = 0; kk < 2; kk++) {
            uint32_t ah[4][4], bh[2][4], bl[2][4];
#pragma unroll
            for (int i = 0; i < 4; i++)
                ldmx4(ah[i], aBase + bp + (uint32_t)i * 1280 + (uint32_t)kk * 32);
#pragma unroll
            for (int p = 0; p < 2; p++) {
                ldmx4(bh[p], bBase + bp + (uint32_t)p * 1280 + (uint32_t)kk * 32);
                ldmx4(bl[p], bBase + bp + 10240 + (uint32_t)p * 1280 + (uint32_t)kk * 32);
            }
#pragma unroll
            for (int i = 0; i < 4; i++)
#pragma unroll
                for (int j = 0; j < 4; j++) {
                    mma_fp16(acc[i][j], ah[i], &bh[j >> 1][(j & 1) * 2]);
                    mma_fp16(acc[i][j], ah[i], &bl[j >> 1][(j & 1) * 2]);
                }
        }
    }

    const int g = lane >> 2, qd = lane & 3;
#pragma unroll
    for (int i = 0; i < 4; i++) {
        int r0 = m0 + wm * 64 + i * 16 + g;
#pragma unroll
        for (int j = 0; j < 4; j++) {
            int c = n0 + wn * 32 + j * 8 + qd * 2;
            float bx = bias ? __ldg(&bias[c]) : 0.f;
            float by = bias ? __ldg(&bias[c + 1]) : 0.f;
            float v0 = acc[i][j][0] + bx, v1 = acc[i][j][1] + by;
            float v2 = acc[i][j][2] + bx, v3 = acc[i][j][3] + by;
            if (RELU) {
                v0 = fmaxf(v0, 0.f); v1 = fmaxf(v1, 0.f);
                v2 = fmaxf(v2, 0.f); v3 = fmaxf(v3, 0.f);
            }
            if (EMIT == 0) {
                float2 o01 = {v0, v1};
                float2 o23 = {v2, v3};
                *(float2*)&Cf[(size_t)r0 * N + c]       = o01;
                *(float2*)&Cf[(size_t)(r0 + 8) * N + c] = o23;
            } else {
                *(uint32_t*)&Ch[(size_t)r0 * N + c]       = pack_h2(v0, v1);
                *(uint32_t*)&Ch[(size_t)(r0 + 8) * N + c] = pack_h2(v2, v3);
            }
        }
    }
}

// ---------------- fused QKV GEMM fp16-2: sel 0 -> single, 1/2 -> pair ------
struct QKVParams {
    const __half* bh[3];
    const __half* bl[3];
    const float* bias[3];
    __half* ch[3];
    __half* cl[3];   // null for sel 0
};
__global__ __launch_bounds__(256) void qkv_fp16_kernel(
    const __half* __restrict__ A16, QKVParams P)
{
    extern __shared__ char sm[];
    const int t = threadIdx.x, lane = t & 31, warp = t >> 5;
    const int wm = warp >> 2, wn = warp & 3;
    const int m0 = blockIdx.y * 128;
    const int sel = blockIdx.x / 6;
    const int n0  = (blockIdx.x % 6) * 128;
    const __half* Bth = P.bh[sel];
    const __half* Btl = P.bl[sel];
    const float* bias = P.bias[sel];
    __half* Ch = P.ch[sel];
    __half* Cl = P.cl[sel];
    const uint32_t sb = smem_u32(sm);
    const int K = EE, N = EE, nch = K / 32;

    float acc[4][4][4];
#pragma unroll
    for (int i = 0; i < 4; i++)
#pragma unroll
        for (int j = 0; j < 4; j++)
#pragma unroll
            for (int u = 0; u < 4; u++) acc[i][j][u] = 0.f;

    const int r0i = t >> 2, c16 = t & 3;
    {
#pragma unroll
        for (int i = 0; i < 2; i++) {
            int row = r0i + i * 64;
            uint32_t so = (uint32_t)row * 80 + (uint32_t)c16 * 16;
            cp16(sb + so,         A16 + (size_t)(m0 + row) * K + c16 * 8);
            cp16(sb + 10240 + so, Bth + (size_t)(n0 + row) * K + c16 * 8);
            cp16(sb + 20480 + so, Btl + (size_t)(n0 + row) * K + c16 * 8);
        }
        cpcommit();
    }

    const uint32_t aBase = sb + (uint32_t)(wm * 64 + (lane & 15)) * 80
                              + (uint32_t)(lane >> 4) * 16;
    const uint32_t bBase = sb + 10240
                              + (uint32_t)(wn * 32 + (lane >> 4) * 8 + (lane & 7)) * 80
                              + (uint32_t)((lane >> 3) & 1) * 16;

    for (int ch = 0; ch < nch; ch++) {
        cpwait0();
        __syncthreads();
        if (ch + 1 < nch) {
            const int koff = (ch + 1) * 32;
            const uint32_t bp = (uint32_t)((ch + 1) & 1) * 30720;
#pragma unroll
            for (int i = 0; i < 2; i++) {
                int row = r0i + i * 64;
                uint32_t so = bp + (uint32_t)row * 80 + (uint32_t)c16 * 16;
                cp16(sb + so,         A16 + (size_t)(m0 + row) * K + koff + c16 * 8);
                cp16(sb + 10240 + so, Bth + (size_t)(n0 + row) * K + koff + c16 * 8);
                cp16(sb + 20480 + so, Btl + (size_t)(n0 + row) * K + koff + c16 * 8);
            }
            cpcommit();
        }

        const uint32_t bp = (uint32_t)(ch & 1) * 30720;
#pragma unroll
        for (int kk = 0; kk < 2; kk++) {
            uint32_t ah[4][4], bh[2][4], bl[2][4];
#pragma unroll
            for (int i = 0; i < 4; i++)
                ldmx4(ah[i], aBase + bp + (uint32_t)i * 1280 + (uint32_t)kk * 32);
#pragma unroll
            for (int p = 0; p < 2; p++) {
                ldmx4(bh[p], bBase + bp + (uint32_t)p * 1280 + (uint32_t)kk * 32);
                ldmx4(bl[p], bBase + bp + 10240 + (uint32_t)p * 1280 + (uint32_t)kk * 32);
            }
#pragma unroll
            for (int i = 0; i < 4; i++)
#pragma unroll
                for (int j = 0; j < 4; j++) {
                    mma_fp16(acc[i][j], ah[i], &bh[j >> 1][(j & 1) * 2]);
                    mma_fp16(acc[i][j], ah[i], &bl[j >> 1][(j & 1) * 2]);
                }
        }
    }

    const int g = lane >> 2, qd = lane & 3;
#pragma unroll
    for (int i = 0; i < 4; i++) {
        int r0 = m0 + wm * 64 + i * 16 + g;
#pragma unroll
        for (int j = 0; j < 4; j++) {
            int c = n0 + wn * 32 + j * 8 + qd * 2;
            float bx = __ldg(&bias[c]), by = __ldg(&bias[c + 1]);
            float v0 = acc[i][j][0] + bx, v1 = acc[i][j][1] + by;
            float v2 = acc[i][j][2] + bx, v3 = acc[i][j][3] + by;
            if (sel == 0) {
                *(uint32_t*)&Ch[(size_t)r0 * N + c]       = pack_h2(v0, v1);
                *(uint32_t*)&Ch[(size_t)(r0 + 8) * N + c] = pack_h2(v2, v3);
            } else {
                uint32_t h01, l01, h23, l23;
                split16(v0, v1, h01, l01);
                split16(v2, v3, h23, l23);
                *(uint32_t*)&Ch[(size_t)r0 * N + c]       = h01;
                *(uint32_t*)&Cl[(size_t)r0 * N + c]       = l01;
                *(uint32_t*)&Ch[(size_t)(r0 + 8) * N + c] = h23;
                *(uint32_t*)&Cl[(size_t)(r0 + 8) * N + c] = l23;
            }
        }
    }
}

// ---------------- scores fp16-2 (band): P16 = exp(QK^T/8-|i-j|) ------------
// smem: Q@0 (18432), Kh@18432, Kl@36864, red@55296 -> 57344
__global__ __launch_bounds__(256) void scores_fp16_kernel(
    const __half* __restrict__ q16,
    const __half* __restrict__ kh16, const __half* __restrict__ kl16,
    __half* __restrict__ P16, float* __restrict__ partials)
{
    extern __shared__ char sm[];
    const uint32_t sb = smem_u32(sm);
    const int t = threadIdx.x, lane = t & 31, warp = t >> 5;
    const int wm = warp >> 2, wn = warp & 3;
    const int bh = blockIdx.z, b = bh / HH, h = bh % HH;
    const int qt = blockIdx.y;
    const int kt = qt + (int)blockIdx.x - 1;
    const int q0 = qt * 128;

    if (kt < 0 || kt >= NQT) {
        if (t < 128)
            partials[((size_t)bh * SS + q0 + t) * BANDW + blockIdx.x] = 0.f;
        return;
    }
    const int k0 = kt * 128;
    float* red = (float*)(sm + 55296);

#pragma unroll
    for (int i = 0; i < 4; i++) {
        int idx = t + i * 256;
        int row = idx >> 3, c = idx & 7;
        uint32_t off = (uint32_t)row * 144 + (uint32_t)c * 16;
        size_t qg = (size_t)(b * SS + q0 + row) * EE + h * DD + c * 8;
        size_t kg = (size_t)(b * SS + k0 + row) * EE + h * DD + c * 8;
        *(uint4*)(sm + off)         = *(const uint4*)&q16[qg];
        *(uint4*)(sm + 18432 + off) = *(const uint4*)&kh16[kg];
        *(uint4*)(sm + 36864 + off) = *(const uint4*)&kl16[kg];
    }
    __syncthreads();

    float acc[4][4][4];
#pragma unroll
    for (int i = 0; i < 4; i++)
#pragma unroll
        for (int j = 0; j < 4; j++)
#pragma unroll
            for (int u = 0; u < 4; u++) acc[i][j][u] = 0.f;

    const uint32_t aAddr = sb + (uint32_t)(wm * 64 + (lane & 15)) * 144
                              + (uint32_t)(lane >> 4) * 16;
    const uint32_t bBase = sb + 18432
                              + (uint32_t)(wn * 32 + (lane >> 4) * 8 + (lane & 7)) * 144
                              + (uint32_t)((lane >> 3) & 1) * 16;
#pragma unroll
    for (int kk = 0; kk < 4; kk++) {
        uint32_t ah[4][4], bh[2][4], bl[2][4];
#pragma unroll
        for (int i = 0; i < 4; i++)
            ldmx4(ah[i], aAddr + (uint32_t)i * 2304 + (uint32_t)kk * 32);
#pragma unroll
        for (int p = 0; p < 2; p++) {
            ldmx4(bh[p], bBase + (uint32_t)p * 2304 + (uint32_t)kk * 32);
            ldmx4(bl[p], bBase + 18432 + (uint32_t)p * 2304 + (uint32_t)kk * 32);
        }
#pragma unroll
        for (int i = 0; i < 4; i++)
#pragma unroll
            for (int j = 0; j < 4; j++) {
                mma_fp16(acc[i][j], ah[i], &bh[j >> 1][(j & 1) * 2]);
                mma_fp16(acc[i][j], ah[i], &bl[j >> 1][(j & 1) * 2]);
            }
    }

    const int g = lane >> 2, qd = lane & 3;
#pragma unroll
    for (int i = 0; i < 4; i++) {
        int rloc = wm * 64 + i * 16 + g;
        int qi = q0 + rloc;
        float s0 = 0.f, s1 = 0.f;
#pragma unroll
        for (int j = 0; j < 4; j++) {
            int kj = k0 + wn * 32 + j * 8 + qd * 2;
            float e0 = __expf(acc[i][j][0] * 0.125f - fabsf((float)(qi - kj)));
            float e1 = __expf(acc[i][j][1] * 0.125f - fabsf((float)(qi - kj - 1)));
            float e2 = __expf(acc[i][j][2] * 0.125f - fabsf((float)(qi + 8 - kj)));
            float e3 = __expf(acc[i][j][3] * 0.125f - fabsf((float)(qi + 8 - kj - 1)));
            s0 += e0 + e1; s1 += e2 + e3;
            size_t o0 = ((size_t)bh * SS + qi) * SS + kj;
            size_t o1 = ((size_t)bh * SS + qi + 8) * SS + kj;
            *(uint32_t*)(P16 + o0) = pack_h2(e0, e1);
            *(uint32_t*)(P16 + o1) = pack_h2(e2, e3);
        }
        s0 += __shfl_xor_sync(0xFFFFFFFF, s0, 1);
        s0 += __shfl_xor_sync(0xFFFFFFFF, s0, 2);
        s1 += __shfl_xor_sync(0xFFFFFFFF, s1, 1);
        s1 += __shfl_xor_sync(0xFFFFFFFF, s1, 2);
        if (qd == 0) {
            red[rloc * 4 + wn]       = s0;
            red[(rloc + 8) * 4 + wn] = s1;
        }
    }
    __syncthreads();
    if (t < 128) {
        float s = red[t * 4] + red[t * 4 + 1] + red[t * 4 + 2] + red[t * 4 + 3];
        partials[((size_t)bh * SS + q0 + t) * BANDW + blockIdx.x] = s;
    }
}

// ---------------- reduce partial row sums -> 1/sum -------------------------
__global__ __launch_bounds__(256) void rowsum_kernel(
    const float* __restrict__ partials, float* __restrict__ inv)
{
    int r = blockIdx.x * 256 + threadIdx.x;
    float s = 0.f;
#pragma unroll
    for (int i = 0; i < BANDW; i++) s += partials[(size_t)r * BANDW + i];
    inv[r] = 1.0f / s;
}

// ---------------- ctx fp16-2 (band); emits ctx fp16 + fp32 attn ------------
// smem: P@0 (10240), Vh@10240 (5120), Vl@15360 (5120), invs@20480 -> 20992
__global__ __launch_bounds__(256) void ctx_fp16_kernel(
    const __half* __restrict__ P16,
    const __half* __restrict__ Vth, const __half* __restrict__ Vtl,
    const float* __restrict__ inv, float* __restrict__ attn,
    __half* __restrict__ ctx16)
{
    extern __shared__ char sm[];
    const uint32_t sb = smem_u32(sm);
    const int t = threadIdx.x, lane = t & 31, warp = t >> 5;
    const int wm = warp >> 1, wn = warp & 1;
    const int bh = blockIdx.y, b = bh / HH, h = bh % HH;
    const int qt = blockIdx.x;
    const int q0 = qt * 128;
    float* invs = (float*)(sm + 20480);

    if (t < 128) invs[t] = inv[(size_t)bh * SS + q0 + t];
    __syncthreads();

    const __half* Pb = P16 + (size_t)bh * SS * SS;
    float* attnb = attn + (size_t)bh * SS * SS;

    const int tlo = (qt > 0) ? qt - 1 : 0;
    const int thi = (qt + 2 < NQT) ? qt + 2 : NQT;
    const int c_lo = tlo * 4, c_hi = thi * 4;

    {
        const float4 fz = {0.f, 0.f, 0.f, 0.f};
#pragma unroll
        for (int seg = 0; seg < 2; seg++) {
            const int cbeg = seg ? thi * 128 : 0;
            const int cend = seg ? SS : tlo * 128;
            const int w4 = (cend - cbeg) >> 2;
            if (w4 <= 0) continue;
            const int n4 = 128 * w4;
            for (int i = t; i < n4; i += 256) {
                int row = i / w4, cc = i % w4;
                *(float4*)&attnb[(size_t)(q0 + row) * SS + cbeg + cc * 4] = fz;
            }
        }
    }

    float acc[2][4][4];
#pragma unroll
    for (int i = 0; i < 2; i++)
#pragma unroll
        for (int j = 0; j < 4; j++)
#pragma unroll
            for (int u = 0; u < 4; u++) acc[i][j][u] = 0.f;

    uint4 p_r[2], vh_r, vl_r;
    const int vr = t >> 2, vc = t & 3;

    // prologue: load chunk c_lo + write its normalized attn
    {
        const int kt = c_lo * 32;
#pragma unroll
        for (int i = 0; i < 2; i++) {
            int idx = t + i * 256;
            int row = idx >> 2, c = idx & 3;
            p_r[i] = *(const uint4*)(Pb + (size_t)(q0 + row) * SS + kt + c * 8);
        }
        vh_r = *(const uint4*)(Vth + ((size_t)bh * DD + vr) * SS + kt + vc * 8);
        vl_r = *(const uint4*)(Vtl + ((size_t)bh * DD + vr) * SS + kt + vc * 8);
#pragma unroll
        for (int i = 0; i < 2; i++) {
            int idx = t + i * 256;
            int row = idx >> 2, c = idx & 3;
            float iv = invs[row];
            const __half2* hp = (const __half2*)&p_r[i];
            float out8[8];
#pragma unroll
            for (int u = 0; u < 4; u++) {
                float2 f = __half22float2(hp[u]);
                out8[u * 2]     = f.x * iv;
                out8[u * 2 + 1] = f.y * iv;
            }
            size_t ao = (size_t)(q0 + row) * SS + kt + c * 8;
            *(float4*)(attnb + ao)     = *(float4*)&out8[0];
            *(float4*)(attnb + ao + 4) = *(float4*)&out8[4];
        }
    }

    const uint32_t aAddr = sb + (uint32_t)(wm * 32 + (lane & 15)) * 80
                              + (uint32_t)(lane >> 4) * 16;
    const uint32_t bBase = sb + 10240
                              + (uint32_t)(wn * 32 + (lane >> 4) * 8 + (lane & 7)) * 80
                              + (uint32_t)((lane >> 3) & 1) * 16;

    for (int ch = c_lo; ch < c_hi; ch++) {
#pragma unroll
        for (int i = 0; i < 2; i++) {
            int idx = t + i * 256;
            int row = idx >> 2, c = idx & 3;
            *(uint4*)(sm + (uint32_t)row * 80 + (uint32_t)c * 16) = p_r[i];
        }
        {
            uint32_t off = (uint32_t)vr * 80 + (uint32_t)vc * 16;
            *(uint4*)(sm + 10240 + off) = vh_r;
            *(uint4*)(sm + 15360 + off) = vl_r;
        }
        __syncthreads();

        if (ch + 1 < c_hi) {
            const int kt = (ch + 1) * 32;
#pragma unroll
            for (int i = 0; i < 2; i++) {
                int idx = t + i * 256;
                int row = idx >> 2, c = idx & 3;
                p_r[i] = *(const uint4*)(Pb + (size_t)(q0 + row) * SS + kt + c * 8);
            }
            vh_r = *(const uint4*)(Vth + ((size_t)bh * DD + vr) * SS + kt + vc * 8);
            vl_r = *(const uint4*)(Vtl + ((size_t)bh * DD + vr) * SS + kt + vc * 8);
#pragma unroll
            for (int i = 0; i < 2; i++) {
                int idx = t + i * 256;
                int row = idx >> 2, c = idx & 3;
                float iv = invs[row];
                const __half2* hp = (const __half2*)&p_r[i];
                float out8[8];
#pragma unroll
                for (int u = 0; u < 4; u++) {
                    float2 f = __half22float2(hp[u]);
                    out8[u * 2]     = f.x * iv;
                    out8[u * 2 + 1] = f.y * iv;
                }
                size_t ao = (size_t)(q0 + row) * SS + kt + c * 8;
                *(float4*)(attnb + ao)     = *(float4*)&out8[0];
                *(float4*)(attnb + ao + 4) = *(float4*)&out8[4];
            }
        }

#pragma unroll
        for (int kk = 0; kk < 2; kk++) {
            uint32_t ah[2][4], bh[2][4], bl[2][4];
#pragma unroll
            for (int i = 0; i < 2; i++)
                ldmx4(ah[i], aAddr + (uint32_t)i * 1280 + (uint32_t)kk * 32);
#pragma unroll
            for (int p = 0; p < 2; p++) {
                ldmx4(bh[p], bBase + (uint32_t)p * 1280 + (uint32_t)kk * 32);
                ldmx4(bl[p], bBase + 5120 + (uint32_t)p * 1280 + (uint32_t)kk * 32);
            }
#pragma unroll
            for (int i = 0; i < 2; i++)
#pragma unroll
                for (int j = 0; j < 4; j++) {
                    mma_fp16(acc[i][j], ah[i], &bh[j >> 1][(j & 1) * 2]);
                    mma_fp16(acc[i][j], ah[i], &bl[j >> 1][(j & 1) * 2]);
                }
        }
        __syncthreads();
    }

    const int g = lane >> 2, qd = lane & 3;
#pragma unroll
    for (int i = 0; i < 2; i++) {
        int rloc = wm * 32 + i * 16 + g;
        float iv0 = invs[rloc], iv1 = invs[rloc + 8];
#pragma unroll
        for (int j = 0; j < 4; j++) {
            int c = wn * 32 + j * 8 + qd * 2;
            float v0 = acc[i][j][0] * iv0, v1 = acc[i][j][1] * iv0;
            float v2 = acc[i][j][2] * iv1, v3 = acc[i][j][3] * iv1;
            size_t o0 = ((size_t)(b * SS + q0 + rloc) * HH + h) * DD + c;
            size_t o1 = ((size_t)(b * SS + q0 + rloc + 8) * HH + h) * DD + c;
            *(uint32_t*)&ctx16[o0] = pack_h2(v0, v1);
            *(uint32_t*)&ctx16[o1] = pack_h2(v2, v3);
        }
    }
}

// ------ out = LayerNorm(A + P0 + P1 + bias) * g + be (opt fp16 emit) -------
template<bool EMIT16>
__global__ __launch_bounds__(256) void add_ln_kernel(
    const float* __restrict__ A, const float* __restrict__ P0,
    const float* __restrict__ P1, const float* __restrict__ bias,
    const float* __restrict__ g, const float* __restrict__ be,
    float* __restrict__ out, __half* __restrict__ O16)
{
    __shared__ float rs[256];
    __shared__ float rs2[256];
    const size_t off = (size_t)blockIdx.x * EE;
    const int t = threadIdx.x;
    float x[3];
    float s = 0.f, s2 = 0.f;
#pragma unroll
    for (int i = 0; i < 3; i++) {
        int c = t + i * 256;
        x[i] = A[off + c] + (P0[off + c] + P1[off + c] + bias[c]);
        s += x[i]; s2 += x[i] * x[i];
    }
    rs[t] = s; rs2[t] = s2; __syncthreads();
    for (int st = 128; st > 0; st >>= 1) {
        if (t < st) { rs[t] += rs[t + st]; rs2[t] += rs2[t + st]; }
        __syncthreads();
    }
    const float mu  = rs[0] * (1.0f / EE);
    const float var = rs2[0] * (1.0f / EE) - mu * mu;
    const float r   = rsqrtf(var + 1e-5f);
#pragma unroll
    for (int i = 0; i < 3; i++) {
        int c = t + i * 256;
        float y = (x[i] - mu) * r * g[c] + be[c];
        out[off + c] = y;
        if (EMIT16) O16[off + c] = __float2half_rn(y);
    }
}

// ---------------- launch --------------------------------------------------
extern "C" void kernel_launch(void* const* d_in, const int* in_sizes, int n_in,
                              void* d_out, int out_size)
{
    const float* x  = (const float*)d_in[0];
    const float* Wq = (const float*)d_in[1];
    const float* bq = (const float*)d_in[2];
    const float* Wk = (const float*)d_in[3];
    const float* bk = (const float*)d_in[4];
    const float* Wv = (const float*)d_in[5];
    const float* bv = (const float*)d_in[6];
    const float* Wo = (const float*)d_in[7];
    const float* bo = (const float*)d_in[8];
    const float* W1 = (const float*)d_in[9];
    const float* b1 = (const float*)d_in[10];
    const float* W2 = (const float*)d_in[11];
    const float* b2 = (const float*)d_in[12];
    const float* g1 = (const float*)d_in[13];
    const float* be1= (const float*)d_in[14];
    const float* g2 = (const float*)d_in[15];
    const float* be2= (const float*)d_in[16];

    float* out  = (float*)d_out;
    float* attn = out + (size_t)BB * SS * EE;

    float *p0, *p1, *h, *part, *inv;
    cudaGetSymbolAddress((void**)&p0,   g_p0);
    cudaGetSymbolAddress((void**)&p1,   g_p1);
    cudaGetSymbolAddress((void**)&h,    g_h);
    cudaGetSymbolAddress((void**)&part, g_part);
    cudaGetSymbolAddress((void**)&inv,  g_inv);
    __half *wqh,*wql,*wkh,*wkl,*wvh,*wvl,*woh,*wol,*w1h,*w1l,*w2h,*w2l;
    __half *x16,*q16,*kh16,*kl16,*vh16,*vl16,*hf16,*ctx16,*f116,*vth,*vtl,*p16;
    cudaGetSymbolAddress((void**)&wqh, g_wqt16_h); cudaGetSymbolAddress((void**)&wql, g_wqt16_l);
    cudaGetSymbolAddress((void**)&wkh, g_wkt16_h); cudaGetSymbolAddress((void**)&wkl, g_wkt16_l);
    cudaGetSymbolAddress((void**)&wvh, g_wvt16_h); cudaGetSymbolAddress((void**)&wvl, g_wvt16_l);
    cudaGetSymbolAddress((void**)&woh, g_wot16_h); cudaGetSymbolAddress((void**)&wol, g_wot16_l);
    cudaGetSymbolAddress((void**)&w1h, g_w1t16_h); cudaGetSymbolAddress((void**)&w1l, g_w1t16_l);
    cudaGetSymbolAddress((void**)&w2h, g_w2t16_h); cudaGetSymbolAddress((void**)&w2l, g_w2t16_l);
    cudaGetSymbolAddress((void**)&x16, g_x16);
    cudaGetSymbolAddress((void**)&q16, g_q16);
    cudaGetSymbolAddress((void**)&kh16, g_kh16); cudaGetSymbolAddress((void**)&kl16, g_kl16);
    cudaGetSymbolAddress((void**)&vh16, g_vh16); cudaGetSymbolAddress((void**)&vl16, g_vl16);
    cudaGetSymbolAddress((void**)&hf16, g_hf16);
    cudaGetSymbolAddress((void**)&ctx16, g_ctx16);
    cudaGetSymbolAddress((void**)&f116, g_f116);
    cudaGetSymbolAddress((void**)&vth, g_vth16); cudaGetSymbolAddress((void**)&vtl, g_vtl16);
    cudaGetSymbolAddress((void**)&p16, g_p16);

    const int GSM_H = 61440;
    cudaFuncSetAttribute(gemm_fp16_kernel<0,false>, cudaFuncAttributeMaxDynamicSharedMemorySize, GSM_H);
    cudaFuncSetAttribute(gemm_fp16_kernel<1,true>,  cudaFuncAttributeMaxDynamicSharedMemorySize, GSM_H);
    cudaFuncSetAttribute(qkv_fp16_kernel,           cudaFuncAttributeMaxDynamicSharedMemorySize, GSM_H);
    cudaFuncSetAttribute(scores_fp16_kernel, cudaFuncAttributeMaxDynamicSharedMemorySize, 57344);
    cudaFuncSetAttribute(ctx_fp16_kernel,    cudaFuncAttributeMaxDynamicSharedMemorySize, 20992);

    // prep
    tohalf_kernel<<<MM*EE/1024, 256>>>(x, x16);
    wtrans16_kernel<<<dim3(EE/32,  EE/32),  256>>>(Wq, wqh, wql, EE, EE);
    wtrans16_kernel<<<dim3(EE/32,  EE/32),  256>>>(Wk, wkh, wkl, EE, EE);
    wtrans16_kernel<<<dim3(EE/32,  EE/32),  256>>>(Wv, wvh, wvl, EE, EE);
    wtrans16_kernel<<<dim3(EE/32,  EE/32),  256>>>(Wo, woh, wol, EE, EE);
    wtrans16_kernel<<<dim3(FFF/32, EE/32),  256>>>(W1, w1h, w1l, EE, FFF);
    wtrans16_kernel<<<dim3(EE/32,  FFF/32), 256>>>(W2, w2h, w2l, FFF, EE);

    // fused QKV (fp16-2): Q single, K/V pairs
    QKVParams qp;
    qp.bh[0] = wqh; qp.bh[1] = wkh; qp.bh[2] = wvh;
    qp.bl[0] = wql; qp.bl[1] = wkl; qp.bl[2] = wvl;
    qp.bias[0] = bq; qp.bias[1] = bk; qp.bias[2] = bv;
    qp.ch[0] = q16;  qp.ch[1] = kh16; qp.ch[2] = vh16;
    qp.cl[0] = nullptr; qp.cl[1] = kl16; qp.cl[2] = vl16;
    qkv_fp16_kernel<<<dim3(18, MM/128), 256, GSM_H>>>(x16, qp);
    vtrans16_kernel<<<dim3(SS/32, DD/32, BH), 256>>>(vh16, vl16, vth, vtl);

    // attention (banded, fp16-2)
    scores_fp16_kernel<<<dim3(BANDW, NQT, BH), 256, 57344>>>(q16, kh16, kl16, p16, part);
    rowsum_kernel<<<NROWS / 256, 256>>>(part, inv);
    ctx_fp16_kernel<<<dim3(NQT, BH), 256, 20992>>>(p16, vth, vtl, inv, attn, ctx16);

    // output projection (fp16-2): K-split x2; merge+bias in add_ln
    gemm_fp16_kernel<0,false><<<dim3(EE/128, MM/128, 2), 256, GSM_H>>>(
        ctx16, woh, wol, nullptr, p0, p1, nullptr, EE, EE, EE/2);
    add_ln_kernel<true><<<MM, 256>>>(x, p0, p1, bo, g1, be1, h, hf16);

    // FFN (fp16-2)
    gemm_fp16_kernel<1,true><<<dim3(FFF/128, MM/128, 1), 256, GSM_H>>>(
        hf16, w1h, w1l, b1, nullptr, nullptr, f116, FFF, EE, EE);
    gemm_fp16_kernel<0,false><<<dim3(EE/128, MM/128, 2), 256, GSM_H>>>(
        f116, w2h, w2l, nullptr, p0, p1, nullptr, EE, FFF, FFF/2);
    add_ln_kernel<false><<<MM, 256>>>(h, p0, p1, b2, g2, be2, out, nullptr);
}

// round 13
// speedup vs baseline: 7.2706x; 1.3984x over previous
#include <cuda_runtime.h>
#include <cuda_fp16.h>
#include <cstdint>

#define BB 2
#define SS 2048
#define EE 768
#define HH 12
#define DD 64
#define FFF 3072
#define MM (BB*SS)          // 4096
#define BH (BB*HH)          // 24
#define NROWS (BH*SS)       // 49152
#define NQT (SS/128)        // 16
#define BANDW 3

// ---------------- scratch (device globals; no allocation) ----------------
__device__ float g_p0 [MM*EE];
__device__ float g_p1 [MM*EE];
__device__ float g_h  [MM*EE];
__device__ float g_part[(size_t)NROWS*BANDW];
__device__ float g_inv [NROWS];
__device__ __half g_wqt[EE*EE], g_wkt[EE*EE], g_wvt[EE*EE], g_wot[EE*EE];
__device__ __half g_w1t[EE*FFF], g_w2t[EE*FFF];
__device__ __half g_x16[MM*EE];
__device__ __half g_q16[MM*EE], g_k16[MM*EE], g_v16[MM*EE];
__device__ __half g_hf16 [MM*EE];
__device__ __half g_ctx16[MM*EE];
__device__ __half g_f116 [(size_t)MM*FFF];
__device__ __half g_vt16[(size_t)BH*DD*SS];
__device__ __half g_p16[(size_t)BH*SS*SS];

// ---------------- helpers ---------------------------------------------------
__device__ __forceinline__ uint32_t smem_u32(const void* p) {
    uint32_t a;
    asm("{ .reg .u64 t; cvta.to.shared.u64 t, %1; cvt.u32.u64 %0, t; }"
        : "=r"(a) : "l"(p));
    return a;
}
__device__ __forceinline__ void ldmx4(uint32_t* r, uint32_t addr) {
    asm volatile("ldmatrix.sync.aligned.m8n8.x4.shared.b16 {%0,%1,%2,%3}, [%4];"
        : "=r"(r[0]), "=r"(r[1]), "=r"(r[2]), "=r"(r[3]) : "r"(addr));
}
__device__ __forceinline__ void mma_fp16(float* d, const uint32_t* a, const uint32_t* b) {
    asm volatile("mma.sync.aligned.m16n8k16.row.col.f32.f16.f16.f32 "
        "{%0,%1,%2,%3}, {%4,%5,%6,%7}, {%8,%9}, {%0,%1,%2,%3};"
        : "+f"(d[0]), "+f"(d[1]), "+f"(d[2]), "+f"(d[3])
        : "r"(a[0]), "r"(a[1]), "r"(a[2]), "r"(a[3]), "r"(b[0]), "r"(b[1]));
}
__device__ __forceinline__ uint32_t pack_h2(float a, float b) {
    __half2 h = __floats2half2_rn(a, b);
    return *(uint32_t*)&h;
}
__device__ __forceinline__ void cp16(uint32_t s, const void* g) {
    asm volatile("cp.async.cg.shared.global [%0], [%1], 16;" :: "r"(s), "l"(g));
}
__device__ __forceinline__ void cpcommit() {
    asm volatile("cp.async.commit_group;" ::: "memory");
}
__device__ __forceinline__ void cpwait0() {
    asm volatile("cp.async.wait_group 0;" ::: "memory");
}

// ---------------- weight transpose (fp16 single) ---------------------------
__global__ __launch_bounds__(256) void wtrans1_kernel(
    const float* __restrict__ W, __half* __restrict__ T, int K, int N)
{
    __shared__ float tile[32][33];
    const int n0 = blockIdx.x * 32, k0 = blockIdx.y * 32;
    const int tx = threadIdx.x & 31, ty = threadIdx.x >> 5;
#pragma unroll
    for (int i = 0; i < 32; i += 8)
        tile[ty + i][tx] = W[(size_t)(k0 + ty + i) * N + n0 + tx];
    __syncthreads();
#pragma unroll
    for (int i = 0; i < 32; i += 8)
        T[(size_t)(n0 + ty + i) * K + k0 + tx] = __float2half_rn(tile[tx][ty + i]);
}

// ---------------- elementwise fp32 -> fp16 single --------------------------
__global__ __launch_bounds__(256) void tohalf_kernel(
    const float* __restrict__ A, __half* __restrict__ O)
{
    size_t idx = ((size_t)blockIdx.x * 256 + threadIdx.x) * 4;
    float4 v = *(const float4*)&A[idx];
    *(uint2*)&O[idx] = make_uint2(pack_h2(v.x, v.y), pack_h2(v.z, v.w));
}

// ---------------- v transpose (fp16 single): -> vt[bh][d][s] ----------------
__global__ __launch_bounds__(256) void vtrans1_kernel(
    const __half* __restrict__ v, __half* __restrict__ T)
{
    __shared__ __half tile[32][40];
    const int s0 = blockIdx.x * 32, d0 = blockIdx.y * 32, bh = blockIdx.z;
    const int b = bh / HH, h = bh % HH;
    const int tx = threadIdx.x & 31, ty = threadIdx.x >> 5;
#pragma unroll
    for (int i = 0; i < 32; i += 8)
        tile[ty + i][tx] = v[(size_t)(b * SS + s0 + ty + i) * EE + h * DD + d0 + tx];
    __syncthreads();
#pragma unroll
    for (int i = 0; i < 32; i += 8)
        T[((size_t)bh * DD + d0 + ty + i) * SS + s0 + tx] = tile[tx][ty + i];
}

// ============ fp16 1-term GEMM (A single, B single) ========================
// Tile 128x128, BK=32; smem per buffer 20480: A@0 B@10240; x2 = 40960.
template<int EMIT, bool RELU>   // EMIT 0: fp32 (K-split); 1: fp16 single
__global__ __launch_bounds__(256) void gemm1_kernel(
    const __half* __restrict__ A16, const __half* __restrict__ B16,
    const float* __restrict__ bias,
    float* __restrict__ Cf0, float* __restrict__ Cf1, __half* __restrict__ Ch,
    int N, int K, int ksize)
{
    extern __shared__ char sm[];
    const int t = threadIdx.x, lane = t & 31, warp = t >> 5;
    const int wm = warp >> 2, wn = warp & 3;
    const int m0 = blockIdx.y * 128, n0 = blockIdx.x * 128;
    const int kbase = blockIdx.z * ksize;
    float* Cf = blockIdx.z ? Cf1 : Cf0;
    const uint32_t sb = smem_u32(sm);
    const int nch = ksize / 32;

    float acc[4][4][4];
#pragma unroll
    for (int i = 0; i < 4; i++)
#pragma unroll
        for (int j = 0; j < 4; j++)
#pragma unroll
            for (int u = 0; u < 4; u++) acc[i][j][u] = 0.f;

    const int r0i = t >> 2, c16 = t & 3;
    {
#pragma unroll
        for (int i = 0; i < 2; i++) {
            int row = r0i + i * 64;
            uint32_t so = (uint32_t)row * 80 + (uint32_t)c16 * 16;
            cp16(sb + so,         A16 + (size_t)(m0 + row) * K + kbase + c16 * 8);
            cp16(sb + 10240 + so, B16 + (size_t)(n0 + row) * K + kbase + c16 * 8);
        }
        cpcommit();
    }

    const uint32_t aBase = sb + (uint32_t)(wm * 64 + (lane & 15)) * 80
                              + (uint32_t)(lane >> 4) * 16;
    const uint32_t bBase = sb + 10240
                              + (uint32_t)(wn * 32 + (lane >> 4) * 8 + (lane & 7)) * 80
                              + (uint32_t)((lane >> 3) & 1) * 16;

    for (int ch = 0; ch < nch; ch++) {
        cpwait0();
        __syncthreads();
        if (ch + 1 < nch) {
            const int koff = kbase + (ch + 1) * 32;
            const uint32_t bp = (uint32_t)((ch + 1) & 1) * 20480;
#pragma unroll
            for (int i = 0; i < 2; i++) {
                int row = r0i + i * 64;
                uint32_t so = bp + (uint32_t)row * 80 + (uint32_t)c16 * 16;
                cp16(sb + so,         A16 + (size_t)(m0 + row) * K + koff + c16 * 8);
                cp16(sb + 10240 + so, B16 + (size_t)(n0 + row) * K + koff + c16 * 8);
            }
            cpcommit();
        }

        const uint32_t bp = (uint32_t)(ch & 1) * 20480;
#pragma unroll
        for (int kk = 0; kk < 2; kk++) {
            uint32_t ah[4][4], bh[2][4];
#pragma unroll
            for (int i = 0; i < 4; i++)
                ldmx4(ah[i], aBase + bp + (uint32_t)i * 1280 + (uint32_t)kk * 32);
#pragma unroll
            for (int p = 0; p < 2; p++)
                ldmx4(bh[p], bBase + bp + (uint32_t)p * 1280 + (uint32_t)kk * 32);
#pragma unroll
            for (int i = 0; i < 4; i++)
#pragma unroll
                for (int j = 0; j < 4; j++)
                    mma_fp16(acc[i][j], ah[i], &bh[j >> 1][(j & 1) * 2]);
        }
    }

    const int g = lane >> 2, qd = lane & 3;
#pragma unroll
    for (int i = 0; i < 4; i++) {
        int r0 = m0 + wm * 64 + i * 16 + g;
#pragma unroll
        for (int j = 0; j < 4; j++) {
            int c = n0 + wn * 32 + j * 8 + qd * 2;
            float bx = bias ? __ldg(&bias[c]) : 0.f;
            float by = bias ? __ldg(&bias[c + 1]) : 0.f;
            float v0 = acc[i][j][0] + bx, v1 = acc[i][j][1] + by;
            float v2 = acc[i][j][2] + bx, v3 = acc[i][j][3] + by;
            if (RELU) {
                v0 = fmaxf(v0, 0.f); v1 = fmaxf(v1, 0.f);
                v2 = fmaxf(v2, 0.f); v3 = fmaxf(v3, 0.f);
            }
            if (EMIT == 0) {
                float2 o01 = {v0, v1};
                float2 o23 = {v2, v3};
                *(float2*)&Cf[(size_t)r0 * N + c]       = o01;
                *(float2*)&Cf[(size_t)(r0 + 8) * N + c] = o23;
            } else {
                *(uint32_t*)&Ch[(size_t)r0 * N + c]       = pack_h2(v0, v1);
                *(uint32_t*)&Ch[(size_t)(r0 + 8) * N + c] = pack_h2(v2, v3);
            }
        }
    }
}

// ---------------- fused QKV GEMM (fp16 1-term) ------------------------------
struct QKVParams {
    const __half* w[3];
    const float* bias[3];
    __half* c[3];
};
__global__ __launch_bounds__(256) void qkv1_kernel(
    const __half* __restrict__ A16, QKVParams P)
{
    extern __shared__ char sm[];
    const int t = threadIdx.x, lane = t & 31, warp = t >> 5;
    const int wm = warp >> 2, wn = warp & 3;
    const int m0 = blockIdx.y * 128;
    const int sel = blockIdx.x / 6;
    const int n0  = (blockIdx.x % 6) * 128;
    const __half* B16 = P.w[sel];
    const float* bias = P.bias[sel];
    __half* Ch = P.c[sel];
    const uint32_t sb = smem_u32(sm);
    const int K = EE, N = EE, nch = K / 32;

    float acc[4][4][4];
#pragma unroll
    for (int i = 0; i < 4; i++)
#pragma unroll
        for (int j = 0; j < 4; j++)
#pragma unroll
            for (int u = 0; u < 4; u++) acc[i][j][u] = 0.f;

    const int r0i = t >> 2, c16 = t & 3;
    {
#pragma unroll
        for (int i = 0; i < 2; i++) {
            int row = r0i + i * 64;
            uint32_t so = (uint32_t)row * 80 + (uint32_t)c16 * 16;
            cp16(sb + so,         A16 + (size_t)(m0 + row) * K + c16 * 8);
            cp16(sb + 10240 + so, B16 + (size_t)(n0 + row) * K + c16 * 8);
        }
        cpcommit();
    }

    const uint32_t aBase = sb + (uint32_t)(wm * 64 + (lane & 15)) * 80
                              + (uint32_t)(lane >> 4) * 16;
    const uint32_t bBase = sb + 10240
                              + (uint32_t)(wn * 32 + (lane >> 4) * 8 + (lane & 7)) * 80
                              + (uint32_t)((lane >> 3) & 1) * 16;

    for (int ch = 0; ch < nch; ch++) {
        cpwait0();
        __syncthreads();
        if (ch + 1 < nch) {
            const int koff = (ch + 1) * 32;
            const uint32_t bp = (uint32_t)((ch + 1) & 1) * 20480;
#pragma unroll
            for (int i = 0; i < 2; i++) {
                int row = r0i + i * 64;
                uint32_t so = bp + (uint32_t)row * 80 + (uint32_t)c16 * 16;
                cp16(sb + so,         A16 + (size_t)(m0 + row) * K + koff + c16 * 8);
                cp16(sb + 10240 + so, B16 + (size_t)(n0 + row) * K + koff + c16 * 8);
            }
            cpcommit();
        }

        const uint32_t bp = (uint32_t)(ch & 1) * 20480;
#pragma unroll
        for (int kk = 0; kk < 2; kk++) {
            uint32_t ah[4][4], bh[2][4];
#pragma unroll
            for (int i = 0; i < 4; i++)
                ldmx4(ah[i], aBase + bp + (uint32_t)i * 1280 + (uint32_t)kk * 32);
#pragma unroll
            for (int p = 0; p < 2; p++)
                ldmx4(bh[p], bBase + bp + (uint32_t)p * 1280 + (uint32_t)kk * 32);
#pragma unroll
            for (int i = 0; i < 4; i++)
#pragma unroll
                for (int j = 0; j < 4; j++)
                    mma_fp16(acc[i][j], ah[i], &bh[j >> 1][(j & 1) * 2]);
        }
    }

    const int g = lane >> 2, qd = lane & 3;
#pragma unroll
    for (int i = 0; i < 4; i++) {
        int r0 = m0 + wm * 64 + i * 16 + g;
#pragma unroll
        for (int j = 0; j < 4; j++) {
            int c = n0 + wn * 32 + j * 8 + qd * 2;
            float bx = __ldg(&bias[c]), by = __ldg(&bias[c + 1]);
            *(uint32_t*)&Ch[(size_t)r0 * N + c] =
                pack_h2(acc[i][j][0] + bx, acc[i][j][1] + by);
            *(uint32_t*)&Ch[(size_t)(r0 + 8) * N + c] =
                pack_h2(acc[i][j][2] + bx, acc[i][j][3] + by);
        }
    }
}

// ---------------- scores fp16-1 (band): P16 = exp(QK^T/8-|i-j|) ------------
// smem: Q@0 (18432), K@18432 (18432), red@36864 -> 38912
__global__ __launch_bounds__(256) void scores1_kernel(
    const __half* __restrict__ q16, const __half* __restrict__ k16,
    __half* __restrict__ P16, float* __restrict__ partials)
{
    extern __shared__ char sm[];
    const uint32_t sb = smem_u32(sm);
    const int t = threadIdx.x, lane = t & 31, warp = t >> 5;
    const int wm = warp >> 2, wn = warp & 3;
    const int bh = blockIdx.z, b = bh / HH, h = bh % HH;
    const int qt = blockIdx.y;
    const int kt = qt + (int)blockIdx.x - 1;
    const int q0 = qt * 128;

    if (kt < 0 || kt >= NQT) {
        if (t < 128)
            partials[((size_t)bh * SS + q0 + t) * BANDW + blockIdx.x] = 0.f;
        return;
    }
    const int k0 = kt * 128;
    float* red = (float*)(sm + 36864);

#pragma unroll
    for (int i = 0; i < 4; i++) {
        int idx = t + i * 256;
        int row = idx >> 3, c = idx & 7;
        uint32_t off = (uint32_t)row * 144 + (uint32_t)c * 16;
        size_t qg = (size_t)(b * SS + q0 + row) * EE + h * DD + c * 8;
        size_t kg = (size_t)(b * SS + k0 + row) * EE + h * DD + c * 8;
        *(uint4*)(sm + off)         = *(const uint4*)&q16[qg];
        *(uint4*)(sm + 18432 + off) = *(const uint4*)&k16[kg];
    }
    __syncthreads();

    float acc[4][4][4];
#pragma unroll
    for (int i = 0; i < 4; i++)
#pragma unroll
        for (int j = 0; j < 4; j++)
#pragma unroll
            for (int u = 0; u < 4; u++) acc[i][j][u] = 0.f;

    const uint32_t aAddr = sb + (uint32_t)(wm * 64 + (lane & 15)) * 144
                              + (uint32_t)(lane >> 4) * 16;
    const uint32_t bBase = sb + 18432
                              + (uint32_t)(wn * 32 + (lane >> 4) * 8 + (lane & 7)) * 144
                              + (uint32_t)((lane >> 3) & 1) * 16;
#pragma unroll
    for (int kk = 0; kk < 4; kk++) {
        uint32_t ah[4][4], bh[2][4];
#pragma unroll
        for (int i = 0; i < 4; i++)
            ldmx4(ah[i], aAddr + (uint32_t)i * 2304 + (uint32_t)kk * 32);
#pragma unroll
        for (int p = 0; p < 2; p++)
            ldmx4(bh[p], bBase + (uint32_t)p * 2304 + (uint32_t)kk * 32);
#pragma unroll
        for (int i = 0; i < 4; i++)
#pragma unroll
            for (int j = 0; j < 4; j++)
                mma_fp16(acc[i][j], ah[i], &bh[j >> 1][(j & 1) * 2]);
    }

    const int g = lane >> 2, qd = lane & 3;
#pragma unroll
    for (int i = 0; i < 4; i++) {
        int rloc = wm * 64 + i * 16 + g;
        int qi = q0 + rloc;
        float s0 = 0.f, s1 = 0.f;
#pragma unroll
        for (int j = 0; j < 4; j++) {
            int kj = k0 + wn * 32 + j * 8 + qd * 2;
            float e0 = __expf(acc[i][j][0] * 0.125f - fabsf((float)(qi - kj)));
            float e1 = __expf(acc[i][j][1] * 0.125f - fabsf((float)(qi - kj - 1)));
            float e2 = __expf(acc[i][j][2] * 0.125f - fabsf((float)(qi + 8 - kj)));
            float e3 = __expf(acc[i][j][3] * 0.125f - fabsf((float)(qi + 8 - kj - 1)));
            s0 += e0 + e1; s1 += e2 + e3;
            size_t o0 = ((size_t)bh * SS + qi) * SS + kj;
            size_t o1 = ((size_t)bh * SS + qi + 8) * SS + kj;
            *(uint32_t*)(P16 + o0) = pack_h2(e0, e1);
            *(uint32_t*)(P16 + o1) = pack_h2(e2, e3);
        }
        s0 += __shfl_xor_sync(0xFFFFFFFF, s0, 1);
        s0 += __shfl_xor_sync(0xFFFFFFFF, s0, 2);
        s1 += __shfl_xor_sync(0xFFFFFFFF, s1, 1);
        s1 += __shfl_xor_sync(0xFFFFFFFF, s1, 2);
        if (qd == 0) {
            red[rloc * 4 + wn]       = s0;
            red[(rloc + 8) * 4 + wn] = s1;
        }
    }
    __syncthreads();
    if (t < 128) {
        float s = red[t * 4] + red[t * 4 + 1] + red[t * 4 + 2] + red[t * 4 + 3];
        partials[((size_t)bh * SS + q0 + t) * BANDW + blockIdx.x] = s;
    }
}

// ---------------- reduce partial row sums -> 1/sum -------------------------
__global__ __launch_bounds__(256) void rowsum_kernel(
    const float* __restrict__ partials, float* __restrict__ inv)
{
    int r = blockIdx.x * 256 + threadIdx.x;
    float s = 0.f;
#pragma unroll
    for (int i = 0; i < BANDW; i++) s += partials[(size_t)r * BANDW + i];
    inv[r] = 1.0f / s;
}

// ---------------- ctx fp16-1 (band); emits ctx fp16 + fp32 attn ------------
// smem: P@0 (10240), V@10240 (5120), invs@15360 -> 15872
__global__ __launch_bounds__(256) void ctx1_kernel(
    const __half* __restrict__ P16, const __half* __restrict__ Vt,
    const float* __restrict__ inv, float* __restrict__ attn,
    __half* __restrict__ ctx16)
{
    extern __shared__ char sm[];
    const uint32_t sb = smem_u32(sm);
    const int t = threadIdx.x, lane = t & 31, warp = t >> 5;
    const int wm = warp >> 1, wn = warp & 1;
    const int bh = blockIdx.y, b = bh / HH, h = bh % HH;
    const int qt = blockIdx.x;
    const int q0 = qt * 128;
    float* invs = (float*)(sm + 15360);

    if (t < 128) invs[t] = inv[(size_t)bh * SS + q0 + t];
    __syncthreads();

    const __half* Pb = P16 + (size_t)bh * SS * SS;
    float* attnb = attn + (size_t)bh * SS * SS;

    const int tlo = (qt > 0) ? qt - 1 : 0;
    const int thi = (qt + 2 < NQT) ? qt + 2 : NQT;
    const int c_lo = tlo * 4, c_hi = thi * 4;

    {
        const float4 fz = {0.f, 0.f, 0.f, 0.f};
#pragma unroll
        for (int seg = 0; seg < 2; seg++) {
            const int cbeg = seg ? thi * 128 : 0;
            const int cend = seg ? SS : tlo * 128;
            const int w4 = (cend - cbeg) >> 2;
            if (w4 <= 0) continue;
            const int n4 = 128 * w4;
            for (int i = t; i < n4; i += 256) {
                int row = i / w4, cc = i % w4;
                *(float4*)&attnb[(size_t)(q0 + row) * SS + cbeg + cc * 4] = fz;
            }
        }
    }

    float acc[2][4][4];
#pragma unroll
    for (int i = 0; i < 2; i++)
#pragma unroll
        for (int j = 0; j < 4; j++)
#pragma unroll
            for (int u = 0; u < 4; u++) acc[i][j][u] = 0.f;

    uint4 p_r[2], v_r;
    const int vr = t >> 2, vc = t & 3;

    {
        const int kt = c_lo * 32;
#pragma unroll
        for (int i = 0; i < 2; i++) {
            int idx = t + i * 256;
            int row = idx >> 2, c = idx & 3;
            p_r[i] = *(const uint4*)(Pb + (size_t)(q0 + row) * SS + kt + c * 8);
        }
        v_r = *(const uint4*)(Vt + ((size_t)bh * DD + vr) * SS + kt + vc * 8);
#pragma unroll
        for (int i = 0; i < 2; i++) {
            int idx = t + i * 256;
            int row = idx >> 2, c = idx & 3;
            float iv = invs[row];
            const __half2* hp = (const __half2*)&p_r[i];
            float out8[8];
#pragma unroll
            for (int u = 0; u < 4; u++) {
                float2 f = __half22float2(hp[u]);
                out8[u * 2]     = f.x * iv;
                out8[u * 2 + 1] = f.y * iv;
            }
            size_t ao = (size_t)(q0 + row) * SS + kt + c * 8;
            *(float4*)(attnb + ao)     = *(float4*)&out8[0];
            *(float4*)(attnb + ao + 4) = *(float4*)&out8[4];
        }
    }

    const uint32_t aAddr = sb + (uint32_t)(wm * 32 + (lane & 15)) * 80
                              + (uint32_t)(lane >> 4) * 16;
    const uint32_t bBase = sb + 10240
                              + (uint32_t)(wn * 32 + (lane >> 4) * 8 + (lane & 7)) * 80
                              + (uint32_t)((lane >> 3) & 1) * 16;

    for (int ch = c_lo; ch < c_hi; ch++) {
#pragma unroll
        for (int i = 0; i < 2; i++) {
            int idx = t + i * 256;
            int row = idx >> 2, c = idx & 3;
            *(uint4*)(sm + (uint32_t)row * 80 + (uint32_t)c * 16) = p_r[i];
        }
        *(uint4*)(sm + 10240 + (uint32_t)vr * 80 + (uint32_t)vc * 16) = v_r;
        __syncthreads();

        if (ch + 1 < c_hi) {
            const int kt = (ch + 1) * 32;
#pragma unroll
            for (int i = 0; i < 2; i++) {
                int idx = t + i * 256;
                int row = idx >> 2, c = idx & 3;
                p_r[i] = *(const uint4*)(Pb + (size_t)(q0 + row) * SS + kt + c * 8);
            }
            v_r = *(const uint4*)(Vt + ((size_t)bh * DD + vr) * SS + kt + vc * 8);
#pragma unroll
            for (int i = 0; i < 2; i++) {
                int idx = t + i * 256;
                int row = idx >> 2, c = idx & 3;
                float iv = invs[row];
                const __half2* hp = (const __half2*)&p_r[i];
                float out8[8];
#pragma unroll
                for (int u = 0; u < 4; u++) {
                    float2 f = __half22float2(hp[u]);
                    out8[u * 2]     = f.x * iv;
                    out8[u * 2 + 1] = f.y * iv;
                }
                size_t ao = (size_t)(q0 + row) * SS + kt + c * 8;
                *(float4*)(attnb + ao)     = *(float4*)&out8[0];
                *(float4*)(attnb + ao + 4) = *(float4*)&out8[4];
            }
        }

#pragma unroll
        for (int kk = 0; kk < 2; kk++) {
            uint32_t ah[2][4], bh[2][4];
#pragma unroll
            for (int i = 0; i < 2; i++)
                ldmx4(ah[i], aAddr + (uint32_t)i * 1280 + (uint32_t)kk * 32);
#pragma unroll
            for (int p = 0; p < 2; p++)
                ldmx4(bh[p], bBase + (uint32_t)p * 1280 + (uint32_t)kk * 32);
#pragma unroll
            for (int i = 0; i < 2; i++)
#pragma unroll
                for (int j = 0; j < 4; j++)
                    mma_fp16(acc[i][j], ah[i], &bh[j >> 1][(j & 1) * 2]);
        }
        __syncthreads();
    }

    const int g = lane >> 2, qd = lane & 3;
#pragma unroll
    for (int i = 0; i < 2; i++) {
        int rloc = wm * 32 + i * 16 + g;
        float iv0 = invs[rloc], iv1 = invs[rloc + 8];
#pragma unroll
        for (int j = 0; j < 4; j++) {
            int c = wn * 32 + j * 8 + qd * 2;
            size_t o0 = ((size_t)(b * SS + q0 + rloc) * HH + h) * DD + c;
            size_t o1 = ((size_t)(b * SS + q0 + rloc + 8) * HH + h) * DD + c;
            *(uint32_t*)&ctx16[o0] = pack_h2(acc[i][j][0] * iv0, acc[i][j][1] * iv0);
            *(uint32_t*)&ctx16[o1] = pack_h2(acc[i][j][2] * iv1, acc[i][j][3] * iv1);
        }
    }
}

// ------ out = LayerNorm(A + P0 + P1 + bias) * g + be (opt fp16 emit) -------
template<bool EMIT16>
__global__ __launch_bounds__(256) void add_ln_kernel(
    const float* __restrict__ A, const float* __restrict__ P0,
    const float* __restrict__ P1, const float* __restrict__ bias,
    const float* __restrict__ g, const float* __restrict__ be,
    float* __restrict__ out, __half* __restrict__ O16)
{
    __shared__ float rs[256];
    __shared__ float rs2[256];
    const size_t off = (size_t)blockIdx.x * EE;
    const int t = threadIdx.x;
    float x[3];
    float s = 0.f, s2 = 0.f;
#pragma unroll
    for (int i = 0; i < 3; i++) {
        int c = t + i * 256;
        x[i] = A[off + c] + (P0[off + c] + P1[off + c] + bias[c]);
        s += x[i]; s2 += x[i] * x[i];
    }
    rs[t] = s; rs2[t] = s2; __syncthreads();
    for (int st = 128; st > 0; st >>= 1) {
        if (t < st) { rs[t] += rs[t + st]; rs2[t] += rs2[t + st]; }
        __syncthreads();
    }
    const float mu  = rs[0] * (1.0f / EE);
    const float var = rs2[0] * (1.0f / EE) - mu * mu;
    const float r   = rsqrtf(var + 1e-5f);
#pragma unroll
    for (int i = 0; i < 3; i++) {
        int c = t + i * 256;
        float y = (x[i] - mu) * r * g[c] + be[c];
        out[off + c] = y;
        if (EMIT16) O16[off + c] = __float2half_rn(y);
    }
}

// ---------------- launch --------------------------------------------------
extern "C" void kernel_launch(void* const* d_in, const int* in_sizes, int n_in,
                              void* d_out, int out_size)
{
    const float* x  = (const float*)d_in[0];
    const float* Wq = (const float*)d_in[1];
    const float* bq = (const float*)d_in[2];
    const float* Wk = (const float*)d_in[3];
    const float* bk = (const float*)d_in[4];
    const float* Wv = (const float*)d_in[5];
    const float* bv = (const float*)d_in[6];
    const float* Wo = (const float*)d_in[7];
    const float* bo = (const float*)d_in[8];
    const float* W1 = (const float*)d_in[9];
    const float* b1 = (const float*)d_in[10];
    const float* W2 = (const float*)d_in[11];
    const float* b2 = (const float*)d_in[12];
    const float* g1 = (const float*)d_in[13];
    const float* be1= (const float*)d_in[14];
    const float* g2 = (const float*)d_in[15];
    const float* be2= (const float*)d_in[16];

    float* out  = (float*)d_out;
    float* attn = out + (size_t)BB * SS * EE;

    float *p0, *p1, *h, *part, *inv;
    cudaGetSymbolAddress((void**)&p0,   g_p0);
    cudaGetSymbolAddress((void**)&p1,   g_p1);
    cudaGetSymbolAddress((void**)&h,    g_h);
    cudaGetSymbolAddress((void**)&part, g_part);
    cudaGetSymbolAddress((void**)&inv,  g_inv);
    __half *wqt,*wkt,*wvt,*wot,*w1t,*w2t;
    __half *x16,*q16,*k16,*v16,*hf16,*ctx16,*f116,*vt16,*p16;
    cudaGetSymbolAddress((void**)&wqt, g_wqt);
    cudaGetSymbolAddress((void**)&wkt, g_wkt);
    cudaGetSymbolAddress((void**)&wvt, g_wvt);
    cudaGetSymbolAddress((void**)&wot, g_wot);
    cudaGetSymbolAddress((void**)&w1t, g_w1t);
    cudaGetSymbolAddress((void**)&w2t, g_w2t);
    cudaGetSymbolAddress((void**)&x16, g_x16);
    cudaGetSymbolAddress((void**)&q16, g_q16);
    cudaGetSymbolAddress((void**)&k16, g_k16);
    cudaGetSymbolAddress((void**)&v16, g_v16);
    cudaGetSymbolAddress((void**)&hf16, g_hf16);
    cudaGetSymbolAddress((void**)&ctx16, g_ctx16);
    cudaGetSymbolAddress((void**)&f116, g_f116);
    cudaGetSymbolAddress((void**)&vt16, g_vt16);
    cudaGetSymbolAddress((void**)&p16, g_p16);

    const int GSM = 40960;
    cudaFuncSetAttribute(gemm1_kernel<0,false>, cudaFuncAttributeMaxDynamicSharedMemorySize, GSM);
    cudaFuncSetAttribute(gemm1_kernel<1,true>,  cudaFuncAttributeMaxDynamicSharedMemorySize, GSM);
    cudaFuncSetAttribute(qkv1_kernel,           cudaFuncAttributeMaxDynamicSharedMemorySize, GSM);
    cudaFuncSetAttribute(scores1_kernel, cudaFuncAttributeMaxDynamicSharedMemorySize, 38912);
    cudaFuncSetAttribute(ctx1_kernel,    cudaFuncAttributeMaxDynamicSharedMemorySize, 15872);

    // prep
    tohalf_kernel<<<MM*EE/1024, 256>>>(x, x16);
    wtrans1_kernel<<<dim3(EE/32,  EE/32),  256>>>(Wq, wqt, EE, EE);
    wtrans1_kernel<<<dim3(EE/32,  EE/32),  256>>>(Wk, wkt, EE, EE);
    wtrans1_kernel<<<dim3(EE/32,  EE/32),  256>>>(Wv, wvt, EE, EE);
    wtrans1_kernel<<<dim3(EE/32,  EE/32),  256>>>(Wo, wot, EE, EE);
    wtrans1_kernel<<<dim3(FFF/32, EE/32),  256>>>(W1, w1t, EE, FFF);
    wtrans1_kernel<<<dim3(EE/32,  FFF/32), 256>>>(W2, w2t, FFF, EE);

    // fused QKV (fp16 1-term)
    QKVParams qp;
    qp.w[0] = wqt; qp.w[1] = wkt; qp.w[2] = wvt;
    qp.bias[0] = bq; qp.bias[1] = bk; qp.bias[2] = bv;
    qp.c[0] = q16; qp.c[1] = k16; qp.c[2] = v16;
    qkv1_kernel<<<dim3(18, MM/128), 256, GSM>>>(x16, qp);
    vtrans1_kernel<<<dim3(SS/32, DD/32, BH), 256>>>(v16, vt16);

    // attention (banded, fp16 1-term)
    scores1_kernel<<<dim3(BANDW, NQT, BH), 256, 38912>>>(q16, k16, p16, part);
    rowsum_kernel<<<NROWS / 256, 256>>>(part, inv);
    ctx1_kernel<<<dim3(NQT, BH), 256, 15872>>>(p16, vt16, inv, attn, ctx16);

    // output projection: K-split x2; merge+bias in add_ln
    gemm1_kernel<0,false><<<dim3(EE/128, MM/128, 2), 256, GSM>>>(
        ctx16, wot, nullptr, p0, p1, nullptr, EE, EE, EE/2);
    add_ln_kernel<true><<<MM, 256>>>(x, p0, p1, bo, g1, be1, h, hf16);

    // FFN
    gemm1_kernel<1,true><<<dim3(FFF/128, MM/128, 1), 256, GSM>>>(
        hf16, w1t, b1, nullptr, nullptr, f116, FFF, EE, EE);
    gemm1_kernel<0,false><<<dim3(EE/128, MM/128, 2), 256, GSM>>>(
        f116, w2t, nullptr, p0, p1, nullptr, EE, FFF, FFF/2);
    add_ln_kernel<false><<<MM, 256>>>(h, p0, p1, b2, g2, be2, out, nullptr);
}

// round 15
// speedup vs baseline: 7.3059x; 1.0049x over previous
#include <cuda_runtime.h>
#include <cuda_fp16.h>
#include <cstdint>

#define BB 2
#define SS 2048
#define EE 768
#define HH 12
#define DD 64
#define FFF 3072
#define MM (BB*SS)          // 4096
#define BH (BB*HH)          // 24
#define NQT (SS/128)        // 16

// ---------------- scratch (device globals; no allocation) ----------------
__device__ float g_p0 [MM*EE];
__device__ float g_p1 [MM*EE];
__device__ float g_h  [MM*EE];
__device__ __half g_wqt[EE*EE], g_wkt[EE*EE], g_wvt[EE*EE], g_wot[EE*EE];
__device__ __half g_w1t[EE*FFF], g_w2t[EE*FFF];
__device__ __half g_x16[MM*EE];
__device__ __half g_q16[MM*EE], g_k16[MM*EE], g_v16[MM*EE];
__device__ __half g_hf16 [MM*EE];
__device__ __half g_ctx16[MM*EE];
__device__ __half g_f116 [(size_t)MM*FFF];
__device__ __half g_vt16[(size_t)BH*DD*SS];

// ---------------- helpers ---------------------------------------------------
__device__ __forceinline__ uint32_t smem_u32(const void* p) {
    uint32_t a;
    asm("{ .reg .u64 t; cvta.to.shared.u64 t, %1; cvt.u32.u64 %0, t; }"
        : "=r"(a) : "l"(p));
    return a;
}
__device__ __forceinline__ void ldmx4(uint32_t* r, uint32_t addr) {
    asm volatile("ldmatrix.sync.aligned.m8n8.x4.shared.b16 {%0,%1,%2,%3}, [%4];"
        : "=r"(r[0]), "=r"(r[1]), "=r"(r[2]), "=r"(r[3]) : "r"(addr));
}
__device__ __forceinline__ void mma_fp16(float* d, const uint32_t* a, const uint32_t* b) {
    asm volatile("mma.sync.aligned.m16n8k16.row.col.f32.f16.f16.f32 "
        "{%0,%1,%2,%3}, {%4,%5,%6,%7}, {%8,%9}, {%0,%1,%2,%3};"
        : "+f"(d[0]), "+f"(d[1]), "+f"(d[2]), "+f"(d[3])
        : "r"(a[0]), "r"(a[1]), "r"(a[2]), "r"(a[3]), "r"(b[0]), "r"(b[1]));
}
__device__ __forceinline__ uint32_t pack_h2(float a, float b) {
    __half2 h = __floats2half2_rn(a, b);
    return *(uint32_t*)&h;
}
__device__ __forceinline__ void cp16(uint32_t s, const void* g) {
    asm volatile("cp.async.cg.shared.global [%0], [%1], 16;" :: "r"(s), "l"(g));
}
__device__ __forceinline__ void cpcommit() {
    asm volatile("cp.async.commit_group;" ::: "memory");
}
__device__ __forceinline__ void cpwait0() {
    asm volatile("cp.async.wait_group 0;" ::: "memory");
}

// ---------------- batched weight transpose (fp16) --------------------------
struct WTParams {
    const float* W[6];
    __half* T[6];
    int K[6], N[6], base[6];
};
__global__ __launch_bounds__(256) void wtrans_all_kernel(WTParams P)
{
    __shared__ float tile[32][33];
    int cfg = 0;
#pragma unroll
    for (int i = 1; i < 6; i++)
        if ((int)blockIdx.x >= P.base[i]) cfg = i;
    const float* W = P.W[cfg];
    __half* T = P.T[cfg];
    const int K = P.K[cfg], N = P.N[cfg];
    const int local = blockIdx.x - P.base[cfg];
    const int nbx = N / 32;
    const int n0 = (local % nbx) * 32, k0 = (local / nbx) * 32;
    const int tx = threadIdx.x & 31, ty = threadIdx.x >> 5;
#pragma unroll
    for (int i = 0; i < 32; i += 8)
        tile[ty + i][tx] = W[(size_t)(k0 + ty + i) * N + n0 + tx];
    __syncthreads();
#pragma unroll
    for (int i = 0; i < 32; i += 8)
        T[(size_t)(n0 + ty + i) * K + k0 + tx] = __float2half_rn(tile[tx][ty + i]);
}

// ---------------- elementwise fp32 -> fp16 single --------------------------
__global__ __launch_bounds__(256) void tohalf_kernel(
    const float* __restrict__ A, __half* __restrict__ O)
{
    size_t idx = ((size_t)blockIdx.x * 256 + threadIdx.x) * 4;
    float4 v = *(const float4*)&A[idx];
    *(uint2*)&O[idx] = make_uint2(pack_h2(v.x, v.y), pack_h2(v.z, v.w));
}

// ---------------- v transpose: -> vt[bh][d][s] ------------------------------
__global__ __launch_bounds__(256) void vtrans1_kernel(
    const __half* __restrict__ v, __half* __restrict__ T)
{
    __shared__ __half tile[32][40];
    const int s0 = blockIdx.x * 32, d0 = blockIdx.y * 32, bh = blockIdx.z;
    const int b = bh / HH, h = bh % HH;
    const int tx = threadIdx.x & 31, ty = threadIdx.x >> 5;
#pragma unroll
    for (int i = 0; i < 32; i += 8)
        tile[ty + i][tx] = v[(size_t)(b * SS + s0 + ty + i) * EE + h * DD + d0 + tx];
    __syncthreads();
#pragma unroll
    for (int i = 0; i < 32; i += 8)
        T[((size_t)bh * DD + d0 + ty + i) * SS + s0 + tx] = tile[tx][ty + i];
}

// ============ fp16 1-term GEMM (A single, B single) ========================
template<int EMIT, bool RELU>
__global__ __launch_bounds__(256) void gemm1_kernel(
    const __half* __restrict__ A16, const __half* __restrict__ B16,
    const float* __restrict__ bias,
    float* __restrict__ Cf0, float* __restrict__ Cf1, __half* __restrict__ Ch,
    int N, int K, int ksize)
{
    extern __shared__ char sm[];
    const int t = threadIdx.x, lane = t & 31, warp = t >> 5;
    const int wm = warp >> 2, wn = warp & 3;
    const int m0 = blockIdx.y * 128, n0 = blockIdx.x * 128;
    const int kbase = blockIdx.z * ksize;
    float* Cf = blockIdx.z ? Cf1 : Cf0;
    const uint32_t sb = smem_u32(sm);
    const int nch = ksize / 32;

    float acc[4][4][4];
#pragma unroll
    for (int i = 0; i < 4; i++)
#pragma unroll
        for (int j = 0; j < 4; j++)
#pragma unroll
            for (int u = 0; u < 4; u++) acc[i][j][u] = 0.f;

    const int r0i = t >> 2, c16 = t & 3;
    {
#pragma unroll
        for (int i = 0; i < 2; i++) {
            int row = r0i + i * 64;
            uint32_t so = (uint32_t)row * 80 + (uint32_t)c16 * 16;
            cp16(sb + so,         A16 + (size_t)(m0 + row) * K + kbase + c16 * 8);
            cp16(sb + 10240 + so, B16 + (size_t)(n0 + row) * K + kbase + c16 * 8);
        }
        cpcommit();
    }

    const uint32_t aBase = sb + (uint32_t)(wm * 64 + (lane & 15)) * 80
                              + (uint32_t)(lane >> 4) * 16;
    const uint32_t bBase = sb + 10240
                              + (uint32_t)(wn * 32 + (lane >> 4) * 8 + (lane & 7)) * 80
                              + (uint32_t)((lane >> 3) & 1) * 16;

    for (int ch = 0; ch < nch; ch++) {
        cpwait0();
        __syncthreads();
        if (ch + 1 < nch) {
            const int koff = kbase + (ch + 1) * 32;
            const uint32_t bp = (uint32_t)((ch + 1) & 1) * 20480;
#pragma unroll
            for (int i = 0; i < 2; i++) {
                int row = r0i + i * 64;
                uint32_t so = bp + (uint32_t)row * 80 + (uint32_t)c16 * 16;
                cp16(sb + so,         A16 + (size_t)(m0 + row) * K + koff + c16 * 8);
                cp16(sb + 10240 + so, B16 + (size_t)(n0 + row) * K + koff + c16 * 8);
            }
            cpcommit();
        }

        const uint32_t bp = (uint32_t)(ch & 1) * 20480;
#pragma unroll
        for (int kk = 0; kk < 2; kk++) {
            uint32_t ah[4][4], bh[2][4];
#pragma unroll
            for (int i = 0; i < 4; i++)
                ldmx4(ah[i], aBase + bp + (uint32_t)i * 1280 + (uint32_t)kk * 32);
#pragma unroll
            for (int p = 0; p < 2; p++)
                ldmx4(bh[p], bBase + bp + (uint32_t)p * 1280 + (uint32_t)kk * 32);
#pragma unroll
            for (int i = 0; i < 4; i++)
#pragma unroll
                for (int j = 0; j < 4; j++)
                    mma_fp16(acc[i][j], ah[i], &bh[j >> 1][(j & 1) * 2]);
        }
    }

    const int g = lane >> 2, qd = lane & 3;
#pragma unroll
    for (int i = 0; i < 4; i++) {
        int r0 = m0 + wm * 64 + i * 16 + g;
#pragma unroll
        for (int j = 0; j < 4; j++) {
            int c = n0 + wn * 32 + j * 8 + qd * 2;
            float bx = bias ? __ldg(&bias[c]) : 0.f;
            float by = bias ? __ldg(&bias[c + 1]) : 0.f;
            float v0 = acc[i][j][0] + bx, v1 = acc[i][j][1] + by;
            float v2 = acc[i][j][2] + bx, v3 = acc[i][j][3] + by;
            if (RELU) {
                v0 = fmaxf(v0, 0.f); v1 = fmaxf(v1, 0.f);
                v2 = fmaxf(v2, 0.f); v3 = fmaxf(v3, 0.f);
            }
            if (EMIT == 0) {
                float2 o01 = {v0, v1};
                float2 o23 = {v2, v3};
                *(float2*)&Cf[(size_t)r0 * N + c]       = o01;
                *(float2*)&Cf[(size_t)(r0 + 8) * N + c] = o23;
            } else {
                *(uint32_t*)&Ch[(size_t)r0 * N + c]       = pack_h2(v0, v1);
                *(uint32_t*)&Ch[(size_t)(r0 + 8) * N + c] = pack_h2(v2, v3);
            }
        }
    }
}

// ---------------- fused QKV GEMM (fp16 1-term) ------------------------------
struct QKVParams {
    const __half* w[3];
    const float* bias[3];
    __half* c[3];
};
__global__ __launch_bounds__(256) void qkv1_kernel(
    const __half* __restrict__ A16, QKVParams P)
{
    extern __shared__ char sm[];
    const int t = threadIdx.x, lane = t & 31, warp = t >> 5;
    const int wm = warp >> 2, wn = warp & 3;
    const int m0 = blockIdx.y * 128;
    const int sel = blockIdx.x / 6;
    const int n0  = (blockIdx.x % 6) * 128;
    const __half* B16 = P.w[sel];
    const float* bias = P.bias[sel];
    __half* Ch = P.c[sel];
    const uint32_t sb = smem_u32(sm);
    const int K = EE, N = EE, nch = K / 32;

    float acc[4][4][4];
#pragma unroll
    for (int i = 0; i < 4; i++)
#pragma unroll
        for (int j = 0; j < 4; j++)
#pragma unroll
            for (int u = 0; u < 4; u++) acc[i][j][u] = 0.f;

    const int r0i = t >> 2, c16 = t & 3;
    {
#pragma unroll
        for (int i = 0; i < 2; i++) {
            int row = r0i + i * 64;
            uint32_t so = (uint32_t)row * 80 + (uint32_t)c16 * 16;
            cp16(sb + so,         A16 + (size_t)(m0 + row) * K + c16 * 8);
            cp16(sb + 10240 + so, B16 + (size_t)(n0 + row) * K + c16 * 8);
        }
        cpcommit();
    }

    const uint32_t aBase = sb + (uint32_t)(wm * 64 + (lane & 15)) * 80
                              + (uint32_t)(lane >> 4) * 16;
    const uint32_t bBase = sb + 10240
                              + (uint32_t)(wn * 32 + (lane >> 4) * 8 + (lane & 7)) * 80
                              + (uint32_t)((lane >> 3) & 1) * 16;

    for (int ch = 0; ch < nch; ch++) {
        cpwait0();
        __syncthreads();
        if (ch + 1 < nch) {
            const int koff = (ch + 1) * 32;
            const uint32_t bp = (uint32_t)((ch + 1) & 1) * 20480;
#pragma unroll
            for (int i = 0; i < 2; i++) {
                int row = r0i + i * 64;
                uint32_t so = bp + (uint32_t)row * 80 + (uint32_t)c16 * 16;
                cp16(sb + so,         A16 + (size_t)(m0 + row) * K + koff + c16 * 8);
                cp16(sb + 10240 + so, B16 + (size_t)(n0 + row) * K + koff + c16 * 8);
            }
            cpcommit();
        }

        const uint32_t bp = (uint32_t)(ch & 1) * 20480;
#pragma unroll
        for (int kk = 0; kk < 2; kk++) {
            uint32_t ah[4][4], bh[2][4];
#pragma unroll
            for (int i = 0; i < 4; i++)
                ldmx4(ah[i], aBase + bp + (uint32_t)i * 1280 + (uint32_t)kk * 32);
#pragma unroll
            for (int p = 0; p < 2; p++)
                ldmx4(bh[p], bBase + bp + (uint32_t)p * 1280 + (uint32_t)kk * 32);
#pragma unroll
            for (int i = 0; i < 4; i++)
#pragma unroll
                for (int j = 0; j < 4; j++)
                    mma_fp16(acc[i][j], ah[i], &bh[j >> 1][(j & 1) * 2]);
        }
    }

    const int g = lane >> 2, qd = lane & 3;
#pragma unroll
    for (int i = 0; i < 4; i++) {
        int r0 = m0 + wm * 64 + i * 16 + g;
#pragma unroll
        for (int j = 0; j < 4; j++) {
            int c = n0 + wn * 32 + j * 8 + qd * 2;
            float bx = __ldg(&bias[c]), by = __ldg(&bias[c + 1]);
            *(uint32_t*)&Ch[(size_t)r0 * N + c] =
                pack_h2(acc[i][j][0] + bx, acc[i][j][1] + by);
            *(uint32_t*)&Ch[(size_t)(r0 + 8) * N + c] =
                pack_h2(acc[i][j][2] + bx, acc[i][j][3] + by);
        }
    }
}

// ================= fused attention (scores + softmax + attn + ctx) ==========
// grid (NQT, BH), 256 threads, 1 CTA owns a full 128-row q-tile.
#define SQ_OFF 0
#define SK_OFF 18432
#define SV_OFF 36864
#define SP_OFF 87040
#define SR_OFF 191488
#define SI_OFF 193536
#define FA_SMEM 194048

__global__ __launch_bounds__(256) void fused_attn_kernel(
    const __half* __restrict__ q16, const __half* __restrict__ k16,
    const __half* __restrict__ Vt, float* __restrict__ attn,
    __half* __restrict__ ctx16)
{
    extern __shared__ char sm[];
    const uint32_t sb = smem_u32(sm);
    const int t = threadIdx.x, lane = t & 31, warp = t >> 5;
    const int bh = blockIdx.y, b = bh / HH, h = bh % HH;
    const int qt = blockIdx.x;
    const int q0 = qt * 128;
    float* red  = (float*)(sm + SR_OFF);
    float* invs = (float*)(sm + SI_OFF);
    float* attnb = attn + (size_t)bh * SS * SS;

    const int tlo = (qt > 0) ? qt - 1 : 0;
    const int thi = (qt + 2 < NQT) ? qt + 2 : NQT;

    // zero-fill off-band attn columns (exactly 0 in ref — fp32 underflow)
    {
        const float4 fz = {0.f, 0.f, 0.f, 0.f};
#pragma unroll
        for (int seg = 0; seg < 2; seg++) {
            const int cbeg = seg ? thi * 128 : 0;
            const int cend = seg ? SS : tlo * 128;
            const int w4 = (cend - cbeg) >> 2;
            if (w4 <= 0) continue;
            const int n4 = 128 * w4;
            for (int i = t; i < n4; i += 256) {
                int row = i / w4, cc = i % w4;
                *(float4*)&attnb[(size_t)(q0 + row) * SS + cbeg + cc * 4] = fz;
            }
        }
    }

    // load Q tile
#pragma unroll
    for (int i = 0; i < 4; i++) {
        int idx = t + i * 256;
        int row = idx >> 3, c = idx & 7;
        *(uint4*)(sm + SQ_OFF + (uint32_t)row * 144 + (uint32_t)c * 16) =
            *(const uint4*)&q16[(size_t)(b * SS + q0 + row) * EE + h * DD + c * 8];
    }
    // load V tiles: per slot 64 rows x 128 halves (256B); FIX: full extent
    for (int s = 0; s < 3; s++) {
        const int kt = qt - 1 + s;
        if (kt < 0 || kt >= NQT) continue;
#pragma unroll
        for (int i = 0; i < 4; i++) {
            int idx = t + i * 256;          // 1024 uint4 = 64 rows x 16 col-groups
            int row = idx >> 4, c = idx & 15;
            *(uint4*)(sm + SV_OFF + (uint32_t)row * 784 + (uint32_t)(s * 256 + c * 16)) =
                *(const uint4*)&Vt[((size_t)bh * DD + row) * SS + kt * 128 + c * 8];
        }
    }

    // ---- scores phase: warp layout 2m x 4n ---------------------------------
    const int wm = warp >> 2, wn = warp & 3;
    const int g = lane >> 2, qd = lane & 3;
    float rs0[4] = {0.f, 0.f, 0.f, 0.f};
    float rs1[4] = {0.f, 0.f, 0.f, 0.f};

    const uint32_t aAddrS = sb + SQ_OFF + (uint32_t)(wm * 64 + (lane & 15)) * 144
                               + (uint32_t)(lane >> 4) * 16;
    const uint32_t bAddrS = sb + SK_OFF
                               + (uint32_t)(wn * 32 + (lane >> 4) * 8 + (lane & 7)) * 144
                               + (uint32_t)((lane >> 3) & 1) * 16;

    for (int s = 0; s < 3; s++) {
        const int kt = qt - 1 + s;
        if (kt < 0 || kt >= NQT) continue;
        const int k0 = kt * 128;
        __syncthreads();   // prior MMA done reading SK; Q/V loads visible 1st iter
#pragma unroll
        for (int i = 0; i < 4; i++) {
            int idx = t + i * 256;
            int row = idx >> 3, c = idx & 7;
            *(uint4*)(sm + SK_OFF + (uint32_t)row * 144 + (uint32_t)c * 16) =
                *(const uint4*)&k16[(size_t)(b * SS + k0 + row) * EE + h * DD + c * 8];
        }
        __syncthreads();

        float acc[4][4][4];
#pragma unroll
        for (int i = 0; i < 4; i++)
#pragma unroll
            for (int j = 0; j < 4; j++)
#pragma unroll
                for (int u = 0; u < 4; u++) acc[i][j][u] = 0.f;

#pragma unroll
        for (int kk = 0; kk < 4; kk++) {
            uint32_t ah[4][4], bhf[2][4];
#pragma unroll
            for (int i = 0; i < 4; i++)
                ldmx4(ah[i], aAddrS + (uint32_t)i * 2304 + (uint32_t)kk * 32);
#pragma unroll
            for (int p = 0; p < 2; p++)
                ldmx4(bhf[p], bAddrS + (uint32_t)p * 2304 + (uint32_t)kk * 32);
#pragma unroll
            for (int i = 0; i < 4; i++)
#pragma unroll
                for (int j = 0; j < 4; j++)
                    mma_fp16(acc[i][j], ah[i], &bhf[j >> 1][(j & 1) * 2]);
        }

        const uint32_t pb = SP_OFF + (uint32_t)s * 34816;
#pragma unroll
        for (int i = 0; i < 4; i++) {
            int rloc = wm * 64 + i * 16 + g;
            int qi = q0 + rloc;
#pragma unroll
            for (int j = 0; j < 4; j++) {
                int ccl = wn * 32 + j * 8 + qd * 2;
                int kj = k0 + ccl;
                float e0 = __expf(acc[i][j][0] * 0.125f - fabsf((float)(qi - kj)));
                float e1 = __expf(acc[i][j][1] * 0.125f - fabsf((float)(qi - kj - 1)));
                float e2 = __expf(acc[i][j][2] * 0.125f - fabsf((float)(qi + 8 - kj)));
                float e3 = __expf(acc[i][j][3] * 0.125f - fabsf((float)(qi + 8 - kj - 1)));
                rs0[i] += e0 + e1; rs1[i] += e2 + e3;
                *(uint32_t*)(sm + pb + (uint32_t)rloc * 272 + (uint32_t)ccl * 2)
                    = pack_h2(e0, e1);
                *(uint32_t*)(sm + pb + (uint32_t)(rloc + 8) * 272 + (uint32_t)ccl * 2)
                    = pack_h2(e2, e3);
            }
        }
    }

    // rowsum reduce -> inv
#pragma unroll
    for (int i = 0; i < 4; i++) {
        float s0 = rs0[i], s1 = rs1[i];
        s0 += __shfl_xor_sync(0xFFFFFFFF, s0, 1);
        s0 += __shfl_xor_sync(0xFFFFFFFF, s0, 2);
        s1 += __shfl_xor_sync(0xFFFFFFFF, s1, 1);
        s1 += __shfl_xor_sync(0xFFFFFFFF, s1, 2);
        if (qd == 0) {
            int rloc = wm * 64 + i * 16 + g;
            red[rloc * 4 + wn]       = s0;
            red[(rloc + 8) * 4 + wn] = s1;
        }
    }
    __syncthreads();
    if (t < 128)
        invs[t] = 1.0f / (red[t * 4] + red[t * 4 + 1] + red[t * 4 + 2] + red[t * 4 + 3]);
    __syncthreads();

    // attn band write: normalized P from smem -> fp32 global
    for (int s = 0; s < 3; s++) {
        const int kt = qt - 1 + s;
        if (kt < 0 || kt >= NQT) continue;
        const int k0 = kt * 128;
        const uint32_t pb = SP_OFF + (uint32_t)s * 34816;
#pragma unroll
        for (int i = 0; i < 8; i++) {
            int idx = t + i * 256;
            int row = idx >> 4, c8 = (idx & 15) * 8;
            uint4 pv = *(uint4*)(sm + pb + (uint32_t)row * 272 + (uint32_t)c8 * 2);
            float iv = invs[row];
            const __half2* hp = (const __half2*)&pv;
            float o[8];
#pragma unroll
            for (int u = 0; u < 4; u++) {
                float2 f = __half22float2(hp[u]);
                o[u * 2]     = f.x * iv;
                o[u * 2 + 1] = f.y * iv;
            }
            size_t ao = (size_t)(q0 + row) * SS + k0 + c8;
            *(float4*)(attnb + ao)     = *(float4*)&o[0];
            *(float4*)(attnb + ao + 4) = *(float4*)&o[4];
        }
    }

    // ---- ctx phase: P(smem) @ V(smem), warp layout 4m x 2n -----------------
    const int wm2 = warp >> 1, wn2 = warp & 1;
    float acc2[2][4][4];
#pragma unroll
    for (int i = 0; i < 2; i++)
#pragma unroll
        for (int j = 0; j < 4; j++)
#pragma unroll
            for (int u = 0; u < 4; u++) acc2[i][j][u] = 0.f;

    const uint32_t aBase2 = sb + SP_OFF + (uint32_t)(wm2 * 32 + (lane & 15)) * 272
                               + (uint32_t)(lane >> 4) * 16;
    const uint32_t bBase2 = sb + SV_OFF
                               + (uint32_t)(wn2 * 32 + (lane >> 4) * 8 + (lane & 7)) * 784
                               + (uint32_t)((lane >> 3) & 1) * 16;

    for (int s = 0; s < 3; s++) {
        const int kt = qt - 1 + s;
        if (kt < 0 || kt >= NQT) continue;
#pragma unroll
        for (int c = 0; c < 4; c++) {
#pragma unroll
            for (int kk = 0; kk < 2; kk++) {
                uint32_t ah[2][4], bhf[2][4];
#pragma unroll
                for (int i = 0; i < 2; i++)
                    ldmx4(ah[i], aBase2 + (uint32_t)s * 34816 + (uint32_t)i * 4352
                                 + (uint32_t)c * 64 + (uint32_t)kk * 32);
#pragma unroll
                for (int p = 0; p < 2; p++)
                    ldmx4(bhf[p], bBase2 + (uint32_t)p * 12544
                                  + (uint32_t)(s * 256 + c * 64) + (uint32_t)kk * 32);
#pragma unroll
                for (int i = 0; i < 2; i++)
#pragma unroll
                    for (int j = 0; j < 4; j++)
                        mma_fp16(acc2[i][j], ah[i], &bhf[j >> 1][(j & 1) * 2]);
            }
        }
    }

    // ctx epilogue: scale by inv, write [b,s,h,d] fp16
#pragma unroll
    for (int i = 0; i < 2; i++) {
        int rloc = wm2 * 32 + i * 16 + g;
        float iv0 = invs[rloc], iv1 = invs[rloc + 8];
#pragma unroll
        for (int j = 0; j < 4; j++) {
            int c = wn2 * 32 + j * 8 + qd * 2;
            size_t o0 = ((size_t)(b * SS + q0 + rloc) * HH + h) * DD + c;
            size_t o1 = ((size_t)(b * SS + q0 + rloc + 8) * HH + h) * DD + c;
            *(uint32_t*)&ctx16[o0] = pack_h2(acc2[i][j][0] * iv0, acc2[i][j][1] * iv0);
            *(uint32_t*)&ctx16[o1] = pack_h2(acc2[i][j][2] * iv1, acc2[i][j][3] * iv1);
        }
    }
}

// ------ out = LayerNorm(A + P0 + P1 + bias) * g + be (opt fp16 emit) -------
template<bool EMIT16>
__global__ __launch_bounds__(256) void add_ln_kernel(
    const float* __restrict__ A, const float* __restrict__ P0,
    const float* __restrict__ P1, const float* __restrict__ bias,
    const float* __restrict__ g, const float* __restrict__ be,
    float* __restrict__ out, __half* __restrict__ O16)
{
    __shared__ float rs[256];
    __shared__ float rs2[256];
    const size_t off = (size_t)blockIdx.x * EE;
    const int t = threadIdx.x;
    float x[3];
    float s = 0.f, s2 = 0.f;
#pragma unroll
    for (int i = 0; i < 3; i++) {
        int c = t + i * 256;
        x[i] = A[off + c] + (P0[off + c] + P1[off + c] + bias[c]);
        s += x[i]; s2 += x[i] * x[i];
    }
    rs[t] = s; rs2[t] = s2; __syncthreads();
    for (int st = 128; st > 0; st >>= 1) {
        if (t < st) { rs[t] += rs[t + st]; rs2[t] += rs2[t + st]; }
        __syncthreads();
    }
    const float mu  = rs[0] * (1.0f / EE);
    const float var = rs2[0] * (1.0f / EE) - mu * mu;
    const float r   = rsqrtf(var + 1e-5f);
#pragma unroll
    for (int i = 0; i < 3; i++) {
        int c = t + i * 256;
        float y = (x[i] - mu) * r * g[c] + be[c];
        out[off + c] = y;
        if (EMIT16) O16[off + c] = __float2half_rn(y);
    }
}

// ---------------- launch --------------------------------------------------
extern "C" void kernel_launch(void* const* d_in, const int* in_sizes, int n_in,
                              void* d_out, int out_size)
{
    const float* x  = (const float*)d_in[0];
    const float* Wq = (const float*)d_in[1];
    const float* bq = (const float*)d_in[2];
    const float* Wk = (const float*)d_in[3];
    const float* bk = (const float*)d_in[4];
    const float* Wv = (const float*)d_in[5];
    const float* bv = (const float*)d_in[6];
    const float* Wo = (const float*)d_in[7];
    const float* bo = (const float*)d_in[8];
    const float* W1 = (const float*)d_in[9];
    const float* b1 = (const float*)d_in[10];
    const float* W2 = (const float*)d_in[11];
    const float* b2 = (const float*)d_in[12];
    const float* g1 = (const float*)d_in[13];
    const float* be1= (const float*)d_in[14];
    const float* g2 = (const float*)d_in[15];
    const float* be2= (const float*)d_in[16];

    float* out  = (float*)d_out;
    float* attn = out + (size_t)BB * SS * EE;

    float *p0, *p1, *h;
    cudaGetSymbolAddress((void**)&p0,   g_p0);
    cudaGetSymbolAddress((void**)&p1,   g_p1);
    cudaGetSymbolAddress((void**)&h,    g_h);
    __half *wqt,*wkt,*wvt,*wot,*w1t,*w2t;
    __half *x16,*q16,*k16,*v16,*hf16,*ctx16,*f116,*vt16;
    cudaGetSymbolAddress((void**)&wqt, g_wqt);
    cudaGetSymbolAddress((void**)&wkt, g_wkt);
    cudaGetSymbolAddress((void**)&wvt, g_wvt);
    cudaGetSymbolAddress((void**)&wot, g_wot);
    cudaGetSymbolAddress((void**)&w1t, g_w1t);
    cudaGetSymbolAddress((void**)&w2t, g_w2t);
    cudaGetSymbolAddress((void**)&x16, g_x16);
    cudaGetSymbolAddress((void**)&q16, g_q16);
    cudaGetSymbolAddress((void**)&k16, g_k16);
    cudaGetSymbolAddress((void**)&v16, g_v16);
    cudaGetSymbolAddress((void**)&hf16, g_hf16);
    cudaGetSymbolAddress((void**)&ctx16, g_ctx16);
    cudaGetSymbolAddress((void**)&f116, g_f116);
    cudaGetSymbolAddress((void**)&vt16, g_vt16);

    const int GSM = 40960;
    cudaFuncSetAttribute(gemm1_kernel<0,false>, cudaFuncAttributeMaxDynamicSharedMemorySize, GSM);
    cudaFuncSetAttribute(gemm1_kernel<1,true>,  cudaFuncAttributeMaxDynamicSharedMemorySize, GSM);
    cudaFuncSetAttribute(qkv1_kernel,           cudaFuncAttributeMaxDynamicSharedMemorySize, GSM);
    cudaFuncSetAttribute(fused_attn_kernel,     cudaFuncAttributeMaxDynamicSharedMemorySize, FA_SMEM);

    // prep: x -> fp16; all weight transposes in ONE launch
    tohalf_kernel<<<MM*EE/1024, 256>>>(x, x16);
    WTParams wp;
    wp.W[0] = Wq; wp.W[1] = Wk; wp.W[2] = Wv; wp.W[3] = Wo; wp.W[4] = W1; wp.W[5] = W2;
    wp.T[0] = wqt; wp.T[1] = wkt; wp.T[2] = wvt; wp.T[3] = wot; wp.T[4] = w1t; wp.T[5] = w2t;
    wp.K[0] = EE; wp.K[1] = EE; wp.K[2] = EE; wp.K[3] = EE; wp.K[4] = EE; wp.K[5] = FFF;
    wp.N[0] = EE; wp.N[1] = EE; wp.N[2] = EE; wp.N[3] = EE; wp.N[4] = FFF; wp.N[5] = EE;
    wp.base[0] = 0;    wp.base[1] = 576;  wp.base[2] = 1152;
    wp.base[3] = 1728; wp.base[4] = 2304; wp.base[5] = 4608;
    wtrans_all_kernel<<<6912, 256>>>(wp);

    // fused QKV (fp16 1-term)
    QKVParams qp;
    qp.w[0] = wqt; qp.w[1] = wkt; qp.w[2] = wvt;
    qp.bias[0] = bq; qp.bias[1] = bk; qp.bias[2] = bv;
    qp.c[0] = q16; qp.c[1] = k16; qp.c[2] = v16;
    qkv1_kernel<<<dim3(18, MM/128), 256, GSM>>>(x16, qp);
    vtrans1_kernel<<<dim3(SS/32, DD/32, BH), 256>>>(v16, vt16);

    // fused attention (banded): scores + softmax + attn_map + ctx
    fused_attn_kernel<<<dim3(NQT, BH), 256, FA_SMEM>>>(q16, k16, vt16, attn, ctx16);

    // output projection: K-split x2; merge+bias in add_ln
    gemm1_kernel<0,false><<<dim3(EE/128, MM/128, 2), 256, GSM>>>(
        ctx16, wot, nullptr, p0, p1, nullptr, EE, EE, EE/2);
    add_ln_kernel<true><<<MM, 256>>>(x, p0, p1, bo, g1, be1, h, hf16);

    // FFN
    gemm1_kernel<1,true><<<dim3(FFF/128, MM/128, 1), 256, GSM>>>(
        hf16, w1t, b1, nullptr, nullptr, f116, FFF, EE, EE);
    gemm1_kernel<0,false><<<dim3(EE/128, MM/128, 2), 256, GSM>>>(
        f116, w2t, nullptr, p0, p1, nullptr, EE, FFF, FFF/2);
    add_ln_kernel<false><<<MM, 256>>>(h, p0, p1, b2, g2, be2, out, nullptr);
}

// round 16
// speedup vs baseline: 7.4194x; 1.0155x over previous
#include <cuda_runtime.h>
#include <cuda_fp16.h>
#include <cstdint>

#define BB 2
#define SS 2048
#define EE 768
#define HH 12
#define DD 64
#define FFF 3072
#define MM (BB*SS)          // 4096
#define BH (BB*HH)          // 24
#define NQT (SS/128)        // 16

// ---------------- scratch (device globals; no allocation) ----------------
__device__ __half g_p0h[MM*EE];
__device__ __half g_p1h[MM*EE];
__device__ __half g_wqt[EE*EE], g_wkt[EE*EE], g_wvt[EE*EE], g_wot[EE*EE];
__device__ __half g_w1t[EE*FFF], g_w2t[EE*FFF];
__device__ __half g_x16[MM*EE];
__device__ __half g_q16[MM*EE], g_k16[MM*EE], g_v16[MM*EE];
__device__ __half g_hf16 [MM*EE];
__device__ __half g_ctx16[MM*EE];
__device__ __half g_f116 [(size_t)MM*FFF];
__device__ __half g_vt16[(size_t)BH*DD*SS];

// ---------------- helpers ---------------------------------------------------
__device__ __forceinline__ uint32_t smem_u32(const void* p) {
    uint32_t a;
    asm("{ .reg .u64 t; cvta.to.shared.u64 t, %1; cvt.u32.u64 %0, t; }"
        : "=r"(a) : "l"(p));
    return a;
}
__device__ __forceinline__ void ldmx4(uint32_t* r, uint32_t addr) {
    asm volatile("ldmatrix.sync.aligned.m8n8.x4.shared.b16 {%0,%1,%2,%3}, [%4];"
        : "=r"(r[0]), "=r"(r[1]), "=r"(r[2]), "=r"(r[3]) : "r"(addr));
}
__device__ __forceinline__ void mma_fp16(float* d, const uint32_t* a, const uint32_t* b) {
    asm volatile("mma.sync.aligned.m16n8k16.row.col.f32.f16.f16.f32 "
        "{%0,%1,%2,%3}, {%4,%5,%6,%7}, {%8,%9}, {%0,%1,%2,%3};"
        : "+f"(d[0]), "+f"(d[1]), "+f"(d[2]), "+f"(d[3])
        : "r"(a[0]), "r"(a[1]), "r"(a[2]), "r"(a[3]), "r"(b[0]), "r"(b[1]));
}
__device__ __forceinline__ uint32_t pack_h2(float a, float b) {
    __half2 h = __floats2half2_rn(a, b);
    return *(uint32_t*)&h;
}
__device__ __forceinline__ void stcs4(float* p, float a, float b, float c, float d) {
    asm volatile("st.global.cs.v4.f32 [%0], {%1,%2,%3,%4};"
        :: "l"(p), "f"(a), "f"(b), "f"(c), "f"(d) : "memory");
}
__device__ __forceinline__ void cp16(uint32_t s, const void* g) {
    asm volatile("cp.async.cg.shared.global [%0], [%1], 16;" :: "r"(s), "l"(g));
}
__device__ __forceinline__ void cpcommit() {
    asm volatile("cp.async.commit_group;" ::: "memory");
}
__device__ __forceinline__ void cpwait0() {
    asm volatile("cp.async.wait_group 0;" ::: "memory");
}

// ---------------- batched weight transpose (fp16) --------------------------
struct WTParams {
    const float* W[6];
    __half* T[6];
    int K[6], N[6], base[6];
};
__global__ __launch_bounds__(256) void wtrans_all_kernel(WTParams P)
{
    __shared__ float tile[32][33];
    int cfg = 0;
#pragma unroll
    for (int i = 1; i < 6; i++)
        if ((int)blockIdx.x >= P.base[i]) cfg = i;
    const float* W = P.W[cfg];
    __half* T = P.T[cfg];
    const int K = P.K[cfg], N = P.N[cfg];
    const int local = blockIdx.x - P.base[cfg];
    const int nbx = N / 32;
    const int n0 = (local % nbx) * 32, k0 = (local / nbx) * 32;
    const int tx = threadIdx.x & 31, ty = threadIdx.x >> 5;
#pragma unroll
    for (int i = 0; i < 32; i += 8)
        tile[ty + i][tx] = W[(size_t)(k0 + ty + i) * N + n0 + tx];
    __syncthreads();
#pragma unroll
    for (int i = 0; i < 32; i += 8)
        T[(size_t)(n0 + ty + i) * K + k0 + tx] = __float2half_rn(tile[tx][ty + i]);
}

// ---------------- elementwise fp32 -> fp16 single --------------------------
__global__ __launch_bounds__(256) void tohalf_kernel(
    const float* __restrict__ A, __half* __restrict__ O)
{
    size_t idx = ((size_t)blockIdx.x * 256 + threadIdx.x) * 4;
    float4 v = *(const float4*)&A[idx];
    *(uint2*)&O[idx] = make_uint2(pack_h2(v.x, v.y), pack_h2(v.z, v.w));
}

// ---------------- v transpose: -> vt[bh][d][s] ------------------------------
__global__ __launch_bounds__(256) void vtrans1_kernel(
    const __half* __restrict__ v, __half* __restrict__ T)
{
    __shared__ __half tile[32][40];
    const int s0 = blockIdx.x * 32, d0 = blockIdx.y * 32, bh = blockIdx.z;
    const int b = bh / HH, h = bh % HH;
    const int tx = threadIdx.x & 31, ty = threadIdx.x >> 5;
#pragma unroll
    for (int i = 0; i < 32; i += 8)
        tile[ty + i][tx] = v[(size_t)(b * SS + s0 + ty + i) * EE + h * DD + d0 + tx];
    __syncthreads();
#pragma unroll
    for (int i = 0; i < 32; i += 8)
        T[((size_t)bh * DD + d0 + ty + i) * SS + s0 + tx] = tile[tx][ty + i];
}

// ============ fp16 1-term GEMM (A single, B single) ========================
// EMIT 0: fp16 partials to Cp0/Cp1 (K-split, no bias). EMIT 1: fp16 out+bias.
template<int EMIT, bool RELU>
__global__ __launch_bounds__(256) void gemm1_kernel(
    const __half* __restrict__ A16, const __half* __restrict__ B16,
    const float* __restrict__ bias,
    __half* __restrict__ Cp0, __half* __restrict__ Cp1, __half* __restrict__ Ch,
    int N, int K, int ksize)
{
    extern __shared__ char sm[];
    const int t = threadIdx.x, lane = t & 31, warp = t >> 5;
    const int wm = warp >> 2, wn = warp & 3;
    const int m0 = blockIdx.y * 128, n0 = blockIdx.x * 128;
    const int kbase = blockIdx.z * ksize;
    __half* Cp = blockIdx.z ? Cp1 : Cp0;
    const uint32_t sb = smem_u32(sm);
    const int nch = ksize / 32;

    float acc[4][4][4];
#pragma unroll
    for (int i = 0; i < 4; i++)
#pragma unroll
        for (int j = 0; j < 4; j++)
#pragma unroll
            for (int u = 0; u < 4; u++) acc[i][j][u] = 0.f;

    const int r0i = t >> 2, c16 = t & 3;
    {
#pragma unroll
        for (int i = 0; i < 2; i++) {
            int row = r0i + i * 64;
            uint32_t so = (uint32_t)row * 80 + (uint32_t)c16 * 16;
            cp16(sb + so,         A16 + (size_t)(m0 + row) * K + kbase + c16 * 8);
            cp16(sb + 10240 + so, B16 + (size_t)(n0 + row) * K + kbase + c16 * 8);
        }
        cpcommit();
    }

    const uint32_t aBase = sb + (uint32_t)(wm * 64 + (lane & 15)) * 80
                              + (uint32_t)(lane >> 4) * 16;
    const uint32_t bBase = sb + 10240
                              + (uint32_t)(wn * 32 + (lane >> 4) * 8 + (lane & 7)) * 80
                              + (uint32_t)((lane >> 3) & 1) * 16;

    for (int ch = 0; ch < nch; ch++) {
        cpwait0();
        __syncthreads();
        if (ch + 1 < nch) {
            const int koff = kbase + (ch + 1) * 32;
            const uint32_t bp = (uint32_t)((ch + 1) & 1) * 20480;
#pragma unroll
            for (int i = 0; i < 2; i++) {
                int row = r0i + i * 64;
                uint32_t so = bp + (uint32_t)row * 80 + (uint32_t)c16 * 16;
                cp16(sb + so,         A16 + (size_t)(m0 + row) * K + koff + c16 * 8);
                cp16(sb + 10240 + so, B16 + (size_t)(n0 + row) * K + koff + c16 * 8);
            }
            cpcommit();
        }

        const uint32_t bp = (uint32_t)(ch & 1) * 20480;
#pragma unroll
        for (int kk = 0; kk < 2; kk++) {
            uint32_t ah[4][4], bh[2][4];
#pragma unroll
            for (int i = 0; i < 4; i++)
                ldmx4(ah[i], aBase + bp + (uint32_t)i * 1280 + (uint32_t)kk * 32);
#pragma unroll
            for (int p = 0; p < 2; p++)
                ldmx4(bh[p], bBase + bp + (uint32_t)p * 1280 + (uint32_t)kk * 32);
#pragma unroll
            for (int i = 0; i < 4; i++)
#pragma unroll
                for (int j = 0; j < 4; j++)
                    mma_fp16(acc[i][j], ah[i], &bh[j >> 1][(j & 1) * 2]);
        }
    }

    const int g = lane >> 2, qd = lane & 3;
#pragma unroll
    for (int i = 0; i < 4; i++) {
        int r0 = m0 + wm * 64 + i * 16 + g;
#pragma unroll
        for (int j = 0; j < 4; j++) {
            int c = n0 + wn * 32 + j * 8 + qd * 2;
            float bx = bias ? __ldg(&bias[c]) : 0.f;
            float by = bias ? __ldg(&bias[c + 1]) : 0.f;
            float v0 = acc[i][j][0] + bx, v1 = acc[i][j][1] + by;
            float v2 = acc[i][j][2] + bx, v3 = acc[i][j][3] + by;
            if (RELU) {
                v0 = fmaxf(v0, 0.f); v1 = fmaxf(v1, 0.f);
                v2 = fmaxf(v2, 0.f); v3 = fmaxf(v3, 0.f);
            }
            if (EMIT == 0) {
                *(uint32_t*)&Cp[(size_t)r0 * N + c]       = pack_h2(v0, v1);
                *(uint32_t*)&Cp[(size_t)(r0 + 8) * N + c] = pack_h2(v2, v3);
            } else {
                *(uint32_t*)&Ch[(size_t)r0 * N + c]       = pack_h2(v0, v1);
                *(uint32_t*)&Ch[(size_t)(r0 + 8) * N + c] = pack_h2(v2, v3);
            }
        }
    }
}

// ---------------- fused QKV GEMM (fp16 1-term) ------------------------------
struct QKVParams {
    const __half* w[3];
    const float* bias[3];
    __half* c[3];
};
__global__ __launch_bounds__(256) void qkv1_kernel(
    const __half* __restrict__ A16, QKVParams P)
{
    extern __shared__ char sm[];
    const int t = threadIdx.x, lane = t & 31, warp = t >> 5;
    const int wm = warp >> 2, wn = warp & 3;
    const int m0 = blockIdx.y * 128;
    const int sel = blockIdx.x / 6;
    const int n0  = (blockIdx.x % 6) * 128;
    const __half* B16 = P.w[sel];
    const float* bias = P.bias[sel];
    __half* Ch = P.c[sel];
    const uint32_t sb = smem_u32(sm);
    const int K = EE, N = EE, nch = K / 32;

    float acc[4][4][4];
#pragma unroll
    for (int i = 0; i < 4; i++)
#pragma unroll
        for (int j = 0; j < 4; j++)
#pragma unroll
            for (int u = 0; u < 4; u++) acc[i][j][u] = 0.f;

    const int r0i = t >> 2, c16 = t & 3;
    {
#pragma unroll
        for (int i = 0; i < 2; i++) {
            int row = r0i + i * 64;
            uint32_t so = (uint32_t)row * 80 + (uint32_t)c16 * 16;
            cp16(sb + so,         A16 + (size_t)(m0 + row) * K + c16 * 8);
            cp16(sb + 10240 + so, B16 + (size_t)(n0 + row) * K + c16 * 8);
        }
        cpcommit();
    }

    const uint32_t aBase = sb + (uint32_t)(wm * 64 + (lane & 15)) * 80
                              + (uint32_t)(lane >> 4) * 16;
    const uint32_t bBase = sb + 10240
                              + (uint32_t)(wn * 32 + (lane >> 4) * 8 + (lane & 7)) * 80
                              + (uint32_t)((lane >> 3) & 1) * 16;

    for (int ch = 0; ch < nch; ch++) {
        cpwait0();
        __syncthreads();
        if (ch + 1 < nch) {
            const int koff = (ch + 1) * 32;
            const uint32_t bp = (uint32_t)((ch + 1) & 1) * 20480;
#pragma unroll
            for (int i = 0; i < 2; i++) {
                int row = r0i + i * 64;
                uint32_t so = bp + (uint32_t)row * 80 + (uint32_t)c16 * 16;
                cp16(sb + so,         A16 + (size_t)(m0 + row) * K + koff + c16 * 8);
                cp16(sb + 10240 + so, B16 + (size_t)(n0 + row) * K + koff + c16 * 8);
            }
            cpcommit();
        }

        const uint32_t bp = (uint32_t)(ch & 1) * 20480;
#pragma unroll
        for (int kk = 0; kk < 2; kk++) {
            uint32_t ah[4][4], bh[2][4];
#pragma unroll
            for (int i = 0; i < 4; i++)
                ldmx4(ah[i], aBase + bp + (uint32_t)i * 1280 + (uint32_t)kk * 32);
#pragma unroll
            for (int p = 0; p < 2; p++)
                ldmx4(bh[p], bBase + bp + (uint32_t)p * 1280 + (uint32_t)kk * 32);
#pragma unroll
            for (int i = 0; i < 4; i++)
#pragma unroll
                for (int j = 0; j < 4; j++)
                    mma_fp16(acc[i][j], ah[i], &bh[j >> 1][(j & 1) * 2]);
        }
    }

    const int g = lane >> 2, qd = lane & 3;
#pragma unroll
    for (int i = 0; i < 4; i++) {
        int r0 = m0 + wm * 64 + i * 16 + g;
#pragma unroll
        for (int j = 0; j < 4; j++) {
            int c = n0 + wn * 32 + j * 8 + qd * 2;
            float bx = __ldg(&bias[c]), by = __ldg(&bias[c + 1]);
            *(uint32_t*)&Ch[(size_t)r0 * N + c] =
                pack_h2(acc[i][j][0] + bx, acc[i][j][1] + by);
            *(uint32_t*)&Ch[(size_t)(r0 + 8) * N + c] =
                pack_h2(acc[i][j][2] + bx, acc[i][j][3] + by);
        }
    }
}

// ================= fused attention (scores + softmax + attn + ctx) ==========
#define SQ_OFF 0
#define SK_OFF 18432
#define SV_OFF 36864
#define SP_OFF 87040
#define SR_OFF 191488
#define SI_OFF 193536
#define FA_SMEM 194048

__global__ __launch_bounds__(256) void fused_attn_kernel(
    const __half* __restrict__ q16, const __half* __restrict__ k16,
    const __half* __restrict__ Vt, float* __restrict__ attn,
    __half* __restrict__ ctx16)
{
    extern __shared__ char sm[];
    const uint32_t sb = smem_u32(sm);
    const int t = threadIdx.x, lane = t & 31, warp = t >> 5;
    const int bh = blockIdx.y, b = bh / HH, h = bh % HH;
    const int qt = blockIdx.x;
    const int q0 = qt * 128;
    float* red  = (float*)(sm + SR_OFF);
    float* invs = (float*)(sm + SI_OFF);
    float* attnb = attn + (size_t)bh * SS * SS;

    const int tlo = (qt > 0) ? qt - 1 : 0;
    const int thi = (qt + 2 < NQT) ? qt + 2 : NQT;

    // zero-fill off-band attn columns (streaming stores)
    {
#pragma unroll
        for (int seg = 0; seg < 2; seg++) {
            const int cbeg = seg ? thi * 128 : 0;
            const int cend = seg ? SS : tlo * 128;
            const int w4 = (cend - cbeg) >> 2;
            if (w4 <= 0) continue;
            const int n4 = 128 * w4;
            for (int i = t; i < n4; i += 256) {
                int row = i / w4, cc = i % w4;
                stcs4(&attnb[(size_t)(q0 + row) * SS + cbeg + cc * 4],
                      0.f, 0.f, 0.f, 0.f);
            }
        }
    }

    // load Q tile
#pragma unroll
    for (int i = 0; i < 4; i++) {
        int idx = t + i * 256;
        int row = idx >> 3, c = idx & 7;
        *(uint4*)(sm + SQ_OFF + (uint32_t)row * 144 + (uint32_t)c * 16) =
            *(const uint4*)&q16[(size_t)(b * SS + q0 + row) * EE + h * DD + c * 8];
    }
    // load V tiles: per slot 64 rows x 128 halves
    for (int s = 0; s < 3; s++) {
        const int kt = qt - 1 + s;
        if (kt < 0 || kt >= NQT) continue;
#pragma unroll
        for (int i = 0; i < 4; i++) {
            int idx = t + i * 256;
            int row = idx >> 4, c = idx & 15;
            *(uint4*)(sm + SV_OFF + (uint32_t)row * 784 + (uint32_t)(s * 256 + c * 16)) =
                *(const uint4*)&Vt[((size_t)bh * DD + row) * SS + kt * 128 + c * 8];
        }
    }

    // ---- scores phase ----
    const int wm = warp >> 2, wn = warp & 3;
    const int g = lane >> 2, qd = lane & 3;
    float rs0[4] = {0.f, 0.f, 0.f, 0.f};
    float rs1[4] = {0.f, 0.f, 0.f, 0.f};

    const uint32_t aAddrS = sb + SQ_OFF + (uint32_t)(wm * 64 + (lane & 15)) * 144
                               + (uint32_t)(lane >> 4) * 16;
    const uint32_t bAddrS = sb + SK_OFF
                               + (uint32_t)(wn * 32 + (lane >> 4) * 8 + (lane & 7)) * 144
                               + (uint32_t)((lane >> 3) & 1) * 16;

    for (int s = 0; s < 3; s++) {
        const int kt = qt - 1 + s;
        if (kt < 0 || kt >= NQT) continue;
        const int k0 = kt * 128;
        __syncthreads();
#pragma unroll
        for (int i = 0; i < 4; i++) {
            int idx = t + i * 256;
            int row = idx >> 3, c = idx & 7;
            *(uint4*)(sm + SK_OFF + (uint32_t)row * 144 + (uint32_t)c * 16) =
                *(const uint4*)&k16[(size_t)(b * SS + k0 + row) * EE + h * DD + c * 8];
        }
        __syncthreads();

        float acc[4][4][4];
#pragma unroll
        for (int i = 0; i < 4; i++)
#pragma unroll
            for (int j = 0; j < 4; j++)
#pragma unroll
                for (int u = 0; u < 4; u++) acc[i][j][u] = 0.f;

#pragma unroll
        for (int kk = 0; kk < 4; kk++) {
            uint32_t ah[4][4], bhf[2][4];
#pragma unroll
            for (int i = 0; i < 4; i++)
                ldmx4(ah[i], aAddrS + (uint32_t)i * 2304 + (uint32_t)kk * 32);
#pragma unroll
            for (int p = 0; p < 2; p++)
                ldmx4(bhf[p], bAddrS + (uint32_t)p * 2304 + (uint32_t)kk * 32);
#pragma unroll
            for (int i = 0; i < 4; i++)
#pragma unroll
                for (int j = 0; j < 4; j++)
                    mma_fp16(acc[i][j], ah[i], &bhf[j >> 1][(j & 1) * 2]);
        }

        const uint32_t pb = SP_OFF + (uint32_t)s * 34816;
#pragma unroll
        for (int i = 0; i < 4; i++) {
            int rloc = wm * 64 + i * 16 + g;
            int qi = q0 + rloc;
#pragma unroll
            for (int j = 0; j < 4; j++) {
                int ccl = wn * 32 + j * 8 + qd * 2;
                int kj = k0 + ccl;
                float e0 = __expf(acc[i][j][0] * 0.125f - fabsf((float)(qi - kj)));
                float e1 = __expf(acc[i][j][1] * 0.125f - fabsf((float)(qi - kj - 1)));
                float e2 = __expf(acc[i][j][2] * 0.125f - fabsf((float)(qi + 8 - kj)));
                float e3 = __expf(acc[i][j][3] * 0.125f - fabsf((float)(qi + 8 - kj - 1)));
                rs0[i] += e0 + e1; rs1[i] += e2 + e3;
                *(uint32_t*)(sm + pb + (uint32_t)rloc * 272 + (uint32_t)ccl * 2)
                    = pack_h2(e0, e1);
                *(uint32_t*)(sm + pb + (uint32_t)(rloc + 8) * 272 + (uint32_t)ccl * 2)
                    = pack_h2(e2, e3);
            }
        }
    }

    // rowsum reduce -> inv
#pragma unroll
    for (int i = 0; i < 4; i++) {
        float s0 = rs0[i], s1 = rs1[i];
        s0 += __shfl_xor_sync(0xFFFFFFFF, s0, 1);
        s0 += __shfl_xor_sync(0xFFFFFFFF, s0, 2);
        s1 += __shfl_xor_sync(0xFFFFFFFF, s1, 1);
        s1 += __shfl_xor_sync(0xFFFFFFFF, s1, 2);
        if (qd == 0) {
            int rloc = wm * 64 + i * 16 + g;
            red[rloc * 4 + wn]       = s0;
            red[(rloc + 8) * 4 + wn] = s1;
        }
    }
    __syncthreads();
    if (t < 128)
        invs[t] = 1.0f / (red[t * 4] + red[t * 4 + 1] + red[t * 4 + 2] + red[t * 4 + 3]);
    __syncthreads();

    // attn band write (streaming stores)
    for (int s = 0; s < 3; s++) {
        const int kt = qt - 1 + s;
        if (kt < 0 || kt >= NQT) continue;
        const int k0 = kt * 128;
        const uint32_t pb = SP_OFF + (uint32_t)s * 34816;
#pragma unroll
        for (int i = 0; i < 8; i++) {
            int idx = t + i * 256;
            int row = idx >> 4, c8 = (idx & 15) * 8;
            uint4 pv = *(uint4*)(sm + pb + (uint32_t)row * 272 + (uint32_t)c8 * 2);
            float iv = invs[row];
            const __half2* hp = (const __half2*)&pv;
            float o[8];
#pragma unroll
            for (int u = 0; u < 4; u++) {
                float2 f = __half22float2(hp[u]);
                o[u * 2]     = f.x * iv;
                o[u * 2 + 1] = f.y * iv;
            }
            size_t ao = (size_t)(q0 + row) * SS + k0 + c8;
            stcs4(attnb + ao,     o[0], o[1], o[2], o[3]);
            stcs4(attnb + ao + 4, o[4], o[5], o[6], o[7]);
        }
    }

    // ---- ctx phase ----
    const int wm2 = warp >> 1, wn2 = warp & 1;
    float acc2[2][4][4];
#pragma unroll
    for (int i = 0; i < 2; i++)
#pragma unroll
        for (int j = 0; j < 4; j++)
#pragma unroll
            for (int u = 0; u < 4; u++) acc2[i][j][u] = 0.f;

    const uint32_t aBase2 = sb + SP_OFF + (uint32_t)(wm2 * 32 + (lane & 15)) * 272
                               + (uint32_t)(lane >> 4) * 16;
    const uint32_t bBase2 = sb + SV_OFF
                               + (uint32_t)(wn2 * 32 + (lane >> 4) * 8 + (lane & 7)) * 784
                               + (uint32_t)((lane >> 3) & 1) * 16;

    for (int s = 0; s < 3; s++) {
        const int kt = qt - 1 + s;
        if (kt < 0 || kt >= NQT) continue;
#pragma unroll
        for (int c = 0; c < 4; c++) {
#pragma unroll
            for (int kk = 0; kk < 2; kk++) {
                uint32_t ah[2][4], bhf[2][4];
#pragma unroll
                for (int i = 0; i < 2; i++)
                    ldmx4(ah[i], aBase2 + (uint32_t)s * 34816 + (uint32_t)i * 4352
                                 + (uint32_t)c * 64 + (uint32_t)kk * 32);
#pragma unroll
                for (int p = 0; p < 2; p++)
                    ldmx4(bhf[p], bBase2 + (uint32_t)p * 12544
                                  + (uint32_t)(s * 256 + c * 64) + (uint32_t)kk * 32);
#pragma unroll
                for (int i = 0; i < 2; i++)
#pragma unroll
                    for (int j = 0; j < 4; j++)
                        mma_fp16(acc2[i][j], ah[i], &bhf[j >> 1][(j & 1) * 2]);
            }
        }
    }

#pragma unroll
    for (int i = 0; i < 2; i++) {
        int rloc = wm2 * 32 + i * 16 + g;
        float iv0 = invs[rloc], iv1 = invs[rloc + 8];
#pragma unroll
        for (int j = 0; j < 4; j++) {
            int c = wn2 * 32 + j * 8 + qd * 2;
            size_t o0 = ((size_t)(b * SS + q0 + rloc) * HH + h) * DD + c;
            size_t o1 = ((size_t)(b * SS + q0 + rloc + 8) * HH + h) * DD + c;
            *(uint32_t*)&ctx16[o0] = pack_h2(acc2[i][j][0] * iv0, acc2[i][j][1] * iv0);
            *(uint32_t*)&ctx16[o1] = pack_h2(acc2[i][j][2] * iv1, acc2[i][j][3] * iv1);
        }
    }
}

// ------ out = LayerNorm(A16 + P0 + P1 + bias) * g + be ---------------------
// OUT32: write fp32 out; else write fp16 O16.
template<bool OUT32>
__global__ __launch_bounds__(256) void add_ln_kernel(
    const __half* __restrict__ A16, const __half* __restrict__ P0,
    const __half* __restrict__ P1, const float* __restrict__ bias,
    const float* __restrict__ g, const float* __restrict__ be,
    float* __restrict__ out, __half* __restrict__ O16)
{
    __shared__ float rs[256];
    __shared__ float rs2[256];
    const size_t off = (size_t)blockIdx.x * EE;
    const int t = threadIdx.x;
    float x[3];
    float s = 0.f, s2 = 0.f;
#pragma unroll
    for (int i = 0; i < 3; i++) {
        int c = t + i * 256;
        x[i] = __half2float(A16[off + c])
             + (__half2float(P0[off + c]) + __half2float(P1[off + c]) + bias[c]);
        s += x[i]; s2 += x[i] * x[i];
    }
    rs[t] = s; rs2[t] = s2; __syncthreads();
    for (int st = 128; st > 0; st >>= 1) {
        if (t < st) { rs[t] += rs[t + st]; rs2[t] += rs2[t + st]; }
        __syncthreads();
    }
    const float mu  = rs[0] * (1.0f / EE);
    const float var = rs2[0] * (1.0f / EE) - mu * mu;
    const float r   = rsqrtf(var + 1e-5f);
#pragma unroll
    for (int i = 0; i < 3; i++) {
        int c = t + i * 256;
        float y = (x[i] - mu) * r * g[c] + be[c];
        if (OUT32) out[off + c] = y;
        else       O16[off + c] = __float2half_rn(y);
    }
}

// ---------------- launch --------------------------------------------------
extern "C" void kernel_launch(void* const* d_in, const int* in_sizes, int n_in,
                              void* d_out, int out_size)
{
    const float* x  = (const float*)d_in[0];
    const float* Wq = (const float*)d_in[1];
    const float* bq = (const float*)d_in[2];
    const float* Wk = (const float*)d_in[3];
    const float* bk = (const float*)d_in[4];
    const float* Wv = (const float*)d_in[5];
    const float* bv = (const float*)d_in[6];
    const float* Wo = (const float*)d_in[7];
    const float* bo = (const float*)d_in[8];
    const float* W1 = (const float*)d_in[9];
    const float* b1 = (const float*)d_in[10];
    const float* W2 = (const float*)d_in[11];
    const float* b2 = (const float*)d_in[12];
    const float* g1 = (const float*)d_in[13];
    const float* be1= (const float*)d_in[14];
    const float* g2 = (const float*)d_in[15];
    const float* be2= (const float*)d_in[16];

    float* out  = (float*)d_out;
    float* attn = out + (size_t)BB * SS * EE;

    __half *p0h, *p1h;
    cudaGetSymbolAddress((void**)&p0h, g_p0h);
    cudaGetSymbolAddress((void**)&p1h, g_p1h);
    __half *wqt,*wkt,*wvt,*wot,*w1t,*w2t;
    __half *x16,*q16,*k16,*v16,*hf16,*ctx16,*f116,*vt16;
    cudaGetSymbolAddress((void**)&wqt, g_wqt);
    cudaGetSymbolAddress((void**)&wkt, g_wkt);
    cudaGetSymbolAddress((void**)&wvt, g_wvt);
    cudaGetSymbolAddress((void**)&wot, g_wot);
    cudaGetSymbolAddress((void**)&w1t, g_w1t);
    cudaGetSymbolAddress((void**)&w2t, g_w2t);
    cudaGetSymbolAddress((void**)&x16, g_x16);
    cudaGetSymbolAddress((void**)&q16, g_q16);
    cudaGetSymbolAddress((void**)&k16, g_k16);
    cudaGetSymbolAddress((void**)&v16, g_v16);
    cudaGetSymbolAddress((void**)&hf16, g_hf16);
    cudaGetSymbolAddress((void**)&ctx16, g_ctx16);
    cudaGetSymbolAddress((void**)&f116, g_f116);
    cudaGetSymbolAddress((void**)&vt16, g_vt16);

    const int GSM = 40960;
    cudaFuncSetAttribute(gemm1_kernel<0,false>, cudaFuncAttributeMaxDynamicSharedMemorySize, GSM);
    cudaFuncSetAttribute(gemm1_kernel<1,true>,  cudaFuncAttributeMaxDynamicSharedMemorySize, GSM);
    cudaFuncSetAttribute(qkv1_kernel,           cudaFuncAttributeMaxDynamicSharedMemorySize, GSM);
    cudaFuncSetAttribute(fused_attn_kernel,     cudaFuncAttributeMaxDynamicSharedMemorySize, FA_SMEM);

    // prep
    tohalf_kernel<<<MM*EE/1024, 256>>>(x, x16);
    WTParams wp;
    wp.W[0] = Wq; wp.W[1] = Wk; wp.W[2] = Wv; wp.W[3] = Wo; wp.W[4] = W1; wp.W[5] = W2;
    wp.T[0] = wqt; wp.T[1] = wkt; wp.T[2] = wvt; wp.T[3] = wot; wp.T[4] = w1t; wp.T[5] = w2t;
    wp.K[0] = EE; wp.K[1] = EE; wp.K[2] = EE; wp.K[3] = EE; wp.K[4] = EE; wp.K[5] = FFF;
    wp.N[0] = EE; wp.N[1] = EE; wp.N[2] = EE; wp.N[3] = EE; wp.N[4] = FFF; wp.N[5] = EE;
    wp.base[0] = 0;    wp.base[1] = 576;  wp.base[2] = 1152;
    wp.base[3] = 1728; wp.base[4] = 2304; wp.base[5] = 4608;
    wtrans_all_kernel<<<6912, 256>>>(wp);

    // fused QKV
    QKVParams qp;
    qp.w[0] = wqt; qp.w[1] = wkt; qp.w[2] = wvt;
    qp.bias[0] = bq; qp.bias[1] = bk; qp.bias[2] = bv;
    qp.c[0] = q16; qp.c[1] = k16; qp.c[2] = v16;
    qkv1_kernel<<<dim3(18, MM/128), 256, GSM>>>(x16, qp);
    vtrans1_kernel<<<dim3(SS/32, DD/32, BH), 256>>>(v16, vt16);

    // fused attention
    fused_attn_kernel<<<dim3(NQT, BH), 256, FA_SMEM>>>(q16, k16, vt16, attn, ctx16);

    // output projection: K-split x2 (fp16 partials); merge+bias in add_ln
    gemm1_kernel<0,false><<<dim3(EE/128, MM/128, 2), 256, GSM>>>(
        ctx16, wot, nullptr, p0h, p1h, nullptr, EE, EE, EE/2);
    add_ln_kernel<false><<<MM, 256>>>(x16, p0h, p1h, bo, g1, be1, nullptr, hf16);

    // FFN
    gemm1_kernel<1,true><<<dim3(FFF/128, MM/128, 1), 256, GSM>>>(
        hf16, w1t, b1, nullptr, nullptr, f116, FFF, EE, EE);
    gemm1_kernel<0,false><<<dim3(EE/128, MM/128, 2), 256, GSM>>>(
        f116, w2t, nullptr, p0h, p1h, nullptr, EE, FFF, FFF/2);
    add_ln_kernel<true><<<MM, 256>>>(hf16, p0h, p1h, b2, g2, be2, out, nullptr);
}

// round 17
// speedup vs baseline: 7.9016x; 1.0650x over previous
#include <cuda_runtime.h>
#include <cuda_fp16.h>
#include <cstdint>

#define BB 2
#define SS 2048
#define EE 768
#define HH 12
#define DD 64
#define FFF 3072
#define MM (BB*SS)          // 4096
#define BH (BB*HH)          // 24
#define NQT (SS/128)        // 16

// ---------------- scratch (device globals; no allocation) ----------------
__device__ __half g_p0h[MM*EE];
__device__ __half g_p1h[MM*EE];
__device__ __half g_wqt[EE*EE], g_wkt[EE*EE], g_wvt[EE*EE], g_wot[EE*EE];
__device__ __half g_w1t[EE*FFF], g_w2t[EE*FFF];
__device__ __half g_x16[MM*EE];
__device__ __half g_q16[MM*EE], g_k16[MM*EE], g_v16[MM*EE];
__device__ __half g_hf16 [MM*EE];
__device__ __half g_ctx16[MM*EE];
__device__ __half g_f116 [(size_t)MM*FFF];
__device__ __half g_vt16[(size_t)BH*DD*SS];

// ---------------- helpers ---------------------------------------------------
__device__ __forceinline__ uint32_t smem_u32(const void* p) {
    uint32_t a;
    asm("{ .reg .u64 t; cvta.to.shared.u64 t, %1; cvt.u32.u64 %0, t; }"
        : "=r"(a) : "l"(p));
    return a;
}
__device__ __forceinline__ void ldmx4(uint32_t* r, uint32_t addr) {
    asm volatile("ldmatrix.sync.aligned.m8n8.x4.shared.b16 {%0,%1,%2,%3}, [%4];"
        : "=r"(r[0]), "=r"(r[1]), "=r"(r[2]), "=r"(r[3]) : "r"(addr));
}
__device__ __forceinline__ void mma_fp16(float* d, const uint32_t* a, const uint32_t* b) {
    asm volatile("mma.sync.aligned.m16n8k16.row.col.f32.f16.f16.f32 "
        "{%0,%1,%2,%3}, {%4,%5,%6,%7}, {%8,%9}, {%0,%1,%2,%3};"
        : "+f"(d[0]), "+f"(d[1]), "+f"(d[2]), "+f"(d[3])
        : "r"(a[0]), "r"(a[1]), "r"(a[2]), "r"(a[3]), "r"(b[0]), "r"(b[1]));
}
__device__ __forceinline__ uint32_t pack_h2(float a, float b) {
    __half2 h = __floats2half2_rn(a, b);
    return *(uint32_t*)&h;
}
__device__ __forceinline__ void stcs4(float* p, float a, float b, float c, float d) {
    asm volatile("st.global.cs.v4.f32 [%0], {%1,%2,%3,%4};"
        :: "l"(p), "f"(a), "f"(b), "f"(c), "f"(d) : "memory");
}
__device__ __forceinline__ void cp16(uint32_t s, const void* g) {
    asm volatile("cp.async.cg.shared.global [%0], [%1], 16;" :: "r"(s), "l"(g));
}
__device__ __forceinline__ void cpcommit() {
    asm volatile("cp.async.commit_group;" ::: "memory");
}
__device__ __forceinline__ void cpwait0() {
    asm volatile("cp.async.wait_group 0;" ::: "memory");
}

// ---------------- batched weight transpose (fp16) --------------------------
struct WTParams {
    const float* W[6];
    __half* T[6];
    int K[6], N[6], base[6];
};
__global__ __launch_bounds__(256) void wtrans_all_kernel(WTParams P)
{
    __shared__ float tile[32][33];
    int cfg = 0;
#pragma unroll
    for (int i = 1; i < 6; i++)
        if ((int)blockIdx.x >= P.base[i]) cfg = i;
    const float* W = P.W[cfg];
    __half* T = P.T[cfg];
    const int K = P.K[cfg], N = P.N[cfg];
    const int local = blockIdx.x - P.base[cfg];
    const int nbx = N / 32;
    const int n0 = (local % nbx) * 32, k0 = (local / nbx) * 32;
    const int tx = threadIdx.x & 31, ty = threadIdx.x >> 5;
#pragma unroll
    for (int i = 0; i < 32; i += 8)
        tile[ty + i][tx] = W[(size_t)(k0 + ty + i) * N + n0 + tx];
    __syncthreads();
#pragma unroll
    for (int i = 0; i < 32; i += 8)
        T[(size_t)(n0 + ty + i) * K + k0 + tx] = __float2half_rn(tile[tx][ty + i]);
}

// ---------------- elementwise fp32 -> fp16 single --------------------------
__global__ __launch_bounds__(256) void tohalf_kernel(
    const float* __restrict__ A, __half* __restrict__ O)
{
    size_t idx = ((size_t)blockIdx.x * 256 + threadIdx.x) * 4;
    float4 v = *(const float4*)&A[idx];
    *(uint2*)&O[idx] = make_uint2(pack_h2(v.x, v.y), pack_h2(v.z, v.w));
}

// ---------------- v transpose: -> vt[bh][d][s] ------------------------------
__global__ __launch_bounds__(256) void vtrans1_kernel(
    const __half* __restrict__ v, __half* __restrict__ T)
{
    __shared__ __half tile[32][40];
    const int s0 = blockIdx.x * 32, d0 = blockIdx.y * 32, bh = blockIdx.z;
    const int b = bh / HH, h = bh % HH;
    const int tx = threadIdx.x & 31, ty = threadIdx.x >> 5;
#pragma unroll
    for (int i = 0; i < 32; i += 8)
        tile[ty + i][tx] = v[(size_t)(b * SS + s0 + ty + i) * EE + h * DD + d0 + tx];
    __syncthreads();
#pragma unroll
    for (int i = 0; i < 32; i += 8)
        T[((size_t)bh * DD + d0 + ty + i) * SS + s0 + tx] = tile[tx][ty + i];
}

// ============ fp16 1-term GEMM, BK=64 stages (A single, B single) ==========
// smem per buffer 36864: A@0 (128x144) B@18432; x2 = 73728.
// EMIT 0: fp16 partials Cp0/Cp1 (K-split, no bias). EMIT 1: fp16 out+bias.
template<int EMIT, bool RELU>
__global__ __launch_bounds__(256) void gemm1_kernel(
    const __half* __restrict__ A16, const __half* __restrict__ B16,
    const float* __restrict__ bias,
    __half* __restrict__ Cp0, __half* __restrict__ Cp1, __half* __restrict__ Ch,
    int N, int K, int ksize)
{
    extern __shared__ char sm[];
    const int t = threadIdx.x, lane = t & 31, warp = t >> 5;
    const int wm = warp >> 2, wn = warp & 3;
    const int m0 = blockIdx.y * 128, n0 = blockIdx.x * 128;
    const int kbase = blockIdx.z * ksize;
    __half* Cp = blockIdx.z ? Cp1 : Cp0;
    const uint32_t sb = smem_u32(sm);
    const int nch = ksize / 64;

    float acc[4][4][4];
#pragma unroll
    for (int i = 0; i < 4; i++)
#pragma unroll
        for (int j = 0; j < 4; j++)
#pragma unroll
            for (int u = 0; u < 4; u++) acc[i][j][u] = 0.f;

    const int r8 = t >> 3, c8 = t & 7;   // 128 rows x 8 col-groups per matrix per pass
    {
#pragma unroll
        for (int i = 0; i < 4; i++) {
            int idx = t + i * 256;
            int row = idx >> 3, c = idx & 7;
            uint32_t so = (uint32_t)row * 144 + (uint32_t)c * 16;
            cp16(sb + so,         A16 + (size_t)(m0 + row) * K + kbase + c * 8);
            cp16(sb + 18432 + so, B16 + (size_t)(n0 + row) * K + kbase + c * 8);
        }
        cpcommit();
    }

    const uint32_t aBase = sb + (uint32_t)(wm * 64 + (lane & 15)) * 144
                              + (uint32_t)(lane >> 4) * 16;
    const uint32_t bBase = sb + 18432
                              + (uint32_t)(wn * 32 + (lane >> 4) * 8 + (lane & 7)) * 144
                              + (uint32_t)((lane >> 3) & 1) * 16;

    for (int ch = 0; ch < nch; ch++) {
        cpwait0();
        __syncthreads();
        if (ch + 1 < nch) {
            const int koff = kbase + (ch + 1) * 64;
            const uint32_t bp = (uint32_t)((ch + 1) & 1) * 73728u / 2u;
#pragma unroll
            for (int i = 0; i < 4; i++) {
                int idx = t + i * 256;
                int row = idx >> 3, c = idx & 7;
                uint32_t so = bp + (uint32_t)row * 144 + (uint32_t)c * 16;
                cp16(sb + so,         A16 + (size_t)(m0 + row) * K + koff + c * 8);
                cp16(sb + 18432 + so, B16 + (size_t)(n0 + row) * K + koff + c * 8);
            }
            cpcommit();
        }

        const uint32_t bp = (uint32_t)(ch & 1) * 36864;
#pragma unroll
        for (int kk = 0; kk < 4; kk++) {
            uint32_t ah[4][4], bh[2][4];
#pragma unroll
            for (int i = 0; i < 4; i++)
                ldmx4(ah[i], aBase + bp + (uint32_t)i * 2304 + (uint32_t)kk * 32);
#pragma unroll
            for (int p = 0; p < 2; p++)
                ldmx4(bh[p], bBase + bp + (uint32_t)p * 2304 + (uint32_t)kk * 32);
#pragma unroll
            for (int i = 0; i < 4; i++)
#pragma unroll
                for (int j = 0; j < 4; j++)
                    mma_fp16(acc[i][j], ah[i], &bh[j >> 1][(j & 1) * 2]);
        }
    }
    (void)r8; (void)c8;

    const int g = lane >> 2, qd = lane & 3;
#pragma unroll
    for (int i = 0; i < 4; i++) {
        int r0 = m0 + wm * 64 + i * 16 + g;
#pragma unroll
        for (int j = 0; j < 4; j++) {
            int c = n0 + wn * 32 + j * 8 + qd * 2;
            float bx = bias ? __ldg(&bias[c]) : 0.f;
            float by = bias ? __ldg(&bias[c + 1]) : 0.f;
            float v0 = acc[i][j][0] + bx, v1 = acc[i][j][1] + by;
            float v2 = acc[i][j][2] + bx, v3 = acc[i][j][3] + by;
            if (RELU) {
                v0 = fmaxf(v0, 0.f); v1 = fmaxf(v1, 0.f);
                v2 = fmaxf(v2, 0.f); v3 = fmaxf(v3, 0.f);
            }
            if (EMIT == 0) {
                *(uint32_t*)&Cp[(size_t)r0 * N + c]       = pack_h2(v0, v1);
                *(uint32_t*)&Cp[(size_t)(r0 + 8) * N + c] = pack_h2(v2, v3);
            } else {
                *(uint32_t*)&Ch[(size_t)r0 * N + c]       = pack_h2(v0, v1);
                *(uint32_t*)&Ch[(size_t)(r0 + 8) * N + c] = pack_h2(v2, v3);
            }
        }
    }
}

// ---------------- fused QKV GEMM (fp16 1-term, BK=64) -----------------------
struct QKVParams {
    const __half* w[3];
    const float* bias[3];
    __half* c[3];
};
__global__ __launch_bounds__(256) void qkv1_kernel(
    const __half* __restrict__ A16, QKVParams P)
{
    extern __shared__ char sm[];
    const int t = threadIdx.x, lane = t & 31, warp = t >> 5;
    const int wm = warp >> 2, wn = warp & 3;
    const int m0 = blockIdx.y * 128;
    const int sel = blockIdx.x / 6;
    const int n0  = (blockIdx.x % 6) * 128;
    const __half* B16 = P.w[sel];
    const float* bias = P.bias[sel];
    __half* Ch = P.c[sel];
    const uint32_t sb = smem_u32(sm);
    const int K = EE, N = EE, nch = K / 64;

    float acc[4][4][4];
#pragma unroll
    for (int i = 0; i < 4; i++)
#pragma unroll
        for (int j = 0; j < 4; j++)
#pragma unroll
            for (int u = 0; u < 4; u++) acc[i][j][u] = 0.f;

    {
#pragma unroll
        for (int i = 0; i < 4; i++) {
            int idx = t + i * 256;
            int row = idx >> 3, c = idx & 7;
            uint32_t so = (uint32_t)row * 144 + (uint32_t)c * 16;
            cp16(sb + so,         A16 + (size_t)(m0 + row) * K + c * 8);
            cp16(sb + 18432 + so, B16 + (size_t)(n0 + row) * K + c * 8);
        }
        cpcommit();
    }

    const uint32_t aBase = sb + (uint32_t)(wm * 64 + (lane & 15)) * 144
                              + (uint32_t)(lane >> 4) * 16;
    const uint32_t bBase = sb + 18432
                              + (uint32_t)(wn * 32 + (lane >> 4) * 8 + (lane & 7)) * 144
                              + (uint32_t)((lane >> 3) & 1) * 16;

    for (int ch = 0; ch < nch; ch++) {
        cpwait0();
        __syncthreads();
        if (ch + 1 < nch) {
            const int koff = (ch + 1) * 64;
            const uint32_t bp = (uint32_t)((ch + 1) & 1) * 36864;
#pragma unroll
            for (int i = 0; i < 4; i++) {
                int idx = t + i * 256;
                int row = idx >> 3, c = idx & 7;
                uint32_t so = bp + (uint32_t)row * 144 + (uint32_t)c * 16;
                cp16(sb + so,         A16 + (size_t)(m0 + row) * K + koff + c * 8);
                cp16(sb + 18432 + so, B16 + (size_t)(n0 + row) * K + koff + c * 8);
            }
            cpcommit();
        }

        const uint32_t bp = (uint32_t)(ch & 1) * 36864;
#pragma unroll
        for (int kk = 0; kk < 4; kk++) {
            uint32_t ah[4][4], bh[2][4];
#pragma unroll
            for (int i = 0; i < 4; i++)
                ldmx4(ah[i], aBase + bp + (uint32_t)i * 2304 + (uint32_t)kk * 32);
#pragma unroll
            for (int p = 0; p < 2; p++)
                ldmx4(bh[p], bBase + bp + (uint32_t)p * 2304 + (uint32_t)kk * 32);
#pragma unroll
            for (int i = 0; i < 4; i++)
#pragma unroll
                for (int j = 0; j < 4; j++)
                    mma_fp16(acc[i][j], ah[i], &bh[j >> 1][(j & 1) * 2]);
        }
    }

    const int g = lane >> 2, qd = lane & 3;
#pragma unroll
    for (int i = 0; i < 4; i++) {
        int r0 = m0 + wm * 64 + i * 16 + g;
#pragma unroll
        for (int j = 0; j < 4; j++) {
            int c = n0 + wn * 32 + j * 8 + qd * 2;
            float bx = __ldg(&bias[c]), by = __ldg(&bias[c + 1]);
            *(uint32_t*)&Ch[(size_t)r0 * N + c] =
                pack_h2(acc[i][j][0] + bx, acc[i][j][1] + by);
            *(uint32_t*)&Ch[(size_t)(r0 + 8) * N + c] =
                pack_h2(acc[i][j][2] + bx, acc[i][j][3] + by);
        }
    }
}

// ================= fused attention (scores + softmax + attn + ctx) ==========
#define SQ_OFF 0
#define SK_OFF 18432
#define SV_OFF 36864
#define SP_OFF 87040
#define SR_OFF 191488
#define SI_OFF 193536
#define FA_SMEM 194048

__global__ __launch_bounds__(256) void fused_attn_kernel(
    const __half* __restrict__ q16, const __half* __restrict__ k16,
    const __half* __restrict__ Vt, float* __restrict__ attn,
    __half* __restrict__ ctx16)
{
    extern __shared__ char sm[];
    const uint32_t sb = smem_u32(sm);
    const int t = threadIdx.x, lane = t & 31, warp = t >> 5;
    const int bh = blockIdx.y, b = bh / HH, h = bh % HH;
    const int qt = blockIdx.x;
    const int q0 = qt * 128;
    float* red  = (float*)(sm + SR_OFF);
    float* invs = (float*)(sm + SI_OFF);
    float* attnb = attn + (size_t)bh * SS * SS;

    const int tlo = (qt > 0) ? qt - 1 : 0;
    const int thi = (qt + 2 < NQT) ? qt + 2 : NQT;

    // zero-fill off-band attn columns (streaming stores)
    {
#pragma unroll
        for (int seg = 0; seg < 2; seg++) {
            const int cbeg = seg ? thi * 128 : 0;
            const int cend = seg ? SS : tlo * 128;
            const int w4 = (cend - cbeg) >> 2;
            if (w4 <= 0) continue;
            const int n4 = 128 * w4;
            for (int i = t; i < n4; i += 256) {
                int row = i / w4, cc = i % w4;
                stcs4(&attnb[(size_t)(q0 + row) * SS + cbeg + cc * 4],
                      0.f, 0.f, 0.f, 0.f);
            }
        }
    }

    // load Q tile
#pragma unroll
    for (int i = 0; i < 4; i++) {
        int idx = t + i * 256;
        int row = idx >> 3, c = idx & 7;
        *(uint4*)(sm + SQ_OFF + (uint32_t)row * 144 + (uint32_t)c * 16) =
            *(const uint4*)&q16[(size_t)(b * SS + q0 + row) * EE + h * DD + c * 8];
    }
    // load V tiles
    for (int s = 0; s < 3; s++) {
        const int kt = qt - 1 + s;
        if (kt < 0 || kt >= NQT) continue;
#pragma unroll
        for (int i = 0; i < 4; i++) {
            int idx = t + i * 256;
            int row = idx >> 4, c = idx & 15;
            *(uint4*)(sm + SV_OFF + (uint32_t)row * 784 + (uint32_t)(s * 256 + c * 16)) =
                *(const uint4*)&Vt[((size_t)bh * DD + row) * SS + kt * 128 + c * 8];
        }
    }

    // ---- scores phase ----
    const int wm = warp >> 2, wn = warp & 3;
    const int g = lane >> 2, qd = lane & 3;
    float rs0[4] = {0.f, 0.f, 0.f, 0.f};
    float rs1[4] = {0.f, 0.f, 0.f, 0.f};

    const uint32_t aAddrS = sb + SQ_OFF + (uint32_t)(wm * 64 + (lane & 15)) * 144
                               + (uint32_t)(lane >> 4) * 16;
    const uint32_t bAddrS = sb + SK_OFF
                               + (uint32_t)(wn * 32 + (lane >> 4) * 8 + (lane & 7)) * 144
                               + (uint32_t)((lane >> 3) & 1) * 16;

    for (int s = 0; s < 3; s++) {
        const int kt = qt - 1 + s;
        if (kt < 0 || kt >= NQT) continue;
        const int k0 = kt * 128;
        __syncthreads();
#pragma unroll
        for (int i = 0; i < 4; i++) {
            int idx = t + i * 256;
            int row = idx >> 3, c = idx & 7;
            *(uint4*)(sm + SK_OFF + (uint32_t)row * 144 + (uint32_t)c * 16) =
                *(const uint4*)&k16[(size_t)(b * SS + k0 + row) * EE + h * DD + c * 8];
        }
        __syncthreads();

        float acc[4][4][4];
#pragma unroll
        for (int i = 0; i < 4; i++)
#pragma unroll
            for (int j = 0; j < 4; j++)
#pragma unroll
                for (int u = 0; u < 4; u++) acc[i][j][u] = 0.f;

#pragma unroll
        for (int kk = 0; kk < 4; kk++) {
            uint32_t ah[4][4], bhf[2][4];
#pragma unroll
            for (int i = 0; i < 4; i++)
                ldmx4(ah[i], aAddrS + (uint32_t)i * 2304 + (uint32_t)kk * 32);
#pragma unroll
            for (int p = 0; p < 2; p++)
                ldmx4(bhf[p], bAddrS + (uint32_t)p * 2304 + (uint32_t)kk * 32);
#pragma unroll
            for (int i = 0; i < 4; i++)
#pragma unroll
                for (int j = 0; j < 4; j++)
                    mma_fp16(acc[i][j], ah[i], &bhf[j >> 1][(j & 1) * 2]);
        }

        const uint32_t pb = SP_OFF + (uint32_t)s * 34816;
#pragma unroll
        for (int i = 0; i < 4; i++) {
            int rloc = wm * 64 + i * 16 + g;
            int qi = q0 + rloc;
#pragma unroll
            for (int j = 0; j < 4; j++) {
                int ccl = wn * 32 + j * 8 + qd * 2;
                int kj = k0 + ccl;
                float e0 = __expf(acc[i][j][0] * 0.125f - fabsf((float)(qi - kj)));
                float e1 = __expf(acc[i][j][1] * 0.125f - fabsf((float)(qi - kj - 1)));
                float e2 = __expf(acc[i][j][2] * 0.125f - fabsf((float)(qi + 8 - kj)));
                float e3 = __expf(acc[i][j][3] * 0.125f - fabsf((float)(qi + 8 - kj - 1)));
                rs0[i] += e0 + e1; rs1[i] += e2 + e3;
                *(uint32_t*)(sm + pb + (uint32_t)rloc * 272 + (uint32_t)ccl * 2)
                    = pack_h2(e0, e1);
                *(uint32_t*)(sm + pb + (uint32_t)(rloc + 8) * 272 + (uint32_t)ccl * 2)
                    = pack_h2(e2, e3);
            }
        }
    }

    // rowsum reduce -> inv
#pragma unroll
    for (int i = 0; i < 4; i++) {
        float s0 = rs0[i], s1 = rs1[i];
        s0 += __shfl_xor_sync(0xFFFFFFFF, s0, 1);
        s0 += __shfl_xor_sync(0xFFFFFFFF, s0, 2);
        s1 += __shfl_xor_sync(0xFFFFFFFF, s1, 1);
        s1 += __shfl_xor_sync(0xFFFFFFFF, s1, 2);
        if (qd == 0) {
            int rloc = wm * 64 + i * 16 + g;
            red[rloc * 4 + wn]       = s0;
            red[(rloc + 8) * 4 + wn] = s1;
        }
    }
    __syncthreads();
    if (t < 128)
        invs[t] = 1.0f / (red[t * 4] + red[t * 4 + 1] + red[t * 4 + 2] + red[t * 4 + 3]);
    __syncthreads();

    // attn band write (streaming stores)
    for (int s = 0; s < 3; s++) {
        const int kt = qt - 1 + s;
        if (kt < 0 || kt >= NQT) continue;
        const int k0 = kt * 128;
        const uint32_t pb = SP_OFF + (uint32_t)s * 34816;
#pragma unroll
        for (int i = 0; i < 8; i++) {
            int idx = t + i * 256;
            int row = idx >> 4, c8 = (idx & 15) * 8;
            uint4 pv = *(uint4*)(sm + pb + (uint32_t)row * 272 + (uint32_t)c8 * 2);
            float iv = invs[row];
            const __half2* hp = (const __half2*)&pv;
            float o[8];
#pragma unroll
            for (int u = 0; u < 4; u++) {
                float2 f = __half22float2(hp[u]);
                o[u * 2]     = f.x * iv;
                o[u * 2 + 1] = f.y * iv;
            }
            size_t ao = (size_t)(q0 + row) * SS + k0 + c8;
            stcs4(attnb + ao,     o[0], o[1], o[2], o[3]);
            stcs4(attnb + ao + 4, o[4], o[5], o[6], o[7]);
        }
    }

    // ---- ctx phase ----
    const int wm2 = warp >> 1, wn2 = warp & 1;
    float acc2[2][4][4];
#pragma unroll
    for (int i = 0; i < 2; i++)
#pragma unroll
        for (int j = 0; j < 4; j++)
#pragma unroll
            for (int u = 0; u < 4; u++) acc2[i][j][u] = 0.f;

    const uint32_t aBase2 = sb + SP_OFF + (uint32_t)(wm2 * 32 + (lane & 15)) * 272
                               + (uint32_t)(lane >> 4) * 16;
    const uint32_t bBase2 = sb + SV_OFF
                               + (uint32_t)(wn2 * 32 + (lane >> 4) * 8 + (lane & 7)) * 784
                               + (uint32_t)((lane >> 3) & 1) * 16;

    for (int s = 0; s < 3; s++) {
        const int kt = qt - 1 + s;
        if (kt < 0 || kt >= NQT) continue;
#pragma unroll
        for (int c = 0; c < 4; c++) {
#pragma unroll
            for (int kk = 0; kk < 2; kk++) {
                uint32_t ah[2][4], bhf[2][4];
#pragma unroll
                for (int i = 0; i < 2; i++)
                    ldmx4(ah[i], aBase2 + (uint32_t)s * 34816 + (uint32_t)i * 4352
                                 + (uint32_t)c * 64 + (uint32_t)kk * 32);
#pragma unroll
                for (int p = 0; p < 2; p++)
                    ldmx4(bhf[p], bBase2 + (uint32_t)p * 12544
                                  + (uint32_t)(s * 256 + c * 64) + (uint32_t)kk * 32);
#pragma unroll
                for (int i = 0; i < 2; i++)
#pragma unroll
                    for (int j = 0; j < 4; j++)
                        mma_fp16(acc2[i][j], ah[i], &bhf[j >> 1][(j & 1) * 2]);
            }
        }
    }

#pragma unroll
    for (int i = 0; i < 2; i++) {
        int rloc = wm2 * 32 + i * 16 + g;
        float iv0 = invs[rloc], iv1 = invs[rloc + 8];
#pragma unroll
        for (int j = 0; j < 4; j++) {
            int c = wn2 * 32 + j * 8 + qd * 2;
            size_t o0 = ((size_t)(b * SS + q0 + rloc) * HH + h) * DD + c;
            size_t o1 = ((size_t)(b * SS + q0 + rloc + 8) * HH + h) * DD + c;
            *(uint32_t*)&ctx16[o0] = pack_h2(acc2[i][j][0] * iv0, acc2[i][j][1] * iv0);
            *(uint32_t*)&ctx16[o1] = pack_h2(acc2[i][j][2] * iv1, acc2[i][j][3] * iv1);
        }
    }
}

// ------ out = LayerNorm(A16 + P0 + P1 + bias) * g + be ---------------------
template<bool OUT32>
__global__ __launch_bounds__(256) void add_ln_kernel(
    const __half* __restrict__ A16, const __half* __restrict__ P0,
    const __half* __restrict__ P1, const float* __restrict__ bias,
    const float* __restrict__ g, const float* __restrict__ be,
    float* __restrict__ out, __half* __restrict__ O16)
{
    __shared__ float rs[256];
    __shared__ float rs2[256];
    const size_t off = (size_t)blockIdx.x * EE;
    const int t = threadIdx.x;
    float x[3];
    float s = 0.f, s2 = 0.f;
#pragma unroll
    for (int i = 0; i < 3; i++) {
        int c = t + i * 256;
        x[i] = __half2float(A16[off + c])
             + (__half2float(P0[off + c]) + __half2float(P1[off + c]) + bias[c]);
        s += x[i]; s2 += x[i] * x[i];
    }
    rs[t] = s; rs2[t] = s2; __syncthreads();
    for (int st = 128; st > 0; st >>= 1) {
        if (t < st) { rs[t] += rs[t + st]; rs2[t] += rs2[t + st]; }
        __syncthreads();
    }
    const float mu  = rs[0] * (1.0f / EE);
    const float var = rs2[0] * (1.0f / EE) - mu * mu;
    const float r   = rsqrtf(var + 1e-5f);
#pragma unroll
    for (int i = 0; i < 3; i++) {
        int c = t + i * 256;
        float y = (x[i] - mu) * r * g[c] + be[c];
        if (OUT32) out[off + c] = y;
        else       O16[off + c] = __float2half_rn(y);
    }
}

// ---------------- launch --------------------------------------------------
extern "C" void kernel_launch(void* const* d_in, const int* in_sizes, int n_in,
                              void* d_out, int out_size)
{
    const float* x  = (const float*)d_in[0];
    const float* Wq = (const float*)d_in[1];
    const float* bq = (const float*)d_in[2];
    const float* Wk = (const float*)d_in[3];
    const float* bk = (const float*)d_in[4];
    const float* Wv = (const float*)d_in[5];
    const float* bv = (const float*)d_in[6];
    const float* Wo = (const float*)d_in[7];
    const float* bo = (const float*)d_in[8];
    const float* W1 = (const float*)d_in[9];
    const float* b1 = (const float*)d_in[10];
    const float* W2 = (const float*)d_in[11];
    const float* b2 = (const float*)d_in[12];
    const float* g1 = (const float*)d_in[13];
    const float* be1= (const float*)d_in[14];
    const float* g2 = (const float*)d_in[15];
    const float* be2= (const float*)d_in[16];

    float* out  = (float*)d_out;
    float* attn = out + (size_t)BB * SS * EE;

    __half *p0h, *p1h;
    cudaGetSymbolAddress((void**)&p0h, g_p0h);
    cudaGetSymbolAddress((void**)&p1h, g_p1h);
    __half *wqt,*wkt,*wvt,*wot,*w1t,*w2t;
    __half *x16,*q16,*k16,*v16,*hf16,*ctx16,*f116,*vt16;
    cudaGetSymbolAddress((void**)&wqt, g_wqt);
    cudaGetSymbolAddress((void**)&wkt, g_wkt);
    cudaGetSymbolAddress((void**)&wvt, g_wvt);
    cudaGetSymbolAddress((void**)&wot, g_wot);
    cudaGetSymbolAddress((void**)&w1t, g_w1t);
    cudaGetSymbolAddress((void**)&w2t, g_w2t);
    cudaGetSymbolAddress((void**)&x16, g_x16);
    cudaGetSymbolAddress((void**)&q16, g_q16);
    cudaGetSymbolAddress((void**)&k16, g_k16);
    cudaGetSymbolAddress((void**)&v16, g_v16);
    cudaGetSymbolAddress((void**)&hf16, g_hf16);
    cudaGetSymbolAddress((void**)&ctx16, g_ctx16);
    cudaGetSymbolAddress((void**)&f116, g_f116);
    cudaGetSymbolAddress((void**)&vt16, g_vt16);

    const int GSM = 73728;
    cudaFuncSetAttribute(gemm1_kernel<0,false>, cudaFuncAttributeMaxDynamicSharedMemorySize, GSM);
    cudaFuncSetAttribute(gemm1_kernel<1,true>,  cudaFuncAttributeMaxDynamicSharedMemorySize, GSM);
    cudaFuncSetAttribute(qkv1_kernel,           cudaFuncAttributeMaxDynamicSharedMemorySize, GSM);
    cudaFuncSetAttribute(fused_attn_kernel,     cudaFuncAttributeMaxDynamicSharedMemorySize, FA_SMEM);

    // prep
    tohalf_kernel<<<MM*EE/1024, 256>>>(x, x16);
    WTParams wp;
    wp.W[0] = Wq; wp.W[1] = Wk; wp.W[2] = Wv; wp.W[3] = Wo; wp.W[4] = W1; wp.W[5] = W2;
    wp.T[0] = wqt; wp.T[1] = wkt; wp.T[2] = wvt; wp.T[3] = wot; wp.T[4] = w1t; wp.T[5] = w2t;
    wp.K[0] = EE; wp.K[1] = EE; wp.K[2] = EE; wp.K[3] = EE; wp.K[4] = EE; wp.K[5] = FFF;
    wp.N[0] = EE; wp.N[1] = EE; wp.N[2] = EE; wp.N[3] = EE; wp.N[4] = FFF; wp.N[5] = EE;
    wp.base[0] = 0;    wp.base[1] = 576;  wp.base[2] = 1152;
    wp.base[3] = 1728; wp.base[4] = 2304; wp.base[5] = 4608;
    wtrans_all_kernel<<<6912, 256>>>(wp);

    // fused QKV
    QKVParams qp;
    qp.w[0] = wqt; qp.w[1] = wkt; qp.w[2] = wvt;
    qp.bias[0] = bq; qp.bias[1] = bk; qp.bias[2] = bv;
    qp.c[0] = q16; qp.c[1] = k16; qp.c[2] = v16;
    qkv1_kernel<<<dim3(18, MM/128), 256, GSM>>>(x16, qp);
    vtrans1_kernel<<<dim3(SS/32, DD/32, BH), 256>>>(v16, vt16);

    // fused attention
    fused_attn_kernel<<<dim3(NQT, BH), 256, FA_SMEM>>>(q16, k16, vt16, attn, ctx16);

    // output projection: K-split x2 (fp16 partials); merge+bias in add_ln
    gemm1_kernel<0,false><<<dim3(EE/128, MM/128, 2), 256, GSM>>>(
        ctx16, wot, nullptr, p0h, p1h, nullptr, EE, EE, EE/2);
    add_ln_kernel<false><<<MM, 256>>>(x16, p0h, p1h, bo, g1, be1, nullptr, hf16);

    // FFN
    gemm1_kernel<1,true><<<dim3(FFF/128, MM/128, 1), 256, GSM>>>(
        hf16, w1t, b1, nullptr, nullptr, f116, FFF, EE, EE);
    gemm1_kernel<0,false><<<dim3(EE/128, MM/128, 2), 256, GSM>>>(
        f116, w2t, nullptr, p0h, p1h, nullptr, EE, FFF, FFF/2);
    add_ln_kernel<true><<<MM, 256>>>(hf16, p0h, p1h, b2, g2, be2, out, nullptr);
}